// round 1
// baseline (speedup 1.0000x reference)
#include <cuda_runtime.h>
#include <math.h>

// ---------------- problem dims ----------------
#define Bt   8
#define Sq   1024
#define Dm   1024
#define NH   16
#define HD1  64
#define NE   8
#define NHM  8
#define HDM  128
#define CAP  320
#define NT   (Bt*Sq)            // 8192 tokens
#define NTD  ((size_t)NT*Dm)    // 8388608
#define EROWS (Bt*CAP)          // 2560 rows per expert
#define EINSZ ((size_t)NE*Bt*CAP*Dm) // 20971520

// ---------------- scratch (device globals; allocation-free per rules) -------
static __device__ float g_q[NTD];
static __device__ float g_k[NTD];
static __device__ float g_v[NTD];
static __device__ float g_o[NTD];
static __device__ float g_attn[NTD];
static __device__ float g_x1[NTD];

static __device__ float g_ein[EINSZ];
static __device__ float g_eq[EINSZ];
static __device__ float g_ek[EINSZ];
static __device__ float g_ev[EINSZ];
static __device__ float g_eo[EINSZ];
static __device__ float g_eout[EINSZ];

static __device__ int   g_i0[NT], g_i1[NT];
static __device__ float g_g0[NT], g_g1[NT];
static __device__ int   g_p0[NT], g_p1[NT];
static __device__ int   g_k0[NT], g_k1[NT];

static __device__ float g_Psum[NE];
static __device__ float g_fcnt[NE];
static __device__ float g_zsum;

// ---------------- zero kernels ----------------
__global__ void zero_stats_kernel() {
    int t = threadIdx.x;
    if (t < NE) { g_Psum[t] = 0.f; g_fcnt[t] = 0.f; }
    if (t == 0) g_zsum = 0.f;
}

__global__ void zero_ein_kernel() {
    size_t n4 = EINSZ / 4;
    float4 z = make_float4(0.f, 0.f, 0.f, 0.f);
    float4* p = (float4*)g_ein;
    for (size_t i = blockIdx.x * (size_t)blockDim.x + threadIdx.x; i < n4;
         i += (size_t)gridDim.x * blockDim.x)
        p[i] = z;
}

// ---------------- SGEMM: C = A[M,K] @ W[K,N] (+bias), batched via grid.z ----
__global__ __launch_bounds__(256) void sgemm_kernel(
    const float* __restrict__ A, const float* __restrict__ W,
    const float* __restrict__ bias, float* __restrict__ Co,
    int M, int N, int K, size_t sA, size_t sW, size_t sC)
{
    __shared__ float As[16][132];
    __shared__ float Bs[16][128];

    A  += blockIdx.z * sA;
    W  += blockIdx.z * sW;
    Co += blockIdx.z * sC;

    int t  = threadIdx.x;
    int tx = t & 15, ty = t >> 4;
    int m0 = blockIdx.y * 128, n0 = blockIdx.x * 128;

    int am = t >> 1;
    int ak = (t & 1) * 8;
    int bk = t >> 4;
    int bn = (t & 15) * 8;

    float acc[8][8];
#pragma unroll
    for (int i = 0; i < 8; i++)
#pragma unroll
        for (int j = 0; j < 8; j++) acc[i][j] = 0.f;

    for (int k0 = 0; k0 < K; k0 += 16) {
        float4 a0 = *(const float4*)&A[(size_t)(m0 + am) * K + k0 + ak];
        float4 a1 = *(const float4*)&A[(size_t)(m0 + am) * K + k0 + ak + 4];
        As[ak + 0][am] = a0.x; As[ak + 1][am] = a0.y;
        As[ak + 2][am] = a0.z; As[ak + 3][am] = a0.w;
        As[ak + 4][am] = a1.x; As[ak + 5][am] = a1.y;
        As[ak + 6][am] = a1.z; As[ak + 7][am] = a1.w;
        float4 b0 = *(const float4*)&W[(size_t)(k0 + bk) * N + n0 + bn];
        float4 b1 = *(const float4*)&W[(size_t)(k0 + bk) * N + n0 + bn + 4];
        *(float4*)&Bs[bk][bn]     = b0;
        *(float4*)&Bs[bk][bn + 4] = b1;
        __syncthreads();

#pragma unroll
        for (int kk = 0; kk < 16; kk++) {
            float4 a01 = *(float4*)&As[kk][ty * 8];
            float4 a23 = *(float4*)&As[kk][ty * 8 + 4];
            float4 b01 = *(float4*)&Bs[kk][tx * 8];
            float4 b23 = *(float4*)&Bs[kk][tx * 8 + 4];
            float aa[8] = {a01.x, a01.y, a01.z, a01.w, a23.x, a23.y, a23.z, a23.w};
            float bb[8] = {b01.x, b01.y, b01.z, b01.w, b23.x, b23.y, b23.z, b23.w};
#pragma unroll
            for (int i = 0; i < 8; i++)
#pragma unroll
                for (int j = 0; j < 8; j++) acc[i][j] += aa[i] * bb[j];
        }
        __syncthreads();
    }

    float bv[8];
#pragma unroll
    for (int j = 0; j < 8; j++) bv[j] = bias ? bias[n0 + tx * 8 + j] : 0.f;
#pragma unroll
    for (int i = 0; i < 8; i++) {
        int row = m0 + ty * 8 + i;
        float4 o0, o1;
        o0.x = acc[i][0] + bv[0]; o0.y = acc[i][1] + bv[1];
        o0.z = acc[i][2] + bv[2]; o0.w = acc[i][3] + bv[3];
        o1.x = acc[i][4] + bv[4]; o1.y = acc[i][5] + bv[5];
        o1.z = acc[i][6] + bv[6]; o1.w = acc[i][7] + bv[7];
        *(float4*)&Co[(size_t)row * N + n0 + tx * 8]     = o0;
        *(float4*)&Co[(size_t)row * N + n0 + tx * 8 + 4] = o1;
    }
}

// ---------------- flash attention (online softmax), 64x64 tiles -------------
// layout: [slice_batch, seq, nheads*HD] rows; slice = sb*nheads + h
template <int HD>
__global__ __launch_bounds__(256) void flash_kernel(
    const float* __restrict__ Q, const float* __restrict__ K,
    const float* __restrict__ V, float* __restrict__ O,
    int seq, int nheads, float scale)
{
    constexpr int CPT = HD / 16;
    constexpr int LDQ = HD + 1;
    extern __shared__ float sm[];
    float* Qs  = sm;
    float* Ks  = Qs + 64 * LDQ;
    float* Vs  = Ks + 64 * LDQ;
    float* Ss  = Vs + 64 * LDQ;      // 64 x 66
    float* m_s = Ss + 64 * 66;
    float* l_s = m_s + 64;
    float* a_s = l_s + 64;
    float* red = a_s + 64;           // 256

    int t  = threadIdx.x;
    int tx = t & 15, ty = t >> 4;
    int slice = blockIdx.y;
    int sb = slice / nheads, h = slice % nheads;
    int ld = nheads * HD;            // == 1024
    size_t base = (size_t)sb * seq * ld + (size_t)h * HD;
    int q0 = blockIdx.x * 64;

    for (int idx = t; idx < 64 * HD; idx += 256) {
        int r = idx / HD, c = idx % HD;
        Qs[r * LDQ + c] = Q[base + (size_t)(q0 + r) * ld + c];
    }
    if (t < 64) { m_s[t] = -1e30f; l_s[t] = 0.f; }

    float acc[4][CPT];
#pragma unroll
    for (int i = 0; i < 4; i++)
#pragma unroll
        for (int j = 0; j < CPT; j++) acc[i][j] = 0.f;
    __syncthreads();

    int r  = t >> 2;
    int qq = t & 3;

    for (int kt = 0; kt < seq; kt += 64) {
        for (int idx = t; idx < 64 * HD; idx += 256) {
            int rr = idx / HD, c = idx % HD;
            Ks[rr * LDQ + c] = K[base + (size_t)(kt + rr) * ld + c];
            Vs[rr * LDQ + c] = V[base + (size_t)(kt + rr) * ld + c];
        }
        __syncthreads();

        // scores: 4x4 per thread
        float s[4][4];
#pragma unroll
        for (int i = 0; i < 4; i++)
#pragma unroll
            for (int j = 0; j < 4; j++) s[i][j] = 0.f;
#pragma unroll 4
        for (int kk = 0; kk < HD; kk++) {
            float a[4], b[4];
#pragma unroll
            for (int i = 0; i < 4; i++) a[i] = Qs[(ty * 4 + i) * LDQ + kk];
#pragma unroll
            for (int j = 0; j < 4; j++) b[j] = Ks[(tx * 4 + j) * LDQ + kk];
#pragma unroll
            for (int i = 0; i < 4; i++)
#pragma unroll
                for (int j = 0; j < 4; j++) s[i][j] += a[i] * b[j];
        }
#pragma unroll
        for (int i = 0; i < 4; i++)
#pragma unroll
            for (int j = 0; j < 4; j++)
                Ss[(ty * 4 + i) * 66 + tx * 4 + j] = s[i][j] * scale;
        __syncthreads();

        // row max (partial over 16 cols)
        float pm = -1e30f;
        for (int c = qq * 16; c < qq * 16 + 16; c++) pm = fmaxf(pm, Ss[r * 66 + c]);
        red[t] = pm;
        __syncthreads();
        if (t < 64) {
            float mx = fmaxf(fmaxf(red[t * 4], red[t * 4 + 1]),
                             fmaxf(red[t * 4 + 2], red[t * 4 + 3]));
            float mn = fmaxf(m_s[t], mx);
            a_s[t] = __expf(m_s[t] - mn);
            m_s[t] = mn;
        }
        __syncthreads();

        // rescale accumulators
#pragma unroll
        for (int i = 0; i < 4; i++) {
            float al = a_s[ty * 4 + i];
#pragma unroll
            for (int j = 0; j < CPT; j++) acc[i][j] *= al;
        }

        // exponentiate + partial sums
        float mrow = m_s[r];
        float ps = 0.f;
        for (int c = qq * 16; c < qq * 16 + 16; c++) {
            float p = __expf(Ss[r * 66 + c] - mrow);
            Ss[r * 66 + c] = p;
            ps += p;
        }
        red[t] = ps;
        __syncthreads();
        if (t < 64)
            l_s[t] = l_s[t] * a_s[t] + red[t * 4] + red[t * 4 + 1] + red[t * 4 + 2] + red[t * 4 + 3];

        // P @ V
#pragma unroll 2
        for (int c2 = 0; c2 < 64; c2++) {
            float p[4];
#pragma unroll
            for (int i = 0; i < 4; i++) p[i] = Ss[(ty * 4 + i) * 66 + c2];
#pragma unroll
            for (int j = 0; j < CPT; j++) {
                float vv = Vs[c2 * LDQ + tx * CPT + j];
#pragma unroll
                for (int i = 0; i < 4; i++) acc[i][j] += p[i] * vv;
            }
        }
        __syncthreads();
    }

#pragma unroll
    for (int i = 0; i < 4; i++) {
        float inv = 1.f / l_s[ty * 4 + i];
#pragma unroll
        for (int j = 0; j < CPT; j++)
            O[base + (size_t)(q0 + ty * 4 + i) * ld + tx * CPT + j] = acc[i][j] * inv;
    }
}

// ---------------- block reduce (sum, sumsq) ----------------
__device__ __forceinline__ void block_reduce2(float& s, float& s2) {
    __shared__ float rs[8], rs2[8];
#pragma unroll
    for (int o = 16; o > 0; o >>= 1) {
        s  += __shfl_xor_sync(0xffffffff, s, o);
        s2 += __shfl_xor_sync(0xffffffff, s2, o);
    }
    int lane = threadIdx.x & 31, w = threadIdx.x >> 5;
    if (lane == 0) { rs[w] = s; rs2[w] = s2; }
    __syncthreads();
    float ts = 0.f, ts2 = 0.f;
#pragma unroll
    for (int i = 0; i < 8; i++) { ts += rs[i]; ts2 += rs2[i]; }
    s = ts; s2 = ts2;
}

// ---------------- LN1: x1 = LN(x + attn) ----------------
__global__ __launch_bounds__(256) void ln1_kernel(
    const float* __restrict__ x, const float* __restrict__ g,
    const float* __restrict__ b)
{
    size_t tok = blockIdx.x;
    int t = threadIdx.x;
    float v[4], s = 0.f, s2 = 0.f;
#pragma unroll
    for (int u = 0; u < 4; u++) {
        int j = t + u * 256;
        float val = x[tok * Dm + j] + g_attn[tok * Dm + j];
        v[u] = val; s += val; s2 += val * val;
    }
    block_reduce2(s, s2);
    float mean = s * (1.f / Dm);
    float var  = s2 * (1.f / Dm) - mean * mean;
    float inv  = rsqrtf(var + 1e-5f);
#pragma unroll
    for (int u = 0; u < 4; u++) {
        int j = t + u * 256;
        g_x1[tok * Dm + j] = (v[u] - mean) * inv * g[j] + b[j];
    }
}

// ---------------- gate: logits, softmax, top2, aux-loss stats ---------------
__global__ __launch_bounds__(256) void gate_kernel(const float* __restrict__ gateW) {
    int warp = threadIdx.x >> 5, lane = threadIdx.x & 31;
    int tok = blockIdx.x * 8 + warp;
    const float* xr = g_x1 + (size_t)tok * Dm;
    float acc[NE];
#pragma unroll
    for (int e = 0; e < NE; e++) acc[e] = 0.f;
    for (int k = lane; k < Dm; k += 32) {
        float xv = xr[k];
        const float* wr = gateW + (size_t)k * NE;
#pragma unroll
        for (int e = 0; e < NE; e++) acc[e] += xv * wr[e];
    }
#pragma unroll
    for (int e = 0; e < NE; e++)
#pragma unroll
        for (int o = 16; o > 0; o >>= 1)
            acc[e] += __shfl_xor_sync(0xffffffff, acc[e], o);
    if (lane == 0) {
        float mx = acc[0];
#pragma unroll
        for (int e = 1; e < NE; e++) mx = fmaxf(mx, acc[e]);
        float p[NE], se = 0.f;
#pragma unroll
        for (int e = 0; e < NE; e++) { p[e] = __expf(acc[e] - mx); se += p[e]; }
        float invs = 1.f / se;
        float lse = mx + logf(se);
        atomicAdd(&g_zsum, lse * lse);
        int i0 = 0, i1 = -1;
        float b0 = -1.f, b1 = -1.f;
#pragma unroll
        for (int e = 0; e < NE; e++) {
            float pe = p[e] * invs;
            atomicAdd(&g_Psum[e], pe);
            if (pe > b0) { b1 = b0; i1 = i0; b0 = pe; i0 = e; }
            else if (pe > b1) { b1 = pe; i1 = e; }
        }
        atomicAdd(&g_fcnt[i0], 1.f);
        g_i0[tok] = i0; g_i1[tok] = i1;
        g_g0[tok] = b0; g_g1[tok] = b1;
    }
}

// ---------------- routing positions (warp-ballot prefix, slot0 then slot1) --
__global__ __launch_bounds__(256) void pos_kernel() {
    int warp = threadIdx.x >> 5, lane = threadIdx.x & 31;
    if (warp >= Bt) return;
    int b = warp;
    unsigned lt = (1u << lane) - 1u;
    int cnt[NE];
#pragma unroll
    for (int e = 0; e < NE; e++) cnt[e] = 0;

    // slot 0: all tokens dispatched
    for (int ch = 0; ch < Sq / 32; ch++) {
        int tok = b * Sq + ch * 32 + lane;
        int e0 = g_i0[tok];
        int myp = 0;
#pragma unroll
        for (int e = 0; e < NE; e++) {
            unsigned m = __ballot_sync(0xffffffff, e0 == e);
            if (e0 == e) myp = cnt[e] + __popc(m & lt);
            cnt[e] += __popc(m);
        }
        g_k0[tok] = (myp < CAP) ? 1 : 0;
        g_p0[tok] = min(myp, CAP - 1);
    }
    // slot 1: only g > THRESHOLD participate (counts carry over)
    for (int ch = 0; ch < Sq / 32; ch++) {
        int tok = b * Sq + ch * 32 + lane;
        int e1 = g_i1[tok];
        bool valid = g_g1[tok] > 0.2f;
        int myp = 0;
#pragma unroll
        for (int e = 0; e < NE; e++) {
            unsigned m = __ballot_sync(0xffffffff, valid && (e1 == e));
            if (valid && (e1 == e)) myp = cnt[e] + __popc(m & lt);
            cnt[e] += __popc(m);
        }
        bool keep = valid && (myp < CAP);
        g_k1[tok] = keep ? 1 : 0;
        g_p1[tok] = valid ? min(myp, CAP - 1) : 0;
    }
}

// ---------------- scatter tokens into expert buffers ----------------
__global__ __launch_bounds__(256) void scatter_kernel() {
    int idx = blockIdx.x;
    int tok = idx >> 1, slot = idx & 1;
    int keep = slot ? g_k1[tok] : g_k0[tok];
    if (!keep) return;
    int e = slot ? g_i1[tok] : g_i0[tok];
    int p = slot ? g_p1[tok] : g_p0[tok];
    int b = tok / Sq;
    const float4* src = (const float4*)(g_x1 + (size_t)tok * Dm);
    float4* dst = (float4*)(g_ein + (((size_t)e * Bt + b) * CAP + p) * Dm);
    dst[threadIdx.x] = src[threadIdx.x];
}

// ---------------- combine + LN2 -> d_out ----------------
__global__ __launch_bounds__(256) void combine_ln_kernel(
    const float* __restrict__ g2, const float* __restrict__ b2,
    float* __restrict__ out)
{
    size_t tok = blockIdx.x;
    int t = threadIdx.x;
    int b = (int)(tok >> 10);  // Sq == 1024
    float w0 = g_k0[tok] ? g_g0[tok] : 0.f;
    float w1 = g_k1[tok] ? g_g1[tok] : 0.f;
    const float* r0 = g_eout + (((size_t)g_i0[tok] * Bt + b) * CAP + g_p0[tok]) * Dm;
    const float* r1 = g_eout + (((size_t)g_i1[tok] * Bt + b) * CAP + g_p1[tok]) * Dm;

    float v[4], s = 0.f, s2 = 0.f;
#pragma unroll
    for (int u = 0; u < 4; u++) {
        int j = t + u * 256;
        float val = g_x1[tok * Dm + j] + w0 * r0[j] + w1 * r1[j];
        v[u] = val; s += val; s2 += val * val;
    }
    block_reduce2(s, s2);
    float mean = s * (1.f / Dm);
    float var  = s2 * (1.f / Dm) - mean * mean;
    float inv  = rsqrtf(var + 1e-5f);
#pragma unroll
    for (int u = 0; u < 4; u++) {
        int j = t + u * 256;
        out[tok * Dm + j] = (v[u] - mean) * inv * g2[j] + b2[j];
    }
}

// ---------------- finalize aux losses ----------------
__global__ void finalize_kernel(float* __restrict__ out) {
    if (threadIdx.x == 0 && blockIdx.x == 0) {
        float invN = 1.f / (float)NT;
        float sfp = 0.f;
#pragma unroll
        for (int e = 0; e < NE; e++)
            sfp += (g_fcnt[e] * invN) * (g_Psum[e] * invN);
        float bal = 0.01f * (float)NE * sfp;
        float zl  = 0.001f * g_zsum * invN;
        out[NTD + 0] = bal + zl;
        out[NTD + 1] = bal;
        out[NTD + 2] = zl;
    }
}

// ---------------- host launcher ----------------
extern "C" void kernel_launch(void* const* d_in, const int* in_sizes, int n_in,
                              void* d_out, int out_size)
{
    const float* x      = (const float*)d_in[0];
    const float* Wq     = (const float*)d_in[1];
    const float* Wk     = (const float*)d_in[2];
    const float* Wv     = (const float*)d_in[3];
    const float* Wo     = (const float*)d_in[4];
    const float* bq     = (const float*)d_in[5];
    const float* bk     = (const float*)d_in[6];
    const float* bv     = (const float*)d_in[7];
    const float* bo     = (const float*)d_in[8];
    const float* ln1_g  = (const float*)d_in[9];
    const float* ln1_b  = (const float*)d_in[10];
    const float* ln2_g  = (const float*)d_in[11];
    const float* ln2_b  = (const float*)d_in[12];
    const float* gate_W = (const float*)d_in[13];
    const float* eWq    = (const float*)d_in[14];
    const float* eWk    = (const float*)d_in[15];
    const float* eWv    = (const float*)d_in[16];
    const float* eWo    = (const float*)d_in[17];
    float* out = (float*)d_out;

    // scratch addresses
    void *pq, *pk, *pv, *po, *pattn, *px1, *pein, *peq, *pek, *pev, *peo, *peout;
    cudaGetSymbolAddress(&pq, g_q);       cudaGetSymbolAddress(&pk, g_k);
    cudaGetSymbolAddress(&pv, g_v);       cudaGetSymbolAddress(&po, g_o);
    cudaGetSymbolAddress(&pattn, g_attn); cudaGetSymbolAddress(&px1, g_x1);
    cudaGetSymbolAddress(&pein, g_ein);   cudaGetSymbolAddress(&peq, g_eq);
    cudaGetSymbolAddress(&pek, g_ek);     cudaGetSymbolAddress(&pev, g_ev);
    cudaGetSymbolAddress(&peo, g_eo);     cudaGetSymbolAddress(&peout, g_eout);

    const int SMEM64  = (64 * 65 * 3 + 64 * 66 + 192 + 256) * 4;   // 68608 B
    const int SMEM128 = (64 * 129 * 3 + 64 * 66 + 192 + 256) * 4;  // 117760 B
    cudaFuncSetAttribute(flash_kernel<HD1>, cudaFuncAttributeMaxDynamicSharedMemorySize, SMEM64);
    cudaFuncSetAttribute(flash_kernel<HDM>, cudaFuncAttributeMaxDynamicSharedMemorySize, SMEM128);

    zero_stats_kernel<<<1, 32>>>();
    zero_ein_kernel<<<4096, 256>>>();

    dim3 gmain(Dm / 128, NT / 128, 1);
    // QKV projections
    sgemm_kernel<<<gmain, 256>>>(x, Wq, bq, (float*)pq, NT, Dm, Dm, 0, 0, 0);
    sgemm_kernel<<<gmain, 256>>>(x, Wk, bk, (float*)pk, NT, Dm, Dm, 0, 0, 0);
    sgemm_kernel<<<gmain, 256>>>(x, Wv, bv, (float*)pv, NT, Dm, Dm, 0, 0, 0);

    // main attention: 16 q-tiles x (B*NH) slices
    flash_kernel<HD1><<<dim3(Sq / 64, Bt * NH), 256, SMEM64>>>(
        (const float*)pq, (const float*)pk, (const float*)pv, (float*)po,
        Sq, NH, 0.125f);

    // output projection
    sgemm_kernel<<<gmain, 256>>>((const float*)po, Wo, bo, (float*)pattn, NT, Dm, Dm, 0, 0, 0);

    // LN1
    ln1_kernel<<<NT, 256>>>(x, ln1_g, ln1_b);

    // router
    gate_kernel<<<NT / 8, 256>>>(gate_W);
    pos_kernel<<<1, 256>>>();
    scatter_kernel<<<NT * 2, 256>>>();

    // expert projections (batched over E)
    size_t sA = (size_t)EROWS * Dm;      // per-expert token block
    size_t sW = (size_t)Dm * Dm;
    dim3 gexp(Dm / 128, EROWS / 128, NE);
    sgemm_kernel<<<gexp, 256>>>((const float*)pein, eWq, nullptr, (float*)peq, EROWS, Dm, Dm, sA, sW, sA);
    sgemm_kernel<<<gexp, 256>>>((const float*)pein, eWk, nullptr, (float*)pek, EROWS, Dm, Dm, sA, sW, sA);
    sgemm_kernel<<<gexp, 256>>>((const float*)pein, eWv, nullptr, (float*)pev, EROWS, Dm, Dm, sA, sW, sA);

    // expert attention: 5 q-tiles x (E*B*NHM) slices
    flash_kernel<HDM><<<dim3(CAP / 64, NE * Bt * NHM), 256, SMEM128>>>(
        (const float*)peq, (const float*)pek, (const float*)pev, (float*)peo,
        CAP, NHM, 0.0883883476483184f);

    // expert output projection
    sgemm_kernel<<<gexp, 256>>>((const float*)peo, eWo, nullptr, (float*)peout, EROWS, Dm, Dm, sA, sW, sA);

    // combine + LN2 + aux scalars
    combine_ln_kernel<<<NT, 256>>>(ln2_g, ln2_b, out);
    finalize_kernel<<<1, 32>>>(out);
}

// round 3
// speedup vs baseline: 1.3207x; 1.3207x over previous
#include <cuda_runtime.h>
#include <cuda_bf16.h>
#include <math.h>
#include <stdint.h>

// ---------------- problem dims ----------------
#define Bt   8
#define Sq   1024
#define Dm   1024
#define NH   16
#define HD1  64
#define NE   8
#define NHM  8
#define HDM  128
#define CAP  320
#define NT   (Bt*Sq)            // 8192 tokens
#define NTD  ((size_t)NT*Dm)    // 8388608
#define EROWS (Bt*CAP)          // 2560 rows per expert
#define EINSZ ((size_t)NE*Bt*CAP*Dm) // 20971520
#define DMDM ((size_t)Dm*Dm)

// ---------------- scratch (device globals) -------
static __device__ float g_q[NTD];
static __device__ float g_k[NTD];
static __device__ float g_v[NTD];
static __device__ float g_o[NTD];
static __device__ float g_attn[NTD];
static __device__ float g_x1[NTD];

static __device__ float g_eq[EINSZ];
static __device__ float g_ek[EINSZ];
static __device__ float g_ev[EINSZ];
static __device__ float g_eo[EINSZ];
static __device__ float g_eout[EINSZ];

// bf16 split buffers (hi/lo)
static __device__ __nv_bfloat16 g_xh[NTD],  g_xl[NTD];
static __device__ __nv_bfloat16 g_oh[NTD],  g_ol[NTD];
static __device__ __nv_bfloat16 g_einh[EINSZ], g_einl[EINSZ];
static __device__ __nv_bfloat16 g_eoh[EINSZ],  g_eol[EINSZ];
// transposed weights [N,K] bf16 hi/lo
static __device__ __nv_bfloat16 g_wqh[DMDM], g_wql[DMDM];
static __device__ __nv_bfloat16 g_wkh[DMDM], g_wkl[DMDM];
static __device__ __nv_bfloat16 g_wvh[DMDM], g_wvl[DMDM];
static __device__ __nv_bfloat16 g_woh[DMDM], g_wol[DMDM];
static __device__ __nv_bfloat16 g_ewqh[NE*DMDM], g_ewql[NE*DMDM];
static __device__ __nv_bfloat16 g_ewkh[NE*DMDM], g_ewkl[NE*DMDM];
static __device__ __nv_bfloat16 g_ewvh[NE*DMDM], g_ewvl[NE*DMDM];
static __device__ __nv_bfloat16 g_ewoh[NE*DMDM], g_ewol[NE*DMDM];

static __device__ int   g_i0[NT], g_i1[NT];
static __device__ float g_g0[NT], g_g1[NT];
static __device__ int   g_p0[NT], g_p1[NT];
static __device__ int   g_k0[NT], g_k1[NT];

static __device__ float g_Psum[NE];
static __device__ float g_fcnt[NE];
static __device__ float g_zsum;

// ---------------- PTX helpers ----------------
__device__ __forceinline__ uint32_t smem_u32(const void* p) {
    uint32_t a;
    asm("{ .reg .u64 t; cvta.to.shared.u64 t, %1; cvt.u32.u64 %0, t; }" : "=r"(a) : "l"(p));
    return a;
}
__device__ __forceinline__ void cp16(uint32_t dst, const void* src) {
    asm volatile("cp.async.cg.shared.global [%0], [%1], 16;" :: "r"(dst), "l"(src));
}
__device__ __forceinline__ void ldmA(uint32_t* a, uint32_t addr) {
    asm volatile("ldmatrix.sync.aligned.m8n8.x4.shared.b16 {%0,%1,%2,%3}, [%4];"
        : "=r"(a[0]), "=r"(a[1]), "=r"(a[2]), "=r"(a[3]) : "r"(addr));
}
__device__ __forceinline__ void mma_bf16(float* d, const uint32_t* a, const uint32_t* b) {
    asm volatile(
        "mma.sync.aligned.m16n8k16.row.col.f32.bf16.bf16.f32 "
        "{%0,%1,%2,%3}, {%4,%5,%6,%7}, {%8,%9}, {%0,%1,%2,%3};"
        : "+f"(d[0]), "+f"(d[1]), "+f"(d[2]), "+f"(d[3])
        : "r"(a[0]), "r"(a[1]), "r"(a[2]), "r"(a[3]), "r"(b[0]), "r"(b[1]));
}

// ---------------- bf16x3 GEMM via mma.sync ----------------
// C[M,N] = A[M,K] @ B^T : A=[M,K] (hi+lo), B=[N,K] (hi+lo), fp32 out.
// CTA tile 128x128, BK=32, 8 warps (4m x 2n), warp tile 32x64.
// Virtual K = 3*K segments: (Ah,Bh), (Ah,Bl), (Al,Bh).
#define BK 32
#define ROWB 80            // 40 bf16 per smem row (80 bytes), 16B aligned, conflict-free
#define STAGEB (128*ROWB)  // 10240 bytes per matrix
#define STAGE2 (2*STAGEB)  // 20480 per stage (A+B)

__global__ __launch_bounds__(256, 1) void gemm_mma_kernel(
    const __nv_bfloat16* __restrict__ Ah, const __nv_bfloat16* __restrict__ Al,
    const __nv_bfloat16* __restrict__ Bh, const __nv_bfloat16* __restrict__ Bl,
    const float* __restrict__ bias, float* __restrict__ C,
    int M, int N, int K, size_t sA, size_t sB, size_t sC)
{
    extern __shared__ char sm_[];
    uint32_t smb = smem_u32(sm_);

    int t = threadIdx.x, lane = t & 31, wid = t >> 5;
    int n0 = blockIdx.x * 128, m0 = blockIdx.y * 128;
    Ah += blockIdx.z * sA; Al += blockIdx.z * sA;
    Bh += blockIdx.z * sB; Bl += blockIdx.z * sB;
    C  += blockIdx.z * sC;

    int wm = (wid & 3) * 32;     // warp m offset in tile
    int wn = (wid >> 2) * 64;    // warp n offset in tile

    const __nv_bfloat16* Aseg[3] = {Ah, Ah, Al};
    const __nv_bfloat16* Bseg[3] = {Bh, Bl, Bh};
    const int KC = K / BK;       // chunks per segment
    const int NC = 3 * KC;

    float acc[2][8][4];
#pragma unroll
    for (int i = 0; i < 2; i++)
#pragma unroll
        for (int j = 0; j < 8; j++)
#pragma unroll
            for (int q = 0; q < 4; q++) acc[i][j][q] = 0.f;

    // per-thread cp.async coords: idx -> (row, 16B segment)
    int r0i = t >> 2, s0i = t & 3;          // idx = t
    int r1i = (t + 256) >> 2, s1i = t & 3;  // idx = t+256

    // ------ pipeline ------
    {
        // issue chunk 0 into stage 0
        const __nv_bfloat16* pA = Aseg[0];
        const __nv_bfloat16* pB = Bseg[0];
        uint32_t ab = smb;
        cp16(ab + r0i * ROWB + s0i * 16, pA + (size_t)(m0 + r0i) * K + s0i * 8);
        cp16(ab + r1i * ROWB + s1i * 16, pA + (size_t)(m0 + r1i) * K + s1i * 8);
        uint32_t bb = smb + STAGEB;
        cp16(bb + r0i * ROWB + s0i * 16, pB + (size_t)(n0 + r0i) * K + s0i * 8);
        cp16(bb + r1i * ROWB + s1i * 16, pB + (size_t)(n0 + r1i) * K + s1i * 8);
        asm volatile("cp.async.commit_group;");
    }

    int nq = lane >> 2, kr = lane & 3;

    for (int c = 0; c < NC; c++) {
        if (c + 1 < NC) {
            int cn = c + 1;
            int seg = cn / KC, kc = (cn - seg * KC) * BK;
            const __nv_bfloat16* pA = Aseg[seg];
            const __nv_bfloat16* pB = Bseg[seg];
            uint32_t ab = smb + (cn & 1) * STAGE2;
            cp16(ab + r0i * ROWB + s0i * 16, pA + (size_t)(m0 + r0i) * K + kc + s0i * 8);
            cp16(ab + r1i * ROWB + s1i * 16, pA + (size_t)(m0 + r1i) * K + kc + s1i * 8);
            uint32_t bb = ab + STAGEB;
            cp16(bb + r0i * ROWB + s0i * 16, pB + (size_t)(n0 + r0i) * K + kc + s0i * 8);
            cp16(bb + r1i * ROWB + s1i * 16, pB + (size_t)(n0 + r1i) * K + kc + s1i * 8);
            asm volatile("cp.async.commit_group;");
            asm volatile("cp.async.wait_group 1;");
        } else {
            asm volatile("cp.async.wait_group 0;");
        }
        __syncthreads();

        uint32_t ab = smb + (c & 1) * STAGE2;
        uint32_t bb = ab + STAGEB;
        const char* bbp = sm_ + (c & 1) * STAGE2 + STAGEB;

        // A fragments via ldmatrix
        uint32_t afr[2][2][4];
#pragma unroll
        for (int mt = 0; mt < 2; mt++)
#pragma unroll
            for (int ks = 0; ks < 2; ks++) {
                uint32_t addr = ab + (wm + mt * 16 + (lane & 15)) * ROWB
                              + (ks * 16 + (lane >> 4) * 8) * 2;
                ldmA(afr[mt][ks], addr);
            }
        // B fragments via scalar LDS (conflict-free by row pitch 80B)
        uint32_t bfr[2][8][2];
#pragma unroll
        for (int ks = 0; ks < 2; ks++)
#pragma unroll
            for (int nt = 0; nt < 8; nt++) {
                const char* p = bbp + (wn + nt * 8 + nq) * ROWB + ks * 32 + kr * 4;
                bfr[ks][nt][0] = *(const uint32_t*)p;
                bfr[ks][nt][1] = *(const uint32_t*)(p + 16);
            }
#pragma unroll
        for (int ks = 0; ks < 2; ks++)
#pragma unroll
            for (int mt = 0; mt < 2; mt++)
#pragma unroll
                for (int nt = 0; nt < 8; nt++)
                    mma_bf16(acc[mt][nt], afr[mt][ks], bfr[ks][nt]);
        __syncthreads();
    }

    // epilogue
#pragma unroll
    for (int mt = 0; mt < 2; mt++) {
        int m = m0 + wm + mt * 16 + (lane >> 2);
#pragma unroll
        for (int nt = 0; nt < 8; nt++) {
            int n = n0 + wn + nt * 8 + (lane & 3) * 2;
            float bv0 = bias ? bias[n] : 0.f;
            float bv1 = bias ? bias[n + 1] : 0.f;
            float2 lo = make_float2(acc[mt][nt][0] + bv0, acc[mt][nt][1] + bv1);
            float2 hi = make_float2(acc[mt][nt][2] + bv0, acc[mt][nt][3] + bv1);
            *(float2*)&C[(size_t)m * N + n]       = lo;
            *(float2*)&C[(size_t)(m + 8) * N + n] = hi;
        }
    }
}

// ---------------- fp32 -> bf16 hi/lo split ----------------
__device__ __forceinline__ void split4(float4 v, uint2& hh, uint2& ll) {
    __nv_bfloat16 h0 = __float2bfloat16(v.x), h1 = __float2bfloat16(v.y);
    __nv_bfloat16 h2 = __float2bfloat16(v.z), h3 = __float2bfloat16(v.w);
    __nv_bfloat16 l0 = __float2bfloat16(v.x - __bfloat162float(h0));
    __nv_bfloat16 l1 = __float2bfloat16(v.y - __bfloat162float(h1));
    __nv_bfloat16 l2 = __float2bfloat16(v.z - __bfloat162float(h2));
    __nv_bfloat16 l3 = __float2bfloat16(v.w - __bfloat162float(h3));
    hh.x = (uint32_t)__bfloat16_as_ushort(h0) | ((uint32_t)__bfloat16_as_ushort(h1) << 16);
    hh.y = (uint32_t)__bfloat16_as_ushort(h2) | ((uint32_t)__bfloat16_as_ushort(h3) << 16);
    ll.x = (uint32_t)__bfloat16_as_ushort(l0) | ((uint32_t)__bfloat16_as_ushort(l1) << 16);
    ll.y = (uint32_t)__bfloat16_as_ushort(l2) | ((uint32_t)__bfloat16_as_ushort(l3) << 16);
}

__global__ __launch_bounds__(256) void csplit_kernel(
    const float4* __restrict__ s, uint2* __restrict__ h, uint2* __restrict__ l, int n4)
{
    int i = blockIdx.x * 256 + threadIdx.x;
    if (i >= n4) return;
    uint2 hh, ll;
    split4(s[i], hh, ll);
    h[i] = hh; l[i] = ll;
}

// ---------------- weight transpose + split: W[K,N] fp32 -> T[N,K] bf16 hi/lo -
__global__ void wtrans_kernel(const float* __restrict__ W,
                              __nv_bfloat16* __restrict__ Th,
                              __nv_bfloat16* __restrict__ Tl, int Kd, int Nd)
{
    __shared__ float tile[32][33];
    int tx = threadIdx.x, ty = threadIdx.y;   // 32 x 8
    int n0 = blockIdx.x * 32, k0 = blockIdx.y * 32;
    size_t ob = (size_t)blockIdx.z * Kd * Nd;
    const float* Wb = W + ob;
#pragma unroll
    for (int r = 0; r < 4; r++)
        tile[ty + 8 * r][tx] = Wb[(size_t)(k0 + ty + 8 * r) * Nd + n0 + tx];
    __syncthreads();
#pragma unroll
    for (int r = 0; r < 4; r++) {
        float v = tile[tx][ty + 8 * r];
        __nv_bfloat16 h = __float2bfloat16(v);
        Th[ob + (size_t)(n0 + ty + 8 * r) * Kd + k0 + tx] = h;
        Tl[ob + (size_t)(n0 + ty + 8 * r) * Kd + k0 + tx] =
            __float2bfloat16(v - __bfloat162float(h));
    }
}

// ---------------- zero kernels ----------------
__global__ void zero_stats_kernel() {
    int t = threadIdx.x;
    if (t < NE) { g_Psum[t] = 0.f; g_fcnt[t] = 0.f; }
    if (t == 0) g_zsum = 0.f;
}

__global__ void zero_ein_kernel() {
    size_t n = EINSZ / 8;
    uint4 z = make_uint4(0, 0, 0, 0);
    uint4* ph = (uint4*)g_einh;
    uint4* pl = (uint4*)g_einl;
    for (size_t i = blockIdx.x * (size_t)blockDim.x + threadIdx.x; i < n;
         i += (size_t)gridDim.x * blockDim.x) { ph[i] = z; pl[i] = z; }
}

// ---------------- flash attention (fp32, online softmax), 64x64 tiles -------
template <int HD>
__global__ __launch_bounds__(256) void flash_kernel(
    const float* __restrict__ Q, const float* __restrict__ K,
    const float* __restrict__ V, float* __restrict__ O,
    int seq, int nheads, float scale)
{
    constexpr int CPT = HD / 16;
    constexpr int LDQ = HD + 1;
    extern __shared__ float sm[];
    float* Qs  = sm;
    float* Ks  = Qs + 64 * LDQ;
    float* Vs  = Ks + 64 * LDQ;
    float* Ss  = Vs + 64 * LDQ;
    float* m_s = Ss + 64 * 66;
    float* l_s = m_s + 64;
    float* a_s = l_s + 64;
    float* red = a_s + 64;

    int t  = threadIdx.x;
    int tx = t & 15, ty = t >> 4;
    int slice = blockIdx.y;
    int sb = slice / nheads, h = slice % nheads;
    int ld = nheads * HD;
    size_t base = (size_t)sb * seq * ld + (size_t)h * HD;
    int q0 = blockIdx.x * 64;

    for (int idx = t; idx < 64 * HD; idx += 256) {
        int r = idx / HD, c = idx % HD;
        Qs[r * LDQ + c] = Q[base + (size_t)(q0 + r) * ld + c];
    }
    if (t < 64) { m_s[t] = -1e30f; l_s[t] = 0.f; }

    float acc[4][CPT];
#pragma unroll
    for (int i = 0; i < 4; i++)
#pragma unroll
        for (int j = 0; j < CPT; j++) acc[i][j] = 0.f;
    __syncthreads();

    int r  = t >> 2;
    int qq = t & 3;

    for (int kt = 0; kt < seq; kt += 64) {
        for (int idx = t; idx < 64 * HD; idx += 256) {
            int rr = idx / HD, c = idx % HD;
            Ks[rr * LDQ + c] = K[base + (size_t)(kt + rr) * ld + c];
            Vs[rr * LDQ + c] = V[base + (size_t)(kt + rr) * ld + c];
        }
        __syncthreads();

        float s[4][4];
#pragma unroll
        for (int i = 0; i < 4; i++)
#pragma unroll
            for (int j = 0; j < 4; j++) s[i][j] = 0.f;
#pragma unroll 4
        for (int kk = 0; kk < HD; kk++) {
            float a[4], b[4];
#pragma unroll
            for (int i = 0; i < 4; i++) a[i] = Qs[(ty * 4 + i) * LDQ + kk];
#pragma unroll
            for (int j = 0; j < 4; j++) b[j] = Ks[(tx * 4 + j) * LDQ + kk];
#pragma unroll
            for (int i = 0; i < 4; i++)
#pragma unroll
                for (int j = 0; j < 4; j++) s[i][j] += a[i] * b[j];
        }
#pragma unroll
        for (int i = 0; i < 4; i++)
#pragma unroll
            for (int j = 0; j < 4; j++)
                Ss[(ty * 4 + i) * 66 + tx * 4 + j] = s[i][j] * scale;
        __syncthreads();

        float pm = -1e30f;
        for (int c = qq * 16; c < qq * 16 + 16; c++) pm = fmaxf(pm, Ss[r * 66 + c]);
        red[t] = pm;
        __syncthreads();
        if (t < 64) {
            float mx = fmaxf(fmaxf(red[t * 4], red[t * 4 + 1]),
                             fmaxf(red[t * 4 + 2], red[t * 4 + 3]));
            float mn = fmaxf(m_s[t], mx);
            a_s[t] = __expf(m_s[t] - mn);
            m_s[t] = mn;
        }
        __syncthreads();

#pragma unroll
        for (int i = 0; i < 4; i++) {
            float al = a_s[ty * 4 + i];
#pragma unroll
            for (int j = 0; j < CPT; j++) acc[i][j] *= al;
        }

        float mrow = m_s[r];
        float ps = 0.f;
        for (int c = qq * 16; c < qq * 16 + 16; c++) {
            float p = __expf(Ss[r * 66 + c] - mrow);
            Ss[r * 66 + c] = p;
            ps += p;
        }
        red[t] = ps;
        __syncthreads();
        if (t < 64)
            l_s[t] = l_s[t] * a_s[t] + red[t * 4] + red[t * 4 + 1] + red[t * 4 + 2] + red[t * 4 + 3];

#pragma unroll 2
        for (int c2 = 0; c2 < 64; c2++) {
            float p[4];
#pragma unroll
            for (int i = 0; i < 4; i++) p[i] = Ss[(ty * 4 + i) * 66 + c2];
#pragma unroll
            for (int j = 0; j < CPT; j++) {
                float vv = Vs[c2 * LDQ + tx * CPT + j];
#pragma unroll
                for (int i = 0; i < 4; i++) acc[i][j] += p[i] * vv;
            }
        }
        __syncthreads();
    }

#pragma unroll
    for (int i = 0; i < 4; i++) {
        float inv = 1.f / l_s[ty * 4 + i];
#pragma unroll
        for (int j = 0; j < CPT; j++)
            O[base + (size_t)(q0 + ty * 4 + i) * ld + tx * CPT + j] = acc[i][j] * inv;
    }
}

// ---------------- block reduce (sum, sumsq) ----------------
__device__ __forceinline__ void block_reduce2(float& s, float& s2) {
    __shared__ float rs[8], rs2[8];
#pragma unroll
    for (int o = 16; o > 0; o >>= 1) {
        s  += __shfl_xor_sync(0xffffffff, s, o);
        s2 += __shfl_xor_sync(0xffffffff, s2, o);
    }
    int lane = threadIdx.x & 31, w = threadIdx.x >> 5;
    if (lane == 0) { rs[w] = s; rs2[w] = s2; }
    __syncthreads();
    float ts = 0.f, ts2 = 0.f;
#pragma unroll
    for (int i = 0; i < 8; i++) { ts += rs[i]; ts2 += rs2[i]; }
    s = ts; s2 = ts2;
}

// ---------------- LN1: x1 = LN(x + attn) ----------------
__global__ __launch_bounds__(256) void ln1_kernel(
    const float* __restrict__ x, const float* __restrict__ g,
    const float* __restrict__ b)
{
    size_t tok = blockIdx.x;
    int t = threadIdx.x;
    float v[4], s = 0.f, s2 = 0.f;
#pragma unroll
    for (int u = 0; u < 4; u++) {
        int j = t + u * 256;
        float val = x[tok * Dm + j] + g_attn[tok * Dm + j];
        v[u] = val; s += val; s2 += val * val;
    }
    block_reduce2(s, s2);
    float mean = s * (1.f / Dm);
    float var  = s2 * (1.f / Dm) - mean * mean;
    float inv  = rsqrtf(var + 1e-5f);
#pragma unroll
    for (int u = 0; u < 4; u++) {
        int j = t + u * 256;
        g_x1[tok * Dm + j] = (v[u] - mean) * inv * g[j] + b[j];
    }
}

// ---------------- gate ----------------
__global__ __launch_bounds__(256) void gate_kernel(const float* __restrict__ gateW) {
    int warp = threadIdx.x >> 5, lane = threadIdx.x & 31;
    int tok = blockIdx.x * 8 + warp;
    const float* xr = g_x1 + (size_t)tok * Dm;
    float acc[NE];
#pragma unroll
    for (int e = 0; e < NE; e++) acc[e] = 0.f;
    for (int k = lane; k < Dm; k += 32) {
        float xv = xr[k];
        const float* wr = gateW + (size_t)k * NE;
#pragma unroll
        for (int e = 0; e < NE; e++) acc[e] += xv * wr[e];
    }
#pragma unroll
    for (int e = 0; e < NE; e++)
#pragma unroll
        for (int o = 16; o > 0; o >>= 1)
            acc[e] += __shfl_xor_sync(0xffffffff, acc[e], o);
    if (lane == 0) {
        float mx = acc[0];
#pragma unroll
        for (int e = 1; e < NE; e++) mx = fmaxf(mx, acc[e]);
        float p[NE], se = 0.f;
#pragma unroll
        for (int e = 0; e < NE; e++) { p[e] = __expf(acc[e] - mx); se += p[e]; }
        float invs = 1.f / se;
        float lse = mx + logf(se);
        atomicAdd(&g_zsum, lse * lse);
        int i0 = 0, i1 = -1;
        float b0 = -1.f, b1 = -1.f;
#pragma unroll
        for (int e = 0; e < NE; e++) {
            float pe = p[e] * invs;
            atomicAdd(&g_Psum[e], pe);
            if (pe > b0) { b1 = b0; i1 = i0; b0 = pe; i0 = e; }
            else if (pe > b1) { b1 = pe; i1 = e; }
        }
        atomicAdd(&g_fcnt[i0], 1.f);
        g_i0[tok] = i0; g_i1[tok] = i1;
        g_g0[tok] = b0; g_g1[tok] = b1;
    }
}

// ---------------- routing positions ----------------
__global__ __launch_bounds__(256) void pos_kernel() {
    int warp = threadIdx.x >> 5, lane = threadIdx.x & 31;
    if (warp >= Bt) return;
    int b = warp;
    unsigned lt = (1u << lane) - 1u;
    int cnt[NE];
#pragma unroll
    for (int e = 0; e < NE; e++) cnt[e] = 0;

    for (int ch = 0; ch < Sq / 32; ch++) {
        int tok = b * Sq + ch * 32 + lane;
        int e0 = g_i0[tok];
        int myp = 0;
#pragma unroll
        for (int e = 0; e < NE; e++) {
            unsigned m = __ballot_sync(0xffffffff, e0 == e);
            if (e0 == e) myp = cnt[e] + __popc(m & lt);
            cnt[e] += __popc(m);
        }
        g_k0[tok] = (myp < CAP) ? 1 : 0;
        g_p0[tok] = min(myp, CAP - 1);
    }
    for (int ch = 0; ch < Sq / 32; ch++) {
        int tok = b * Sq + ch * 32 + lane;
        int e1 = g_i1[tok];
        bool valid = g_g1[tok] > 0.2f;
        int myp = 0;
#pragma unroll
        for (int e = 0; e < NE; e++) {
            unsigned m = __ballot_sync(0xffffffff, valid && (e1 == e));
            if (valid && (e1 == e)) myp = cnt[e] + __popc(m & lt);
            cnt[e] += __popc(m);
        }
        bool keep = valid && (myp < CAP);
        g_k1[tok] = keep ? 1 : 0;
        g_p1[tok] = valid ? min(myp, CAP - 1) : 0;
    }
}

// ---------------- scatter tokens (x1 fp32 -> expert buffers bf16 hi/lo) -----
__global__ __launch_bounds__(256) void scatter_kernel() {
    int idx = blockIdx.x;
    int tok = idx >> 1, slot = idx & 1;
    int keep = slot ? g_k1[tok] : g_k0[tok];
    if (!keep) return;
    int e = slot ? g_i1[tok] : g_i0[tok];
    int p = slot ? g_p1[tok] : g_p0[tok];
    int b = tok / Sq;
    const float4* src = (const float4*)(g_x1 + (size_t)tok * Dm);
    size_t ro = (((size_t)e * Bt + b) * CAP + p) * Dm;
    uint2* dh = (uint2*)(g_einh + ro);
    uint2* dl = (uint2*)(g_einl + ro);
    uint2 hh, ll;
    split4(src[threadIdx.x], hh, ll);
    dh[threadIdx.x] = hh; dl[threadIdx.x] = ll;
}

// ---------------- combine + LN2 -> d_out ----------------
__global__ __launch_bounds__(256) void combine_ln_kernel(
    const float* __restrict__ g2, const float* __restrict__ b2,
    float* __restrict__ out)
{
    size_t tok = blockIdx.x;
    int t = threadIdx.x;
    int b = (int)(tok >> 10);
    float w0 = g_k0[tok] ? g_g0[tok] : 0.f;
    float w1 = g_k1[tok] ? g_g1[tok] : 0.f;
    const float* r0 = g_eout + (((size_t)g_i0[tok] * Bt + b) * CAP + g_p0[tok]) * Dm;
    const float* r1 = g_eout + (((size_t)g_i1[tok] * Bt + b) * CAP + g_p1[tok]) * Dm;

    float v[4], s = 0.f, s2 = 0.f;
#pragma unroll
    for (int u = 0; u < 4; u++) {
        int j = t + u * 256;
        float val = g_x1[tok * Dm + j] + w0 * r0[j] + w1 * r1[j];
        v[u] = val; s += val; s2 += val * val;
    }
    block_reduce2(s, s2);
    float mean = s * (1.f / Dm);
    float var  = s2 * (1.f / Dm) - mean * mean;
    float inv  = rsqrtf(var + 1e-5f);
#pragma unroll
    for (int u = 0; u < 4; u++) {
        int j = t + u * 256;
        out[tok * Dm + j] = (v[u] - mean) * inv * g2[j] + b2[j];
    }
}

// ---------------- finalize aux losses ----------------
__global__ void finalize_kernel(float* __restrict__ out) {
    if (threadIdx.x == 0 && blockIdx.x == 0) {
        float invN = 1.f / (float)NT;
        float sfp = 0.f;
#pragma unroll
        for (int e = 0; e < NE; e++)
            sfp += (g_fcnt[e] * invN) * (g_Psum[e] * invN);
        float bal = 0.01f * (float)NE * sfp;
        float zl  = 0.001f * g_zsum * invN;
        out[NTD + 0] = bal + zl;
        out[NTD + 1] = bal;
        out[NTD + 2] = zl;
    }
}

// ---------------- host launcher ----------------
extern "C" void kernel_launch(void* const* d_in, const int* in_sizes, int n_in,
                              void* d_out, int out_size)
{
    const float* x      = (const float*)d_in[0];
    const float* Wq     = (const float*)d_in[1];
    const float* Wk     = (const float*)d_in[2];
    const float* Wv     = (const float*)d_in[3];
    const float* Wo     = (const float*)d_in[4];
    const float* bq     = (const float*)d_in[5];
    const float* bk     = (const float*)d_in[6];
    const float* bv     = (const float*)d_in[7];
    const float* bo     = (const float*)d_in[8];
    const float* ln1_g  = (const float*)d_in[9];
    const float* ln1_b  = (const float*)d_in[10];
    const float* ln2_g  = (const float*)d_in[11];
    const float* ln2_b  = (const float*)d_in[12];
    const float* gate_W = (const float*)d_in[13];
    const float* eWq    = (const float*)d_in[14];
    const float* eWk    = (const float*)d_in[15];
    const float* eWv    = (const float*)d_in[16];
    const float* eWo    = (const float*)d_in[17];
    float* out = (float*)d_out;

    void *pq, *pk, *pv, *po, *pattn, *px1;
    void *peq, *pek, *pev, *peo, *peout;
    void *pxh, *pxl, *poh, *pol, *peinh, *peinl, *peoh, *peol;
    void *pwqh, *pwql, *pwkh, *pwkl, *pwvh, *pwvl, *pwoh, *pwol;
    void *pewqh, *pewql, *pewkh, *pewkl, *pewvh, *pewvl, *pewoh, *pewol;
    cudaGetSymbolAddress(&pq, g_q);       cudaGetSymbolAddress(&pk, g_k);
    cudaGetSymbolAddress(&pv, g_v);       cudaGetSymbolAddress(&po, g_o);
    cudaGetSymbolAddress(&pattn, g_attn); cudaGetSymbolAddress(&px1, g_x1);
    cudaGetSymbolAddress(&peq, g_eq);     cudaGetSymbolAddress(&pek, g_ek);
    cudaGetSymbolAddress(&pev, g_ev);     cudaGetSymbolAddress(&peo, g_eo);
    cudaGetSymbolAddress(&peout, g_eout);
    cudaGetSymbolAddress(&pxh, g_xh);     cudaGetSymbolAddress(&pxl, g_xl);
    cudaGetSymbolAddress(&poh, g_oh);     cudaGetSymbolAddress(&pol, g_ol);
    cudaGetSymbolAddress(&peinh, g_einh); cudaGetSymbolAddress(&peinl, g_einl);
    cudaGetSymbolAddress(&peoh, g_eoh);   cudaGetSymbolAddress(&peol, g_eol);
    cudaGetSymbolAddress(&pwqh, g_wqh);   cudaGetSymbolAddress(&pwql, g_wql);
    cudaGetSymbolAddress(&pwkh, g_wkh);   cudaGetSymbolAddress(&pwkl, g_wkl);
    cudaGetSymbolAddress(&pwvh, g_wvh);   cudaGetSymbolAddress(&pwvl, g_wvl);
    cudaGetSymbolAddress(&pwoh, g_woh);   cudaGetSymbolAddress(&pwol, g_wol);
    cudaGetSymbolAddress(&pewqh, g_ewqh); cudaGetSymbolAddress(&pewql, g_ewql);
    cudaGetSymbolAddress(&pewkh, g_ewkh); cudaGetSymbolAddress(&pewkl, g_ewkl);
    cudaGetSymbolAddress(&pewvh, g_ewvh); cudaGetSymbolAddress(&pewvl, g_ewvl);
    cudaGetSymbolAddress(&pewoh, g_ewoh); cudaGetSymbolAddress(&pewol, g_ewol);

    const int GEMM_SMEM = 2 * STAGE2;   // 40960 B
    cudaFuncSetAttribute(gemm_mma_kernel, cudaFuncAttributeMaxDynamicSharedMemorySize, GEMM_SMEM);
    const int SMEM64  = (64 * 65 * 3 + 64 * 66 + 192 + 256) * 4;
    const int SMEM128 = (64 * 129 * 3 + 64 * 66 + 192 + 256) * 4;
    cudaFuncSetAttribute(flash_kernel<HD1>, cudaFuncAttributeMaxDynamicSharedMemorySize, SMEM64);
    cudaFuncSetAttribute(flash_kernel<HDM>, cudaFuncAttributeMaxDynamicSharedMemorySize, SMEM128);

    zero_stats_kernel<<<1, 32>>>();
    zero_ein_kernel<<<4096, 256>>>();

    dim3 tb(32, 8);
    wtrans_kernel<<<dim3(32, 32, 1), tb>>>(Wq, (__nv_bfloat16*)pwqh, (__nv_bfloat16*)pwql, Dm, Dm);
    wtrans_kernel<<<dim3(32, 32, 1), tb>>>(Wk, (__nv_bfloat16*)pwkh, (__nv_bfloat16*)pwkl, Dm, Dm);
    wtrans_kernel<<<dim3(32, 32, 1), tb>>>(Wv, (__nv_bfloat16*)pwvh, (__nv_bfloat16*)pwvl, Dm, Dm);
    wtrans_kernel<<<dim3(32, 32, 1), tb>>>(Wo, (__nv_bfloat16*)pwoh, (__nv_bfloat16*)pwol, Dm, Dm);
    wtrans_kernel<<<dim3(32, 32, NE), tb>>>(eWq, (__nv_bfloat16*)pewqh, (__nv_bfloat16*)pewql, Dm, Dm);
    wtrans_kernel<<<dim3(32, 32, NE), tb>>>(eWk, (__nv_bfloat16*)pewkh, (__nv_bfloat16*)pewkl, Dm, Dm);
    wtrans_kernel<<<dim3(32, 32, NE), tb>>>(eWv, (__nv_bfloat16*)pewvh, (__nv_bfloat16*)pewvl, Dm, Dm);
    wtrans_kernel<<<dim3(32, 32, NE), tb>>>(eWo, (__nv_bfloat16*)pewoh, (__nv_bfloat16*)pewol, Dm, Dm);

    csplit_kernel<<<(int)(NTD / 4 / 256), 256>>>((const float4*)x, (uint2*)pxh, (uint2*)pxl, (int)(NTD / 4));

    dim3 gmain(Dm / 128, NT / 128, 1);
    gemm_mma_kernel<<<gmain, 256, GEMM_SMEM>>>((__nv_bfloat16*)pxh, (__nv_bfloat16*)pxl,
        (__nv_bfloat16*)pwqh, (__nv_bfloat16*)pwql, bq, (float*)pq, NT, Dm, Dm, 0, 0, 0);
    gemm_mma_kernel<<<gmain, 256, GEMM_SMEM>>>((__nv_bfloat16*)pxh, (__nv_bfloat16*)pxl,
        (__nv_bfloat16*)pwkh, (__nv_bfloat16*)pwkl, bk, (float*)pk, NT, Dm, Dm, 0, 0, 0);
    gemm_mma_kernel<<<gmain, 256, GEMM_SMEM>>>((__nv_bfloat16*)pxh, (__nv_bfloat16*)pxl,
        (__nv_bfloat16*)pwvh, (__nv_bfloat16*)pwvl, bv, (float*)pv, NT, Dm, Dm, 0, 0, 0);

    flash_kernel<HD1><<<dim3(Sq / 64, Bt * NH), 256, SMEM64>>>(
        (const float*)pq, (const float*)pk, (const float*)pv, (float*)po, Sq, NH, 0.125f);

    csplit_kernel<<<(int)(NTD / 4 / 256), 256>>>((const float4*)po, (uint2*)poh, (uint2*)pol, (int)(NTD / 4));
    gemm_mma_kernel<<<gmain, 256, GEMM_SMEM>>>((__nv_bfloat16*)poh, (__nv_bfloat16*)pol,
        (__nv_bfloat16*)pwoh, (__nv_bfloat16*)pwol, bo, (float*)pattn, NT, Dm, Dm, 0, 0, 0);

    ln1_kernel<<<NT, 256>>>(x, ln1_g, ln1_b);
    gate_kernel<<<NT / 8, 256>>>(gate_W);
    pos_kernel<<<1, 256>>>();
    scatter_kernel<<<NT * 2, 256>>>();

    size_t sA = (size_t)EROWS * Dm;
    size_t sW = DMDM;
    dim3 gexp(Dm / 128, EROWS / 128, NE);
    gemm_mma_kernel<<<gexp, 256, GEMM_SMEM>>>((__nv_bfloat16*)peinh, (__nv_bfloat16*)peinl,
        (__nv_bfloat16*)pewqh, (__nv_bfloat16*)pewql, nullptr, (float*)peq, EROWS, Dm, Dm, sA, sW, sA);
    gemm_mma_kernel<<<gexp, 256, GEMM_SMEM>>>((__nv_bfloat16*)peinh, (__nv_bfloat16*)peinl,
        (__nv_bfloat16*)pewkh, (__nv_bfloat16*)pewkl, nullptr, (float*)pek, EROWS, Dm, Dm, sA, sW, sA);
    gemm_mma_kernel<<<gexp, 256, GEMM_SMEM>>>((__nv_bfloat16*)peinh, (__nv_bfloat16*)peinl,
        (__nv_bfloat16*)pewvh, (__nv_bfloat16*)pewvl, nullptr, (float*)pev, EROWS, Dm, Dm, sA, sW, sA);

    flash_kernel<HDM><<<dim3(CAP / 64, NE * Bt * NHM), 256, SMEM128>>>(
        (const float*)peq, (const float*)pek, (const float*)pev, (float*)peo,
        CAP, NHM, 0.0883883476483184f);

    csplit_kernel<<<(int)(EINSZ / 4 / 256), 256>>>((const float4*)peo, (uint2*)peoh, (uint2*)peol, (int)(EINSZ / 4));
    gemm_mma_kernel<<<gexp, 256, GEMM_SMEM>>>((__nv_bfloat16*)peoh, (__nv_bfloat16*)peol,
        (__nv_bfloat16*)pewoh, (__nv_bfloat16*)pewol, nullptr, (float*)peout, EROWS, Dm, Dm, sA, sW, sA);

    combine_ln_kernel<<<NT, 256>>>(ln2_g, ln2_b, out);
    finalize_kernel<<<1, 32>>>(out);
}

// round 4
// speedup vs baseline: 2.0245x; 1.5329x over previous
#include <cuda_runtime.h>
#include <cuda_bf16.h>
#include <math.h>
#include <stdint.h>

// ---------------- problem dims ----------------
#define Bt   8
#define Sq   1024
#define Dm   1024
#define NH   16
#define HD1  64
#define NE   8
#define NHM  8
#define HDM  128
#define CAP  320
#define NT   (Bt*Sq)
#define NTD  ((size_t)NT*Dm)
#define EROWS (Bt*CAP)
#define EINSZ ((size_t)NE*Bt*CAP*Dm)
#define DMDM ((size_t)Dm*Dm)

// ---------------- scratch ----------------
static __device__ float g_q[NTD];
static __device__ float g_k[NTD];
static __device__ float g_v[NTD];
static __device__ float g_o[NTD];
static __device__ float g_attn[NTD];
static __device__ float g_x1[NTD];
static __device__ float g_eout[EINSZ];

static __device__ __nv_bfloat16 g_xh[NTD],  g_xl[NTD];
static __device__ __nv_bfloat16 g_oh[NTD],  g_ol[NTD];
static __device__ __nv_bfloat16 g_einh[EINSZ];
static __device__ __nv_bfloat16 g_eqh[EINSZ];
static __device__ __nv_bfloat16 g_ekh[EINSZ];
static __device__ __nv_bfloat16 g_evh[EINSZ];
static __device__ __nv_bfloat16 g_eoh[EINSZ];
static __device__ __nv_bfloat16 g_wqh[DMDM], g_wql[DMDM];
static __device__ __nv_bfloat16 g_wkh[DMDM], g_wkl[DMDM];
static __device__ __nv_bfloat16 g_wvh[DMDM], g_wvl[DMDM];
static __device__ __nv_bfloat16 g_woh[DMDM], g_wol[DMDM];
static __device__ __nv_bfloat16 g_ewqh[NE*DMDM], g_ewql[NE*DMDM];
static __device__ __nv_bfloat16 g_ewkh[NE*DMDM], g_ewkl[NE*DMDM];
static __device__ __nv_bfloat16 g_ewvh[NE*DMDM], g_ewvl[NE*DMDM];
static __device__ __nv_bfloat16 g_ewoh[NE*DMDM], g_ewol[NE*DMDM];

static __device__ int   g_i0[NT], g_i1[NT];
static __device__ float g_g0[NT], g_g1[NT];
static __device__ int   g_p0[NT], g_p1[NT];
static __device__ int   g_k0[NT], g_k1[NT];

static __device__ float g_Psum[NE];
static __device__ float g_fcnt[NE];
static __device__ float g_zsum;

// ---------------- PTX helpers ----------------
__device__ __forceinline__ uint32_t smem_u32(const void* p) {
    uint32_t a;
    asm("{ .reg .u64 t; cvta.to.shared.u64 t, %1; cvt.u32.u64 %0, t; }" : "=r"(a) : "l"(p));
    return a;
}
__device__ __forceinline__ void cp16(uint32_t dst, const void* src) {
    asm volatile("cp.async.cg.shared.global [%0], [%1], 16;" :: "r"(dst), "l"(src));
}
__device__ __forceinline__ void ldmA(uint32_t* a, uint32_t addr) {
    asm volatile("ldmatrix.sync.aligned.m8n8.x4.shared.b16 {%0,%1,%2,%3}, [%4];"
        : "=r"(a[0]), "=r"(a[1]), "=r"(a[2]), "=r"(a[3]) : "r"(addr));
}
__device__ __forceinline__ void ldmT(uint32_t* a, uint32_t addr) {
    asm volatile("ldmatrix.sync.aligned.m8n8.x4.trans.shared.b16 {%0,%1,%2,%3}, [%4];"
        : "=r"(a[0]), "=r"(a[1]), "=r"(a[2]), "=r"(a[3]) : "r"(addr));
}
__device__ __forceinline__ void mma_bf16(float* d, const uint32_t* a, const uint32_t* b) {
    asm volatile(
        "mma.sync.aligned.m16n8k16.row.col.f32.bf16.bf16.f32 "
        "{%0,%1,%2,%3}, {%4,%5,%6,%7}, {%8,%9}, {%0,%1,%2,%3};"
        : "+f"(d[0]), "+f"(d[1]), "+f"(d[2]), "+f"(d[3])
        : "r"(a[0]), "r"(a[1]), "r"(a[2]), "r"(a[3]), "r"(b[0]), "r"(b[1]));
}
__device__ __forceinline__ uint32_t packbf(float a, float b) {
    __nv_bfloat162 v = __float22bfloat162_rn(make_float2(a, b));
    return *(uint32_t*)&v;
}

// ---------------- GEMM via mma.sync ----------------
// C[M,N] = A[M,K] @ B^T.  NSEG=3: (Ah,Bh)+(Ah,Bl)+(Al,Bh). NSEG=2: (Ah,Bh)+(Ah,Bl).
// OUTBF: 0 = fp32 out, 1 = bf16 out.
#define BK 32
#define ROWB 80
#define STAGEB (128*ROWB)
#define STAGE2 (2*STAGEB)

template <int NSEG, int OUTBF>
__global__ __launch_bounds__(256, 1) void gemm_mma_kernel(
    const __nv_bfloat16* __restrict__ Ah, const __nv_bfloat16* __restrict__ Al,
    const __nv_bfloat16* __restrict__ Bh, const __nv_bfloat16* __restrict__ Bl,
    const float* __restrict__ bias, void* __restrict__ Cv,
    int M, int N, int K, size_t sA, size_t sB, size_t sC)
{
    extern __shared__ char sm_[];
    uint32_t smb = smem_u32(sm_);

    int t = threadIdx.x, lane = t & 31, wid = t >> 5;
    int n0 = blockIdx.x * 128, m0 = blockIdx.y * 128;
    Ah += blockIdx.z * sA; Al += blockIdx.z * sA;
    Bh += blockIdx.z * sB; Bl += blockIdx.z * sB;

    int wm = (wid & 3) * 32;
    int wn = (wid >> 2) * 64;

    const __nv_bfloat16* Aseg[3];
    const __nv_bfloat16* Bseg[3];
    Aseg[0] = Ah; Bseg[0] = Bh;
    Aseg[1] = Ah; Bseg[1] = Bl;
    Aseg[2] = (NSEG == 3) ? Al : Ah; Bseg[2] = Bh;
    const int KC = K / BK;
    const int NC = NSEG * KC;

    float acc[2][8][4];
#pragma unroll
    for (int i = 0; i < 2; i++)
#pragma unroll
        for (int j = 0; j < 8; j++)
#pragma unroll
            for (int q = 0; q < 4; q++) acc[i][j][q] = 0.f;

    int r0i = t >> 2, s0i = t & 3;
    int r1i = (t + 256) >> 2, s1i = t & 3;

    {
        const __nv_bfloat16* pA = Aseg[0];
        const __nv_bfloat16* pB = Bseg[0];
        uint32_t ab = smb;
        cp16(ab + r0i * ROWB + s0i * 16, pA + (size_t)(m0 + r0i) * K + s0i * 8);
        cp16(ab + r1i * ROWB + s1i * 16, pA + (size_t)(m0 + r1i) * K + s1i * 8);
        uint32_t bb = smb + STAGEB;
        cp16(bb + r0i * ROWB + s0i * 16, pB + (size_t)(n0 + r0i) * K + s0i * 8);
        cp16(bb + r1i * ROWB + s1i * 16, pB + (size_t)(n0 + r1i) * K + s1i * 8);
        asm volatile("cp.async.commit_group;");
    }

    int nq = lane >> 2, kr = lane & 3;

    for (int c = 0; c < NC; c++) {
        if (c + 1 < NC) {
            int cn = c + 1;
            int seg = cn / KC, kc = (cn - seg * KC) * BK;
            const __nv_bfloat16* pA = Aseg[seg];
            const __nv_bfloat16* pB = Bseg[seg];
            uint32_t ab = smb + (cn & 1) * STAGE2;
            cp16(ab + r0i * ROWB + s0i * 16, pA + (size_t)(m0 + r0i) * K + kc + s0i * 8);
            cp16(ab + r1i * ROWB + s1i * 16, pA + (size_t)(m0 + r1i) * K + kc + s1i * 8);
            uint32_t bb = ab + STAGEB;
            cp16(bb + r0i * ROWB + s0i * 16, pB + (size_t)(n0 + r0i) * K + kc + s0i * 8);
            cp16(bb + r1i * ROWB + s1i * 16, pB + (size_t)(n0 + r1i) * K + kc + s1i * 8);
            asm volatile("cp.async.commit_group;");
            asm volatile("cp.async.wait_group 1;");
        } else {
            asm volatile("cp.async.wait_group 0;");
        }
        __syncthreads();

        uint32_t ab = smb + (c & 1) * STAGE2;
        const char* bbp = sm_ + (c & 1) * STAGE2 + STAGEB;

        uint32_t afr[2][2][4];
#pragma unroll
        for (int mt = 0; mt < 2; mt++)
#pragma unroll
            for (int ks = 0; ks < 2; ks++) {
                uint32_t addr = ab + (wm + mt * 16 + (lane & 15)) * ROWB
                              + (ks * 16 + (lane >> 4) * 8) * 2;
                ldmA(afr[mt][ks], addr);
            }
        uint32_t bfr[2][8][2];
#pragma unroll
        for (int ks = 0; ks < 2; ks++)
#pragma unroll
            for (int nt = 0; nt < 8; nt++) {
                const char* p = bbp + (wn + nt * 8 + nq) * ROWB + ks * 32 + kr * 4;
                bfr[ks][nt][0] = *(const uint32_t*)p;
                bfr[ks][nt][1] = *(const uint32_t*)(p + 16);
            }
#pragma unroll
        for (int ks = 0; ks < 2; ks++)
#pragma unroll
            for (int mt = 0; mt < 2; mt++)
#pragma unroll
                for (int nt = 0; nt < 8; nt++)
                    mma_bf16(acc[mt][nt], afr[mt][ks], bfr[ks][nt]);
        __syncthreads();
    }

    // epilogue
#pragma unroll
    for (int mt = 0; mt < 2; mt++) {
        int m = m0 + wm + mt * 16 + (lane >> 2);
#pragma unroll
        for (int nt = 0; nt < 8; nt++) {
            int n = n0 + wn + nt * 8 + (lane & 3) * 2;
            float bv0 = bias ? bias[n] : 0.f;
            float bv1 = bias ? bias[n + 1] : 0.f;
            if (OUTBF) {
                __nv_bfloat16* C = (__nv_bfloat16*)Cv + blockIdx.z * sC;
                __nv_bfloat162 lo = __float22bfloat162_rn(
                    make_float2(acc[mt][nt][0] + bv0, acc[mt][nt][1] + bv1));
                __nv_bfloat162 hi = __float22bfloat162_rn(
                    make_float2(acc[mt][nt][2] + bv0, acc[mt][nt][3] + bv1));
                *(__nv_bfloat162*)&C[(size_t)m * N + n]       = lo;
                *(__nv_bfloat162*)&C[(size_t)(m + 8) * N + n] = hi;
            } else {
                float* C = (float*)Cv + blockIdx.z * sC;
                float2 lo = make_float2(acc[mt][nt][0] + bv0, acc[mt][nt][1] + bv1);
                float2 hi = make_float2(acc[mt][nt][2] + bv0, acc[mt][nt][3] + bv1);
                *(float2*)&C[(size_t)m * N + n]       = lo;
                *(float2*)&C[(size_t)(m + 8) * N + n] = hi;
            }
        }
    }
}

// ---------------- expert flash: bf16 mma, fp32 online softmax ----------------
// Q/K/V/O bf16 [slice: sb rows CAP x 1024, head offset h*128]. Br=Bc=64, HD=128.
// 8 warps: S warp grid 4m x 2n (wm=(wid&3)*16, wn2=(wid>>2)*32).
#define EF_PITCH 272
#define EF_QS 0
#define EF_KS 17408
#define EF_VS 34816
#define EF_OB 52224
#define EF_MS 86016
#define EF_LS 86272
#define EF_AS 86528
#define EF_RM 86784
#define EF_RS 87296
#define EF_SMEM 87808

__global__ __launch_bounds__(256) void eflash_kernel(
    const __nv_bfloat16* __restrict__ Q, const __nv_bfloat16* __restrict__ K,
    const __nv_bfloat16* __restrict__ V, __nv_bfloat16* __restrict__ O,
    float scale)
{
    extern __shared__ char sm_[];
    float* Obuf = (float*)(sm_ + EF_OB);   // 64 x 132
    float* m_s  = (float*)(sm_ + EF_MS);
    float* l_s  = (float*)(sm_ + EF_LS);
    float* a_s  = (float*)(sm_ + EF_AS);
    float* redm = (float*)(sm_ + EF_RM);   // [2][64]
    float* reds = (float*)(sm_ + EF_RS);   // [2][64]
    uint32_t smb = smem_u32(sm_);

    int t = threadIdx.x, lane = t & 31, wid = t >> 5;
    int half = wid >> 2, wm = (wid & 3) * 16, wn2 = half * 32;
    int slice = blockIdx.y;
    int sb = slice >> 3, h = slice & 7;
    size_t base = (size_t)sb * CAP * 1024 + (size_t)h * HDM;
    int q0 = blockIdx.x * 64;

    // load Q tile: 64 rows x 128 bf16 (16 chunks of 16B per row)
#pragma unroll
    for (int j = 0; j < 4; j++) {
        int id = t + 256 * j;
        int r = id >> 4, c = id & 15;
        *(uint4*)(sm_ + EF_QS + r * EF_PITCH + c * 16) =
            *(const uint4*)(Q + base + (size_t)(q0 + r) * 1024 + c * 8);
    }
    if (t < 64) { m_s[t] = -1e30f; l_s[t] = 0.f; }

    float o[16][4];
#pragma unroll
    for (int i = 0; i < 16; i++)
#pragma unroll
        for (int q = 0; q < 4; q++) o[i][q] = 0.f;

    int rl = wm + (lane >> 2), rh = rl + 8;
    int nq = lane >> 2, kr = lane & 3;

    for (int kt = 0; kt < CAP / 64; kt++) {
        __syncthreads();
#pragma unroll
        for (int j = 0; j < 4; j++) {
            int id = t + 256 * j;
            int r = id >> 4, c = id & 15;
            *(uint4*)(sm_ + EF_KS + r * EF_PITCH + c * 16) =
                *(const uint4*)(K + base + (size_t)(kt * 64 + r) * 1024 + c * 8);
            *(uint4*)(sm_ + EF_VS + r * EF_PITCH + c * 16) =
                *(const uint4*)(V + base + (size_t)(kt * 64 + r) * 1024 + c * 8);
        }
        __syncthreads();

        // S = Q @ K^T  (64x64, K=128)
        float s[4][4];
#pragma unroll
        for (int nt = 0; nt < 4; nt++)
#pragma unroll
            for (int q = 0; q < 4; q++) s[nt][q] = 0.f;
#pragma unroll
        for (int ks = 0; ks < 8; ks++) {
            uint32_t af[4];
            ldmA(af, smb + EF_QS + (wm + (lane & 15)) * EF_PITCH + ks * 32 + (lane >> 4) * 16);
#pragma unroll
            for (int nt = 0; nt < 4; nt++) {
                const char* p = sm_ + EF_KS + (wn2 + nt * 8 + nq) * EF_PITCH + ks * 32 + kr * 4;
                uint32_t bb[2];
                bb[0] = *(const uint32_t*)p;
                bb[1] = *(const uint32_t*)(p + 16);
                mma_bf16(s[nt], af, bb);
            }
        }

        // scale + row max (thread-local, quad reduce)
        float mxlo = -1e30f, mxhi = -1e30f;
#pragma unroll
        for (int nt = 0; nt < 4; nt++) {
            s[nt][0] *= scale; s[nt][1] *= scale; s[nt][2] *= scale; s[nt][3] *= scale;
            mxlo = fmaxf(mxlo, fmaxf(s[nt][0], s[nt][1]));
            mxhi = fmaxf(mxhi, fmaxf(s[nt][2], s[nt][3]));
        }
        mxlo = fmaxf(mxlo, __shfl_xor_sync(0xffffffff, mxlo, 1));
        mxlo = fmaxf(mxlo, __shfl_xor_sync(0xffffffff, mxlo, 2));
        mxhi = fmaxf(mxhi, __shfl_xor_sync(0xffffffff, mxhi, 1));
        mxhi = fmaxf(mxhi, __shfl_xor_sync(0xffffffff, mxhi, 2));
        if ((lane & 3) == 0) { redm[half * 64 + rl] = mxlo; redm[half * 64 + rh] = mxhi; }
        __syncthreads();
        if (t < 64) {
            float mo = m_s[t];
            float mn = fmaxf(mo, fmaxf(redm[t], redm[64 + t]));
            float al = __expf(mo - mn);
            a_s[t] = al; m_s[t] = mn; l_s[t] *= al;
        }
        __syncthreads();

        float mlo = m_s[rl], mhi = m_s[rh], alo = a_s[rl], ahi = a_s[rh];
        float slo = 0.f, shi = 0.f;
        uint32_t afr[2][4];
#pragma unroll
        for (int ks = 0; ks < 2; ks++) {
#pragma unroll
            for (int jj = 0; jj < 2; jj++) {
                int nt = ks * 2 + jj;
                float p0 = __expf(s[nt][0] - mlo), p1 = __expf(s[nt][1] - mlo);
                float p2 = __expf(s[nt][2] - mhi), p3 = __expf(s[nt][3] - mhi);
                slo += p0 + p1; shi += p2 + p3;
                afr[ks][jj * 2 + 0] = packbf(p0, p1);   // a0 / a2
                afr[ks][jj * 2 + 1] = packbf(p2, p3);   // a1 / a3
            }
            // reorder: need {a0,a1,a2,a3} = {lo(nt=2ks), hi(2ks), lo(2ks+1), hi(2ks+1)}
        }
        slo += __shfl_xor_sync(0xffffffff, slo, 1);
        slo += __shfl_xor_sync(0xffffffff, slo, 2);
        shi += __shfl_xor_sync(0xffffffff, shi, 1);
        shi += __shfl_xor_sync(0xffffffff, shi, 2);
        if ((lane & 3) == 0) { reds[half * 64 + rl] = slo; reds[half * 64 + rh] = shi; }

        // rescale O accumulators
#pragma unroll
        for (int nt = 0; nt < 16; nt++) {
            o[nt][0] *= alo; o[nt][1] *= alo; o[nt][2] *= ahi; o[nt][3] *= ahi;
        }

        // O += P @ V   (warp k-range = its 32 S-cols; V rows wn2..wn2+31 of tile)
#pragma unroll
        for (int ks = 0; ks < 2; ks++) {
#pragma unroll
            for (int nb = 0; nb < 8; nb++) {
                uint32_t b4[4];
                ldmT(b4, smb + EF_VS + (wn2 + ks * 16 + (lane & 15)) * EF_PITCH
                         + nb * 32 + (lane >> 4) * 16);
                mma_bf16(o[2 * nb],     afr[ks], b4);
                mma_bf16(o[2 * nb + 1], afr[ks], b4 + 2);
            }
        }
        __syncthreads();
        if (t < 64) l_s[t] += reds[t] + reds[64 + t];
    }

    // cross-warp partial-O reduction + store
    __syncthreads();
    if (half == 0) {
#pragma unroll
        for (int nt = 0; nt < 16; nt++) {
            float* plo = Obuf + rl * 132 + nt * 8 + (lane & 3) * 2;
            float* phi = Obuf + rh * 132 + nt * 8 + (lane & 3) * 2;
            plo[0] = o[nt][0]; plo[1] = o[nt][1];
            phi[0] = o[nt][2]; phi[1] = o[nt][3];
        }
    }
    __syncthreads();
    if (half == 1) {
#pragma unroll
        for (int nt = 0; nt < 16; nt++) {
            float* plo = Obuf + rl * 132 + nt * 8 + (lane & 3) * 2;
            float* phi = Obuf + rh * 132 + nt * 8 + (lane & 3) * 2;
            plo[0] += o[nt][0]; plo[1] += o[nt][1];
            phi[0] += o[nt][2]; phi[1] += o[nt][3];
        }
    }
    __syncthreads();
#pragma unroll
    for (int j = 0; j < 16; j++) {
        int id = t + 256 * j;
        int r = id >> 6, cp = id & 63;
        float inv = 1.f / l_s[r];
        float2 v = *(float2*)(Obuf + r * 132 + cp * 2);
        __nv_bfloat162 ob = __float22bfloat162_rn(make_float2(v.x * inv, v.y * inv));
        *(__nv_bfloat162*)(O + base + (size_t)(q0 + r) * 1024 + cp * 2) = ob;
    }
}

// ---------------- fp32 -> bf16 hi/lo split ----------------
__device__ __forceinline__ void split4(float4 v, uint2& hh, uint2& ll) {
    __nv_bfloat16 h0 = __float2bfloat16(v.x), h1 = __float2bfloat16(v.y);
    __nv_bfloat16 h2 = __float2bfloat16(v.z), h3 = __float2bfloat16(v.w);
    __nv_bfloat16 l0 = __float2bfloat16(v.x - __bfloat162float(h0));
    __nv_bfloat16 l1 = __float2bfloat16(v.y - __bfloat162float(h1));
    __nv_bfloat16 l2 = __float2bfloat16(v.z - __bfloat162float(h2));
    __nv_bfloat16 l3 = __float2bfloat16(v.w - __bfloat162float(h3));
    hh.x = (uint32_t)__bfloat16_as_ushort(h0) | ((uint32_t)__bfloat16_as_ushort(h1) << 16);
    hh.y = (uint32_t)__bfloat16_as_ushort(h2) | ((uint32_t)__bfloat16_as_ushort(h3) << 16);
    ll.x = (uint32_t)__bfloat16_as_ushort(l0) | ((uint32_t)__bfloat16_as_ushort(l1) << 16);
    ll.y = (uint32_t)__bfloat16_as_ushort(l2) | ((uint32_t)__bfloat16_as_ushort(l3) << 16);
}

__global__ __launch_bounds__(256) void csplit_kernel(
    const float4* __restrict__ s, uint2* __restrict__ h, uint2* __restrict__ l, int n4)
{
    int i = blockIdx.x * 256 + threadIdx.x;
    if (i >= n4) return;
    uint2 hh, ll;
    split4(s[i], hh, ll);
    h[i] = hh; l[i] = ll;
}

// ---------------- weight transpose + split ----------------
__global__ void wtrans_kernel(const float* __restrict__ W,
                              __nv_bfloat16* __restrict__ Th,
                              __nv_bfloat16* __restrict__ Tl, int Kd, int Nd)
{
    __shared__ float tile[32][33];
    int tx = threadIdx.x, ty = threadIdx.y;
    int n0 = blockIdx.x * 32, k0 = blockIdx.y * 32;
    size_t ob = (size_t)blockIdx.z * Kd * Nd;
    const float* Wb = W + ob;
#pragma unroll
    for (int r = 0; r < 4; r++)
        tile[ty + 8 * r][tx] = Wb[(size_t)(k0 + ty + 8 * r) * Nd + n0 + tx];
    __syncthreads();
#pragma unroll
    for (int r = 0; r < 4; r++) {
        float v = tile[tx][ty + 8 * r];
        __nv_bfloat16 h = __float2bfloat16(v);
        Th[ob + (size_t)(n0 + ty + 8 * r) * Kd + k0 + tx] = h;
        Tl[ob + (size_t)(n0 + ty + 8 * r) * Kd + k0 + tx] =
            __float2bfloat16(v - __bfloat162float(h));
    }
}

// ---------------- zero kernels ----------------
__global__ void zero_stats_kernel() {
    int t = threadIdx.x;
    if (t < NE) { g_Psum[t] = 0.f; g_fcnt[t] = 0.f; }
    if (t == 0) g_zsum = 0.f;
}

__global__ void zero_ein_kernel() {
    size_t n = EINSZ / 8;
    uint4 z = make_uint4(0, 0, 0, 0);
    uint4* ph = (uint4*)g_einh;
    for (size_t i = blockIdx.x * (size_t)blockDim.x + threadIdx.x; i < n;
         i += (size_t)gridDim.x * blockDim.x) ph[i] = z;
}

// ---------------- main flash attention (fp32 SIMT) ----------------
template <int HD>
__global__ __launch_bounds__(256) void flash_kernel(
    const float* __restrict__ Q, const float* __restrict__ K,
    const float* __restrict__ V, float* __restrict__ O,
    int seq, int nheads, float scale)
{
    constexpr int CPT = HD / 16;
    constexpr int LDQ = HD + 1;
    extern __shared__ float sm[];
    float* Qs  = sm;
    float* Ks  = Qs + 64 * LDQ;
    float* Vs  = Ks + 64 * LDQ;
    float* Ss  = Vs + 64 * LDQ;
    float* m_s = Ss + 64 * 66;
    float* l_s = m_s + 64;
    float* a_s = l_s + 64;
    float* red = a_s + 64;

    int t  = threadIdx.x;
    int tx = t & 15, ty = t >> 4;
    int slice = blockIdx.y;
    int sb = slice / nheads, h = slice % nheads;
    int ld = nheads * HD;
    size_t base = (size_t)sb * seq * ld + (size_t)h * HD;
    int q0 = blockIdx.x * 64;

    for (int idx = t; idx < 64 * HD; idx += 256) {
        int r = idx / HD, c = idx % HD;
        Qs[r * LDQ + c] = Q[base + (size_t)(q0 + r) * ld + c];
    }
    if (t < 64) { m_s[t] = -1e30f; l_s[t] = 0.f; }

    float acc[4][CPT];
#pragma unroll
    for (int i = 0; i < 4; i++)
#pragma unroll
        for (int j = 0; j < CPT; j++) acc[i][j] = 0.f;
    __syncthreads();

    int r  = t >> 2;
    int qq = t & 3;

    for (int kt = 0; kt < seq; kt += 64) {
        for (int idx = t; idx < 64 * HD; idx += 256) {
            int rr = idx / HD, c = idx % HD;
            Ks[rr * LDQ + c] = K[base + (size_t)(kt + rr) * ld + c];
            Vs[rr * LDQ + c] = V[base + (size_t)(kt + rr) * ld + c];
        }
        __syncthreads();

        float s[4][4];
#pragma unroll
        for (int i = 0; i < 4; i++)
#pragma unroll
            for (int j = 0; j < 4; j++) s[i][j] = 0.f;
#pragma unroll 4
        for (int kk = 0; kk < HD; kk++) {
            float a[4], b[4];
#pragma unroll
            for (int i = 0; i < 4; i++) a[i] = Qs[(ty * 4 + i) * LDQ + kk];
#pragma unroll
            for (int j = 0; j < 4; j++) b[j] = Ks[(tx * 4 + j) * LDQ + kk];
#pragma unroll
            for (int i = 0; i < 4; i++)
#pragma unroll
                for (int j = 0; j < 4; j++) s[i][j] += a[i] * b[j];
        }
#pragma unroll
        for (int i = 0; i < 4; i++)
#pragma unroll
            for (int j = 0; j < 4; j++)
                Ss[(ty * 4 + i) * 66 + tx * 4 + j] = s[i][j] * scale;
        __syncthreads();

        float pm = -1e30f;
        for (int c = qq * 16; c < qq * 16 + 16; c++) pm = fmaxf(pm, Ss[r * 66 + c]);
        red[t] = pm;
        __syncthreads();
        if (t < 64) {
            float mx = fmaxf(fmaxf(red[t * 4], red[t * 4 + 1]),
                             fmaxf(red[t * 4 + 2], red[t * 4 + 3]));
            float mn = fmaxf(m_s[t], mx);
            a_s[t] = __expf(m_s[t] - mn);
            m_s[t] = mn;
        }
        __syncthreads();

#pragma unroll
        for (int i = 0; i < 4; i++) {
            float al = a_s[ty * 4 + i];
#pragma unroll
            for (int j = 0; j < CPT; j++) acc[i][j] *= al;
        }

        float mrow = m_s[r];
        float ps = 0.f;
        for (int c = qq * 16; c < qq * 16 + 16; c++) {
            float p = __expf(Ss[r * 66 + c] - mrow);
            Ss[r * 66 + c] = p;
            ps += p;
        }
        red[t] = ps;
        __syncthreads();
        if (t < 64)
            l_s[t] = l_s[t] * a_s[t] + red[t * 4] + red[t * 4 + 1] + red[t * 4 + 2] + red[t * 4 + 3];

#pragma unroll 2
        for (int c2 = 0; c2 < 64; c2++) {
            float p[4];
#pragma unroll
            for (int i = 0; i < 4; i++) p[i] = Ss[(ty * 4 + i) * 66 + c2];
#pragma unroll
            for (int j = 0; j < CPT; j++) {
                float vv = Vs[c2 * LDQ + tx * CPT + j];
#pragma unroll
                for (int i = 0; i < 4; i++) acc[i][j] += p[i] * vv;
            }
        }
        __syncthreads();
    }

#pragma unroll
    for (int i = 0; i < 4; i++) {
        float inv = 1.f / l_s[ty * 4 + i];
#pragma unroll
        for (int j = 0; j < CPT; j++)
            O[base + (size_t)(q0 + ty * 4 + i) * ld + tx * CPT + j] = acc[i][j] * inv;
    }
}

// ---------------- block reduce ----------------
__device__ __forceinline__ void block_reduce2(float& s, float& s2) {
    __shared__ float rs[8], rs2[8];
#pragma unroll
    for (int o = 16; o > 0; o >>= 1) {
        s  += __shfl_xor_sync(0xffffffff, s, o);
        s2 += __shfl_xor_sync(0xffffffff, s2, o);
    }
    int lane = threadIdx.x & 31, w = threadIdx.x >> 5;
    if (lane == 0) { rs[w] = s; rs2[w] = s2; }
    __syncthreads();
    float ts = 0.f, ts2 = 0.f;
#pragma unroll
    for (int i = 0; i < 8; i++) { ts += rs[i]; ts2 += rs2[i]; }
    s = ts; s2 = ts2;
}

// ---------------- LN1 ----------------
__global__ __launch_bounds__(256) void ln1_kernel(
    const float* __restrict__ x, const float* __restrict__ g,
    const float* __restrict__ b)
{
    size_t tok = blockIdx.x;
    int t = threadIdx.x;
    float v[4], s = 0.f, s2 = 0.f;
#pragma unroll
    for (int u = 0; u < 4; u++) {
        int j = t + u * 256;
        float val = x[tok * Dm + j] + g_attn[tok * Dm + j];
        v[u] = val; s += val; s2 += val * val;
    }
    block_reduce2(s, s2);
    float mean = s * (1.f / Dm);
    float var  = s2 * (1.f / Dm) - mean * mean;
    float inv  = rsqrtf(var + 1e-5f);
#pragma unroll
    for (int u = 0; u < 4; u++) {
        int j = t + u * 256;
        g_x1[tok * Dm + j] = (v[u] - mean) * inv * g[j] + b[j];
    }
}

// ---------------- gate ----------------
__global__ __launch_bounds__(256) void gate_kernel(const float* __restrict__ gateW) {
    int warp = threadIdx.x >> 5, lane = threadIdx.x & 31;
    int tok = blockIdx.x * 8 + warp;
    const float* xr = g_x1 + (size_t)tok * Dm;
    float acc[NE];
#pragma unroll
    for (int e = 0; e < NE; e++) acc[e] = 0.f;
    for (int k = lane; k < Dm; k += 32) {
        float xv = xr[k];
        const float* wr = gateW + (size_t)k * NE;
#pragma unroll
        for (int e = 0; e < NE; e++) acc[e] += xv * wr[e];
    }
#pragma unroll
    for (int e = 0; e < NE; e++)
#pragma unroll
        for (int o = 16; o > 0; o >>= 1)
            acc[e] += __shfl_xor_sync(0xffffffff, acc[e], o);
    if (lane == 0) {
        float mx = acc[0];
#pragma unroll
        for (int e = 1; e < NE; e++) mx = fmaxf(mx, acc[e]);
        float p[NE], se = 0.f;
#pragma unroll
        for (int e = 0; e < NE; e++) { p[e] = __expf(acc[e] - mx); se += p[e]; }
        float invs = 1.f / se;
        float lse = mx + logf(se);
        atomicAdd(&g_zsum, lse * lse);
        int i0 = 0, i1 = -1;
        float b0 = -1.f, b1 = -1.f;
#pragma unroll
        for (int e = 0; e < NE; e++) {
            float pe = p[e] * invs;
            atomicAdd(&g_Psum[e], pe);
            if (pe > b0) { b1 = b0; i1 = i0; b0 = pe; i0 = e; }
            else if (pe > b1) { b1 = pe; i1 = e; }
        }
        atomicAdd(&g_fcnt[i0], 1.f);
        g_i0[tok] = i0; g_i1[tok] = i1;
        g_g0[tok] = b0; g_g1[tok] = b1;
    }
}

// ---------------- routing positions ----------------
__global__ __launch_bounds__(256) void pos_kernel() {
    int warp = threadIdx.x >> 5, lane = threadIdx.x & 31;
    if (warp >= Bt) return;
    int b = warp;
    unsigned lt = (1u << lane) - 1u;
    int cnt[NE];
#pragma unroll
    for (int e = 0; e < NE; e++) cnt[e] = 0;

    for (int ch = 0; ch < Sq / 32; ch++) {
        int tok = b * Sq + ch * 32 + lane;
        int e0 = g_i0[tok];
        int myp = 0;
#pragma unroll
        for (int e = 0; e < NE; e++) {
            unsigned m = __ballot_sync(0xffffffff, e0 == e);
            if (e0 == e) myp = cnt[e] + __popc(m & lt);
            cnt[e] += __popc(m);
        }
        g_k0[tok] = (myp < CAP) ? 1 : 0;
        g_p0[tok] = min(myp, CAP - 1);
    }
    for (int ch = 0; ch < Sq / 32; ch++) {
        int tok = b * Sq + ch * 32 + lane;
        int e1 = g_i1[tok];
        bool valid = g_g1[tok] > 0.2f;
        int myp = 0;
#pragma unroll
        for (int e = 0; e < NE; e++) {
            unsigned m = __ballot_sync(0xffffffff, valid && (e1 == e));
            if (valid && (e1 == e)) myp = cnt[e] + __popc(m & lt);
            cnt[e] += __popc(m);
        }
        bool keep = valid && (myp < CAP);
        g_k1[tok] = keep ? 1 : 0;
        g_p1[tok] = valid ? min(myp, CAP - 1) : 0;
    }
}

// ---------------- scatter (x1 fp32 -> einh bf16) ----------------
__global__ __launch_bounds__(256) void scatter_kernel() {
    int idx = blockIdx.x;
    int tok = idx >> 1, slot = idx & 1;
    int keep = slot ? g_k1[tok] : g_k0[tok];
    if (!keep) return;
    int e = slot ? g_i1[tok] : g_i0[tok];
    int p = slot ? g_p1[tok] : g_p0[tok];
    int b = tok / Sq;
    const float4* src = (const float4*)(g_x1 + (size_t)tok * Dm);
    size_t ro = (((size_t)e * Bt + b) * CAP + p) * Dm;
    uint2* dh = (uint2*)(g_einh + ro);
    uint2 hh, ll;
    split4(src[threadIdx.x], hh, ll);
    dh[threadIdx.x] = hh;
}

// ---------------- combine + LN2 ----------------
__global__ __launch_bounds__(256) void combine_ln_kernel(
    const float* __restrict__ g2, const float* __restrict__ b2,
    float* __restrict__ out)
{
    size_t tok = blockIdx.x;
    int t = threadIdx.x;
    int b = (int)(tok >> 10);
    float w0 = g_k0[tok] ? g_g0[tok] : 0.f;
    float w1 = g_k1[tok] ? g_g1[tok] : 0.f;
    const float* r0 = g_eout + (((size_t)g_i0[tok] * Bt + b) * CAP + g_p0[tok]) * Dm;
    const float* r1 = g_eout + (((size_t)g_i1[tok] * Bt + b) * CAP + g_p1[tok]) * Dm;

    float v[4], s = 0.f, s2 = 0.f;
#pragma unroll
    for (int u = 0; u < 4; u++) {
        int j = t + u * 256;
        float val = g_x1[tok * Dm + j] + w0 * r0[j] + w1 * r1[j];
        v[u] = val; s += val; s2 += val * val;
    }
    block_reduce2(s, s2);
    float mean = s * (1.f / Dm);
    float var  = s2 * (1.f / Dm) - mean * mean;
    float inv  = rsqrtf(var + 1e-5f);
#pragma unroll
    for (int u = 0; u < 4; u++) {
        int j = t + u * 256;
        out[tok * Dm + j] = (v[u] - mean) * inv * g2[j] + b2[j];
    }
}

// ---------------- finalize aux ----------------
__global__ void finalize_kernel(float* __restrict__ out) {
    if (threadIdx.x == 0 && blockIdx.x == 0) {
        float invN = 1.f / (float)NT;
        float sfp = 0.f;
#pragma unroll
        for (int e = 0; e < NE; e++)
            sfp += (g_fcnt[e] * invN) * (g_Psum[e] * invN);
        float bal = 0.01f * (float)NE * sfp;
        float zl  = 0.001f * g_zsum * invN;
        out[NTD + 0] = bal + zl;
        out[NTD + 1] = bal;
        out[NTD + 2] = zl;
    }
}

// ---------------- host launcher ----------------
extern "C" void kernel_launch(void* const* d_in, const int* in_sizes, int n_in,
                              void* d_out, int out_size)
{
    const float* x      = (const float*)d_in[0];
    const float* Wq     = (const float*)d_in[1];
    const float* Wk     = (const float*)d_in[2];
    const float* Wv     = (const float*)d_in[3];
    const float* Wo     = (const float*)d_in[4];
    const float* bq     = (const float*)d_in[5];
    const float* bk     = (const float*)d_in[6];
    const float* bv     = (const float*)d_in[7];
    const float* bo     = (const float*)d_in[8];
    const float* ln1_g  = (const float*)d_in[9];
    const float* ln1_b  = (const float*)d_in[10];
    const float* ln2_g  = (const float*)d_in[11];
    const float* ln2_b  = (const float*)d_in[12];
    const float* gate_W = (const float*)d_in[13];
    const float* eWq    = (const float*)d_in[14];
    const float* eWk    = (const float*)d_in[15];
    const float* eWv    = (const float*)d_in[16];
    const float* eWo    = (const float*)d_in[17];
    float* out = (float*)d_out;

    void *pq, *pk, *pv, *po, *pattn, *px1, *peout;
    void *pxh, *pxl, *poh, *pol, *peinh, *peqh, *pekh, *pevh, *peoh;
    void *pwqh, *pwql, *pwkh, *pwkl, *pwvh, *pwvl, *pwoh, *pwol;
    void *pewqh, *pewql, *pewkh, *pewkl, *pewvh, *pewvl, *pewoh, *pewol;
    cudaGetSymbolAddress(&pq, g_q);       cudaGetSymbolAddress(&pk, g_k);
    cudaGetSymbolAddress(&pv, g_v);       cudaGetSymbolAddress(&po, g_o);
    cudaGetSymbolAddress(&pattn, g_attn); cudaGetSymbolAddress(&px1, g_x1);
    cudaGetSymbolAddress(&peout, g_eout);
    cudaGetSymbolAddress(&pxh, g_xh);     cudaGetSymbolAddress(&pxl, g_xl);
    cudaGetSymbolAddress(&poh, g_oh);     cudaGetSymbolAddress(&pol, g_ol);
    cudaGetSymbolAddress(&peinh, g_einh);
    cudaGetSymbolAddress(&peqh, g_eqh);   cudaGetSymbolAddress(&pekh, g_ekh);
    cudaGetSymbolAddress(&pevh, g_evh);   cudaGetSymbolAddress(&peoh, g_eoh);
    cudaGetSymbolAddress(&pwqh, g_wqh);   cudaGetSymbolAddress(&pwql, g_wql);
    cudaGetSymbolAddress(&pwkh, g_wkh);   cudaGetSymbolAddress(&pwkl, g_wkl);
    cudaGetSymbolAddress(&pwvh, g_wvh);   cudaGetSymbolAddress(&pwvl, g_wvl);
    cudaGetSymbolAddress(&pwoh, g_woh);   cudaGetSymbolAddress(&pwol, g_wol);
    cudaGetSymbolAddress(&pewqh, g_ewqh); cudaGetSymbolAddress(&pewql, g_ewql);
    cudaGetSymbolAddress(&pewkh, g_ewkh); cudaGetSymbolAddress(&pewkl, g_ewkl);
    cudaGetSymbolAddress(&pewvh, g_ewvh); cudaGetSymbolAddress(&pewvl, g_ewvl);
    cudaGetSymbolAddress(&pewoh, g_ewoh); cudaGetSymbolAddress(&pewol, g_ewol);

    const int GEMM_SMEM = 2 * STAGE2;
    cudaFuncSetAttribute(gemm_mma_kernel<3,0>, cudaFuncAttributeMaxDynamicSharedMemorySize, GEMM_SMEM);
    cudaFuncSetAttribute(gemm_mma_kernel<2,1>, cudaFuncAttributeMaxDynamicSharedMemorySize, GEMM_SMEM);
    cudaFuncSetAttribute(gemm_mma_kernel<2,0>, cudaFuncAttributeMaxDynamicSharedMemorySize, GEMM_SMEM);
    const int SMEM64 = (64 * 65 * 3 + 64 * 66 + 192 + 256) * 4;
    cudaFuncSetAttribute(flash_kernel<HD1>, cudaFuncAttributeMaxDynamicSharedMemorySize, SMEM64);
    cudaFuncSetAttribute(eflash_kernel, cudaFuncAttributeMaxDynamicSharedMemorySize, EF_SMEM);

    zero_stats_kernel<<<1, 32>>>();
    zero_ein_kernel<<<2048, 256>>>();

    dim3 tb(32, 8);
    wtrans_kernel<<<dim3(32, 32, 1), tb>>>(Wq, (__nv_bfloat16*)pwqh, (__nv_bfloat16*)pwql, Dm, Dm);
    wtrans_kernel<<<dim3(32, 32, 1), tb>>>(Wk, (__nv_bfloat16*)pwkh, (__nv_bfloat16*)pwkl, Dm, Dm);
    wtrans_kernel<<<dim3(32, 32, 1), tb>>>(Wv, (__nv_bfloat16*)pwvh, (__nv_bfloat16*)pwvl, Dm, Dm);
    wtrans_kernel<<<dim3(32, 32, 1), tb>>>(Wo, (__nv_bfloat16*)pwoh, (__nv_bfloat16*)pwol, Dm, Dm);
    wtrans_kernel<<<dim3(32, 32, NE), tb>>>(eWq, (__nv_bfloat16*)pewqh, (__nv_bfloat16*)pewql, Dm, Dm);
    wtrans_kernel<<<dim3(32, 32, NE), tb>>>(eWk, (__nv_bfloat16*)pewkh, (__nv_bfloat16*)pewkl, Dm, Dm);
    wtrans_kernel<<<dim3(32, 32, NE), tb>>>(eWv, (__nv_bfloat16*)pewvh, (__nv_bfloat16*)pewvl, Dm, Dm);
    wtrans_kernel<<<dim3(32, 32, NE), tb>>>(eWo, (__nv_bfloat16*)pewoh, (__nv_bfloat16*)pewol, Dm, Dm);

    csplit_kernel<<<(int)(NTD / 4 / 256), 256>>>((const float4*)x, (uint2*)pxh, (uint2*)pxl, (int)(NTD / 4));

    // main QKV (3-pass, fp32 out) — feeds router, needs ~1e-5
    dim3 gmain(Dm / 128, NT / 128, 1);
    gemm_mma_kernel<3,0><<<gmain, 256, GEMM_SMEM>>>((__nv_bfloat16*)pxh, (__nv_bfloat16*)pxl,
        (__nv_bfloat16*)pwqh, (__nv_bfloat16*)pwql, bq, pq, NT, Dm, Dm, 0, 0, 0);
    gemm_mma_kernel<3,0><<<gmain, 256, GEMM_SMEM>>>((__nv_bfloat16*)pxh, (__nv_bfloat16*)pxl,
        (__nv_bfloat16*)pwkh, (__nv_bfloat16*)pwkl, bk, pk, NT, Dm, Dm, 0, 0, 0);
    gemm_mma_kernel<3,0><<<gmain, 256, GEMM_SMEM>>>((__nv_bfloat16*)pxh, (__nv_bfloat16*)pxl,
        (__nv_bfloat16*)pwvh, (__nv_bfloat16*)pwvl, bv, pv, NT, Dm, Dm, 0, 0, 0);

    flash_kernel<HD1><<<dim3(Sq / 64, Bt * NH), 256, SMEM64>>>(
        (const float*)pq, (const float*)pk, (const float*)pv, (float*)po, Sq, NH, 0.125f);

    csplit_kernel<<<(int)(NTD / 4 / 256), 256>>>((const float4*)po, (uint2*)poh, (uint2*)pol, (int)(NTD / 4));
    gemm_mma_kernel<3,0><<<gmain, 256, GEMM_SMEM>>>((__nv_bfloat16*)poh, (__nv_bfloat16*)pol,
        (__nv_bfloat16*)pwoh, (__nv_bfloat16*)pwol, bo, pattn, NT, Dm, Dm, 0, 0, 0);

    ln1_kernel<<<NT, 256>>>(x, ln1_g, ln1_b);
    gate_kernel<<<NT / 8, 256>>>(gate_W);
    pos_kernel<<<1, 256>>>();
    scatter_kernel<<<NT * 2, 256>>>();

    // expert path (post-routing): 2-pass GEMMs, bf16 tensor flash
    size_t sA = (size_t)EROWS * Dm;
    size_t sW = DMDM;
    dim3 gexp(Dm / 128, EROWS / 128, NE);
    gemm_mma_kernel<2,1><<<gexp, 256, GEMM_SMEM>>>((__nv_bfloat16*)peinh, (__nv_bfloat16*)peinh,
        (__nv_bfloat16*)pewqh, (__nv_bfloat16*)pewql, nullptr, peqh, EROWS, Dm, Dm, sA, sW, sA);
    gemm_mma_kernel<2,1><<<gexp, 256, GEMM_SMEM>>>((__nv_bfloat16*)peinh, (__nv_bfloat16*)peinh,
        (__nv_bfloat16*)pewkh, (__nv_bfloat16*)pewkl, nullptr, pekh, EROWS, Dm, Dm, sA, sW, sA);
    gemm_mma_kernel<2,1><<<gexp, 256, GEMM_SMEM>>>((__nv_bfloat16*)peinh, (__nv_bfloat16*)peinh,
        (__nv_bfloat16*)pewvh, (__nv_bfloat16*)pewvl, nullptr, pevh, EROWS, Dm, Dm, sA, sW, sA);

    eflash_kernel<<<dim3(CAP / 64, NE * Bt * NHM), 256, EF_SMEM>>>(
        (const __nv_bfloat16*)peqh, (const __nv_bfloat16*)pekh,
        (const __nv_bfloat16*)pevh, (__nv_bfloat16*)peoh, 0.0883883476483184f);

    gemm_mma_kernel<2,0><<<gexp, 256, GEMM_SMEM>>>((__nv_bfloat16*)peoh, (__nv_bfloat16*)peoh,
        (__nv_bfloat16*)pewoh, (__nv_bfloat16*)pewol, nullptr, peout, EROWS, Dm, Dm, sA, sW, sA);

    combine_ln_kernel<<<NT, 256>>>(ln2_g, ln2_b, out);
    finalize_kernel<<<1, 32>>>(out);
}

// round 5
// speedup vs baseline: 3.7967x; 1.8754x over previous
#include <cuda_runtime.h>
#include <cuda_bf16.h>
#include <math.h>
#include <stdint.h>

// ---------------- problem dims ----------------
#define Bt   8
#define Sq   1024
#define Dm   1024
#define NH   16
#define HD1  64
#define NE   8
#define NHM  8
#define HDM  128
#define CAP  320
#define NT   (Bt*Sq)
#define NTD  ((size_t)NT*Dm)
#define EROWS (Bt*CAP)
#define EINSZ ((size_t)NE*Bt*CAP*Dm)
#define DMDM ((size_t)Dm*Dm)

// ---------------- scratch ----------------
static __device__ float g_attn[NTD];
static __device__ float g_x1[NTD];
static __device__ float g_eout[EINSZ];

static __device__ __nv_bfloat16 g_xh[NTD];
static __device__ __nv_bfloat16 g_qh[NTD], g_ql[NTD];
static __device__ __nv_bfloat16 g_kh[NTD], g_kl[NTD];
static __device__ __nv_bfloat16 g_vh[NTD], g_vl[NTD];
static __device__ __nv_bfloat16 g_oh[NTD];
static __device__ __nv_bfloat16 g_einh[EINSZ];
static __device__ __nv_bfloat16 g_eqh[EINSZ];
static __device__ __nv_bfloat16 g_ekh[EINSZ];
static __device__ __nv_bfloat16 g_evh[EINSZ];
static __device__ __nv_bfloat16 g_eoh[EINSZ];
static __device__ __nv_bfloat16 g_wqh[DMDM], g_wql[DMDM];
static __device__ __nv_bfloat16 g_wkh[DMDM], g_wkl[DMDM];
static __device__ __nv_bfloat16 g_wvh[DMDM], g_wvl[DMDM];
static __device__ __nv_bfloat16 g_woh[DMDM], g_wol[DMDM];
static __device__ __nv_bfloat16 g_ewqh[NE*DMDM];
static __device__ __nv_bfloat16 g_ewkh[NE*DMDM];
static __device__ __nv_bfloat16 g_ewvh[NE*DMDM];
static __device__ __nv_bfloat16 g_ewoh[NE*DMDM];

static __device__ int   g_i0[NT], g_i1[NT];
static __device__ float g_g0[NT], g_g1[NT];
static __device__ int   g_p0[NT], g_p1[NT];
static __device__ int   g_k0[NT], g_k1[NT];

static __device__ float g_Psum[NE];
static __device__ float g_fcnt[NE];
static __device__ float g_zsum;

// ---------------- PTX helpers ----------------
__device__ __forceinline__ uint32_t smem_u32(const void* p) {
    uint32_t a;
    asm("{ .reg .u64 t; cvta.to.shared.u64 t, %1; cvt.u32.u64 %0, t; }" : "=r"(a) : "l"(p));
    return a;
}
__device__ __forceinline__ void cp16(uint32_t dst, const void* src) {
    asm volatile("cp.async.cg.shared.global [%0], [%1], 16;" :: "r"(dst), "l"(src));
}
__device__ __forceinline__ void ldmA(uint32_t* a, uint32_t addr) {
    asm volatile("ldmatrix.sync.aligned.m8n8.x4.shared.b16 {%0,%1,%2,%3}, [%4];"
        : "=r"(a[0]), "=r"(a[1]), "=r"(a[2]), "=r"(a[3]) : "r"(addr));
}
__device__ __forceinline__ void ldmT(uint32_t* a, uint32_t addr) {
    asm volatile("ldmatrix.sync.aligned.m8n8.x4.trans.shared.b16 {%0,%1,%2,%3}, [%4];"
        : "=r"(a[0]), "=r"(a[1]), "=r"(a[2]), "=r"(a[3]) : "r"(addr));
}
__device__ __forceinline__ void mma_bf16(float* d, const uint32_t* a, const uint32_t* b) {
    asm volatile(
        "mma.sync.aligned.m16n8k16.row.col.f32.bf16.bf16.f32 "
        "{%0,%1,%2,%3}, {%4,%5,%6,%7}, {%8,%9}, {%0,%1,%2,%3};"
        : "+f"(d[0]), "+f"(d[1]), "+f"(d[2]), "+f"(d[3])
        : "r"(a[0]), "r"(a[1]), "r"(a[2]), "r"(a[3]), "r"(b[0]), "r"(b[1]));
}
__device__ __forceinline__ uint32_t packbf(float a, float b) {
    __nv_bfloat162 v = __float22bfloat162_rn(make_float2(a, b));
    return *(uint32_t*)&v;
}

// ---------------- GEMM via mma.sync ----------------
// C[M,N] = A[M,K] @ B^T.
// NSEG=1: Ah*Bh. NSEG=2: Ah*Bh + Ah*Bl. NSEG=3: + Al*Bh.
// OUTBF: 0 fp32 out; 1 bf16 out (Cv); 2 bf16 hi/lo split out (Cv, Cv2).
#define BK 32
#define ROWB 80
#define STAGEB (128*ROWB)
#define STAGE2 (2*STAGEB)

template <int NSEG, int OUTBF>
__global__ __launch_bounds__(256, 1) void gemm_mma_kernel(
    const __nv_bfloat16* __restrict__ Ah, const __nv_bfloat16* __restrict__ Al,
    const __nv_bfloat16* __restrict__ Bh, const __nv_bfloat16* __restrict__ Bl,
    const float* __restrict__ bias, void* __restrict__ Cv, void* __restrict__ Cv2,
    int M, int N, int K, size_t sA, size_t sB, size_t sC)
{
    extern __shared__ char sm_[];
    uint32_t smb = smem_u32(sm_);

    int t = threadIdx.x, lane = t & 31, wid = t >> 5;
    int n0 = blockIdx.x * 128, m0 = blockIdx.y * 128;
    Ah += blockIdx.z * sA; Al += blockIdx.z * sA;
    Bh += blockIdx.z * sB; Bl += blockIdx.z * sB;

    int wm = (wid & 3) * 32;
    int wn = (wid >> 2) * 64;

    const __nv_bfloat16* Aseg[3];
    const __nv_bfloat16* Bseg[3];
    Aseg[0] = Ah; Bseg[0] = Bh;
    Aseg[1] = Ah; Bseg[1] = Bl;
    Aseg[2] = (NSEG == 3) ? Al : Ah; Bseg[2] = Bh;
    const int KC = K / BK;
    const int NC = NSEG * KC;

    float acc[2][8][4];
#pragma unroll
    for (int i = 0; i < 2; i++)
#pragma unroll
        for (int j = 0; j < 8; j++)
#pragma unroll
            for (int q = 0; q < 4; q++) acc[i][j][q] = 0.f;

    int r0i = t >> 2, s0i = t & 3;
    int r1i = (t + 256) >> 2, s1i = t & 3;

    {
        const __nv_bfloat16* pA = Aseg[0];
        const __nv_bfloat16* pB = Bseg[0];
        uint32_t ab = smb;
        cp16(ab + r0i * ROWB + s0i * 16, pA + (size_t)(m0 + r0i) * K + s0i * 8);
        cp16(ab + r1i * ROWB + s1i * 16, pA + (size_t)(m0 + r1i) * K + s1i * 8);
        uint32_t bb = smb + STAGEB;
        cp16(bb + r0i * ROWB + s0i * 16, pB + (size_t)(n0 + r0i) * K + s0i * 8);
        cp16(bb + r1i * ROWB + s1i * 16, pB + (size_t)(n0 + r1i) * K + s1i * 8);
        asm volatile("cp.async.commit_group;");
    }

    int nq = lane >> 2, kr = lane & 3;

    for (int c = 0; c < NC; c++) {
        if (c + 1 < NC) {
            int cn = c + 1;
            int seg = cn / KC, kc = (cn - seg * KC) * BK;
            const __nv_bfloat16* pA = Aseg[seg];
            const __nv_bfloat16* pB = Bseg[seg];
            uint32_t ab = smb + (cn & 1) * STAGE2;
            cp16(ab + r0i * ROWB + s0i * 16, pA + (size_t)(m0 + r0i) * K + kc + s0i * 8);
            cp16(ab + r1i * ROWB + s1i * 16, pA + (size_t)(m0 + r1i) * K + kc + s1i * 8);
            uint32_t bb = ab + STAGEB;
            cp16(bb + r0i * ROWB + s0i * 16, pB + (size_t)(n0 + r0i) * K + kc + s0i * 8);
            cp16(bb + r1i * ROWB + s1i * 16, pB + (size_t)(n0 + r1i) * K + kc + s1i * 8);
            asm volatile("cp.async.commit_group;");
            asm volatile("cp.async.wait_group 1;");
        } else {
            asm volatile("cp.async.wait_group 0;");
        }
        __syncthreads();

        uint32_t ab = smb + (c & 1) * STAGE2;
        const char* bbp = sm_ + (c & 1) * STAGE2 + STAGEB;

        uint32_t afr[2][2][4];
#pragma unroll
        for (int mt = 0; mt < 2; mt++)
#pragma unroll
            for (int ks = 0; ks < 2; ks++) {
                uint32_t addr = ab + (wm + mt * 16 + (lane & 15)) * ROWB
                              + (ks * 16 + (lane >> 4) * 8) * 2;
                ldmA(afr[mt][ks], addr);
            }
        uint32_t bfr[2][8][2];
#pragma unroll
        for (int ks = 0; ks < 2; ks++)
#pragma unroll
            for (int nt = 0; nt < 8; nt++) {
                const char* p = bbp + (wn + nt * 8 + nq) * ROWB + ks * 32 + kr * 4;
                bfr[ks][nt][0] = *(const uint32_t*)p;
                bfr[ks][nt][1] = *(const uint32_t*)(p + 16);
            }
#pragma unroll
        for (int ks = 0; ks < 2; ks++)
#pragma unroll
            for (int mt = 0; mt < 2; mt++)
#pragma unroll
                for (int nt = 0; nt < 8; nt++)
                    mma_bf16(acc[mt][nt], afr[mt][ks], bfr[ks][nt]);
        __syncthreads();
    }

    // epilogue
#pragma unroll
    for (int mt = 0; mt < 2; mt++) {
        int m = m0 + wm + mt * 16 + (lane >> 2);
#pragma unroll
        for (int nt = 0; nt < 8; nt++) {
            int n = n0 + wn + nt * 8 + (lane & 3) * 2;
            float bv0 = bias ? bias[n] : 0.f;
            float bv1 = bias ? bias[n + 1] : 0.f;
            float v0 = acc[mt][nt][0] + bv0, v1 = acc[mt][nt][1] + bv1;
            float v2 = acc[mt][nt][2] + bv0, v3 = acc[mt][nt][3] + bv1;
            if (OUTBF == 0) {
                float* C = (float*)Cv + blockIdx.z * sC;
                *(float2*)&C[(size_t)m * N + n]       = make_float2(v0, v1);
                *(float2*)&C[(size_t)(m + 8) * N + n] = make_float2(v2, v3);
            } else if (OUTBF == 1) {
                __nv_bfloat16* C = (__nv_bfloat16*)Cv + blockIdx.z * sC;
                *(uint32_t*)&C[(size_t)m * N + n]       = packbf(v0, v1);
                *(uint32_t*)&C[(size_t)(m + 8) * N + n] = packbf(v2, v3);
            } else {
                __nv_bfloat16* Ch = (__nv_bfloat16*)Cv  + blockIdx.z * sC;
                __nv_bfloat16* Cl = (__nv_bfloat16*)Cv2 + blockIdx.z * sC;
                __nv_bfloat16 h0 = __float2bfloat16(v0), h1 = __float2bfloat16(v1);
                __nv_bfloat16 h2 = __float2bfloat16(v2), h3 = __float2bfloat16(v3);
                float l0 = v0 - __bfloat162float(h0), l1 = v1 - __bfloat162float(h1);
                float l2 = v2 - __bfloat162float(h2), l3 = v3 - __bfloat162float(h3);
                *(uint32_t*)&Ch[(size_t)m * N + n] =
                    (uint32_t)__bfloat16_as_ushort(h0) | ((uint32_t)__bfloat16_as_ushort(h1) << 16);
                *(uint32_t*)&Ch[(size_t)(m + 8) * N + n] =
                    (uint32_t)__bfloat16_as_ushort(h2) | ((uint32_t)__bfloat16_as_ushort(h3) << 16);
                *(uint32_t*)&Cl[(size_t)m * N + n]       = packbf(l0, l1);
                *(uint32_t*)&Cl[(size_t)(m + 8) * N + n] = packbf(l2, l3);
            }
        }
    }
}

// ---------------- expert flash (bf16 mma, HD=128) ----------------
#define EF_PITCH 272
#define EF_QS 0
#define EF_KS 17408
#define EF_VS 34816
#define EF_OB 52224
#define EF_MS 86016
#define EF_LS 86272
#define EF_AS 86528
#define EF_RM 86784
#define EF_RS 87296
#define EF_SMEM 87808

__global__ __launch_bounds__(256) void eflash_kernel(
    const __nv_bfloat16* __restrict__ Q, const __nv_bfloat16* __restrict__ K,
    const __nv_bfloat16* __restrict__ V, __nv_bfloat16* __restrict__ O,
    float scale)
{
    extern __shared__ char sm_[];
    float* Obuf = (float*)(sm_ + EF_OB);
    float* m_s  = (float*)(sm_ + EF_MS);
    float* l_s  = (float*)(sm_ + EF_LS);
    float* a_s  = (float*)(sm_ + EF_AS);
    float* redm = (float*)(sm_ + EF_RM);
    float* reds = (float*)(sm_ + EF_RS);
    uint32_t smb = smem_u32(sm_);

    int t = threadIdx.x, lane = t & 31, wid = t >> 5;
    int half = wid >> 2, wm = (wid & 3) * 16, wn2 = half * 32;
    int slice = blockIdx.y;
    int sb = slice >> 3, h = slice & 7;
    size_t base = (size_t)sb * CAP * 1024 + (size_t)h * HDM;
    int q0 = blockIdx.x * 64;

#pragma unroll
    for (int j = 0; j < 4; j++) {
        int id = t + 256 * j;
        int r = id >> 4, c = id & 15;
        *(uint4*)(sm_ + EF_QS + r * EF_PITCH + c * 16) =
            *(const uint4*)(Q + base + (size_t)(q0 + r) * 1024 + c * 8);
    }
    if (t < 64) { m_s[t] = -1e30f; l_s[t] = 0.f; }

    float o[16][4];
#pragma unroll
    for (int i = 0; i < 16; i++)
#pragma unroll
        for (int q = 0; q < 4; q++) o[i][q] = 0.f;

    int rl = wm + (lane >> 2), rh = rl + 8;
    int nq = lane >> 2, kr = lane & 3;

    for (int kt = 0; kt < CAP / 64; kt++) {
        __syncthreads();
#pragma unroll
        for (int j = 0; j < 4; j++) {
            int id = t + 256 * j;
            int r = id >> 4, c = id & 15;
            *(uint4*)(sm_ + EF_KS + r * EF_PITCH + c * 16) =
                *(const uint4*)(K + base + (size_t)(kt * 64 + r) * 1024 + c * 8);
            *(uint4*)(sm_ + EF_VS + r * EF_PITCH + c * 16) =
                *(const uint4*)(V + base + (size_t)(kt * 64 + r) * 1024 + c * 8);
        }
        __syncthreads();

        float s[4][4];
#pragma unroll
        for (int nt = 0; nt < 4; nt++)
#pragma unroll
            for (int q = 0; q < 4; q++) s[nt][q] = 0.f;
#pragma unroll
        for (int ks = 0; ks < 8; ks++) {
            uint32_t af[4];
            ldmA(af, smb + EF_QS + (wm + (lane & 15)) * EF_PITCH + ks * 32 + (lane >> 4) * 16);
#pragma unroll
            for (int nt = 0; nt < 4; nt++) {
                const char* p = sm_ + EF_KS + (wn2 + nt * 8 + nq) * EF_PITCH + ks * 32 + kr * 4;
                uint32_t bb[2];
                bb[0] = *(const uint32_t*)p;
                bb[1] = *(const uint32_t*)(p + 16);
                mma_bf16(s[nt], af, bb);
            }
        }

        float mxlo = -1e30f, mxhi = -1e30f;
#pragma unroll
        for (int nt = 0; nt < 4; nt++) {
            s[nt][0] *= scale; s[nt][1] *= scale; s[nt][2] *= scale; s[nt][3] *= scale;
            mxlo = fmaxf(mxlo, fmaxf(s[nt][0], s[nt][1]));
            mxhi = fmaxf(mxhi, fmaxf(s[nt][2], s[nt][3]));
        }
        mxlo = fmaxf(mxlo, __shfl_xor_sync(0xffffffff, mxlo, 1));
        mxlo = fmaxf(mxlo, __shfl_xor_sync(0xffffffff, mxlo, 2));
        mxhi = fmaxf(mxhi, __shfl_xor_sync(0xffffffff, mxhi, 1));
        mxhi = fmaxf(mxhi, __shfl_xor_sync(0xffffffff, mxhi, 2));
        if ((lane & 3) == 0) { redm[half * 64 + rl] = mxlo; redm[half * 64 + rh] = mxhi; }
        __syncthreads();
        if (t < 64) {
            float mo = m_s[t];
            float mn = fmaxf(mo, fmaxf(redm[t], redm[64 + t]));
            float al = __expf(mo - mn);
            a_s[t] = al; m_s[t] = mn; l_s[t] *= al;
        }
        __syncthreads();

        float mlo = m_s[rl], mhi = m_s[rh], alo = a_s[rl], ahi = a_s[rh];
        float slo = 0.f, shi = 0.f;
        uint32_t afr[2][4];
#pragma unroll
        for (int ks = 0; ks < 2; ks++) {
#pragma unroll
            for (int jj = 0; jj < 2; jj++) {
                int nt = ks * 2 + jj;
                float p0 = __expf(s[nt][0] - mlo), p1 = __expf(s[nt][1] - mlo);
                float p2 = __expf(s[nt][2] - mhi), p3 = __expf(s[nt][3] - mhi);
                slo += p0 + p1; shi += p2 + p3;
                afr[ks][jj * 2 + 0] = packbf(p0, p1);
                afr[ks][jj * 2 + 1] = packbf(p2, p3);
            }
        }
        slo += __shfl_xor_sync(0xffffffff, slo, 1);
        slo += __shfl_xor_sync(0xffffffff, slo, 2);
        shi += __shfl_xor_sync(0xffffffff, shi, 1);
        shi += __shfl_xor_sync(0xffffffff, shi, 2);
        if ((lane & 3) == 0) { reds[half * 64 + rl] = slo; reds[half * 64 + rh] = shi; }

#pragma unroll
        for (int nt = 0; nt < 16; nt++) {
            o[nt][0] *= alo; o[nt][1] *= alo; o[nt][2] *= ahi; o[nt][3] *= ahi;
        }

#pragma unroll
        for (int ks = 0; ks < 2; ks++) {
#pragma unroll
            for (int nb = 0; nb < 8; nb++) {
                uint32_t b4[4];
                ldmT(b4, smb + EF_VS + (wn2 + ks * 16 + (lane & 15)) * EF_PITCH
                         + nb * 32 + (lane >> 4) * 16);
                mma_bf16(o[2 * nb],     afr[ks], b4);
                mma_bf16(o[2 * nb + 1], afr[ks], b4 + 2);
            }
        }
        __syncthreads();
        if (t < 64) l_s[t] += reds[t] + reds[64 + t];
    }

    __syncthreads();
    if (half == 0) {
#pragma unroll
        for (int nt = 0; nt < 16; nt++) {
            float* plo = Obuf + rl * 132 + nt * 8 + (lane & 3) * 2;
            float* phi = Obuf + rh * 132 + nt * 8 + (lane & 3) * 2;
            plo[0] = o[nt][0]; plo[1] = o[nt][1];
            phi[0] = o[nt][2]; phi[1] = o[nt][3];
        }
    }
    __syncthreads();
    if (half == 1) {
#pragma unroll
        for (int nt = 0; nt < 16; nt++) {
            float* plo = Obuf + rl * 132 + nt * 8 + (lane & 3) * 2;
            float* phi = Obuf + rh * 132 + nt * 8 + (lane & 3) * 2;
            plo[0] += o[nt][0]; plo[1] += o[nt][1];
            phi[0] += o[nt][2]; phi[1] += o[nt][3];
        }
    }
    __syncthreads();
#pragma unroll
    for (int j = 0; j < 16; j++) {
        int id = t + 256 * j;
        int r = id >> 6, cp = id & 63;
        float inv = 1.f / l_s[r];
        float2 v = *(float2*)(Obuf + r * 132 + cp * 2);
        __nv_bfloat162 ob = __float22bfloat162_rn(make_float2(v.x * inv, v.y * inv));
        *(__nv_bfloat162*)(O + base + (size_t)(q0 + r) * 1024 + cp * 2) = ob;
    }
}

// ---------------- main flash (bf16 mma, HD=64, split-precision S) ------------
#define MF_PITCH 144
#define MF_QH 0
#define MF_QL 9216
#define MF_KH 18432
#define MF_KL 27648
#define MF_VH 36864
#define MF_VL 46080
#define MF_OB 55296
#define MF_MS 72704
#define MF_LS 72960
#define MF_AS 73216
#define MF_RM 73472
#define MF_RS 73984
#define MF_SMEM 74496

__global__ __launch_bounds__(256) void mflash_kernel(
    const __nv_bfloat16* __restrict__ Qh, const __nv_bfloat16* __restrict__ Ql,
    const __nv_bfloat16* __restrict__ Kh, const __nv_bfloat16* __restrict__ Kl,
    const __nv_bfloat16* __restrict__ Vh, const __nv_bfloat16* __restrict__ Vl,
    __nv_bfloat16* __restrict__ O, float scale)
{
    extern __shared__ char sm_[];
    float* Obuf = (float*)(sm_ + MF_OB);   // 64 x 68 fp32
    float* m_s  = (float*)(sm_ + MF_MS);
    float* l_s  = (float*)(sm_ + MF_LS);
    float* a_s  = (float*)(sm_ + MF_AS);
    float* redm = (float*)(sm_ + MF_RM);
    float* reds = (float*)(sm_ + MF_RS);
    uint32_t smb = smem_u32(sm_);

    int t = threadIdx.x, lane = t & 31, wid = t >> 5;
    int half = wid >> 2, wm = (wid & 3) * 16, wn2 = half * 32;
    int slice = blockIdx.y;
    int sb = slice >> 4, h = slice & 15;
    size_t base = (size_t)sb * Sq * 1024 + (size_t)h * HD1;
    int q0 = blockIdx.x * 64;

    // load Q hi/lo: 64 rows x 128B
#pragma unroll
    for (int j = 0; j < 2; j++) {
        int id = t + 256 * j;
        int r = id >> 3, c = id & 7;
        size_t g = base + (size_t)(q0 + r) * 1024 + c * 8;
        *(uint4*)(sm_ + MF_QH + r * MF_PITCH + c * 16) = *(const uint4*)(Qh + g);
        *(uint4*)(sm_ + MF_QL + r * MF_PITCH + c * 16) = *(const uint4*)(Ql + g);
    }
    if (t < 64) { m_s[t] = -1e30f; l_s[t] = 0.f; }

    float o[8][4];
#pragma unroll
    for (int i = 0; i < 8; i++)
#pragma unroll
        for (int q = 0; q < 4; q++) o[i][q] = 0.f;

    int rl = wm + (lane >> 2), rh = rl + 8;
    int nq = lane >> 2, kr = lane & 3;

    for (int kt = 0; kt < Sq / 64; kt++) {
        __syncthreads();
#pragma unroll
        for (int j = 0; j < 2; j++) {
            int id = t + 256 * j;
            int r = id >> 3, c = id & 7;
            size_t g = base + (size_t)(kt * 64 + r) * 1024 + c * 8;
            *(uint4*)(sm_ + MF_KH + r * MF_PITCH + c * 16) = *(const uint4*)(Kh + g);
            *(uint4*)(sm_ + MF_KL + r * MF_PITCH + c * 16) = *(const uint4*)(Kl + g);
            *(uint4*)(sm_ + MF_VH + r * MF_PITCH + c * 16) = *(const uint4*)(Vh + g);
            *(uint4*)(sm_ + MF_VL + r * MF_PITCH + c * 16) = *(const uint4*)(Vl + g);
        }
        __syncthreads();

        // S = Qh*Kh + Qh*Kl + Ql*Kh (64x64, K=64 per segment)
        float s[4][4];
#pragma unroll
        for (int nt = 0; nt < 4; nt++)
#pragma unroll
            for (int q = 0; q < 4; q++) s[nt][q] = 0.f;

        const int QOFF[3] = {MF_QH, MF_QH, MF_QL};
        const int KOFF[3] = {MF_KH, MF_KL, MF_KH};
#pragma unroll
        for (int seg = 0; seg < 3; seg++) {
#pragma unroll
            for (int ks = 0; ks < 4; ks++) {
                uint32_t af[4];
                ldmA(af, smb + QOFF[seg] + (wm + (lane & 15)) * MF_PITCH
                         + ks * 32 + (lane >> 4) * 16);
#pragma unroll
                for (int nt = 0; nt < 4; nt++) {
                    const char* p = sm_ + KOFF[seg] + (wn2 + nt * 8 + nq) * MF_PITCH
                                  + ks * 32 + kr * 4;
                    uint32_t bb[2];
                    bb[0] = *(const uint32_t*)p;
                    bb[1] = *(const uint32_t*)(p + 16);
                    mma_bf16(s[nt], af, bb);
                }
            }
        }

        float mxlo = -1e30f, mxhi = -1e30f;
#pragma unroll
        for (int nt = 0; nt < 4; nt++) {
            s[nt][0] *= scale; s[nt][1] *= scale; s[nt][2] *= scale; s[nt][3] *= scale;
            mxlo = fmaxf(mxlo, fmaxf(s[nt][0], s[nt][1]));
            mxhi = fmaxf(mxhi, fmaxf(s[nt][2], s[nt][3]));
        }
        mxlo = fmaxf(mxlo, __shfl_xor_sync(0xffffffff, mxlo, 1));
        mxlo = fmaxf(mxlo, __shfl_xor_sync(0xffffffff, mxlo, 2));
        mxhi = fmaxf(mxhi, __shfl_xor_sync(0xffffffff, mxhi, 1));
        mxhi = fmaxf(mxhi, __shfl_xor_sync(0xffffffff, mxhi, 2));
        if ((lane & 3) == 0) { redm[half * 64 + rl] = mxlo; redm[half * 64 + rh] = mxhi; }
        __syncthreads();
        if (t < 64) {
            float mo = m_s[t];
            float mn = fmaxf(mo, fmaxf(redm[t], redm[64 + t]));
            float al = __expf(mo - mn);
            a_s[t] = al; m_s[t] = mn; l_s[t] *= al;
        }
        __syncthreads();

        float mlo = m_s[rl], mhi = m_s[rh], alo = a_s[rl], ahi = a_s[rh];
        float slo = 0.f, shi = 0.f;
        uint32_t afr[2][4];
#pragma unroll
        for (int ks = 0; ks < 2; ks++) {
#pragma unroll
            for (int jj = 0; jj < 2; jj++) {
                int nt = ks * 2 + jj;
                float p0 = __expf(s[nt][0] - mlo), p1 = __expf(s[nt][1] - mlo);
                float p2 = __expf(s[nt][2] - mhi), p3 = __expf(s[nt][3] - mhi);
                slo += p0 + p1; shi += p2 + p3;
                afr[ks][jj * 2 + 0] = packbf(p0, p1);
                afr[ks][jj * 2 + 1] = packbf(p2, p3);
            }
        }
        slo += __shfl_xor_sync(0xffffffff, slo, 1);
        slo += __shfl_xor_sync(0xffffffff, slo, 2);
        shi += __shfl_xor_sync(0xffffffff, shi, 1);
        shi += __shfl_xor_sync(0xffffffff, shi, 2);
        if ((lane & 3) == 0) { reds[half * 64 + rl] = slo; reds[half * 64 + rh] = shi; }

#pragma unroll
        for (int nt = 0; nt < 8; nt++) {
            o[nt][0] *= alo; o[nt][1] *= alo; o[nt][2] *= ahi; o[nt][3] *= ahi;
        }

        // O += Ph*(Vh + Vl)
#pragma unroll
        for (int ks = 0; ks < 2; ks++) {
#pragma unroll
            for (int nb = 0; nb < 4; nb++) {
                uint32_t b4[4];
                uint32_t rowoff = (wn2 + ks * 16 + (lane & 15)) * MF_PITCH
                                + nb * 32 + (lane >> 4) * 16;
                ldmT(b4, smb + MF_VH + rowoff);
                mma_bf16(o[2 * nb],     afr[ks], b4);
                mma_bf16(o[2 * nb + 1], afr[ks], b4 + 2);
                ldmT(b4, smb + MF_VL + rowoff);
                mma_bf16(o[2 * nb],     afr[ks], b4);
                mma_bf16(o[2 * nb + 1], afr[ks], b4 + 2);
            }
        }
        __syncthreads();
        if (t < 64) l_s[t] += reds[t] + reds[64 + t];
    }

    __syncthreads();
    if (half == 0) {
#pragma unroll
        for (int nt = 0; nt < 8; nt++) {
            float* plo = Obuf + rl * 68 + nt * 8 + (lane & 3) * 2;
            float* phi = Obuf + rh * 68 + nt * 8 + (lane & 3) * 2;
            plo[0] = o[nt][0]; plo[1] = o[nt][1];
            phi[0] = o[nt][2]; phi[1] = o[nt][3];
        }
    }
    __syncthreads();
    if (half == 1) {
#pragma unroll
        for (int nt = 0; nt < 8; nt++) {
            float* plo = Obuf + rl * 68 + nt * 8 + (lane & 3) * 2;
            float* phi = Obuf + rh * 68 + nt * 8 + (lane & 3) * 2;
            plo[0] += o[nt][0]; plo[1] += o[nt][1];
            phi[0] += o[nt][2]; phi[1] += o[nt][3];
        }
    }
    __syncthreads();
#pragma unroll
    for (int j = 0; j < 8; j++) {
        int id = t + 256 * j;
        int r = id >> 5, cp = id & 31;
        float inv = 1.f / l_s[r];
        float2 v = *(float2*)(Obuf + r * 68 + cp * 2);
        __nv_bfloat162 ob = __float22bfloat162_rn(make_float2(v.x * inv, v.y * inv));
        *(__nv_bfloat162*)(O + base + (size_t)(q0 + r) * 1024 + cp * 2) = ob;
    }
}

// ---------------- fp32 -> bf16 convert (hi only) ----------------
__global__ __launch_bounds__(256) void cvt_kernel(
    const float4* __restrict__ s, uint2* __restrict__ h, int n4)
{
    int i = blockIdx.x * 256 + threadIdx.x;
    if (i >= n4) return;
    float4 v = s[i];
    uint2 hh;
    hh.x = packbf(v.x, v.y);
    hh.y = packbf(v.z, v.w);
    h[i] = hh;
}

// ---------------- weight transpose + split (hi/lo; Tl may be null) ----------
__global__ void wtrans_kernel(const float* __restrict__ W,
                              __nv_bfloat16* __restrict__ Th,
                              __nv_bfloat16* __restrict__ Tl, int Kd, int Nd)
{
    __shared__ float tile[32][33];
    int tx = threadIdx.x, ty = threadIdx.y;
    int n0 = blockIdx.x * 32, k0 = blockIdx.y * 32;
    size_t ob = (size_t)blockIdx.z * Kd * Nd;
    const float* Wb = W + ob;
#pragma unroll
    for (int r = 0; r < 4; r++)
        tile[ty + 8 * r][tx] = Wb[(size_t)(k0 + ty + 8 * r) * Nd + n0 + tx];
    __syncthreads();
#pragma unroll
    for (int r = 0; r < 4; r++) {
        float v = tile[tx][ty + 8 * r];
        __nv_bfloat16 hv = __float2bfloat16(v);
        Th[ob + (size_t)(n0 + ty + 8 * r) * Kd + k0 + tx] = hv;
        if (Tl)
            Tl[ob + (size_t)(n0 + ty + 8 * r) * Kd + k0 + tx] =
                __float2bfloat16(v - __bfloat162float(hv));
    }
}

// ---------------- zero kernels ----------------
__global__ void zero_stats_kernel() {
    int t = threadIdx.x;
    if (t < NE) { g_Psum[t] = 0.f; g_fcnt[t] = 0.f; }
    if (t == 0) g_zsum = 0.f;
}

__global__ void zero_ein_kernel() {
    size_t n = EINSZ / 8;
    uint4 z = make_uint4(0, 0, 0, 0);
    uint4* ph = (uint4*)g_einh;
    for (size_t i = blockIdx.x * (size_t)blockDim.x + threadIdx.x; i < n;
         i += (size_t)gridDim.x * blockDim.x) ph[i] = z;
}

// ---------------- block reduce ----------------
__device__ __forceinline__ void block_reduce2(float& s, float& s2) {
    __shared__ float rs[8], rs2[8];
#pragma unroll
    for (int o = 16; o > 0; o >>= 1) {
        s  += __shfl_xor_sync(0xffffffff, s, o);
        s2 += __shfl_xor_sync(0xffffffff, s2, o);
    }
    int lane = threadIdx.x & 31, w = threadIdx.x >> 5;
    if (lane == 0) { rs[w] = s; rs2[w] = s2; }
    __syncthreads();
    float ts = 0.f, ts2 = 0.f;
#pragma unroll
    for (int i = 0; i < 8; i++) { ts += rs[i]; ts2 += rs2[i]; }
    s = ts; s2 = ts2;
}

// ---------------- LN1 ----------------
__global__ __launch_bounds__(256) void ln1_kernel(
    const float* __restrict__ x, const float* __restrict__ g,
    const float* __restrict__ b)
{
    size_t tok = blockIdx.x;
    int t = threadIdx.x;
    float v[4], s = 0.f, s2 = 0.f;
#pragma unroll
    for (int u = 0; u < 4; u++) {
        int j = t + u * 256;
        float val = x[tok * Dm + j] + g_attn[tok * Dm + j];
        v[u] = val; s += val; s2 += val * val;
    }
    block_reduce2(s, s2);
    float mean = s * (1.f / Dm);
    float var  = s2 * (1.f / Dm) - mean * mean;
    float inv  = rsqrtf(var + 1e-5f);
#pragma unroll
    for (int u = 0; u < 4; u++) {
        int j = t + u * 256;
        g_x1[tok * Dm + j] = (v[u] - mean) * inv * g[j] + b[j];
    }
}

// ---------------- gate ----------------
__global__ __launch_bounds__(256) void gate_kernel(const float* __restrict__ gateW) {
    int warp = threadIdx.x >> 5, lane = threadIdx.x & 31;
    int tok = blockIdx.x * 8 + warp;
    const float* xr = g_x1 + (size_t)tok * Dm;
    float acc[NE];
#pragma unroll
    for (int e = 0; e < NE; e++) acc[e] = 0.f;
    for (int k = lane; k < Dm; k += 32) {
        float xv = xr[k];
        const float* wr = gateW + (size_t)k * NE;
#pragma unroll
        for (int e = 0; e < NE; e++) acc[e] += xv * wr[e];
    }
#pragma unroll
    for (int e = 0; e < NE; e++)
#pragma unroll
        for (int o = 16; o > 0; o >>= 1)
            acc[e] += __shfl_xor_sync(0xffffffff, acc[e], o);
    if (lane == 0) {
        float mx = acc[0];
#pragma unroll
        for (int e = 1; e < NE; e++) mx = fmaxf(mx, acc[e]);
        float p[NE], se = 0.f;
#pragma unroll
        for (int e = 0; e < NE; e++) { p[e] = __expf(acc[e] - mx); se += p[e]; }
        float invs = 1.f / se;
        float lse = mx + logf(se);
        atomicAdd(&g_zsum, lse * lse);
        int i0 = 0, i1 = -1;
        float b0 = -1.f, b1 = -1.f;
#pragma unroll
        for (int e = 0; e < NE; e++) {
            float pe = p[e] * invs;
            atomicAdd(&g_Psum[e], pe);
            if (pe > b0) { b1 = b0; i1 = i0; b0 = pe; i0 = e; }
            else if (pe > b1) { b1 = pe; i1 = e; }
        }
        atomicAdd(&g_fcnt[i0], 1.f);
        g_i0[tok] = i0; g_i1[tok] = i1;
        g_g0[tok] = b0; g_g1[tok] = b1;
    }
}

// ---------------- routing positions ----------------
__global__ __launch_bounds__(256) void pos_kernel() {
    int warp = threadIdx.x >> 5, lane = threadIdx.x & 31;
    if (warp >= Bt) return;
    int b = warp;
    unsigned lt = (1u << lane) - 1u;
    int cnt[NE];
#pragma unroll
    for (int e = 0; e < NE; e++) cnt[e] = 0;

    for (int ch = 0; ch < Sq / 32; ch++) {
        int tok = b * Sq + ch * 32 + lane;
        int e0 = g_i0[tok];
        int myp = 0;
#pragma unroll
        for (int e = 0; e < NE; e++) {
            unsigned m = __ballot_sync(0xffffffff, e0 == e);
            if (e0 == e) myp = cnt[e] + __popc(m & lt);
            cnt[e] += __popc(m);
        }
        g_k0[tok] = (myp < CAP) ? 1 : 0;
        g_p0[tok] = min(myp, CAP - 1);
    }
    for (int ch = 0; ch < Sq / 32; ch++) {
        int tok = b * Sq + ch * 32 + lane;
        int e1 = g_i1[tok];
        bool valid = g_g1[tok] > 0.2f;
        int myp = 0;
#pragma unroll
        for (int e = 0; e < NE; e++) {
            unsigned m = __ballot_sync(0xffffffff, valid && (e1 == e));
            if (valid && (e1 == e)) myp = cnt[e] + __popc(m & lt);
            cnt[e] += __popc(m);
        }
        bool keep = valid && (myp < CAP);
        g_k1[tok] = keep ? 1 : 0;
        g_p1[tok] = valid ? min(myp, CAP - 1) : 0;
    }
}

// ---------------- scatter (x1 fp32 -> einh bf16) ----------------
__global__ __launch_bounds__(256) void scatter_kernel() {
    int idx = blockIdx.x;
    int tok = idx >> 1, slot = idx & 1;
    int keep = slot ? g_k1[tok] : g_k0[tok];
    if (!keep) return;
    int e = slot ? g_i1[tok] : g_i0[tok];
    int p = slot ? g_p1[tok] : g_p0[tok];
    int b = tok / Sq;
    const float4* src = (const float4*)(g_x1 + (size_t)tok * Dm);
    size_t ro = (((size_t)e * Bt + b) * CAP + p) * Dm;
    uint2* dh = (uint2*)(g_einh + ro);
    float4 v = src[threadIdx.x];
    uint2 hh;
    hh.x = packbf(v.x, v.y);
    hh.y = packbf(v.z, v.w);
    dh[threadIdx.x] = hh;
}

// ---------------- combine + LN2 ----------------
__global__ __launch_bounds__(256) void combine_ln_kernel(
    const float* __restrict__ g2, const float* __restrict__ b2,
    float* __restrict__ out)
{
    size_t tok = blockIdx.x;
    int t = threadIdx.x;
    int b = (int)(tok >> 10);
    float w0 = g_k0[tok] ? g_g0[tok] : 0.f;
    float w1 = g_k1[tok] ? g_g1[tok] : 0.f;
    const float* r0 = g_eout + (((size_t)g_i0[tok] * Bt + b) * CAP + g_p0[tok]) * Dm;
    const float* r1 = g_eout + (((size_t)g_i1[tok] * Bt + b) * CAP + g_p1[tok]) * Dm;

    float v[4], s = 0.f, s2 = 0.f;
#pragma unroll
    for (int u = 0; u < 4; u++) {
        int j = t + u * 256;
        float val = g_x1[tok * Dm + j] + w0 * r0[j] + w1 * r1[j];
        v[u] = val; s += val; s2 += val * val;
    }
    block_reduce2(s, s2);
    float mean = s * (1.f / Dm);
    float var  = s2 * (1.f / Dm) - mean * mean;
    float inv  = rsqrtf(var + 1e-5f);
#pragma unroll
    for (int u = 0; u < 4; u++) {
        int j = t + u * 256;
        out[tok * Dm + j] = (v[u] - mean) * inv * g2[j] + b2[j];
    }
}

// ---------------- finalize aux ----------------
__global__ void finalize_kernel(float* __restrict__ out) {
    if (threadIdx.x == 0 && blockIdx.x == 0) {
        float invN = 1.f / (float)NT;
        float sfp = 0.f;
#pragma unroll
        for (int e = 0; e < NE; e++)
            sfp += (g_fcnt[e] * invN) * (g_Psum[e] * invN);
        float bal = 0.01f * (float)NE * sfp;
        float zl  = 0.001f * g_zsum * invN;
        out[NTD + 0] = bal + zl;
        out[NTD + 1] = bal;
        out[NTD + 2] = zl;
    }
}

// ---------------- host launcher ----------------
extern "C" void kernel_launch(void* const* d_in, const int* in_sizes, int n_in,
                              void* d_out, int out_size)
{
    const float* x      = (const float*)d_in[0];
    const float* Wq     = (const float*)d_in[1];
    const float* Wk     = (const float*)d_in[2];
    const float* Wv     = (const float*)d_in[3];
    const float* Wo     = (const float*)d_in[4];
    const float* bq     = (const float*)d_in[5];
    const float* bk     = (const float*)d_in[6];
    const float* bv     = (const float*)d_in[7];
    const float* bo     = (const float*)d_in[8];
    const float* ln1_g  = (const float*)d_in[9];
    const float* ln1_b  = (const float*)d_in[10];
    const float* ln2_g  = (const float*)d_in[11];
    const float* ln2_b  = (const float*)d_in[12];
    const float* gate_W = (const float*)d_in[13];
    const float* eWq    = (const float*)d_in[14];
    const float* eWk    = (const float*)d_in[15];
    const float* eWv    = (const float*)d_in[16];
    const float* eWo    = (const float*)d_in[17];
    float* out = (float*)d_out;

    void *pattn, *px1, *peout, *pxh;
    void *pqh, *pql, *pkh, *pkl, *pvh, *pvl, *poh;
    void *peinh, *peqh, *pekh, *pevh, *peoh;
    void *pwqh, *pwql, *pwkh, *pwkl, *pwvh, *pwvl, *pwoh, *pwol;
    void *pewqh, *pewkh, *pewvh, *pewoh;
    cudaGetSymbolAddress(&pattn, g_attn); cudaGetSymbolAddress(&px1, g_x1);
    cudaGetSymbolAddress(&peout, g_eout); cudaGetSymbolAddress(&pxh, g_xh);
    cudaGetSymbolAddress(&pqh, g_qh);     cudaGetSymbolAddress(&pql, g_ql);
    cudaGetSymbolAddress(&pkh, g_kh);     cudaGetSymbolAddress(&pkl, g_kl);
    cudaGetSymbolAddress(&pvh, g_vh);     cudaGetSymbolAddress(&pvl, g_vl);
    cudaGetSymbolAddress(&poh, g_oh);
    cudaGetSymbolAddress(&peinh, g_einh);
    cudaGetSymbolAddress(&peqh, g_eqh);   cudaGetSymbolAddress(&pekh, g_ekh);
    cudaGetSymbolAddress(&pevh, g_evh);   cudaGetSymbolAddress(&peoh, g_eoh);
    cudaGetSymbolAddress(&pwqh, g_wqh);   cudaGetSymbolAddress(&pwql, g_wql);
    cudaGetSymbolAddress(&pwkh, g_wkh);   cudaGetSymbolAddress(&pwkl, g_wkl);
    cudaGetSymbolAddress(&pwvh, g_wvh);   cudaGetSymbolAddress(&pwvl, g_wvl);
    cudaGetSymbolAddress(&pwoh, g_woh);   cudaGetSymbolAddress(&pwol, g_wol);
    cudaGetSymbolAddress(&pewqh, g_ewqh); cudaGetSymbolAddress(&pewkh, g_ewkh);
    cudaGetSymbolAddress(&pewvh, g_ewvh); cudaGetSymbolAddress(&pewoh, g_ewoh);

    const int GEMM_SMEM = 2 * STAGE2;
    cudaFuncSetAttribute(gemm_mma_kernel<2,2>, cudaFuncAttributeMaxDynamicSharedMemorySize, GEMM_SMEM);
    cudaFuncSetAttribute(gemm_mma_kernel<2,0>, cudaFuncAttributeMaxDynamicSharedMemorySize, GEMM_SMEM);
    cudaFuncSetAttribute(gemm_mma_kernel<1,1>, cudaFuncAttributeMaxDynamicSharedMemorySize, GEMM_SMEM);
    cudaFuncSetAttribute(gemm_mma_kernel<1,0>, cudaFuncAttributeMaxDynamicSharedMemorySize, GEMM_SMEM);
    cudaFuncSetAttribute(mflash_kernel, cudaFuncAttributeMaxDynamicSharedMemorySize, MF_SMEM);
    cudaFuncSetAttribute(eflash_kernel, cudaFuncAttributeMaxDynamicSharedMemorySize, EF_SMEM);

    zero_stats_kernel<<<1, 32>>>();
    zero_ein_kernel<<<2048, 256>>>();

    dim3 tb(32, 8);
    wtrans_kernel<<<dim3(32, 32, 1), tb>>>(Wq, (__nv_bfloat16*)pwqh, (__nv_bfloat16*)pwql, Dm, Dm);
    wtrans_kernel<<<dim3(32, 32, 1), tb>>>(Wk, (__nv_bfloat16*)pwkh, (__nv_bfloat16*)pwkl, Dm, Dm);
    wtrans_kernel<<<dim3(32, 32, 1), tb>>>(Wv, (__nv_bfloat16*)pwvh, (__nv_bfloat16*)pwvl, Dm, Dm);
    wtrans_kernel<<<dim3(32, 32, 1), tb>>>(Wo, (__nv_bfloat16*)pwoh, (__nv_bfloat16*)pwol, Dm, Dm);
    wtrans_kernel<<<dim3(32, 32, NE), tb>>>(eWq, (__nv_bfloat16*)pewqh, nullptr, Dm, Dm);
    wtrans_kernel<<<dim3(32, 32, NE), tb>>>(eWk, (__nv_bfloat16*)pewkh, nullptr, Dm, Dm);
    wtrans_kernel<<<dim3(32, 32, NE), tb>>>(eWv, (__nv_bfloat16*)pewvh, nullptr, Dm, Dm);
    wtrans_kernel<<<dim3(32, 32, NE), tb>>>(eWo, (__nv_bfloat16*)pewoh, nullptr, Dm, Dm);

    cvt_kernel<<<(int)(NTD / 4 / 256), 256>>>((const float4*)x, (uint2*)pxh, (int)(NTD / 4));

    // main QKV: 2-pass, split bf16 hi/lo output
    dim3 gmain(Dm / 128, NT / 128, 1);
    gemm_mma_kernel<2,2><<<gmain, 256, GEMM_SMEM>>>((__nv_bfloat16*)pxh, (__nv_bfloat16*)pxh,
        (__nv_bfloat16*)pwqh, (__nv_bfloat16*)pwql, bq, pqh, pql, NT, Dm, Dm, 0, 0, 0);
    gemm_mma_kernel<2,2><<<gmain, 256, GEMM_SMEM>>>((__nv_bfloat16*)pxh, (__nv_bfloat16*)pxh,
        (__nv_bfloat16*)pwkh, (__nv_bfloat16*)pwkl, bk, pkh, pkl, NT, Dm, Dm, 0, 0, 0);
    gemm_mma_kernel<2,2><<<gmain, 256, GEMM_SMEM>>>((__nv_bfloat16*)pxh, (__nv_bfloat16*)pxh,
        (__nv_bfloat16*)pwvh, (__nv_bfloat16*)pwvl, bv, pvh, pvl, NT, Dm, Dm, 0, 0, 0);

    // main attention: bf16 tensor flash, split-precision S
    mflash_kernel<<<dim3(Sq / 64, Bt * NH), 256, MF_SMEM>>>(
        (const __nv_bfloat16*)pqh, (const __nv_bfloat16*)pql,
        (const __nv_bfloat16*)pkh, (const __nv_bfloat16*)pkl,
        (const __nv_bfloat16*)pvh, (const __nv_bfloat16*)pvl,
        (__nv_bfloat16*)poh, 0.125f);

    // Wo: 2-pass, fp32 out
    gemm_mma_kernel<2,0><<<gmain, 256, GEMM_SMEM>>>((__nv_bfloat16*)poh, (__nv_bfloat16*)poh,
        (__nv_bfloat16*)pwoh, (__nv_bfloat16*)pwol, bo, pattn, nullptr, NT, Dm, Dm, 0, 0, 0);

    ln1_kernel<<<NT, 256>>>(x, ln1_g, ln1_b);
    gate_kernel<<<NT / 8, 256>>>(gate_W);
    pos_kernel<<<1, 256>>>();
    scatter_kernel<<<NT * 2, 256>>>();

    // expert path: single-pass GEMMs, bf16 tensor flash
    size_t sA = (size_t)EROWS * Dm;
    size_t sW = DMDM;
    dim3 gexp(Dm / 128, EROWS / 128, NE);
    gemm_mma_kernel<1,1><<<gexp, 256, GEMM_SMEM>>>((__nv_bfloat16*)peinh, (__nv_bfloat16*)peinh,
        (__nv_bfloat16*)pewqh, (__nv_bfloat16*)pewqh, nullptr, peqh, nullptr, EROWS, Dm, Dm, sA, sW, sA);
    gemm_mma_kernel<1,1><<<gexp, 256, GEMM_SMEM>>>((__nv_bfloat16*)peinh, (__nv_bfloat16*)peinh,
        (__nv_bfloat16*)pewkh, (__nv_bfloat16*)pewkh, nullptr, pekh, nullptr, EROWS, Dm, Dm, sA, sW, sA);
    gemm_mma_kernel<1,1><<<gexp, 256, GEMM_SMEM>>>((__nv_bfloat16*)peinh, (__nv_bfloat16*)peinh,
        (__nv_bfloat16*)pewvh, (__nv_bfloat16*)pewvh, nullptr, pevh, nullptr, EROWS, Dm, Dm, sA, sW, sA);

    eflash_kernel<<<dim3(CAP / 64, NE * Bt * NHM), 256, EF_SMEM>>>(
        (const __nv_bfloat16*)peqh, (const __nv_bfloat16*)pekh,
        (const __nv_bfloat16*)pevh, (__nv_bfloat16*)peoh, 0.0883883476483184f);

    gemm_mma_kernel<1,0><<<gexp, 256, GEMM_SMEM>>>((__nv_bfloat16*)peoh, (__nv_bfloat16*)peoh,
        (__nv_bfloat16*)pewoh, (__nv_bfloat16*)pewoh, nullptr, peout, nullptr, EROWS, Dm, Dm, sA, sW, sA);

    combine_ln_kernel<<<NT, 256>>>(ln2_g, ln2_b, out);
    finalize_kernel<<<1, 32>>>(out);
}

// round 6
// speedup vs baseline: 5.2990x; 1.3957x over previous
#include <cuda_runtime.h>
#include <cuda_bf16.h>
#include <math.h>
#include <stdint.h>

// ---------------- problem dims ----------------
#define Bt   8
#define Sq   1024
#define Dm   1024
#define NH   16
#define HD1  64
#define NE   8
#define NHM  8
#define HDM  128
#define CAP  320
#define NT   (Bt*Sq)
#define NTD  ((size_t)NT*Dm)
#define EROWS (Bt*CAP)
#define EINSZ ((size_t)NE*Bt*CAP*Dm)
#define DMDM ((size_t)Dm*Dm)

// ---------------- scratch ----------------
static __device__ float g_attn[NTD];
static __device__ float g_x1[NTD];
static __device__ float g_eout[EINSZ];

static __device__ __nv_bfloat16 g_xh[NTD];
static __device__ __nv_bfloat16 g_qkvh[3*NTD];       // [q|k|v]
static __device__ __nv_bfloat16 g_oh[NTD];
static __device__ __nv_bfloat16 g_einh[EINSZ];
static __device__ __nv_bfloat16 g_eqkv[3*EINSZ];     // [q|k|v] expert
static __device__ __nv_bfloat16 g_eoh[EINSZ];
static __device__ __nv_bfloat16 g_wqkvh[3*DMDM];     // [wq|wk|wv] transposed
static __device__ __nv_bfloat16 g_woh[DMDM];
static __device__ __nv_bfloat16 g_ewh[3*NE*DMDM];    // [q experts][k experts][v experts]
static __device__ __nv_bfloat16 g_ewoh[NE*DMDM];
static __device__ float g_bqkv[3*Dm];

static __device__ int   g_i0[NT], g_i1[NT];
static __device__ float g_g0[NT], g_g1[NT];
static __device__ int   g_p0[NT], g_p1[NT];
static __device__ int   g_k0[NT], g_k1[NT];

static __device__ float g_Psum[NE];
static __device__ float g_fcnt[NE];
static __device__ float g_zsum;

// ---------------- PTX helpers ----------------
__device__ __forceinline__ uint32_t smem_u32(const void* p) {
    uint32_t a;
    asm("{ .reg .u64 t; cvta.to.shared.u64 t, %1; cvt.u32.u64 %0, t; }" : "=r"(a) : "l"(p));
    return a;
}
__device__ __forceinline__ void cp16(uint32_t dst, const void* src) {
    asm volatile("cp.async.cg.shared.global [%0], [%1], 16;" :: "r"(dst), "l"(src));
}
__device__ __forceinline__ void ldmA(uint32_t* a, uint32_t addr) {
    asm volatile("ldmatrix.sync.aligned.m8n8.x4.shared.b16 {%0,%1,%2,%3}, [%4];"
        : "=r"(a[0]), "=r"(a[1]), "=r"(a[2]), "=r"(a[3]) : "r"(addr));
}
__device__ __forceinline__ void ldmT(uint32_t* a, uint32_t addr) {
    asm volatile("ldmatrix.sync.aligned.m8n8.x4.trans.shared.b16 {%0,%1,%2,%3}, [%4];"
        : "=r"(a[0]), "=r"(a[1]), "=r"(a[2]), "=r"(a[3]) : "r"(addr));
}
__device__ __forceinline__ void mma_bf16(float* d, const uint32_t* a, const uint32_t* b) {
    asm volatile(
        "mma.sync.aligned.m16n8k16.row.col.f32.bf16.bf16.f32 "
        "{%0,%1,%2,%3}, {%4,%5,%6,%7}, {%8,%9}, {%0,%1,%2,%3};"
        : "+f"(d[0]), "+f"(d[1]), "+f"(d[2]), "+f"(d[3])
        : "r"(a[0]), "r"(a[1]), "r"(a[2]), "r"(a[3]), "r"(b[0]), "r"(b[1]));
}
__device__ __forceinline__ uint32_t packbf(float a, float b) {
    __nv_bfloat162 v = __float22bfloat162_rn(make_float2(a, b));
    return *(uint32_t*)&v;
}

// ---------------- GEMM via mma.sync (single-pass bf16) ----------------
// C[z][M,N] = A[z%zmod][M,K] @ B[z]^T (+bias[z]); OUTBF: 0 fp32 out, 1 bf16 out.
#define BK 32
#define ROWB 80
#define STAGEB (128*ROWB)
#define STAGE2 (2*STAGEB)

template <int OUTBF>
__global__ __launch_bounds__(256, 1) void gemm_mma_kernel(
    const __nv_bfloat16* __restrict__ A, const __nv_bfloat16* __restrict__ B,
    const float* __restrict__ bias, void* __restrict__ Cv,
    int M, int N, int K, size_t sA, size_t sB, size_t sC, size_t sbias, int zmod)
{
    extern __shared__ char sm_[];
    uint32_t smb = smem_u32(sm_);

    int t = threadIdx.x, lane = t & 31, wid = t >> 5;
    int n0 = blockIdx.x * 128, m0 = blockIdx.y * 128;
    int z = blockIdx.z;
    A += (size_t)(z % zmod) * sA;
    B += (size_t)z * sB;
    if (bias) bias += (size_t)z * sbias;

    int wm = (wid & 3) * 32;
    int wn = (wid >> 2) * 64;
    const int NC = K / BK;

    float acc[2][8][4];
#pragma unroll
    for (int i = 0; i < 2; i++)
#pragma unroll
        for (int j = 0; j < 8; j++)
#pragma unroll
            for (int q = 0; q < 4; q++) acc[i][j][q] = 0.f;

    int r0i = t >> 2, s0i = t & 3;
    int r1i = (t + 256) >> 2, s1i = t & 3;

    {
        uint32_t ab = smb;
        cp16(ab + r0i * ROWB + s0i * 16, A + (size_t)(m0 + r0i) * K + s0i * 8);
        cp16(ab + r1i * ROWB + s1i * 16, A + (size_t)(m0 + r1i) * K + s1i * 8);
        uint32_t bb = smb + STAGEB;
        cp16(bb + r0i * ROWB + s0i * 16, B + (size_t)(n0 + r0i) * K + s0i * 8);
        cp16(bb + r1i * ROWB + s1i * 16, B + (size_t)(n0 + r1i) * K + s1i * 8);
        asm volatile("cp.async.commit_group;");
    }

    int nq = lane >> 2, kr = lane & 3;

    for (int c = 0; c < NC; c++) {
        if (c + 1 < NC) {
            int kc = (c + 1) * BK;
            uint32_t ab = smb + ((c + 1) & 1) * STAGE2;
            cp16(ab + r0i * ROWB + s0i * 16, A + (size_t)(m0 + r0i) * K + kc + s0i * 8);
            cp16(ab + r1i * ROWB + s1i * 16, A + (size_t)(m0 + r1i) * K + kc + s1i * 8);
            uint32_t bb = ab + STAGEB;
            cp16(bb + r0i * ROWB + s0i * 16, B + (size_t)(n0 + r0i) * K + kc + s0i * 8);
            cp16(bb + r1i * ROWB + s1i * 16, B + (size_t)(n0 + r1i) * K + kc + s1i * 8);
            asm volatile("cp.async.commit_group;");
            asm volatile("cp.async.wait_group 1;");
        } else {
            asm volatile("cp.async.wait_group 0;");
        }
        __syncthreads();

        uint32_t ab = smb + (c & 1) * STAGE2;
        const char* bbp = sm_ + (c & 1) * STAGE2 + STAGEB;

        uint32_t afr[2][2][4];
#pragma unroll
        for (int mt = 0; mt < 2; mt++)
#pragma unroll
            for (int ks = 0; ks < 2; ks++) {
                uint32_t addr = ab + (wm + mt * 16 + (lane & 15)) * ROWB
                              + (ks * 16 + (lane >> 4) * 8) * 2;
                ldmA(afr[mt][ks], addr);
            }
        uint32_t bfr[2][8][2];
#pragma unroll
        for (int ks = 0; ks < 2; ks++)
#pragma unroll
            for (int nt = 0; nt < 8; nt++) {
                const char* p = bbp + (wn + nt * 8 + nq) * ROWB + ks * 32 + kr * 4;
                bfr[ks][nt][0] = *(const uint32_t*)p;
                bfr[ks][nt][1] = *(const uint32_t*)(p + 16);
            }
#pragma unroll
        for (int ks = 0; ks < 2; ks++)
#pragma unroll
            for (int mt = 0; mt < 2; mt++)
#pragma unroll
                for (int nt = 0; nt < 8; nt++)
                    mma_bf16(acc[mt][nt], afr[mt][ks], bfr[ks][nt]);
        __syncthreads();
    }

#pragma unroll
    for (int mt = 0; mt < 2; mt++) {
        int m = m0 + wm + mt * 16 + (lane >> 2);
#pragma unroll
        for (int nt = 0; nt < 8; nt++) {
            int n = n0 + wn + nt * 8 + (lane & 3) * 2;
            float bv0 = bias ? bias[n] : 0.f;
            float bv1 = bias ? bias[n + 1] : 0.f;
            float v0 = acc[mt][nt][0] + bv0, v1 = acc[mt][nt][1] + bv1;
            float v2 = acc[mt][nt][2] + bv0, v3 = acc[mt][nt][3] + bv1;
            if (OUTBF == 0) {
                float* C = (float*)Cv + (size_t)z * sC;
                *(float2*)&C[(size_t)m * N + n]       = make_float2(v0, v1);
                *(float2*)&C[(size_t)(m + 8) * N + n] = make_float2(v2, v3);
            } else {
                __nv_bfloat16* C = (__nv_bfloat16*)Cv + (size_t)z * sC;
                *(uint32_t*)&C[(size_t)m * N + n]       = packbf(v0, v1);
                *(uint32_t*)&C[(size_t)(m + 8) * N + n] = packbf(v2, v3);
            }
        }
    }
}

// ---------------- expert flash (bf16 mma, HD=128) ----------------
#define EF_PITCH 272
#define EF_QS 0
#define EF_KS 17408
#define EF_VS 34816
#define EF_OB 52224
#define EF_MS 86016
#define EF_LS 86272
#define EF_AS 86528
#define EF_RM 86784
#define EF_RS 87296
#define EF_SMEM 87808

__global__ __launch_bounds__(256) void eflash_kernel(
    const __nv_bfloat16* __restrict__ Q, const __nv_bfloat16* __restrict__ K,
    const __nv_bfloat16* __restrict__ V, __nv_bfloat16* __restrict__ O,
    float scale)
{
    extern __shared__ char sm_[];
    float* Obuf = (float*)(sm_ + EF_OB);
    float* m_s  = (float*)(sm_ + EF_MS);
    float* l_s  = (float*)(sm_ + EF_LS);
    float* a_s  = (float*)(sm_ + EF_AS);
    float* redm = (float*)(sm_ + EF_RM);
    float* reds = (float*)(sm_ + EF_RS);
    uint32_t smb = smem_u32(sm_);

    int t = threadIdx.x, lane = t & 31, wid = t >> 5;
    int half = wid >> 2, wm = (wid & 3) * 16, wn2 = half * 32;
    int slice = blockIdx.y;
    int sb = slice >> 3, h = slice & 7;
    size_t base = (size_t)sb * CAP * 1024 + (size_t)h * HDM;
    int q0 = blockIdx.x * 64;

#pragma unroll
    for (int j = 0; j < 4; j++) {
        int id = t + 256 * j;
        int r = id >> 4, c = id & 15;
        *(uint4*)(sm_ + EF_QS + r * EF_PITCH + c * 16) =
            *(const uint4*)(Q + base + (size_t)(q0 + r) * 1024 + c * 8);
    }
    if (t < 64) { m_s[t] = -1e30f; l_s[t] = 0.f; }

    float o[16][4];
#pragma unroll
    for (int i = 0; i < 16; i++)
#pragma unroll
        for (int q = 0; q < 4; q++) o[i][q] = 0.f;

    int rl = wm + (lane >> 2), rh = rl + 8;
    int nq = lane >> 2, kr = lane & 3;

    for (int kt = 0; kt < CAP / 64; kt++) {
        __syncthreads();
#pragma unroll
        for (int j = 0; j < 4; j++) {
            int id = t + 256 * j;
            int r = id >> 4, c = id & 15;
            *(uint4*)(sm_ + EF_KS + r * EF_PITCH + c * 16) =
                *(const uint4*)(K + base + (size_t)(kt * 64 + r) * 1024 + c * 8);
            *(uint4*)(sm_ + EF_VS + r * EF_PITCH + c * 16) =
                *(const uint4*)(V + base + (size_t)(kt * 64 + r) * 1024 + c * 8);
        }
        __syncthreads();

        float s[4][4];
#pragma unroll
        for (int nt = 0; nt < 4; nt++)
#pragma unroll
            for (int q = 0; q < 4; q++) s[nt][q] = 0.f;
#pragma unroll
        for (int ks = 0; ks < 8; ks++) {
            uint32_t af[4];
            ldmA(af, smb + EF_QS + (wm + (lane & 15)) * EF_PITCH + ks * 32 + (lane >> 4) * 16);
#pragma unroll
            for (int nt = 0; nt < 4; nt++) {
                const char* p = sm_ + EF_KS + (wn2 + nt * 8 + nq) * EF_PITCH + ks * 32 + kr * 4;
                uint32_t bb[2];
                bb[0] = *(const uint32_t*)p;
                bb[1] = *(const uint32_t*)(p + 16);
                mma_bf16(s[nt], af, bb);
            }
        }

        float mxlo = -1e30f, mxhi = -1e30f;
#pragma unroll
        for (int nt = 0; nt < 4; nt++) {
            s[nt][0] *= scale; s[nt][1] *= scale; s[nt][2] *= scale; s[nt][3] *= scale;
            mxlo = fmaxf(mxlo, fmaxf(s[nt][0], s[nt][1]));
            mxhi = fmaxf(mxhi, fmaxf(s[nt][2], s[nt][3]));
        }
        mxlo = fmaxf(mxlo, __shfl_xor_sync(0xffffffff, mxlo, 1));
        mxlo = fmaxf(mxlo, __shfl_xor_sync(0xffffffff, mxlo, 2));
        mxhi = fmaxf(mxhi, __shfl_xor_sync(0xffffffff, mxhi, 1));
        mxhi = fmaxf(mxhi, __shfl_xor_sync(0xffffffff, mxhi, 2));
        if ((lane & 3) == 0) { redm[half * 64 + rl] = mxlo; redm[half * 64 + rh] = mxhi; }
        __syncthreads();
        if (t < 64) {
            float mo = m_s[t];
            float mn = fmaxf(mo, fmaxf(redm[t], redm[64 + t]));
            float al = __expf(mo - mn);
            a_s[t] = al; m_s[t] = mn; l_s[t] *= al;
        }
        __syncthreads();

        float mlo = m_s[rl], mhi = m_s[rh], alo = a_s[rl], ahi = a_s[rh];
        float slo = 0.f, shi = 0.f;
        uint32_t afr[2][4];
#pragma unroll
        for (int ks = 0; ks < 2; ks++) {
#pragma unroll
            for (int jj = 0; jj < 2; jj++) {
                int nt = ks * 2 + jj;
                float p0 = __expf(s[nt][0] - mlo), p1 = __expf(s[nt][1] - mlo);
                float p2 = __expf(s[nt][2] - mhi), p3 = __expf(s[nt][3] - mhi);
                slo += p0 + p1; shi += p2 + p3;
                afr[ks][jj * 2 + 0] = packbf(p0, p1);
                afr[ks][jj * 2 + 1] = packbf(p2, p3);
            }
        }
        slo += __shfl_xor_sync(0xffffffff, slo, 1);
        slo += __shfl_xor_sync(0xffffffff, slo, 2);
        shi += __shfl_xor_sync(0xffffffff, shi, 1);
        shi += __shfl_xor_sync(0xffffffff, shi, 2);
        if ((lane & 3) == 0) { reds[half * 64 + rl] = slo; reds[half * 64 + rh] = shi; }

#pragma unroll
        for (int nt = 0; nt < 16; nt++) {
            o[nt][0] *= alo; o[nt][1] *= alo; o[nt][2] *= ahi; o[nt][3] *= ahi;
        }

#pragma unroll
        for (int ks = 0; ks < 2; ks++) {
#pragma unroll
            for (int nb = 0; nb < 8; nb++) {
                uint32_t b4[4];
                ldmT(b4, smb + EF_VS + (wn2 + ks * 16 + (lane & 15)) * EF_PITCH
                         + nb * 32 + (lane >> 4) * 16);
                mma_bf16(o[2 * nb],     afr[ks], b4);
                mma_bf16(o[2 * nb + 1], afr[ks], b4 + 2);
            }
        }
        __syncthreads();
        if (t < 64) l_s[t] += reds[t] + reds[64 + t];
    }

    __syncthreads();
    if (half == 0) {
#pragma unroll
        for (int nt = 0; nt < 16; nt++) {
            float* plo = Obuf + rl * 132 + nt * 8 + (lane & 3) * 2;
            float* phi = Obuf + rh * 132 + nt * 8 + (lane & 3) * 2;
            plo[0] = o[nt][0]; plo[1] = o[nt][1];
            phi[0] = o[nt][2]; phi[1] = o[nt][3];
        }
    }
    __syncthreads();
    if (half == 1) {
#pragma unroll
        for (int nt = 0; nt < 16; nt++) {
            float* plo = Obuf + rl * 132 + nt * 8 + (lane & 3) * 2;
            float* phi = Obuf + rh * 132 + nt * 8 + (lane & 3) * 2;
            plo[0] += o[nt][0]; plo[1] += o[nt][1];
            phi[0] += o[nt][2]; phi[1] += o[nt][3];
        }
    }
    __syncthreads();
#pragma unroll
    for (int j = 0; j < 16; j++) {
        int id = t + 256 * j;
        int r = id >> 6, cp = id & 63;
        float inv = 1.f / l_s[r];
        float2 v = *(float2*)(Obuf + r * 132 + cp * 2);
        __nv_bfloat162 ob = __float22bfloat162_rn(make_float2(v.x * inv, v.y * inv));
        *(__nv_bfloat162*)(O + base + (size_t)(q0 + r) * 1024 + cp * 2) = ob;
    }
}

// ---------------- main flash (bf16 mma, HD=64) ----------------
#define MF_PITCH 144
#define MF_QS 0
#define MF_KS 9216
#define MF_VS 18432
#define MF_OB 27648
#define MF_MS 45056
#define MF_LS 45312
#define MF_AS 45568
#define MF_RM 45824
#define MF_RS 46336
#define MF_SMEM 46848

__global__ __launch_bounds__(256) void mflash_kernel(
    const __nv_bfloat16* __restrict__ Q, const __nv_bfloat16* __restrict__ K,
    const __nv_bfloat16* __restrict__ V, __nv_bfloat16* __restrict__ O,
    float scale)
{
    extern __shared__ char sm_[];
    float* Obuf = (float*)(sm_ + MF_OB);
    float* m_s  = (float*)(sm_ + MF_MS);
    float* l_s  = (float*)(sm_ + MF_LS);
    float* a_s  = (float*)(sm_ + MF_AS);
    float* redm = (float*)(sm_ + MF_RM);
    float* reds = (float*)(sm_ + MF_RS);
    uint32_t smb = smem_u32(sm_);

    int t = threadIdx.x, lane = t & 31, wid = t >> 5;
    int half = wid >> 2, wm = (wid & 3) * 16, wn2 = half * 32;
    int slice = blockIdx.y;
    int sb = slice >> 4, h = slice & 15;
    size_t base = (size_t)sb * Sq * 1024 + (size_t)h * HD1;
    int q0 = blockIdx.x * 64;

#pragma unroll
    for (int j = 0; j < 2; j++) {
        int id = t + 256 * j;
        int r = id >> 3, c = id & 7;
        *(uint4*)(sm_ + MF_QS + r * MF_PITCH + c * 16) =
            *(const uint4*)(Q + base + (size_t)(q0 + r) * 1024 + c * 8);
    }
    if (t < 64) { m_s[t] = -1e30f; l_s[t] = 0.f; }

    float o[8][4];
#pragma unroll
    for (int i = 0; i < 8; i++)
#pragma unroll
        for (int q = 0; q < 4; q++) o[i][q] = 0.f;

    int rl = wm + (lane >> 2), rh = rl + 8;
    int nq = lane >> 2, kr = lane & 3;

    for (int kt = 0; kt < Sq / 64; kt++) {
        __syncthreads();
#pragma unroll
        for (int j = 0; j < 2; j++) {
            int id = t + 256 * j;
            int r = id >> 3, c = id & 7;
            size_t g = base + (size_t)(kt * 64 + r) * 1024 + c * 8;
            *(uint4*)(sm_ + MF_KS + r * MF_PITCH + c * 16) = *(const uint4*)(K + g);
            *(uint4*)(sm_ + MF_VS + r * MF_PITCH + c * 16) = *(const uint4*)(V + g);
        }
        __syncthreads();

        float s[4][4];
#pragma unroll
        for (int nt = 0; nt < 4; nt++)
#pragma unroll
            for (int q = 0; q < 4; q++) s[nt][q] = 0.f;
#pragma unroll
        for (int ks = 0; ks < 4; ks++) {
            uint32_t af[4];
            ldmA(af, smb + MF_QS + (wm + (lane & 15)) * MF_PITCH + ks * 32 + (lane >> 4) * 16);
#pragma unroll
            for (int nt = 0; nt < 4; nt++) {
                const char* p = sm_ + MF_KS + (wn2 + nt * 8 + nq) * MF_PITCH + ks * 32 + kr * 4;
                uint32_t bb[2];
                bb[0] = *(const uint32_t*)p;
                bb[1] = *(const uint32_t*)(p + 16);
                mma_bf16(s[nt], af, bb);
            }
        }

        float mxlo = -1e30f, mxhi = -1e30f;
#pragma unroll
        for (int nt = 0; nt < 4; nt++) {
            s[nt][0] *= scale; s[nt][1] *= scale; s[nt][2] *= scale; s[nt][3] *= scale;
            mxlo = fmaxf(mxlo, fmaxf(s[nt][0], s[nt][1]));
            mxhi = fmaxf(mxhi, fmaxf(s[nt][2], s[nt][3]));
        }
        mxlo = fmaxf(mxlo, __shfl_xor_sync(0xffffffff, mxlo, 1));
        mxlo = fmaxf(mxlo, __shfl_xor_sync(0xffffffff, mxlo, 2));
        mxhi = fmaxf(mxhi, __shfl_xor_sync(0xffffffff, mxhi, 1));
        mxhi = fmaxf(mxhi, __shfl_xor_sync(0xffffffff, mxhi, 2));
        if ((lane & 3) == 0) { redm[half * 64 + rl] = mxlo; redm[half * 64 + rh] = mxhi; }
        __syncthreads();
        if (t < 64) {
            float mo = m_s[t];
            float mn = fmaxf(mo, fmaxf(redm[t], redm[64 + t]));
            float al = __expf(mo - mn);
            a_s[t] = al; m_s[t] = mn; l_s[t] *= al;
        }
        __syncthreads();

        float mlo = m_s[rl], mhi = m_s[rh], alo = a_s[rl], ahi = a_s[rh];
        float slo = 0.f, shi = 0.f;
        uint32_t afr[2][4];
#pragma unroll
        for (int ks = 0; ks < 2; ks++) {
#pragma unroll
            for (int jj = 0; jj < 2; jj++) {
                int nt = ks * 2 + jj;
                float p0 = __expf(s[nt][0] - mlo), p1 = __expf(s[nt][1] - mlo);
                float p2 = __expf(s[nt][2] - mhi), p3 = __expf(s[nt][3] - mhi);
                slo += p0 + p1; shi += p2 + p3;
                afr[ks][jj * 2 + 0] = packbf(p0, p1);
                afr[ks][jj * 2 + 1] = packbf(p2, p3);
            }
        }
        slo += __shfl_xor_sync(0xffffffff, slo, 1);
        slo += __shfl_xor_sync(0xffffffff, slo, 2);
        shi += __shfl_xor_sync(0xffffffff, shi, 1);
        shi += __shfl_xor_sync(0xffffffff, shi, 2);
        if ((lane & 3) == 0) { reds[half * 64 + rl] = slo; reds[half * 64 + rh] = shi; }

#pragma unroll
        for (int nt = 0; nt < 8; nt++) {
            o[nt][0] *= alo; o[nt][1] *= alo; o[nt][2] *= ahi; o[nt][3] *= ahi;
        }

#pragma unroll
        for (int ks = 0; ks < 2; ks++) {
#pragma unroll
            for (int nb = 0; nb < 4; nb++) {
                uint32_t b4[4];
                ldmT(b4, smb + MF_VS + (wn2 + ks * 16 + (lane & 15)) * MF_PITCH
                         + nb * 32 + (lane >> 4) * 16);
                mma_bf16(o[2 * nb],     afr[ks], b4);
                mma_bf16(o[2 * nb + 1], afr[ks], b4 + 2);
            }
        }
        __syncthreads();
        if (t < 64) l_s[t] += reds[t] + reds[64 + t];
    }

    __syncthreads();
    if (half == 0) {
#pragma unroll
        for (int nt = 0; nt < 8; nt++) {
            float* plo = Obuf + rl * 68 + nt * 8 + (lane & 3) * 2;
            float* phi = Obuf + rh * 68 + nt * 8 + (lane & 3) * 2;
            plo[0] = o[nt][0]; plo[1] = o[nt][1];
            phi[0] = o[nt][2]; phi[1] = o[nt][3];
        }
    }
    __syncthreads();
    if (half == 1) {
#pragma unroll
        for (int nt = 0; nt < 8; nt++) {
            float* plo = Obuf + rl * 68 + nt * 8 + (lane & 3) * 2;
            float* phi = Obuf + rh * 68 + nt * 8 + (lane & 3) * 2;
            plo[0] += o[nt][0]; plo[1] += o[nt][1];
            phi[0] += o[nt][2]; phi[1] += o[nt][3];
        }
    }
    __syncthreads();
#pragma unroll
    for (int j = 0; j < 8; j++) {
        int id = t + 256 * j;
        int r = id >> 5, cp = id & 31;
        float inv = 1.f / l_s[r];
        float2 v = *(float2*)(Obuf + r * 68 + cp * 2);
        __nv_bfloat162 ob = __float22bfloat162_rn(make_float2(v.x * inv, v.y * inv));
        *(__nv_bfloat162*)(O + base + (size_t)(q0 + r) * 1024 + cp * 2) = ob;
    }
}

// ---------------- fp32 -> bf16 convert ----------------
__global__ __launch_bounds__(256) void cvt_kernel(
    const float4* __restrict__ s, uint2* __restrict__ h, int n4)
{
    int i = blockIdx.x * 256 + threadIdx.x;
    if (i >= n4) return;
    float4 v = s[i];
    uint2 hh;
    hh.x = packbf(v.x, v.y);
    hh.y = packbf(v.z, v.w);
    h[i] = hh;
}

// ---------------- weight transpose (fp32 [K,N] -> bf16 [N,K]) ----------------
__global__ void wtrans_kernel(const float* __restrict__ W,
                              __nv_bfloat16* __restrict__ Th, int Kd, int Nd)
{
    __shared__ float tile[32][33];
    int tx = threadIdx.x, ty = threadIdx.y;
    int n0 = blockIdx.x * 32, k0 = blockIdx.y * 32;
    size_t ob = (size_t)blockIdx.z * Kd * Nd;
    const float* Wb = W + ob;
#pragma unroll
    for (int r = 0; r < 4; r++)
        tile[ty + 8 * r][tx] = Wb[(size_t)(k0 + ty + 8 * r) * Nd + n0 + tx];
    __syncthreads();
#pragma unroll
    for (int r = 0; r < 4; r++)
        Th[ob + (size_t)(n0 + ty + 8 * r) * Kd + k0 + tx] =
            __float2bfloat16(tile[tx][ty + 8 * r]);
}

// ---------------- zero kernels ----------------
__global__ void zero_stats_kernel() {
    int t = threadIdx.x;
    if (t < NE) { g_Psum[t] = 0.f; g_fcnt[t] = 0.f; }
    if (t == 0) g_zsum = 0.f;
}

__global__ void zero_ein_kernel() {
    size_t n = EINSZ / 8;
    uint4 z = make_uint4(0, 0, 0, 0);
    uint4* ph = (uint4*)g_einh;
    for (size_t i = blockIdx.x * (size_t)blockDim.x + threadIdx.x; i < n;
         i += (size_t)gridDim.x * blockDim.x) ph[i] = z;
}

// ---------------- block reduce ----------------
__device__ __forceinline__ void block_reduce2(float& s, float& s2) {
    __shared__ float rs[8], rs2[8];
#pragma unroll
    for (int o = 16; o > 0; o >>= 1) {
        s  += __shfl_xor_sync(0xffffffff, s, o);
        s2 += __shfl_xor_sync(0xffffffff, s2, o);
    }
    int lane = threadIdx.x & 31, w = threadIdx.x >> 5;
    if (lane == 0) { rs[w] = s; rs2[w] = s2; }
    __syncthreads();
    float ts = 0.f, ts2 = 0.f;
#pragma unroll
    for (int i = 0; i < 8; i++) { ts += rs[i]; ts2 += rs2[i]; }
    s = ts; s2 = ts2;
}

// ---------------- LN1 ----------------
__global__ __launch_bounds__(256) void ln1_kernel(
    const float* __restrict__ x, const float* __restrict__ g,
    const float* __restrict__ b)
{
    size_t tok = blockIdx.x;
    int t = threadIdx.x;
    float v[4], s = 0.f, s2 = 0.f;
#pragma unroll
    for (int u = 0; u < 4; u++) {
        int j = t + u * 256;
        float val = x[tok * Dm + j] + g_attn[tok * Dm + j];
        v[u] = val; s += val; s2 += val * val;
    }
    block_reduce2(s, s2);
    float mean = s * (1.f / Dm);
    float var  = s2 * (1.f / Dm) - mean * mean;
    float inv  = rsqrtf(var + 1e-5f);
#pragma unroll
    for (int u = 0; u < 4; u++) {
        int j = t + u * 256;
        g_x1[tok * Dm + j] = (v[u] - mean) * inv * g[j] + b[j];
    }
}

// ---------------- gate ----------------
__global__ __launch_bounds__(256) void gate_kernel(const float* __restrict__ gateW) {
    int warp = threadIdx.x >> 5, lane = threadIdx.x & 31;
    int tok = blockIdx.x * 8 + warp;
    const float* xr = g_x1 + (size_t)tok * Dm;
    float acc[NE];
#pragma unroll
    for (int e = 0; e < NE; e++) acc[e] = 0.f;
    for (int k = lane; k < Dm; k += 32) {
        float xv = xr[k];
        const float* wr = gateW + (size_t)k * NE;
#pragma unroll
        for (int e = 0; e < NE; e++) acc[e] += xv * wr[e];
    }
#pragma unroll
    for (int e = 0; e < NE; e++)
#pragma unroll
        for (int o = 16; o > 0; o >>= 1)
            acc[e] += __shfl_xor_sync(0xffffffff, acc[e], o);
    if (lane == 0) {
        float mx = acc[0];
#pragma unroll
        for (int e = 1; e < NE; e++) mx = fmaxf(mx, acc[e]);
        float p[NE], se = 0.f;
#pragma unroll
        for (int e = 0; e < NE; e++) { p[e] = __expf(acc[e] - mx); se += p[e]; }
        float invs = 1.f / se;
        float lse = mx + logf(se);
        atomicAdd(&g_zsum, lse * lse);
        int i0 = 0, i1 = -1;
        float b0 = -1.f, b1 = -1.f;
#pragma unroll
        for (int e = 0; e < NE; e++) {
            float pe = p[e] * invs;
            atomicAdd(&g_Psum[e], pe);
            if (pe > b0) { b1 = b0; i1 = i0; b0 = pe; i0 = e; }
            else if (pe > b1) { b1 = pe; i1 = e; }
        }
        atomicAdd(&g_fcnt[i0], 1.f);
        g_i0[tok] = i0; g_i1[tok] = i1;
        g_g0[tok] = b0; g_g1[tok] = b1;
    }
}

// ---------------- routing positions ----------------
__global__ __launch_bounds__(256) void pos_kernel() {
    int warp = threadIdx.x >> 5, lane = threadIdx.x & 31;
    if (warp >= Bt) return;
    int b = warp;
    unsigned lt = (1u << lane) - 1u;
    int cnt[NE];
#pragma unroll
    for (int e = 0; e < NE; e++) cnt[e] = 0;

    for (int ch = 0; ch < Sq / 32; ch++) {
        int tok = b * Sq + ch * 32 + lane;
        int e0 = g_i0[tok];
        int myp = 0;
#pragma unroll
        for (int e = 0; e < NE; e++) {
            unsigned m = __ballot_sync(0xffffffff, e0 == e);
            if (e0 == e) myp = cnt[e] + __popc(m & lt);
            cnt[e] += __popc(m);
        }
        g_k0[tok] = (myp < CAP) ? 1 : 0;
        g_p0[tok] = min(myp, CAP - 1);
    }
    for (int ch = 0; ch < Sq / 32; ch++) {
        int tok = b * Sq + ch * 32 + lane;
        int e1 = g_i1[tok];
        bool valid = g_g1[tok] > 0.2f;
        int myp = 0;
#pragma unroll
        for (int e = 0; e < NE; e++) {
            unsigned m = __ballot_sync(0xffffffff, valid && (e1 == e));
            if (valid && (e1 == e)) myp = cnt[e] + __popc(m & lt);
            cnt[e] += __popc(m);
        }
        bool keep = valid && (myp < CAP);
        g_k1[tok] = keep ? 1 : 0;
        g_p1[tok] = valid ? min(myp, CAP - 1) : 0;
    }
}

// ---------------- scatter (x1 fp32 -> einh bf16) ----------------
__global__ __launch_bounds__(256) void scatter_kernel() {
    int idx = blockIdx.x;
    int tok = idx >> 1, slot = idx & 1;
    int keep = slot ? g_k1[tok] : g_k0[tok];
    if (!keep) return;
    int e = slot ? g_i1[tok] : g_i0[tok];
    int p = slot ? g_p1[tok] : g_p0[tok];
    int b = tok / Sq;
    const float4* src = (const float4*)(g_x1 + (size_t)tok * Dm);
    size_t ro = (((size_t)e * Bt + b) * CAP + p) * Dm;
    uint2* dh = (uint2*)(g_einh + ro);
    float4 v = src[threadIdx.x];
    uint2 hh;
    hh.x = packbf(v.x, v.y);
    hh.y = packbf(v.z, v.w);
    dh[threadIdx.x] = hh;
}

// ---------------- combine + LN2 ----------------
__global__ __launch_bounds__(256) void combine_ln_kernel(
    const float* __restrict__ g2, const float* __restrict__ b2,
    float* __restrict__ out)
{
    size_t tok = blockIdx.x;
    int t = threadIdx.x;
    int b = (int)(tok >> 10);
    float w0 = g_k0[tok] ? g_g0[tok] : 0.f;
    float w1 = g_k1[tok] ? g_g1[tok] : 0.f;
    const float* r0 = g_eout + (((size_t)g_i0[tok] * Bt + b) * CAP + g_p0[tok]) * Dm;
    const float* r1 = g_eout + (((size_t)g_i1[tok] * Bt + b) * CAP + g_p1[tok]) * Dm;

    float v[4], s = 0.f, s2 = 0.f;
#pragma unroll
    for (int u = 0; u < 4; u++) {
        int j = t + u * 256;
        float val = g_x1[tok * Dm + j] + w0 * r0[j] + w1 * r1[j];
        v[u] = val; s += val; s2 += val * val;
    }
    block_reduce2(s, s2);
    float mean = s * (1.f / Dm);
    float var  = s2 * (1.f / Dm) - mean * mean;
    float inv  = rsqrtf(var + 1e-5f);
#pragma unroll
    for (int u = 0; u < 4; u++) {
        int j = t + u * 256;
        out[tok * Dm + j] = (v[u] - mean) * inv * g2[j] + b2[j];
    }
}

// ---------------- finalize aux ----------------
__global__ void finalize_kernel(float* __restrict__ out) {
    if (threadIdx.x == 0 && blockIdx.x == 0) {
        float invN = 1.f / (float)NT;
        float sfp = 0.f;
#pragma unroll
        for (int e = 0; e < NE; e++)
            sfp += (g_fcnt[e] * invN) * (g_Psum[e] * invN);
        float bal = 0.01f * (float)NE * sfp;
        float zl  = 0.001f * g_zsum * invN;
        out[NTD + 0] = bal + zl;
        out[NTD + 1] = bal;
        out[NTD + 2] = zl;
    }
}

// ---------------- host launcher ----------------
extern "C" void kernel_launch(void* const* d_in, const int* in_sizes, int n_in,
                              void* d_out, int out_size)
{
    const float* x      = (const float*)d_in[0];
    const float* Wq     = (const float*)d_in[1];
    const float* Wk     = (const float*)d_in[2];
    const float* Wv     = (const float*)d_in[3];
    const float* Wo     = (const float*)d_in[4];
    const float* bq     = (const float*)d_in[5];
    const float* bk     = (const float*)d_in[6];
    const float* bv     = (const float*)d_in[7];
    const float* bo     = (const float*)d_in[8];
    const float* ln1_g  = (const float*)d_in[9];
    const float* ln1_b  = (const float*)d_in[10];
    const float* ln2_g  = (const float*)d_in[11];
    const float* ln2_b  = (const float*)d_in[12];
    const float* gate_W = (const float*)d_in[13];
    const float* eWq    = (const float*)d_in[14];
    const float* eWk    = (const float*)d_in[15];
    const float* eWv    = (const float*)d_in[16];
    const float* eWo    = (const float*)d_in[17];
    float* out = (float*)d_out;

    void *pattn, *px1, *peout, *pxh, *pqkvh, *poh;
    void *peinh, *peqkv, *peoh;
    void *pwqkvh, *pwoh, *pewh, *pewoh, *pbqkv;
    cudaGetSymbolAddress(&pattn, g_attn);   cudaGetSymbolAddress(&px1, g_x1);
    cudaGetSymbolAddress(&peout, g_eout);   cudaGetSymbolAddress(&pxh, g_xh);
    cudaGetSymbolAddress(&pqkvh, g_qkvh);   cudaGetSymbolAddress(&poh, g_oh);
    cudaGetSymbolAddress(&peinh, g_einh);   cudaGetSymbolAddress(&peqkv, g_eqkv);
    cudaGetSymbolAddress(&peoh, g_eoh);
    cudaGetSymbolAddress(&pwqkvh, g_wqkvh); cudaGetSymbolAddress(&pwoh, g_woh);
    cudaGetSymbolAddress(&pewh, g_ewh);     cudaGetSymbolAddress(&pewoh, g_ewoh);
    cudaGetSymbolAddress(&pbqkv, g_bqkv);

    const int GEMM_SMEM = 2 * STAGE2;
    cudaFuncSetAttribute(gemm_mma_kernel<0>, cudaFuncAttributeMaxDynamicSharedMemorySize, GEMM_SMEM);
    cudaFuncSetAttribute(gemm_mma_kernel<1>, cudaFuncAttributeMaxDynamicSharedMemorySize, GEMM_SMEM);
    cudaFuncSetAttribute(mflash_kernel, cudaFuncAttributeMaxDynamicSharedMemorySize, MF_SMEM);
    cudaFuncSetAttribute(eflash_kernel, cudaFuncAttributeMaxDynamicSharedMemorySize, EF_SMEM);

    zero_stats_kernel<<<1, 32>>>();
    zero_ein_kernel<<<2048, 256>>>();

    // combined bias buffer for batched QKV
    cudaMemcpyAsync((float*)pbqkv,          bq, Dm * sizeof(float), cudaMemcpyDeviceToDevice);
    cudaMemcpyAsync((float*)pbqkv + Dm,     bk, Dm * sizeof(float), cudaMemcpyDeviceToDevice);
    cudaMemcpyAsync((float*)pbqkv + 2 * Dm, bv, Dm * sizeof(float), cudaMemcpyDeviceToDevice);

    dim3 tb(32, 8);
    __nv_bfloat16* wqkv = (__nv_bfloat16*)pwqkvh;
    __nv_bfloat16* ewh  = (__nv_bfloat16*)pewh;
    wtrans_kernel<<<dim3(32, 32, 1), tb>>>(Wq, wqkv,            Dm, Dm);
    wtrans_kernel<<<dim3(32, 32, 1), tb>>>(Wk, wqkv + DMDM,     Dm, Dm);
    wtrans_kernel<<<dim3(32, 32, 1), tb>>>(Wv, wqkv + 2 * DMDM, Dm, Dm);
    wtrans_kernel<<<dim3(32, 32, 1), tb>>>(Wo, (__nv_bfloat16*)pwoh, Dm, Dm);
    wtrans_kernel<<<dim3(32, 32, NE), tb>>>(eWq, ewh,                 Dm, Dm);
    wtrans_kernel<<<dim3(32, 32, NE), tb>>>(eWk, ewh + NE * DMDM,     Dm, Dm);
    wtrans_kernel<<<dim3(32, 32, NE), tb>>>(eWv, ewh + 2 * NE * DMDM, Dm, Dm);
    wtrans_kernel<<<dim3(32, 32, NE), tb>>>(eWo, (__nv_bfloat16*)pewoh, Dm, Dm);

    cvt_kernel<<<(int)(NTD / 4 / 256), 256>>>((const float4*)x, (uint2*)pxh, (int)(NTD / 4));

    // main QKV: one batched launch, z in [0,3)
    gemm_mma_kernel<1><<<dim3(Dm / 128, NT / 128, 3), 256, GEMM_SMEM>>>(
        (__nv_bfloat16*)pxh, wqkv, (const float*)pbqkv, pqkvh,
        NT, Dm, Dm, 0, DMDM, NTD, Dm, 3);

    __nv_bfloat16* qkv = (__nv_bfloat16*)pqkvh;
    mflash_kernel<<<dim3(Sq / 64, Bt * NH), 256, MF_SMEM>>>(
        qkv, qkv + NTD, qkv + 2 * NTD, (__nv_bfloat16*)poh, 0.125f);

    // Wo
    gemm_mma_kernel<0><<<dim3(Dm / 128, NT / 128, 1), 256, GEMM_SMEM>>>(
        (__nv_bfloat16*)poh, (__nv_bfloat16*)pwoh, bo, pattn,
        NT, Dm, Dm, 0, 0, 0, 0, 1);

    ln1_kernel<<<NT, 256>>>(x, ln1_g, ln1_b);
    gate_kernel<<<NT / 8, 256>>>(gate_W);
    pos_kernel<<<1, 256>>>();
    scatter_kernel<<<NT * 2, 256>>>();

    // expert QKV: one batched launch, z = p*NE + e in [0,24)
    size_t sA = (size_t)EROWS * Dm;
    gemm_mma_kernel<1><<<dim3(Dm / 128, EROWS / 128, 24), 256, GEMM_SMEM>>>(
        (__nv_bfloat16*)peinh, ewh, nullptr, peqkv,
        EROWS, Dm, Dm, sA, DMDM, sA, 0, NE);

    __nv_bfloat16* eqkv = (__nv_bfloat16*)peqkv;
    eflash_kernel<<<dim3(CAP / 64, NE * Bt * NHM), 256, EF_SMEM>>>(
        eqkv, eqkv + EINSZ, eqkv + 2 * EINSZ, (__nv_bfloat16*)peoh, 0.0883883476483184f);

    // expert Wo: z in [0,8)
    gemm_mma_kernel<0><<<dim3(Dm / 128, EROWS / 128, NE), 256, GEMM_SMEM>>>(
        (__nv_bfloat16*)peoh, (__nv_bfloat16*)pewoh, nullptr, peout,
        EROWS, Dm, Dm, sA, DMDM, sA, 0, NE);

    combine_ln_kernel<<<NT, 256>>>(ln2_g, ln2_b, out);
    finalize_kernel<<<1, 32>>>(out);
}

// round 7
// speedup vs baseline: 6.2729x; 1.1838x over previous
#include <cuda_runtime.h>
#include <cuda_bf16.h>
#include <math.h>
#include <stdint.h>

// ---------------- problem dims ----------------
#define Bt   8
#define Sq   1024
#define Dm   1024
#define NH   16
#define HD1  64
#define NE   8
#define NHM  8
#define HDM  128
#define CAP  320
#define NT   (Bt*Sq)
#define NTD  ((size_t)NT*Dm)
#define EROWS (Bt*CAP)
#define EINSZ ((size_t)NE*Bt*CAP*Dm)
#define DMDM ((size_t)Dm*Dm)

// ---------------- scratch ----------------
static __device__ float g_attn[NTD];
static __device__ float g_x1[NTD];
static __device__ float g_eout[EINSZ];

static __device__ __nv_bfloat16 g_xh[NTD];
static __device__ __nv_bfloat16 g_qkvh[3*NTD];       // [q|k|v]
static __device__ __nv_bfloat16 g_oh[NTD];
static __device__ __nv_bfloat16 g_einh[EINSZ];
static __device__ __nv_bfloat16 g_eqkv[3*EINSZ];     // [q|k|v] expert
static __device__ __nv_bfloat16 g_eoh[EINSZ];
static __device__ __nv_bfloat16 g_wqkvh[3*DMDM];     // [wq|wk|wv] transposed
static __device__ __nv_bfloat16 g_woh[DMDM];
static __device__ __nv_bfloat16 g_ewh[3*NE*DMDM];    // [q experts][k experts][v experts]
static __device__ __nv_bfloat16 g_ewoh[NE*DMDM];
static __device__ float g_bqkv[3*Dm];

static __device__ int   g_i0[NT], g_i1[NT];
static __device__ float g_g0[NT], g_g1[NT];
static __device__ int   g_p0[NT], g_p1[NT];
static __device__ int   g_k0[NT], g_k1[NT];

static __device__ float g_Psum[NE];
static __device__ float g_fcnt[NE];
static __device__ float g_zsum;

// ---------------- PTX helpers ----------------
__device__ __forceinline__ uint32_t smem_u32(const void* p) {
    uint32_t a;
    asm("{ .reg .u64 t; cvta.to.shared.u64 t, %1; cvt.u32.u64 %0, t; }" : "=r"(a) : "l"(p));
    return a;
}
__device__ __forceinline__ void cp16(uint32_t dst, const void* src) {
    asm volatile("cp.async.cg.shared.global [%0], [%1], 16;" :: "r"(dst), "l"(src));
}
__device__ __forceinline__ void ldmA(uint32_t* a, uint32_t addr) {
    asm volatile("ldmatrix.sync.aligned.m8n8.x4.shared.b16 {%0,%1,%2,%3}, [%4];"
        : "=r"(a[0]), "=r"(a[1]), "=r"(a[2]), "=r"(a[3]) : "r"(addr));
}
__device__ __forceinline__ void ldmT(uint32_t* a, uint32_t addr) {
    asm volatile("ldmatrix.sync.aligned.m8n8.x4.trans.shared.b16 {%0,%1,%2,%3}, [%4];"
        : "=r"(a[0]), "=r"(a[1]), "=r"(a[2]), "=r"(a[3]) : "r"(addr));
}
__device__ __forceinline__ void mma_bf16(float* d, const uint32_t* a, const uint32_t* b) {
    asm volatile(
        "mma.sync.aligned.m16n8k16.row.col.f32.bf16.bf16.f32 "
        "{%0,%1,%2,%3}, {%4,%5,%6,%7}, {%8,%9}, {%0,%1,%2,%3};"
        : "+f"(d[0]), "+f"(d[1]), "+f"(d[2]), "+f"(d[3])
        : "r"(a[0]), "r"(a[1]), "r"(a[2]), "r"(a[3]), "r"(b[0]), "r"(b[1]));
}
__device__ __forceinline__ uint32_t packbf(float a, float b) {
    __nv_bfloat162 v = __float22bfloat162_rn(make_float2(a, b));
    return *(uint32_t*)&v;
}

// ---------------- GEMM via mma.sync (bf16, 4-stage cp.async, ldmatrix A+B) ---
// C[z][M,N] = A[z%zmod][M,K] @ B[z]^T (+bias[z]); OUTBF: 0 fp32 out, 1 bf16 out.
#define BK 32
#define ROWB 80
#define STAGEB (128*ROWB)      // 10240 per matrix
#define STAGE2 (2*STAGEB)      // 20480 per stage (A+B)
#define NSTG 4
#define GEMM_SMEM (NSTG*STAGE2)  // 81920

template <int OUTBF>
__global__ __launch_bounds__(256, 1) void gemm_mma_kernel(
    const __nv_bfloat16* __restrict__ A, const __nv_bfloat16* __restrict__ B,
    const float* __restrict__ bias, void* __restrict__ Cv,
    int M, int N, int K, size_t sA, size_t sB, size_t sC, size_t sbias, int zmod)
{
    extern __shared__ char sm_[];
    uint32_t smb = smem_u32(sm_);

    int t = threadIdx.x, lane = t & 31, wid = t >> 5;
    int n0 = blockIdx.x * 128, m0 = blockIdx.y * 128;
    int z = blockIdx.z;
    A += (size_t)(z % zmod) * sA;
    B += (size_t)z * sB;
    if (bias) bias += (size_t)z * sbias;

    int wm = (wid & 3) * 32;
    int wn = (wid >> 2) * 64;
    const int NC = K / BK;

    float acc[2][8][4];
#pragma unroll
    for (int i = 0; i < 2; i++)
#pragma unroll
        for (int j = 0; j < 8; j++)
#pragma unroll
            for (int q = 0; q < 4; q++) acc[i][j][q] = 0.f;

    // cp.async per-thread coords
    int r0 = t >> 2, s0 = t & 3;
    int r1 = r0 + 64;
    const __nv_bfloat16* Ap0 = A + (size_t)(m0 + r0) * K + s0 * 8;
    const __nv_bfloat16* Ap1 = A + (size_t)(m0 + r1) * K + s0 * 8;
    const __nv_bfloat16* Bp0 = B + (size_t)(n0 + r0) * K + s0 * 8;
    const __nv_bfloat16* Bp1 = B + (size_t)(n0 + r1) * K + s0 * 8;
    uint32_t wa0 = (uint32_t)r0 * ROWB + s0 * 16;
    uint32_t wa1 = (uint32_t)r1 * ROWB + s0 * 16;

    // prefetch 3 stages
#pragma unroll
    for (int s = 0; s < 3; s++) {
        uint32_t stg = smb + s * STAGE2;
        int kc = s * BK;
        cp16(stg + wa0, Ap0 + kc);
        cp16(stg + wa1, Ap1 + kc);
        cp16(stg + STAGEB + wa0, Bp0 + kc);
        cp16(stg + STAGEB + wa1, Bp1 + kc);
        asm volatile("cp.async.commit_group;");
    }

    // fragment base addresses
    int fj = lane >> 3, fr = lane & 7;
    uint32_t b_row = (uint32_t)(wn + (fj >> 1) * 8 + fr) * ROWB + (fj & 1) * 16;
    uint32_t a_row = (uint32_t)(wm + (lane & 15)) * ROWB + (lane >> 4) * 16;

    for (int c = 0; c < NC; c++) {
        asm volatile("cp.async.wait_group 2;");
        __syncthreads();
        if (c + 3 < NC) {
            uint32_t stg = smb + ((c + 3) & (NSTG - 1)) * STAGE2;
            int kc = (c + 3) * BK;
            cp16(stg + wa0, Ap0 + kc);
            cp16(stg + wa1, Ap1 + kc);
            cp16(stg + STAGEB + wa0, Bp0 + kc);
            cp16(stg + STAGEB + wa1, Bp1 + kc);
        }
        asm volatile("cp.async.commit_group;");

        uint32_t ab = smb + (c & (NSTG - 1)) * STAGE2;
        uint32_t bb = ab + STAGEB;

        uint32_t afr[2][2][4];
#pragma unroll
        for (int mt = 0; mt < 2; mt++)
#pragma unroll
            for (int ks = 0; ks < 2; ks++)
                ldmA(afr[mt][ks], ab + a_row + mt * (16 * ROWB) + ks * 32);

        uint32_t bfr[2][8][2];
#pragma unroll
        for (int ks = 0; ks < 2; ks++)
#pragma unroll
            for (int nb = 0; nb < 4; nb++) {
                uint32_t q[4];
                ldmA(q, bb + b_row + nb * (16 * ROWB) + ks * 32);
                bfr[ks][nb * 2][0]     = q[0]; bfr[ks][nb * 2][1]     = q[1];
                bfr[ks][nb * 2 + 1][0] = q[2]; bfr[ks][nb * 2 + 1][1] = q[3];
            }

#pragma unroll
        for (int ks = 0; ks < 2; ks++)
#pragma unroll
            for (int mt = 0; mt < 2; mt++)
#pragma unroll
                for (int nt = 0; nt < 8; nt++)
                    mma_bf16(acc[mt][nt], afr[mt][ks], bfr[ks][nt]);
    }

    // epilogue
#pragma unroll
    for (int mt = 0; mt < 2; mt++) {
        int m = m0 + wm + mt * 16 + (lane >> 2);
#pragma unroll
        for (int nt = 0; nt < 8; nt++) {
            int n = n0 + wn + nt * 8 + (lane & 3) * 2;
            float bv0 = bias ? bias[n] : 0.f;
            float bv1 = bias ? bias[n + 1] : 0.f;
            float v0 = acc[mt][nt][0] + bv0, v1 = acc[mt][nt][1] + bv1;
            float v2 = acc[mt][nt][2] + bv0, v3 = acc[mt][nt][3] + bv1;
            if (OUTBF == 0) {
                float* C = (float*)Cv + (size_t)z * sC;
                *(float2*)&C[(size_t)m * N + n]       = make_float2(v0, v1);
                *(float2*)&C[(size_t)(m + 8) * N + n] = make_float2(v2, v3);
            } else {
                __nv_bfloat16* C = (__nv_bfloat16*)Cv + (size_t)z * sC;
                *(uint32_t*)&C[(size_t)m * N + n]       = packbf(v0, v1);
                *(uint32_t*)&C[(size_t)(m + 8) * N + n] = packbf(v2, v3);
            }
        }
    }
}

// ---------------- expert flash (bf16 mma, HD=128) ----------------
#define EF_PITCH 272
#define EF_QS 0
#define EF_KS 17408
#define EF_VS 34816
#define EF_OB 52224
#define EF_MS 86016
#define EF_LS 86272
#define EF_AS 86528
#define EF_RM 86784
#define EF_RS 87296
#define EF_SMEM 87808

__global__ __launch_bounds__(256) void eflash_kernel(
    const __nv_bfloat16* __restrict__ Q, const __nv_bfloat16* __restrict__ K,
    const __nv_bfloat16* __restrict__ V, __nv_bfloat16* __restrict__ O,
    float scale)
{
    extern __shared__ char sm_[];
    float* Obuf = (float*)(sm_ + EF_OB);
    float* m_s  = (float*)(sm_ + EF_MS);
    float* l_s  = (float*)(sm_ + EF_LS);
    float* a_s  = (float*)(sm_ + EF_AS);
    float* redm = (float*)(sm_ + EF_RM);
    float* reds = (float*)(sm_ + EF_RS);
    uint32_t smb = smem_u32(sm_);

    int t = threadIdx.x, lane = t & 31, wid = t >> 5;
    int half = wid >> 2, wm = (wid & 3) * 16, wn2 = half * 32;
    int slice = blockIdx.y;
    int sb = slice >> 3, h = slice & 7;
    size_t base = (size_t)sb * CAP * 1024 + (size_t)h * HDM;
    int q0 = blockIdx.x * 64;

#pragma unroll
    for (int j = 0; j < 4; j++) {
        int id = t + 256 * j;
        int r = id >> 4, c = id & 15;
        *(uint4*)(sm_ + EF_QS + r * EF_PITCH + c * 16) =
            *(const uint4*)(Q + base + (size_t)(q0 + r) * 1024 + c * 8);
    }
    if (t < 64) { m_s[t] = -1e30f; l_s[t] = 0.f; }

    float o[16][4];
#pragma unroll
    for (int i = 0; i < 16; i++)
#pragma unroll
        for (int q = 0; q < 4; q++) o[i][q] = 0.f;

    int rl = wm + (lane >> 2), rh = rl + 8;
    int nq = lane >> 2, kr = lane & 3;

    for (int kt = 0; kt < CAP / 64; kt++) {
        __syncthreads();
#pragma unroll
        for (int j = 0; j < 4; j++) {
            int id = t + 256 * j;
            int r = id >> 4, c = id & 15;
            *(uint4*)(sm_ + EF_KS + r * EF_PITCH + c * 16) =
                *(const uint4*)(K + base + (size_t)(kt * 64 + r) * 1024 + c * 8);
            *(uint4*)(sm_ + EF_VS + r * EF_PITCH + c * 16) =
                *(const uint4*)(V + base + (size_t)(kt * 64 + r) * 1024 + c * 8);
        }
        __syncthreads();

        float s[4][4];
#pragma unroll
        for (int nt = 0; nt < 4; nt++)
#pragma unroll
            for (int q = 0; q < 4; q++) s[nt][q] = 0.f;
#pragma unroll
        for (int ks = 0; ks < 8; ks++) {
            uint32_t af[4];
            ldmA(af, smb + EF_QS + (wm + (lane & 15)) * EF_PITCH + ks * 32 + (lane >> 4) * 16);
#pragma unroll
            for (int nt = 0; nt < 4; nt++) {
                const char* p = sm_ + EF_KS + (wn2 + nt * 8 + nq) * EF_PITCH + ks * 32 + kr * 4;
                uint32_t bb[2];
                bb[0] = *(const uint32_t*)p;
                bb[1] = *(const uint32_t*)(p + 16);
                mma_bf16(s[nt], af, bb);
            }
        }

        float mxlo = -1e30f, mxhi = -1e30f;
#pragma unroll
        for (int nt = 0; nt < 4; nt++) {
            s[nt][0] *= scale; s[nt][1] *= scale; s[nt][2] *= scale; s[nt][3] *= scale;
            mxlo = fmaxf(mxlo, fmaxf(s[nt][0], s[nt][1]));
            mxhi = fmaxf(mxhi, fmaxf(s[nt][2], s[nt][3]));
        }
        mxlo = fmaxf(mxlo, __shfl_xor_sync(0xffffffff, mxlo, 1));
        mxlo = fmaxf(mxlo, __shfl_xor_sync(0xffffffff, mxlo, 2));
        mxhi = fmaxf(mxhi, __shfl_xor_sync(0xffffffff, mxhi, 1));
        mxhi = fmaxf(mxhi, __shfl_xor_sync(0xffffffff, mxhi, 2));
        if ((lane & 3) == 0) { redm[half * 64 + rl] = mxlo; redm[half * 64 + rh] = mxhi; }
        __syncthreads();
        if (t < 64) {
            float mo = m_s[t];
            float mn = fmaxf(mo, fmaxf(redm[t], redm[64 + t]));
            float al = __expf(mo - mn);
            a_s[t] = al; m_s[t] = mn; l_s[t] *= al;
        }
        __syncthreads();

        float mlo = m_s[rl], mhi = m_s[rh], alo = a_s[rl], ahi = a_s[rh];
        float slo = 0.f, shi = 0.f;
        uint32_t afr[2][4];
#pragma unroll
        for (int ks = 0; ks < 2; ks++) {
#pragma unroll
            for (int jj = 0; jj < 2; jj++) {
                int nt = ks * 2 + jj;
                float p0 = __expf(s[nt][0] - mlo), p1 = __expf(s[nt][1] - mlo);
                float p2 = __expf(s[nt][2] - mhi), p3 = __expf(s[nt][3] - mhi);
                slo += p0 + p1; shi += p2 + p3;
                afr[ks][jj * 2 + 0] = packbf(p0, p1);
                afr[ks][jj * 2 + 1] = packbf(p2, p3);
            }
        }
        slo += __shfl_xor_sync(0xffffffff, slo, 1);
        slo += __shfl_xor_sync(0xffffffff, slo, 2);
        shi += __shfl_xor_sync(0xffffffff, shi, 1);
        shi += __shfl_xor_sync(0xffffffff, shi, 2);
        if ((lane & 3) == 0) { reds[half * 64 + rl] = slo; reds[half * 64 + rh] = shi; }

#pragma unroll
        for (int nt = 0; nt < 16; nt++) {
            o[nt][0] *= alo; o[nt][1] *= alo; o[nt][2] *= ahi; o[nt][3] *= ahi;
        }

#pragma unroll
        for (int ks = 0; ks < 2; ks++) {
#pragma unroll
            for (int nb = 0; nb < 8; nb++) {
                uint32_t b4[4];
                ldmT(b4, smb + EF_VS + (wn2 + ks * 16 + (lane & 15)) * EF_PITCH
                         + nb * 32 + (lane >> 4) * 16);
                mma_bf16(o[2 * nb],     afr[ks], b4);
                mma_bf16(o[2 * nb + 1], afr[ks], b4 + 2);
            }
        }
        __syncthreads();
        if (t < 64) l_s[t] += reds[t] + reds[64 + t];
    }

    __syncthreads();
    if (half == 0) {
#pragma unroll
        for (int nt = 0; nt < 16; nt++) {
            float* plo = Obuf + rl * 132 + nt * 8 + (lane & 3) * 2;
            float* phi = Obuf + rh * 132 + nt * 8 + (lane & 3) * 2;
            plo[0] = o[nt][0]; plo[1] = o[nt][1];
            phi[0] = o[nt][2]; phi[1] = o[nt][3];
        }
    }
    __syncthreads();
    if (half == 1) {
#pragma unroll
        for (int nt = 0; nt < 16; nt++) {
            float* plo = Obuf + rl * 132 + nt * 8 + (lane & 3) * 2;
            float* phi = Obuf + rh * 132 + nt * 8 + (lane & 3) * 2;
            plo[0] += o[nt][0]; plo[1] += o[nt][1];
            phi[0] += o[nt][2]; phi[1] += o[nt][3];
        }
    }
    __syncthreads();
#pragma unroll
    for (int j = 0; j < 16; j++) {
        int id = t + 256 * j;
        int r = id >> 6, cp = id & 63;
        float inv = 1.f / l_s[r];
        float2 v = *(float2*)(Obuf + r * 132 + cp * 2);
        __nv_bfloat162 ob = __float22bfloat162_rn(make_float2(v.x * inv, v.y * inv));
        *(__nv_bfloat162*)(O + base + (size_t)(q0 + r) * 1024 + cp * 2) = ob;
    }
}

// ---------------- main flash (bf16 mma, HD=64) ----------------
#define MF_PITCH 144
#define MF_QS 0
#define MF_KS 9216
#define MF_VS 18432
#define MF_OB 27648
#define MF_MS 45056
#define MF_LS 45312
#define MF_AS 45568
#define MF_RM 45824
#define MF_RS 46336
#define MF_SMEM 46848

__global__ __launch_bounds__(256) void mflash_kernel(
    const __nv_bfloat16* __restrict__ Q, const __nv_bfloat16* __restrict__ K,
    const __nv_bfloat16* __restrict__ V, __nv_bfloat16* __restrict__ O,
    float scale)
{
    extern __shared__ char sm_[];
    float* Obuf = (float*)(sm_ + MF_OB);
    float* m_s  = (float*)(sm_ + MF_MS);
    float* l_s  = (float*)(sm_ + MF_LS);
    float* a_s  = (float*)(sm_ + MF_AS);
    float* redm = (float*)(sm_ + MF_RM);
    float* reds = (float*)(sm_ + MF_RS);
    uint32_t smb = smem_u32(sm_);

    int t = threadIdx.x, lane = t & 31, wid = t >> 5;
    int half = wid >> 2, wm = (wid & 3) * 16, wn2 = half * 32;
    int slice = blockIdx.y;
    int sb = slice >> 4, h = slice & 15;
    size_t base = (size_t)sb * Sq * 1024 + (size_t)h * HD1;
    int q0 = blockIdx.x * 64;

#pragma unroll
    for (int j = 0; j < 2; j++) {
        int id = t + 256 * j;
        int r = id >> 3, c = id & 7;
        *(uint4*)(sm_ + MF_QS + r * MF_PITCH + c * 16) =
            *(const uint4*)(Q + base + (size_t)(q0 + r) * 1024 + c * 8);
    }
    if (t < 64) { m_s[t] = -1e30f; l_s[t] = 0.f; }

    float o[8][4];
#pragma unroll
    for (int i = 0; i < 8; i++)
#pragma unroll
        for (int q = 0; q < 4; q++) o[i][q] = 0.f;

    int rl = wm + (lane >> 2), rh = rl + 8;
    int nq = lane >> 2, kr = lane & 3;

    for (int kt = 0; kt < Sq / 64; kt++) {
        __syncthreads();
#pragma unroll
        for (int j = 0; j < 2; j++) {
            int id = t + 256 * j;
            int r = id >> 3, c = id & 7;
            size_t g = base + (size_t)(kt * 64 + r) * 1024 + c * 8;
            *(uint4*)(sm_ + MF_KS + r * MF_PITCH + c * 16) = *(const uint4*)(K + g);
            *(uint4*)(sm_ + MF_VS + r * MF_PITCH + c * 16) = *(const uint4*)(V + g);
        }
        __syncthreads();

        float s[4][4];
#pragma unroll
        for (int nt = 0; nt < 4; nt++)
#pragma unroll
            for (int q = 0; q < 4; q++) s[nt][q] = 0.f;
#pragma unroll
        for (int ks = 0; ks < 4; ks++) {
            uint32_t af[4];
            ldmA(af, smb + MF_QS + (wm + (lane & 15)) * MF_PITCH + ks * 32 + (lane >> 4) * 16);
#pragma unroll
            for (int nt = 0; nt < 4; nt++) {
                const char* p = sm_ + MF_KS + (wn2 + nt * 8 + nq) * MF_PITCH + ks * 32 + kr * 4;
                uint32_t bb[2];
                bb[0] = *(const uint32_t*)p;
                bb[1] = *(const uint32_t*)(p + 16);
                mma_bf16(s[nt], af, bb);
            }
        }

        float mxlo = -1e30f, mxhi = -1e30f;
#pragma unroll
        for (int nt = 0; nt < 4; nt++) {
            s[nt][0] *= scale; s[nt][1] *= scale; s[nt][2] *= scale; s[nt][3] *= scale;
            mxlo = fmaxf(mxlo, fmaxf(s[nt][0], s[nt][1]));
            mxhi = fmaxf(mxhi, fmaxf(s[nt][2], s[nt][3]));
        }
        mxlo = fmaxf(mxlo, __shfl_xor_sync(0xffffffff, mxlo, 1));
        mxlo = fmaxf(mxlo, __shfl_xor_sync(0xffffffff, mxlo, 2));
        mxhi = fmaxf(mxhi, __shfl_xor_sync(0xffffffff, mxhi, 1));
        mxhi = fmaxf(mxhi, __shfl_xor_sync(0xffffffff, mxhi, 2));
        if ((lane & 3) == 0) { redm[half * 64 + rl] = mxlo; redm[half * 64 + rh] = mxhi; }
        __syncthreads();
        if (t < 64) {
            float mo = m_s[t];
            float mn = fmaxf(mo, fmaxf(redm[t], redm[64 + t]));
            float al = __expf(mo - mn);
            a_s[t] = al; m_s[t] = mn; l_s[t] *= al;
        }
        __syncthreads();

        float mlo = m_s[rl], mhi = m_s[rh], alo = a_s[rl], ahi = a_s[rh];
        float slo = 0.f, shi = 0.f;
        uint32_t afr[2][4];
#pragma unroll
        for (int ks = 0; ks < 2; ks++) {
#pragma unroll
            for (int jj = 0; jj < 2; jj++) {
                int nt = ks * 2 + jj;
                float p0 = __expf(s[nt][0] - mlo), p1 = __expf(s[nt][1] - mlo);
                float p2 = __expf(s[nt][2] - mhi), p3 = __expf(s[nt][3] - mhi);
                slo += p0 + p1; shi += p2 + p3;
                afr[ks][jj * 2 + 0] = packbf(p0, p1);
                afr[ks][jj * 2 + 1] = packbf(p2, p3);
            }
        }
        slo += __shfl_xor_sync(0xffffffff, slo, 1);
        slo += __shfl_xor_sync(0xffffffff, slo, 2);
        shi += __shfl_xor_sync(0xffffffff, shi, 1);
        shi += __shfl_xor_sync(0xffffffff, shi, 2);
        if ((lane & 3) == 0) { reds[half * 64 + rl] = slo; reds[half * 64 + rh] = shi; }

#pragma unroll
        for (int nt = 0; nt < 8; nt++) {
            o[nt][0] *= alo; o[nt][1] *= alo; o[nt][2] *= ahi; o[nt][3] *= ahi;
        }

#pragma unroll
        for (int ks = 0; ks < 2; ks++) {
#pragma unroll
            for (int nb = 0; nb < 4; nb++) {
                uint32_t b4[4];
                ldmT(b4, smb + MF_VS + (wn2 + ks * 16 + (lane & 15)) * MF_PITCH
                         + nb * 32 + (lane >> 4) * 16);
                mma_bf16(o[2 * nb],     afr[ks], b4);
                mma_bf16(o[2 * nb + 1], afr[ks], b4 + 2);
            }
        }
        __syncthreads();
        if (t < 64) l_s[t] += reds[t] + reds[64 + t];
    }

    __syncthreads();
    if (half == 0) {
#pragma unroll
        for (int nt = 0; nt < 8; nt++) {
            float* plo = Obuf + rl * 68 + nt * 8 + (lane & 3) * 2;
            float* phi = Obuf + rh * 68 + nt * 8 + (lane & 3) * 2;
            plo[0] = o[nt][0]; plo[1] = o[nt][1];
            phi[0] = o[nt][2]; phi[1] = o[nt][3];
        }
    }
    __syncthreads();
    if (half == 1) {
#pragma unroll
        for (int nt = 0; nt < 8; nt++) {
            float* plo = Obuf + rl * 68 + nt * 8 + (lane & 3) * 2;
            float* phi = Obuf + rh * 68 + nt * 8 + (lane & 3) * 2;
            plo[0] += o[nt][0]; plo[1] += o[nt][1];
            phi[0] += o[nt][2]; phi[1] += o[nt][3];
        }
    }
    __syncthreads();
#pragma unroll
    for (int j = 0; j < 8; j++) {
        int id = t + 256 * j;
        int r = id >> 5, cp = id & 31;
        float inv = 1.f / l_s[r];
        float2 v = *(float2*)(Obuf + r * 68 + cp * 2);
        __nv_bfloat162 ob = __float22bfloat162_rn(make_float2(v.x * inv, v.y * inv));
        *(__nv_bfloat162*)(O + base + (size_t)(q0 + r) * 1024 + cp * 2) = ob;
    }
}

// ---------------- fp32 -> bf16 convert ----------------
__global__ __launch_bounds__(256) void cvt_kernel(
    const float4* __restrict__ s, uint2* __restrict__ h, int n4)
{
    int i = blockIdx.x * 256 + threadIdx.x;
    if (i >= n4) return;
    float4 v = s[i];
    uint2 hh;
    hh.x = packbf(v.x, v.y);
    hh.y = packbf(v.z, v.w);
    h[i] = hh;
}

// ---------------- weight transpose (fp32 [K,N] -> bf16 [N,K]) ----------------
__global__ void wtrans_kernel(const float* __restrict__ W,
                              __nv_bfloat16* __restrict__ Th, int Kd, int Nd)
{
    __shared__ float tile[32][33];
    int tx = threadIdx.x, ty = threadIdx.y;
    int n0 = blockIdx.x * 32, k0 = blockIdx.y * 32;
    size_t ob = (size_t)blockIdx.z * Kd * Nd;
    const float* Wb = W + ob;
#pragma unroll
    for (int r = 0; r < 4; r++)
        tile[ty + 8 * r][tx] = Wb[(size_t)(k0 + ty + 8 * r) * Nd + n0 + tx];
    __syncthreads();
#pragma unroll
    for (int r = 0; r < 4; r++)
        Th[ob + (size_t)(n0 + ty + 8 * r) * Kd + k0 + tx] =
            __float2bfloat16(tile[tx][ty + 8 * r]);
}

// ---------------- zero kernels ----------------
__global__ void zero_stats_kernel() {
    int t = threadIdx.x;
    if (t < NE) { g_Psum[t] = 0.f; g_fcnt[t] = 0.f; }
    if (t == 0) g_zsum = 0.f;
}

__global__ void zero_ein_kernel() {
    size_t n = EINSZ / 8;
    uint4 z = make_uint4(0, 0, 0, 0);
    uint4* ph = (uint4*)g_einh;
    for (size_t i = blockIdx.x * (size_t)blockDim.x + threadIdx.x; i < n;
         i += (size_t)gridDim.x * blockDim.x) ph[i] = z;
}

// ---------------- block reduce ----------------
__device__ __forceinline__ void block_reduce2(float& s, float& s2) {
    __shared__ float rs[8], rs2[8];
#pragma unroll
    for (int o = 16; o > 0; o >>= 1) {
        s  += __shfl_xor_sync(0xffffffff, s, o);
        s2 += __shfl_xor_sync(0xffffffff, s2, o);
    }
    int lane = threadIdx.x & 31, w = threadIdx.x >> 5;
    if (lane == 0) { rs[w] = s; rs2[w] = s2; }
    __syncthreads();
    float ts = 0.f, ts2 = 0.f;
#pragma unroll
    for (int i = 0; i < 8; i++) { ts += rs[i]; ts2 += rs2[i]; }
    s = ts; s2 = ts2;
}

// ---------------- LN1 ----------------
__global__ __launch_bounds__(256) void ln1_kernel(
    const float* __restrict__ x, const float* __restrict__ g,
    const float* __restrict__ b)
{
    size_t tok = blockIdx.x;
    int t = threadIdx.x;
    float v[4], s = 0.f, s2 = 0.f;
#pragma unroll
    for (int u = 0; u < 4; u++) {
        int j = t + u * 256;
        float val = x[tok * Dm + j] + g_attn[tok * Dm + j];
        v[u] = val; s += val; s2 += val * val;
    }
    block_reduce2(s, s2);
    float mean = s * (1.f / Dm);
    float var  = s2 * (1.f / Dm) - mean * mean;
    float inv  = rsqrtf(var + 1e-5f);
#pragma unroll
    for (int u = 0; u < 4; u++) {
        int j = t + u * 256;
        g_x1[tok * Dm + j] = (v[u] - mean) * inv * g[j] + b[j];
    }
}

// ---------------- gate ----------------
__global__ __launch_bounds__(256) void gate_kernel(const float* __restrict__ gateW) {
    int warp = threadIdx.x >> 5, lane = threadIdx.x & 31;
    int tok = blockIdx.x * 8 + warp;
    const float* xr = g_x1 + (size_t)tok * Dm;
    float acc[NE];
#pragma unroll
    for (int e = 0; e < NE; e++) acc[e] = 0.f;
    for (int k = lane; k < Dm; k += 32) {
        float xv = xr[k];
        const float* wr = gateW + (size_t)k * NE;
#pragma unroll
        for (int e = 0; e < NE; e++) acc[e] += xv * wr[e];
    }
#pragma unroll
    for (int e = 0; e < NE; e++)
#pragma unroll
        for (int o = 16; o > 0; o >>= 1)
            acc[e] += __shfl_xor_sync(0xffffffff, acc[e], o);
    if (lane == 0) {
        float mx = acc[0];
#pragma unroll
        for (int e = 1; e < NE; e++) mx = fmaxf(mx, acc[e]);
        float p[NE], se = 0.f;
#pragma unroll
        for (int e = 0; e < NE; e++) { p[e] = __expf(acc[e] - mx); se += p[e]; }
        float invs = 1.f / se;
        float lse = mx + logf(se);
        atomicAdd(&g_zsum, lse * lse);
        int i0 = 0, i1 = -1;
        float b0 = -1.f, b1 = -1.f;
#pragma unroll
        for (int e = 0; e < NE; e++) {
            float pe = p[e] * invs;
            atomicAdd(&g_Psum[e], pe);
            if (pe > b0) { b1 = b0; i1 = i0; b0 = pe; i0 = e; }
            else if (pe > b1) { b1 = pe; i1 = e; }
        }
        atomicAdd(&g_fcnt[i0], 1.f);
        g_i0[tok] = i0; g_i1[tok] = i1;
        g_g0[tok] = b0; g_g1[tok] = b1;
    }
}

// ---------------- routing positions ----------------
__global__ __launch_bounds__(256) void pos_kernel() {
    int warp = threadIdx.x >> 5, lane = threadIdx.x & 31;
    if (warp >= Bt) return;
    int b = warp;
    unsigned lt = (1u << lane) - 1u;
    int cnt[NE];
#pragma unroll
    for (int e = 0; e < NE; e++) cnt[e] = 0;

    for (int ch = 0; ch < Sq / 32; ch++) {
        int tok = b * Sq + ch * 32 + lane;
        int e0 = g_i0[tok];
        int myp = 0;
#pragma unroll
        for (int e = 0; e < NE; e++) {
            unsigned m = __ballot_sync(0xffffffff, e0 == e);
            if (e0 == e) myp = cnt[e] + __popc(m & lt);
            cnt[e] += __popc(m);
        }
        g_k0[tok] = (myp < CAP) ? 1 : 0;
        g_p0[tok] = min(myp, CAP - 1);
    }
    for (int ch = 0; ch < Sq / 32; ch++) {
        int tok = b * Sq + ch * 32 + lane;
        int e1 = g_i1[tok];
        bool valid = g_g1[tok] > 0.2f;
        int myp = 0;
#pragma unroll
        for (int e = 0; e < NE; e++) {
            unsigned m = __ballot_sync(0xffffffff, valid && (e1 == e));
            if (valid && (e1 == e)) myp = cnt[e] + __popc(m & lt);
            cnt[e] += __popc(m);
        }
        bool keep = valid && (myp < CAP);
        g_k1[tok] = keep ? 1 : 0;
        g_p1[tok] = valid ? min(myp, CAP - 1) : 0;
    }
}

// ---------------- scatter (x1 fp32 -> einh bf16) ----------------
__global__ __launch_bounds__(256) void scatter_kernel() {
    int idx = blockIdx.x;
    int tok = idx >> 1, slot = idx & 1;
    int keep = slot ? g_k1[tok] : g_k0[tok];
    if (!keep) return;
    int e = slot ? g_i1[tok] : g_i0[tok];
    int p = slot ? g_p1[tok] : g_p0[tok];
    int b = tok / Sq;
    const float4* src = (const float4*)(g_x1 + (size_t)tok * Dm);
    size_t ro = (((size_t)e * Bt + b) * CAP + p) * Dm;
    uint2* dh = (uint2*)(g_einh + ro);
    float4 v = src[threadIdx.x];
    uint2 hh;
    hh.x = packbf(v.x, v.y);
    hh.y = packbf(v.z, v.w);
    dh[threadIdx.x] = hh;
}

// ---------------- combine + LN2 ----------------
__global__ __launch_bounds__(256) void combine_ln_kernel(
    const float* __restrict__ g2, const float* __restrict__ b2,
    float* __restrict__ out)
{
    size_t tok = blockIdx.x;
    int t = threadIdx.x;
    int b = (int)(tok >> 10);
    float w0 = g_k0[tok] ? g_g0[tok] : 0.f;
    float w1 = g_k1[tok] ? g_g1[tok] : 0.f;
    const float* r0 = g_eout + (((size_t)g_i0[tok] * Bt + b) * CAP + g_p0[tok]) * Dm;
    const float* r1 = g_eout + (((size_t)g_i1[tok] * Bt + b) * CAP + g_p1[tok]) * Dm;

    float v[4], s = 0.f, s2 = 0.f;
#pragma unroll
    for (int u = 0; u < 4; u++) {
        int j = t + u * 256;
        float val = g_x1[tok * Dm + j] + w0 * r0[j] + w1 * r1[j];
        v[u] = val; s += val; s2 += val * val;
    }
    block_reduce2(s, s2);
    float mean = s * (1.f / Dm);
    float var  = s2 * (1.f / Dm) - mean * mean;
    float inv  = rsqrtf(var + 1e-5f);
#pragma unroll
    for (int u = 0; u < 4; u++) {
        int j = t + u * 256;
        out[tok * Dm + j] = (v[u] - mean) * inv * g2[j] + b2[j];
    }
}

// ---------------- finalize aux ----------------
__global__ void finalize_kernel(float* __restrict__ out) {
    if (threadIdx.x == 0 && blockIdx.x == 0) {
        float invN = 1.f / (float)NT;
        float sfp = 0.f;
#pragma unroll
        for (int e = 0; e < NE; e++)
            sfp += (g_fcnt[e] * invN) * (g_Psum[e] * invN);
        float bal = 0.01f * (float)NE * sfp;
        float zl  = 0.001f * g_zsum * invN;
        out[NTD + 0] = bal + zl;
        out[NTD + 1] = bal;
        out[NTD + 2] = zl;
    }
}

// ---------------- host launcher ----------------
extern "C" void kernel_launch(void* const* d_in, const int* in_sizes, int n_in,
                              void* d_out, int out_size)
{
    const float* x      = (const float*)d_in[0];
    const float* Wq     = (const float*)d_in[1];
    const float* Wk     = (const float*)d_in[2];
    const float* Wv     = (const float*)d_in[3];
    const float* Wo     = (const float*)d_in[4];
    const float* bq     = (const float*)d_in[5];
    const float* bk     = (const float*)d_in[6];
    const float* bv     = (const float*)d_in[7];
    const float* bo     = (const float*)d_in[8];
    const float* ln1_g  = (const float*)d_in[9];
    const float* ln1_b  = (const float*)d_in[10];
    const float* ln2_g  = (const float*)d_in[11];
    const float* ln2_b  = (const float*)d_in[12];
    const float* gate_W = (const float*)d_in[13];
    const float* eWq    = (const float*)d_in[14];
    const float* eWk    = (const float*)d_in[15];
    const float* eWv    = (const float*)d_in[16];
    const float* eWo    = (const float*)d_in[17];
    float* out = (float*)d_out;

    void *pattn, *px1, *peout, *pxh, *pqkvh, *poh;
    void *peinh, *peqkv, *peoh;
    void *pwqkvh, *pwoh, *pewh, *pewoh, *pbqkv;
    cudaGetSymbolAddress(&pattn, g_attn);   cudaGetSymbolAddress(&px1, g_x1);
    cudaGetSymbolAddress(&peout, g_eout);   cudaGetSymbolAddress(&pxh, g_xh);
    cudaGetSymbolAddress(&pqkvh, g_qkvh);   cudaGetSymbolAddress(&poh, g_oh);
    cudaGetSymbolAddress(&peinh, g_einh);   cudaGetSymbolAddress(&peqkv, g_eqkv);
    cudaGetSymbolAddress(&peoh, g_eoh);
    cudaGetSymbolAddress(&pwqkvh, g_wqkvh); cudaGetSymbolAddress(&pwoh, g_woh);
    cudaGetSymbolAddress(&pewh, g_ewh);     cudaGetSymbolAddress(&pewoh, g_ewoh);
    cudaGetSymbolAddress(&pbqkv, g_bqkv);

    cudaFuncSetAttribute(gemm_mma_kernel<0>, cudaFuncAttributeMaxDynamicSharedMemorySize, GEMM_SMEM);
    cudaFuncSetAttribute(gemm_mma_kernel<1>, cudaFuncAttributeMaxDynamicSharedMemorySize, GEMM_SMEM);
    cudaFuncSetAttribute(mflash_kernel, cudaFuncAttributeMaxDynamicSharedMemorySize, MF_SMEM);
    cudaFuncSetAttribute(eflash_kernel, cudaFuncAttributeMaxDynamicSharedMemorySize, EF_SMEM);

    zero_stats_kernel<<<1, 32>>>();
    zero_ein_kernel<<<2048, 256>>>();

    cudaMemcpyAsync((float*)pbqkv,          bq, Dm * sizeof(float), cudaMemcpyDeviceToDevice);
    cudaMemcpyAsync((float*)pbqkv + Dm,     bk, Dm * sizeof(float), cudaMemcpyDeviceToDevice);
    cudaMemcpyAsync((float*)pbqkv + 2 * Dm, bv, Dm * sizeof(float), cudaMemcpyDeviceToDevice);

    dim3 tb(32, 8);
    __nv_bfloat16* wqkv = (__nv_bfloat16*)pwqkvh;
    __nv_bfloat16* ewh  = (__nv_bfloat16*)pewh;
    wtrans_kernel<<<dim3(32, 32, 1), tb>>>(Wq, wqkv,            Dm, Dm);
    wtrans_kernel<<<dim3(32, 32, 1), tb>>>(Wk, wqkv + DMDM,     Dm, Dm);
    wtrans_kernel<<<dim3(32, 32, 1), tb>>>(Wv, wqkv + 2 * DMDM, Dm, Dm);
    wtrans_kernel<<<dim3(32, 32, 1), tb>>>(Wo, (__nv_bfloat16*)pwoh, Dm, Dm);
    wtrans_kernel<<<dim3(32, 32, NE), tb>>>(eWq, ewh,                 Dm, Dm);
    wtrans_kernel<<<dim3(32, 32, NE), tb>>>(eWk, ewh + NE * DMDM,     Dm, Dm);
    wtrans_kernel<<<dim3(32, 32, NE), tb>>>(eWv, ewh + 2 * NE * DMDM, Dm, Dm);
    wtrans_kernel<<<dim3(32, 32, NE), tb>>>(eWo, (__nv_bfloat16*)pewoh, Dm, Dm);

    cvt_kernel<<<(int)(NTD / 4 / 256), 256>>>((const float4*)x, (uint2*)pxh, (int)(NTD / 4));

    // main QKV: one batched launch, z in [0,3)
    gemm_mma_kernel<1><<<dim3(Dm / 128, NT / 128, 3), 256, GEMM_SMEM>>>(
        (__nv_bfloat16*)pxh, wqkv, (const float*)pbqkv, pqkvh,
        NT, Dm, Dm, 0, DMDM, NTD, Dm, 3);

    __nv_bfloat16* qkv = (__nv_bfloat16*)pqkvh;
    mflash_kernel<<<dim3(Sq / 64, Bt * NH), 256, MF_SMEM>>>(
        qkv, qkv + NTD, qkv + 2 * NTD, (__nv_bfloat16*)poh, 0.125f);

    // Wo
    gemm_mma_kernel<0><<<dim3(Dm / 128, NT / 128, 1), 256, GEMM_SMEM>>>(
        (__nv_bfloat16*)poh, (__nv_bfloat16*)pwoh, bo, pattn,
        NT, Dm, Dm, 0, 0, 0, 0, 1);

    ln1_kernel<<<NT, 256>>>(x, ln1_g, ln1_b);
    gate_kernel<<<NT / 8, 256>>>(gate_W);
    pos_kernel<<<1, 256>>>();
    scatter_kernel<<<NT * 2, 256>>>();

    // expert QKV: one batched launch, z = p*NE + e in [0,24)
    size_t sA = (size_t)EROWS * Dm;
    gemm_mma_kernel<1><<<dim3(Dm / 128, EROWS / 128, 24), 256, GEMM_SMEM>>>(
        (__nv_bfloat16*)peinh, ewh, nullptr, peqkv,
        EROWS, Dm, Dm, sA, DMDM, sA, 0, NE);

    __nv_bfloat16* eqkv = (__nv_bfloat16*)peqkv;
    eflash_kernel<<<dim3(CAP / 64, NE * Bt * NHM), 256, EF_SMEM>>>(
        eqkv, eqkv + EINSZ, eqkv + 2 * EINSZ, (__nv_bfloat16*)peoh, 0.0883883476483184f);

    // expert Wo: z in [0,8)
    gemm_mma_kernel<0><<<dim3(Dm / 128, EROWS / 128, NE), 256, GEMM_SMEM>>>(
        (__nv_bfloat16*)peoh, (__nv_bfloat16*)pewoh, nullptr, peout,
        EROWS, Dm, Dm, sA, DMDM, sA, 0, NE);

    combine_ln_kernel<<<NT, 256>>>(ln2_g, ln2_b, out);
    finalize_kernel<<<1, 32>>>(out);
}

// round 8
// speedup vs baseline: 6.4295x; 1.0250x over previous
#include <cuda_runtime.h>
#include <cuda_bf16.h>
#include <math.h>
#include <stdint.h>

// ---------------- problem dims ----------------
#define Bt   8
#define Sq   1024
#define Dm   1024
#define NH   16
#define HD1  64
#define NE   8
#define NHM  8
#define HDM  128
#define CAP  320
#define NT   (Bt*Sq)
#define NTD  ((size_t)NT*Dm)
#define EROWS (Bt*CAP)
#define EINSZ ((size_t)NE*Bt*CAP*Dm)
#define DMDM ((size_t)Dm*Dm)

// ---------------- scratch ----------------
static __device__ float g_attn[NTD];
static __device__ float g_x1[NTD];

static __device__ __nv_bfloat16 g_xh[NTD];
static __device__ __nv_bfloat16 g_qkvh[3*NTD];       // [q|k|v]
static __device__ __nv_bfloat16 g_oh[NTD];
static __device__ __nv_bfloat16 g_einh[EINSZ];
static __device__ __nv_bfloat16 g_eqkv[3*EINSZ];     // [q|k|v] expert
static __device__ __nv_bfloat16 g_eoh[EINSZ];
static __device__ __nv_bfloat16 g_eoutb[EINSZ];      // expert output (bf16)
static __device__ __nv_bfloat16 g_wqkvh[3*DMDM];
static __device__ __nv_bfloat16 g_woh[DMDM];
static __device__ __nv_bfloat16 g_ewh[3*NE*DMDM];
static __device__ __nv_bfloat16 g_ewoh[NE*DMDM];
static __device__ float g_bqkv[3*Dm];

static __device__ int   g_i0[NT], g_i1[NT];
static __device__ float g_g0[NT], g_g1[NT];
static __device__ int   g_p0[NT], g_p1[NT];
static __device__ int   g_k0[NT], g_k1[NT];

static __device__ float g_Psum[NE];
static __device__ float g_fcnt[NE];
static __device__ float g_zsum;

// ---------------- PTX helpers ----------------
__device__ __forceinline__ uint32_t smem_u32(const void* p) {
    uint32_t a;
    asm("{ .reg .u64 t; cvta.to.shared.u64 t, %1; cvt.u32.u64 %0, t; }" : "=r"(a) : "l"(p));
    return a;
}
__device__ __forceinline__ void cp16(uint32_t dst, const void* src) {
    asm volatile("cp.async.cg.shared.global [%0], [%1], 16;" :: "r"(dst), "l"(src));
}
__device__ __forceinline__ void ldmA(uint32_t* a, uint32_t addr) {
    asm volatile("ldmatrix.sync.aligned.m8n8.x4.shared.b16 {%0,%1,%2,%3}, [%4];"
        : "=r"(a[0]), "=r"(a[1]), "=r"(a[2]), "=r"(a[3]) : "r"(addr));
}
__device__ __forceinline__ void ldmT(uint32_t* a, uint32_t addr) {
    asm volatile("ldmatrix.sync.aligned.m8n8.x4.trans.shared.b16 {%0,%1,%2,%3}, [%4];"
        : "=r"(a[0]), "=r"(a[1]), "=r"(a[2]), "=r"(a[3]) : "r"(addr));
}
__device__ __forceinline__ void mma_bf16(float* d, const uint32_t* a, const uint32_t* b) {
    asm volatile(
        "mma.sync.aligned.m16n8k16.row.col.f32.bf16.bf16.f32 "
        "{%0,%1,%2,%3}, {%4,%5,%6,%7}, {%8,%9}, {%0,%1,%2,%3};"
        : "+f"(d[0]), "+f"(d[1]), "+f"(d[2]), "+f"(d[3])
        : "r"(a[0]), "r"(a[1]), "r"(a[2]), "r"(a[3]), "r"(b[0]), "r"(b[1]));
}
__device__ __forceinline__ uint32_t packbf(float a, float b) {
    __nv_bfloat162 v = __float22bfloat162_rn(make_float2(a, b));
    return *(uint32_t*)&v;
}

// ---------------- GEMM via mma.sync (bf16, BK=64, 4-stage cp.async) ----------
// C[z][M,N] = A[z%zmod][M,K] @ B[z]^T (+bias[z]); OUTBF: 0 fp32 out, 1 bf16 out.
#define BK 64
#define ROWB 144               // 64 bf16 = 128B data + 16B pad, conflict-free
#define STAGEB (128*ROWB)      // 18432 per matrix
#define STAGE2 (2*STAGEB)      // 36864 per stage
#define NSTG 4
#define GEMM_SMEM (NSTG*STAGE2)  // 147456

template <int OUTBF>
__global__ __launch_bounds__(256, 1) void gemm_mma_kernel(
    const __nv_bfloat16* __restrict__ A, const __nv_bfloat16* __restrict__ B,
    const float* __restrict__ bias, void* __restrict__ Cv,
    int M, int N, int K, size_t sA, size_t sB, size_t sC, size_t sbias, int zmod)
{
    extern __shared__ char sm_[];
    uint32_t smb = smem_u32(sm_);

    int t = threadIdx.x, lane = t & 31, wid = t >> 5;
    int n0 = blockIdx.x * 128, m0 = blockIdx.y * 128;
    int z = blockIdx.z;
    A += (size_t)(z % zmod) * sA;
    B += (size_t)z * sB;
    if (bias) bias += (size_t)z * sbias;

    int wm = (wid & 3) * 32;
    int wn = (wid >> 2) * 64;
    const int NC = K / BK;   // 16

    float acc[2][8][4];
#pragma unroll
    for (int i = 0; i < 2; i++)
#pragma unroll
        for (int j = 0; j < 8; j++)
#pragma unroll
            for (int q = 0; q < 4; q++) acc[i][j][q] = 0.f;

    // cp.async per-thread coords: 4 rows per thread per matrix per stage
    int rb = t >> 3, c8 = t & 7;
    const __nv_bfloat16* Ap = A + (size_t)(m0 + rb) * K + c8 * 8;
    const __nv_bfloat16* Bp = B + (size_t)(n0 + rb) * K + c8 * 8;
    uint32_t wab = (uint32_t)rb * ROWB + c8 * 16;
    const size_t rstep = (size_t)32 * K;

    // prefetch 3 stages
#pragma unroll
    for (int s = 0; s < 3; s++) {
        uint32_t stg = smb + s * STAGE2;
        int kc = s * BK;
#pragma unroll
        for (int j = 0; j < 4; j++) {
            cp16(stg + wab + j * (32 * ROWB), Ap + kc + j * rstep);
            cp16(stg + STAGEB + wab + j * (32 * ROWB), Bp + kc + j * rstep);
        }
        asm volatile("cp.async.commit_group;");
    }

    // fragment base addresses
    int fj = lane >> 3, fr = lane & 7;
    uint32_t b_row = (uint32_t)(wn + (fj >> 1) * 8 + fr) * ROWB + (fj & 1) * 16;
    uint32_t a_row = (uint32_t)(wm + (lane & 15)) * ROWB + (lane >> 4) * 16;

    for (int c = 0; c < NC; c++) {
        asm volatile("cp.async.wait_group 2;");
        __syncthreads();
        if (c + 3 < NC) {
            uint32_t stg = smb + ((c + 3) & (NSTG - 1)) * STAGE2;
            int kc = (c + 3) * BK;
#pragma unroll
            for (int j = 0; j < 4; j++) {
                cp16(stg + wab + j * (32 * ROWB), Ap + kc + j * rstep);
                cp16(stg + STAGEB + wab + j * (32 * ROWB), Bp + kc + j * rstep);
            }
        }
        asm volatile("cp.async.commit_group;");

        uint32_t ab = smb + (c & (NSTG - 1)) * STAGE2;
        uint32_t bb = ab + STAGEB;

#pragma unroll
        for (int ks = 0; ks < 4; ks++) {
            uint32_t afr[2][4];
#pragma unroll
            for (int mt = 0; mt < 2; mt++)
                ldmA(afr[mt], ab + a_row + mt * (16 * ROWB) + ks * 32);

            uint32_t bfr[8][2];
#pragma unroll
            for (int nb = 0; nb < 4; nb++) {
                uint32_t q[4];
                ldmA(q, bb + b_row + nb * (16 * ROWB) + ks * 32);
                bfr[nb * 2][0]     = q[0]; bfr[nb * 2][1]     = q[1];
                bfr[nb * 2 + 1][0] = q[2]; bfr[nb * 2 + 1][1] = q[3];
            }
#pragma unroll
            for (int mt = 0; mt < 2; mt++)
#pragma unroll
                for (int nt = 0; nt < 8; nt++)
                    mma_bf16(acc[mt][nt], afr[mt], bfr[nt]);
        }
    }

    // epilogue
#pragma unroll
    for (int mt = 0; mt < 2; mt++) {
        int m = m0 + wm + mt * 16 + (lane >> 2);
#pragma unroll
        for (int nt = 0; nt < 8; nt++) {
            int n = n0 + wn + nt * 8 + (lane & 3) * 2;
            float bv0 = bias ? bias[n] : 0.f;
            float bv1 = bias ? bias[n + 1] : 0.f;
            float v0 = acc[mt][nt][0] + bv0, v1 = acc[mt][nt][1] + bv1;
            float v2 = acc[mt][nt][2] + bv0, v3 = acc[mt][nt][3] + bv1;
            if (OUTBF == 0) {
                float* C = (float*)Cv + (size_t)z * sC;
                *(float2*)&C[(size_t)m * N + n]       = make_float2(v0, v1);
                *(float2*)&C[(size_t)(m + 8) * N + n] = make_float2(v2, v3);
            } else {
                __nv_bfloat16* C = (__nv_bfloat16*)Cv + (size_t)z * sC;
                *(uint32_t*)&C[(size_t)m * N + n]       = packbf(v0, v1);
                *(uint32_t*)&C[(size_t)(m + 8) * N + n] = packbf(v2, v3);
            }
        }
    }
}

// ---------------- expert flash (bf16 mma, HD=128) ----------------
#define EF_PITCH 272
#define EF_QS 0
#define EF_KS 17408
#define EF_VS 34816
#define EF_OB 52224
#define EF_MS 86016
#define EF_LS 86272
#define EF_AS 86528
#define EF_RM 86784
#define EF_RS 87296
#define EF_SMEM 87808

__global__ __launch_bounds__(256) void eflash_kernel(
    const __nv_bfloat16* __restrict__ Q, const __nv_bfloat16* __restrict__ K,
    const __nv_bfloat16* __restrict__ V, __nv_bfloat16* __restrict__ O,
    float scale)
{
    extern __shared__ char sm_[];
    float* Obuf = (float*)(sm_ + EF_OB);
    float* m_s  = (float*)(sm_ + EF_MS);
    float* l_s  = (float*)(sm_ + EF_LS);
    float* a_s  = (float*)(sm_ + EF_AS);
    float* redm = (float*)(sm_ + EF_RM);
    float* reds = (float*)(sm_ + EF_RS);
    uint32_t smb = smem_u32(sm_);

    int t = threadIdx.x, lane = t & 31, wid = t >> 5;
    int half = wid >> 2, wm = (wid & 3) * 16, wn2 = half * 32;
    int slice = blockIdx.y;
    int sb = slice >> 3, h = slice & 7;
    size_t base = (size_t)sb * CAP * 1024 + (size_t)h * HDM;
    int q0 = blockIdx.x * 64;

#pragma unroll
    for (int j = 0; j < 4; j++) {
        int id = t + 256 * j;
        int r = id >> 4, c = id & 15;
        *(uint4*)(sm_ + EF_QS + r * EF_PITCH + c * 16) =
            *(const uint4*)(Q + base + (size_t)(q0 + r) * 1024 + c * 8);
    }
    if (t < 64) { m_s[t] = -1e30f; l_s[t] = 0.f; }

    float o[16][4];
#pragma unroll
    for (int i = 0; i < 16; i++)
#pragma unroll
        for (int q = 0; q < 4; q++) o[i][q] = 0.f;

    int rl = wm + (lane >> 2), rh = rl + 8;
    int nq = lane >> 2, kr = lane & 3;

    for (int kt = 0; kt < CAP / 64; kt++) {
        __syncthreads();
#pragma unroll
        for (int j = 0; j < 4; j++) {
            int id = t + 256 * j;
            int r = id >> 4, c = id & 15;
            *(uint4*)(sm_ + EF_KS + r * EF_PITCH + c * 16) =
                *(const uint4*)(K + base + (size_t)(kt * 64 + r) * 1024 + c * 8);
            *(uint4*)(sm_ + EF_VS + r * EF_PITCH + c * 16) =
                *(const uint4*)(V + base + (size_t)(kt * 64 + r) * 1024 + c * 8);
        }
        __syncthreads();

        float s[4][4];
#pragma unroll
        for (int nt = 0; nt < 4; nt++)
#pragma unroll
            for (int q = 0; q < 4; q++) s[nt][q] = 0.f;
#pragma unroll
        for (int ks = 0; ks < 8; ks++) {
            uint32_t af[4];
            ldmA(af, smb + EF_QS + (wm + (lane & 15)) * EF_PITCH + ks * 32 + (lane >> 4) * 16);
#pragma unroll
            for (int nt = 0; nt < 4; nt++) {
                const char* p = sm_ + EF_KS + (wn2 + nt * 8 + nq) * EF_PITCH + ks * 32 + kr * 4;
                uint32_t bb[2];
                bb[0] = *(const uint32_t*)p;
                bb[1] = *(const uint32_t*)(p + 16);
                mma_bf16(s[nt], af, bb);
            }
        }

        float mxlo = -1e30f, mxhi = -1e30f;
#pragma unroll
        for (int nt = 0; nt < 4; nt++) {
            s[nt][0] *= scale; s[nt][1] *= scale; s[nt][2] *= scale; s[nt][3] *= scale;
            mxlo = fmaxf(mxlo, fmaxf(s[nt][0], s[nt][1]));
            mxhi = fmaxf(mxhi, fmaxf(s[nt][2], s[nt][3]));
        }
        mxlo = fmaxf(mxlo, __shfl_xor_sync(0xffffffff, mxlo, 1));
        mxlo = fmaxf(mxlo, __shfl_xor_sync(0xffffffff, mxlo, 2));
        mxhi = fmaxf(mxhi, __shfl_xor_sync(0xffffffff, mxhi, 1));
        mxhi = fmaxf(mxhi, __shfl_xor_sync(0xffffffff, mxhi, 2));
        if ((lane & 3) == 0) { redm[half * 64 + rl] = mxlo; redm[half * 64 + rh] = mxhi; }
        __syncthreads();
        if (t < 64) {
            float mo = m_s[t];
            float mn = fmaxf(mo, fmaxf(redm[t], redm[64 + t]));
            float al = __expf(mo - mn);
            a_s[t] = al; m_s[t] = mn; l_s[t] *= al;
        }
        __syncthreads();

        float mlo = m_s[rl], mhi = m_s[rh], alo = a_s[rl], ahi = a_s[rh];
        float slo = 0.f, shi = 0.f;
        uint32_t afr[2][4];
#pragma unroll
        for (int ks = 0; ks < 2; ks++) {
#pragma unroll
            for (int jj = 0; jj < 2; jj++) {
                int nt = ks * 2 + jj;
                float p0 = __expf(s[nt][0] - mlo), p1 = __expf(s[nt][1] - mlo);
                float p2 = __expf(s[nt][2] - mhi), p3 = __expf(s[nt][3] - mhi);
                slo += p0 + p1; shi += p2 + p3;
                afr[ks][jj * 2 + 0] = packbf(p0, p1);
                afr[ks][jj * 2 + 1] = packbf(p2, p3);
            }
        }
        slo += __shfl_xor_sync(0xffffffff, slo, 1);
        slo += __shfl_xor_sync(0xffffffff, slo, 2);
        shi += __shfl_xor_sync(0xffffffff, shi, 1);
        shi += __shfl_xor_sync(0xffffffff, shi, 2);
        if ((lane & 3) == 0) { reds[half * 64 + rl] = slo; reds[half * 64 + rh] = shi; }

#pragma unroll
        for (int nt = 0; nt < 16; nt++) {
            o[nt][0] *= alo; o[nt][1] *= alo; o[nt][2] *= ahi; o[nt][3] *= ahi;
        }

#pragma unroll
        for (int ks = 0; ks < 2; ks++) {
#pragma unroll
            for (int nb = 0; nb < 8; nb++) {
                uint32_t b4[4];
                ldmT(b4, smb + EF_VS + (wn2 + ks * 16 + (lane & 15)) * EF_PITCH
                         + nb * 32 + (lane >> 4) * 16);
                mma_bf16(o[2 * nb],     afr[ks], b4);
                mma_bf16(o[2 * nb + 1], afr[ks], b4 + 2);
            }
        }
        __syncthreads();
        if (t < 64) l_s[t] += reds[t] + reds[64 + t];
    }

    __syncthreads();
    if (half == 0) {
#pragma unroll
        for (int nt = 0; nt < 16; nt++) {
            float* plo = Obuf + rl * 132 + nt * 8 + (lane & 3) * 2;
            float* phi = Obuf + rh * 132 + nt * 8 + (lane & 3) * 2;
            plo[0] = o[nt][0]; plo[1] = o[nt][1];
            phi[0] = o[nt][2]; phi[1] = o[nt][3];
        }
    }
    __syncthreads();
    if (half == 1) {
#pragma unroll
        for (int nt = 0; nt < 16; nt++) {
            float* plo = Obuf + rl * 132 + nt * 8 + (lane & 3) * 2;
            float* phi = Obuf + rh * 132 + nt * 8 + (lane & 3) * 2;
            plo[0] += o[nt][0]; plo[1] += o[nt][1];
            phi[0] += o[nt][2]; phi[1] += o[nt][3];
        }
    }
    __syncthreads();
#pragma unroll
    for (int j = 0; j < 16; j++) {
        int id = t + 256 * j;
        int r = id >> 6, cp = id & 63;
        float inv = 1.f / l_s[r];
        float2 v = *(float2*)(Obuf + r * 132 + cp * 2);
        __nv_bfloat162 ob = __float22bfloat162_rn(make_float2(v.x * inv, v.y * inv));
        *(__nv_bfloat162*)(O + base + (size_t)(q0 + r) * 1024 + cp * 2) = ob;
    }
}

// ---------------- main flash (bf16 mma, HD=64) ----------------
#define MF_PITCH 144
#define MF_QS 0
#define MF_KS 9216
#define MF_VS 18432
#define MF_OB 27648
#define MF_MS 45056
#define MF_LS 45312
#define MF_AS 45568
#define MF_RM 45824
#define MF_RS 46336
#define MF_SMEM 46848

__global__ __launch_bounds__(256) void mflash_kernel(
    const __nv_bfloat16* __restrict__ Q, const __nv_bfloat16* __restrict__ K,
    const __nv_bfloat16* __restrict__ V, __nv_bfloat16* __restrict__ O,
    float scale)
{
    extern __shared__ char sm_[];
    float* Obuf = (float*)(sm_ + MF_OB);
    float* m_s  = (float*)(sm_ + MF_MS);
    float* l_s  = (float*)(sm_ + MF_LS);
    float* a_s  = (float*)(sm_ + MF_AS);
    float* redm = (float*)(sm_ + MF_RM);
    float* reds = (float*)(sm_ + MF_RS);
    uint32_t smb = smem_u32(sm_);

    int t = threadIdx.x, lane = t & 31, wid = t >> 5;
    int half = wid >> 2, wm = (wid & 3) * 16, wn2 = half * 32;
    int slice = blockIdx.y;
    int sb = slice >> 4, h = slice & 15;
    size_t base = (size_t)sb * Sq * 1024 + (size_t)h * HD1;
    int q0 = blockIdx.x * 64;

#pragma unroll
    for (int j = 0; j < 2; j++) {
        int id = t + 256 * j;
        int r = id >> 3, c = id & 7;
        *(uint4*)(sm_ + MF_QS + r * MF_PITCH + c * 16) =
            *(const uint4*)(Q + base + (size_t)(q0 + r) * 1024 + c * 8);
    }
    if (t < 64) { m_s[t] = -1e30f; l_s[t] = 0.f; }

    float o[8][4];
#pragma unroll
    for (int i = 0; i < 8; i++)
#pragma unroll
        for (int q = 0; q < 4; q++) o[i][q] = 0.f;

    int rl = wm + (lane >> 2), rh = rl + 8;
    int nq = lane >> 2, kr = lane & 3;

    for (int kt = 0; kt < Sq / 64; kt++) {
        __syncthreads();
#pragma unroll
        for (int j = 0; j < 2; j++) {
            int id = t + 256 * j;
            int r = id >> 3, c = id & 7;
            size_t g = base + (size_t)(kt * 64 + r) * 1024 + c * 8;
            *(uint4*)(sm_ + MF_KS + r * MF_PITCH + c * 16) = *(const uint4*)(K + g);
            *(uint4*)(sm_ + MF_VS + r * MF_PITCH + c * 16) = *(const uint4*)(V + g);
        }
        __syncthreads();

        float s[4][4];
#pragma unroll
        for (int nt = 0; nt < 4; nt++)
#pragma unroll
            for (int q = 0; q < 4; q++) s[nt][q] = 0.f;
#pragma unroll
        for (int ks = 0; ks < 4; ks++) {
            uint32_t af[4];
            ldmA(af, smb + MF_QS + (wm + (lane & 15)) * MF_PITCH + ks * 32 + (lane >> 4) * 16);
#pragma unroll
            for (int nt = 0; nt < 4; nt++) {
                const char* p = sm_ + MF_KS + (wn2 + nt * 8 + nq) * MF_PITCH + ks * 32 + kr * 4;
                uint32_t bb[2];
                bb[0] = *(const uint32_t*)p;
                bb[1] = *(const uint32_t*)(p + 16);
                mma_bf16(s[nt], af, bb);
            }
        }

        float mxlo = -1e30f, mxhi = -1e30f;
#pragma unroll
        for (int nt = 0; nt < 4; nt++) {
            s[nt][0] *= scale; s[nt][1] *= scale; s[nt][2] *= scale; s[nt][3] *= scale;
            mxlo = fmaxf(mxlo, fmaxf(s[nt][0], s[nt][1]));
            mxhi = fmaxf(mxhi, fmaxf(s[nt][2], s[nt][3]));
        }
        mxlo = fmaxf(mxlo, __shfl_xor_sync(0xffffffff, mxlo, 1));
        mxlo = fmaxf(mxlo, __shfl_xor_sync(0xffffffff, mxlo, 2));
        mxhi = fmaxf(mxhi, __shfl_xor_sync(0xffffffff, mxhi, 1));
        mxhi = fmaxf(mxhi, __shfl_xor_sync(0xffffffff, mxhi, 2));
        if ((lane & 3) == 0) { redm[half * 64 + rl] = mxlo; redm[half * 64 + rh] = mxhi; }
        __syncthreads();
        if (t < 64) {
            float mo = m_s[t];
            float mn = fmaxf(mo, fmaxf(redm[t], redm[64 + t]));
            float al = __expf(mo - mn);
            a_s[t] = al; m_s[t] = mn; l_s[t] *= al;
        }
        __syncthreads();

        float mlo = m_s[rl], mhi = m_s[rh], alo = a_s[rl], ahi = a_s[rh];
        float slo = 0.f, shi = 0.f;
        uint32_t afr[2][4];
#pragma unroll
        for (int ks = 0; ks < 2; ks++) {
#pragma unroll
            for (int jj = 0; jj < 2; jj++) {
                int nt = ks * 2 + jj;
                float p0 = __expf(s[nt][0] - mlo), p1 = __expf(s[nt][1] - mlo);
                float p2 = __expf(s[nt][2] - mhi), p3 = __expf(s[nt][3] - mhi);
                slo += p0 + p1; shi += p2 + p3;
                afr[ks][jj * 2 + 0] = packbf(p0, p1);
                afr[ks][jj * 2 + 1] = packbf(p2, p3);
            }
        }
        slo += __shfl_xor_sync(0xffffffff, slo, 1);
        slo += __shfl_xor_sync(0xffffffff, slo, 2);
        shi += __shfl_xor_sync(0xffffffff, shi, 1);
        shi += __shfl_xor_sync(0xffffffff, shi, 2);
        if ((lane & 3) == 0) { reds[half * 64 + rl] = slo; reds[half * 64 + rh] = shi; }

#pragma unroll
        for (int nt = 0; nt < 8; nt++) {
            o[nt][0] *= alo; o[nt][1] *= alo; o[nt][2] *= ahi; o[nt][3] *= ahi;
        }

#pragma unroll
        for (int ks = 0; ks < 2; ks++) {
#pragma unroll
            for (int nb = 0; nb < 4; nb++) {
                uint32_t b4[4];
                ldmT(b4, smb + MF_VS + (wn2 + ks * 16 + (lane & 15)) * MF_PITCH
                         + nb * 32 + (lane >> 4) * 16);
                mma_bf16(o[2 * nb],     afr[ks], b4);
                mma_bf16(o[2 * nb + 1], afr[ks], b4 + 2);
            }
        }
        __syncthreads();
        if (t < 64) l_s[t] += reds[t] + reds[64 + t];
    }

    __syncthreads();
    if (half == 0) {
#pragma unroll
        for (int nt = 0; nt < 8; nt++) {
            float* plo = Obuf + rl * 68 + nt * 8 + (lane & 3) * 2;
            float* phi = Obuf + rh * 68 + nt * 8 + (lane & 3) * 2;
            plo[0] = o[nt][0]; plo[1] = o[nt][1];
            phi[0] = o[nt][2]; phi[1] = o[nt][3];
        }
    }
    __syncthreads();
    if (half == 1) {
#pragma unroll
        for (int nt = 0; nt < 8; nt++) {
            float* plo = Obuf + rl * 68 + nt * 8 + (lane & 3) * 2;
            float* phi = Obuf + rh * 68 + nt * 8 + (lane & 3) * 2;
            plo[0] += o[nt][0]; plo[1] += o[nt][1];
            phi[0] += o[nt][2]; phi[1] += o[nt][3];
        }
    }
    __syncthreads();
#pragma unroll
    for (int j = 0; j < 8; j++) {
        int id = t + 256 * j;
        int r = id >> 5, cp = id & 31;
        float inv = 1.f / l_s[r];
        float2 v = *(float2*)(Obuf + r * 68 + cp * 2);
        __nv_bfloat162 ob = __float22bfloat162_rn(make_float2(v.x * inv, v.y * inv));
        *(__nv_bfloat162*)(O + base + (size_t)(q0 + r) * 1024 + cp * 2) = ob;
    }
}

// ---------------- fp32 -> bf16 convert ----------------
__global__ __launch_bounds__(256) void cvt_kernel(
    const float4* __restrict__ s, uint2* __restrict__ h, int n4)
{
    int i = blockIdx.x * 256 + threadIdx.x;
    if (i >= n4) return;
    float4 v = s[i];
    uint2 hh;
    hh.x = packbf(v.x, v.y);
    hh.y = packbf(v.z, v.w);
    h[i] = hh;
}

// ---------------- weight transpose (fp32 [K,N] -> bf16 [N,K]) ----------------
__global__ void wtrans_kernel(const float* __restrict__ W,
                              __nv_bfloat16* __restrict__ Th, int Kd, int Nd)
{
    __shared__ float tile[32][33];
    int tx = threadIdx.x, ty = threadIdx.y;
    int n0 = blockIdx.x * 32, k0 = blockIdx.y * 32;
    size_t ob = (size_t)blockIdx.z * Kd * Nd;
    const float* Wb = W + ob;
#pragma unroll
    for (int r = 0; r < 4; r++)
        tile[ty + 8 * r][tx] = Wb[(size_t)(k0 + ty + 8 * r) * Nd + n0 + tx];
    __syncthreads();
#pragma unroll
    for (int r = 0; r < 4; r++)
        Th[ob + (size_t)(n0 + ty + 8 * r) * Kd + k0 + tx] =
            __float2bfloat16(tile[tx][ty + 8 * r]);
}

// ---------------- zero (ein + stats merged) ----------------
__global__ void zero_ein_kernel() {
    if (blockIdx.x == 0 && threadIdx.x < 32) {
        int t = threadIdx.x;
        if (t < NE) { g_Psum[t] = 0.f; g_fcnt[t] = 0.f; }
        if (t == 0) g_zsum = 0.f;
    }
    size_t n = EINSZ / 8;
    uint4 z = make_uint4(0, 0, 0, 0);
    uint4* ph = (uint4*)g_einh;
    for (size_t i = blockIdx.x * (size_t)blockDim.x + threadIdx.x; i < n;
         i += (size_t)gridDim.x * blockDim.x) ph[i] = z;
}

// ---------------- block reduce ----------------
__device__ __forceinline__ void block_reduce2(float& s, float& s2) {
    __shared__ float rs[8], rs2[8];
#pragma unroll
    for (int o = 16; o > 0; o >>= 1) {
        s  += __shfl_xor_sync(0xffffffff, s, o);
        s2 += __shfl_xor_sync(0xffffffff, s2, o);
    }
    int lane = threadIdx.x & 31, w = threadIdx.x >> 5;
    if (lane == 0) { rs[w] = s; rs2[w] = s2; }
    __syncthreads();
    float ts = 0.f, ts2 = 0.f;
#pragma unroll
    for (int i = 0; i < 8; i++) { ts += rs[i]; ts2 += rs2[i]; }
    s = ts; s2 = ts2;
}

// ---------------- LN1 ----------------
__global__ __launch_bounds__(256) void ln1_kernel(
    const float* __restrict__ x, const float* __restrict__ g,
    const float* __restrict__ b)
{
    size_t tok = blockIdx.x;
    int t = threadIdx.x;
    float v[4], s = 0.f, s2 = 0.f;
#pragma unroll
    for (int u = 0; u < 4; u++) {
        int j = t + u * 256;
        float val = x[tok * Dm + j] + g_attn[tok * Dm + j];
        v[u] = val; s += val; s2 += val * val;
    }
    block_reduce2(s, s2);
    float mean = s * (1.f / Dm);
    float var  = s2 * (1.f / Dm) - mean * mean;
    float inv  = rsqrtf(var + 1e-5f);
#pragma unroll
    for (int u = 0; u < 4; u++) {
        int j = t + u * 256;
        g_x1[tok * Dm + j] = (v[u] - mean) * inv * g[j] + b[j];
    }
}

// ---------------- gate ----------------
__global__ __launch_bounds__(256) void gate_kernel(const float* __restrict__ gateW) {
    int warp = threadIdx.x >> 5, lane = threadIdx.x & 31;
    int tok = blockIdx.x * 8 + warp;
    const float* xr = g_x1 + (size_t)tok * Dm;
    float acc[NE];
#pragma unroll
    for (int e = 0; e < NE; e++) acc[e] = 0.f;
    for (int k = lane; k < Dm; k += 32) {
        float xv = xr[k];
        const float* wr = gateW + (size_t)k * NE;
#pragma unroll
        for (int e = 0; e < NE; e++) acc[e] += xv * wr[e];
    }
#pragma unroll
    for (int e = 0; e < NE; e++)
#pragma unroll
        for (int o = 16; o > 0; o >>= 1)
            acc[e] += __shfl_xor_sync(0xffffffff, acc[e], o);
    if (lane == 0) {
        float mx = acc[0];
#pragma unroll
        for (int e = 1; e < NE; e++) mx = fmaxf(mx, acc[e]);
        float p[NE], se = 0.f;
#pragma unroll
        for (int e = 0; e < NE; e++) { p[e] = __expf(acc[e] - mx); se += p[e]; }
        float invs = 1.f / se;
        float lse = mx + logf(se);
        atomicAdd(&g_zsum, lse * lse);
        int i0 = 0, i1 = -1;
        float b0 = -1.f, b1 = -1.f;
#pragma unroll
        for (int e = 0; e < NE; e++) {
            float pe = p[e] * invs;
            atomicAdd(&g_Psum[e], pe);
            if (pe > b0) { b1 = b0; i1 = i0; b0 = pe; i0 = e; }
            else if (pe > b1) { b1 = pe; i1 = e; }
        }
        atomicAdd(&g_fcnt[i0], 1.f);
        g_i0[tok] = i0; g_i1[tok] = i1;
        g_g0[tok] = b0; g_g1[tok] = b1;
    }
}

// ---------------- routing positions ----------------
__global__ __launch_bounds__(256) void pos_kernel() {
    int warp = threadIdx.x >> 5, lane = threadIdx.x & 31;
    if (warp >= Bt) return;
    int b = warp;
    unsigned lt = (1u << lane) - 1u;
    int cnt[NE];
#pragma unroll
    for (int e = 0; e < NE; e++) cnt[e] = 0;

    for (int ch = 0; ch < Sq / 32; ch++) {
        int tok = b * Sq + ch * 32 + lane;
        int e0 = g_i0[tok];
        int myp = 0;
#pragma unroll
        for (int e = 0; e < NE; e++) {
            unsigned m = __ballot_sync(0xffffffff, e0 == e);
            if (e0 == e) myp = cnt[e] + __popc(m & lt);
            cnt[e] += __popc(m);
        }
        g_k0[tok] = (myp < CAP) ? 1 : 0;
        g_p0[tok] = min(myp, CAP - 1);
    }
    for (int ch = 0; ch < Sq / 32; ch++) {
        int tok = b * Sq + ch * 32 + lane;
        int e1 = g_i1[tok];
        bool valid = g_g1[tok] > 0.2f;
        int myp = 0;
#pragma unroll
        for (int e = 0; e < NE; e++) {
            unsigned m = __ballot_sync(0xffffffff, valid && (e1 == e));
            if (valid && (e1 == e)) myp = cnt[e] + __popc(m & lt);
            cnt[e] += __popc(m);
        }
        bool keep = valid && (myp < CAP);
        g_k1[tok] = keep ? 1 : 0;
        g_p1[tok] = valid ? min(myp, CAP - 1) : 0;
    }
}

// ---------------- scatter (x1 fp32 -> einh bf16) ----------------
__global__ __launch_bounds__(256) void scatter_kernel() {
    int idx = blockIdx.x;
    int tok = idx >> 1, slot = idx & 1;
    int keep = slot ? g_k1[tok] : g_k0[tok];
    if (!keep) return;
    int e = slot ? g_i1[tok] : g_i0[tok];
    int p = slot ? g_p1[tok] : g_p0[tok];
    int b = tok / Sq;
    const float4* src = (const float4*)(g_x1 + (size_t)tok * Dm);
    size_t ro = (((size_t)e * Bt + b) * CAP + p) * Dm;
    uint2* dh = (uint2*)(g_einh + ro);
    float4 v = src[threadIdx.x];
    uint2 hh;
    hh.x = packbf(v.x, v.y);
    hh.y = packbf(v.z, v.w);
    dh[threadIdx.x] = hh;
}

// ---------------- combine + LN2 (expert out in bf16) ----------------
__global__ __launch_bounds__(256) void combine_ln_kernel(
    const float* __restrict__ g2, const float* __restrict__ b2,
    float* __restrict__ out)
{
    size_t tok = blockIdx.x;
    int t = threadIdx.x;
    int b = (int)(tok >> 10);
    float w0 = g_k0[tok] ? g_g0[tok] : 0.f;
    float w1 = g_k1[tok] ? g_g1[tok] : 0.f;
    const __nv_bfloat16* r0 = g_eoutb + (((size_t)g_i0[tok] * Bt + b) * CAP + g_p0[tok]) * Dm;
    const __nv_bfloat16* r1 = g_eoutb + (((size_t)g_i1[tok] * Bt + b) * CAP + g_p1[tok]) * Dm;

    float v[4], s = 0.f, s2 = 0.f;
#pragma unroll
    for (int u = 0; u < 4; u++) {
        int j = t + u * 256;
        float val = g_x1[tok * Dm + j]
                  + w0 * __bfloat162float(r0[j]) + w1 * __bfloat162float(r1[j]);
        v[u] = val; s += val; s2 += val * val;
    }
    block_reduce2(s, s2);
    float mean = s * (1.f / Dm);
    float var  = s2 * (1.f / Dm) - mean * mean;
    float inv  = rsqrtf(var + 1e-5f);
#pragma unroll
    for (int u = 0; u < 4; u++) {
        int j = t + u * 256;
        out[tok * Dm + j] = (v[u] - mean) * inv * g2[j] + b2[j];
    }
}

// ---------------- finalize aux ----------------
__global__ void finalize_kernel(float* __restrict__ out) {
    if (threadIdx.x == 0 && blockIdx.x == 0) {
        float invN = 1.f / (float)NT;
        float sfp = 0.f;
#pragma unroll
        for (int e = 0; e < NE; e++)
            sfp += (g_fcnt[e] * invN) * (g_Psum[e] * invN);
        float bal = 0.01f * (float)NE * sfp;
        float zl  = 0.001f * g_zsum * invN;
        out[NTD + 0] = bal + zl;
        out[NTD + 1] = bal;
        out[NTD + 2] = zl;
    }
}

// ---------------- host launcher ----------------
extern "C" void kernel_launch(void* const* d_in, const int* in_sizes, int n_in,
                              void* d_out, int out_size)
{
    const float* x      = (const float*)d_in[0];
    const float* Wq     = (const float*)d_in[1];
    const float* Wk     = (const float*)d_in[2];
    const float* Wv     = (const float*)d_in[3];
    const float* Wo     = (const float*)d_in[4];
    const float* bq     = (const float*)d_in[5];
    const float* bk     = (const float*)d_in[6];
    const float* bv     = (const float*)d_in[7];
    const float* bo     = (const float*)d_in[8];
    const float* ln1_g  = (const float*)d_in[9];
    const float* ln1_b  = (const float*)d_in[10];
    const float* ln2_g  = (const float*)d_in[11];
    const float* ln2_b  = (const float*)d_in[12];
    const float* gate_W = (const float*)d_in[13];
    const float* eWq    = (const float*)d_in[14];
    const float* eWk    = (const float*)d_in[15];
    const float* eWv    = (const float*)d_in[16];
    const float* eWo    = (const float*)d_in[17];
    float* out = (float*)d_out;

    void *pattn, *px1, *peoutb, *pxh, *pqkvh, *poh;
    void *peinh, *peqkv, *peoh;
    void *pwqkvh, *pwoh, *pewh, *pewoh, *pbqkv;
    cudaGetSymbolAddress(&pattn, g_attn);   cudaGetSymbolAddress(&px1, g_x1);
    cudaGetSymbolAddress(&peoutb, g_eoutb); cudaGetSymbolAddress(&pxh, g_xh);
    cudaGetSymbolAddress(&pqkvh, g_qkvh);   cudaGetSymbolAddress(&poh, g_oh);
    cudaGetSymbolAddress(&peinh, g_einh);   cudaGetSymbolAddress(&peqkv, g_eqkv);
    cudaGetSymbolAddress(&peoh, g_eoh);
    cudaGetSymbolAddress(&pwqkvh, g_wqkvh); cudaGetSymbolAddress(&pwoh, g_woh);
    cudaGetSymbolAddress(&pewh, g_ewh);     cudaGetSymbolAddress(&pewoh, g_ewoh);
    cudaGetSymbolAddress(&pbqkv, g_bqkv);

    cudaFuncSetAttribute(gemm_mma_kernel<0>, cudaFuncAttributeMaxDynamicSharedMemorySize, GEMM_SMEM);
    cudaFuncSetAttribute(gemm_mma_kernel<1>, cudaFuncAttributeMaxDynamicSharedMemorySize, GEMM_SMEM);
    cudaFuncSetAttribute(mflash_kernel, cudaFuncAttributeMaxDynamicSharedMemorySize, MF_SMEM);
    cudaFuncSetAttribute(eflash_kernel, cudaFuncAttributeMaxDynamicSharedMemorySize, EF_SMEM);

    zero_ein_kernel<<<2048, 256>>>();

    cudaMemcpyAsync((float*)pbqkv,          bq, Dm * sizeof(float), cudaMemcpyDeviceToDevice);
    cudaMemcpyAsync((float*)pbqkv + Dm,     bk, Dm * sizeof(float), cudaMemcpyDeviceToDevice);
    cudaMemcpyAsync((float*)pbqkv + 2 * Dm, bv, Dm * sizeof(float), cudaMemcpyDeviceToDevice);

    dim3 tb(32, 8);
    __nv_bfloat16* wqkv = (__nv_bfloat16*)pwqkvh;
    __nv_bfloat16* ewh  = (__nv_bfloat16*)pewh;
    wtrans_kernel<<<dim3(32, 32, 1), tb>>>(Wq, wqkv,            Dm, Dm);
    wtrans_kernel<<<dim3(32, 32, 1), tb>>>(Wk, wqkv + DMDM,     Dm, Dm);
    wtrans_kernel<<<dim3(32, 32, 1), tb>>>(Wv, wqkv + 2 * DMDM, Dm, Dm);
    wtrans_kernel<<<dim3(32, 32, 1), tb>>>(Wo, (__nv_bfloat16*)pwoh, Dm, Dm);
    wtrans_kernel<<<dim3(32, 32, NE), tb>>>(eWq, ewh,                 Dm, Dm);
    wtrans_kernel<<<dim3(32, 32, NE), tb>>>(eWk, ewh + NE * DMDM,     Dm, Dm);
    wtrans_kernel<<<dim3(32, 32, NE), tb>>>(eWv, ewh + 2 * NE * DMDM, Dm, Dm);
    wtrans_kernel<<<dim3(32, 32, NE), tb>>>(eWo, (__nv_bfloat16*)pewoh, Dm, Dm);

    cvt_kernel<<<(int)(NTD / 4 / 256), 256>>>((const float4*)x, (uint2*)pxh, (int)(NTD / 4));

    // main QKV: one batched launch, z in [0,3)
    gemm_mma_kernel<1><<<dim3(Dm / 128, NT / 128, 3), 256, GEMM_SMEM>>>(
        (__nv_bfloat16*)pxh, wqkv, (const float*)pbqkv, pqkvh,
        NT, Dm, Dm, 0, DMDM, NTD, Dm, 3);

    __nv_bfloat16* qkv = (__nv_bfloat16*)pqkvh;
    mflash_kernel<<<dim3(Sq / 64, Bt * NH), 256, MF_SMEM>>>(
        qkv, qkv + NTD, qkv + 2 * NTD, (__nv_bfloat16*)poh, 0.125f);

    // Wo
    gemm_mma_kernel<0><<<dim3(Dm / 128, NT / 128, 1), 256, GEMM_SMEM>>>(
        (__nv_bfloat16*)poh, (__nv_bfloat16*)pwoh, bo, pattn,
        NT, Dm, Dm, 0, 0, 0, 0, 1);

    ln1_kernel<<<NT, 256>>>(x, ln1_g, ln1_b);
    gate_kernel<<<NT / 8, 256>>>(gate_W);
    pos_kernel<<<1, 256>>>();
    scatter_kernel<<<NT * 2, 256>>>();

    // expert QKV: one batched launch, z = p*NE + e in [0,24)
    size_t sA = (size_t)EROWS * Dm;
    gemm_mma_kernel<1><<<dim3(Dm / 128, EROWS / 128, 24), 256, GEMM_SMEM>>>(
        (__nv_bfloat16*)peinh, ewh, nullptr, peqkv,
        EROWS, Dm, Dm, sA, DMDM, sA, 0, NE);

    __nv_bfloat16* eqkv = (__nv_bfloat16*)peqkv;
    eflash_kernel<<<dim3(CAP / 64, NE * Bt * NHM), 256, EF_SMEM>>>(
        eqkv, eqkv + EINSZ, eqkv + 2 * EINSZ, (__nv_bfloat16*)peoh, 0.0883883476483184f);

    // expert Wo: bf16 out
    gemm_mma_kernel<1><<<dim3(Dm / 128, EROWS / 128, NE), 256, GEMM_SMEM>>>(
        (__nv_bfloat16*)peoh, (__nv_bfloat16*)pewoh, nullptr, peoutb,
        EROWS, Dm, Dm, sA, DMDM, sA, 0, NE);

    combine_ln_kernel<<<NT, 256>>>(ln2_g, ln2_b, out);
    finalize_kernel<<<1, 32>>>(out);
}

// round 9
// speedup vs baseline: 6.9457x; 1.0803x over previous
#include <cuda_runtime.h>
#include <cuda_bf16.h>
#include <math.h>
#include <stdint.h>

// ---------------- problem dims ----------------
#define Bt   8
#define Sq   1024
#define Dm   1024
#define NH   16
#define HD1  64
#define NE   8
#define NHM  8
#define HDM  128
#define CAP  320
#define NT   (Bt*Sq)
#define NTD  ((size_t)NT*Dm)
#define EROWS (Bt*CAP)
#define EINSZ ((size_t)NE*Bt*CAP*Dm)
#define DMDM ((size_t)Dm*Dm)

// ---------------- scratch ----------------
static __device__ float g_attn[NTD];
static __device__ float g_x1[NTD];

static __device__ __nv_bfloat16 g_xh[NTD];
static __device__ __nv_bfloat16 g_qkvh[3*NTD];       // [q|k|v]
static __device__ __nv_bfloat16 g_oh[NTD];
static __device__ __nv_bfloat16 g_einh[EINSZ];
static __device__ __nv_bfloat16 g_eqkv[3*EINSZ];     // [q|k|v] expert
static __device__ __nv_bfloat16 g_eoh[EINSZ];
static __device__ __nv_bfloat16 g_eoutb[EINSZ];      // expert output (bf16)
static __device__ __nv_bfloat16 g_wqkvh[3*DMDM];     // [K,N] bf16 (no transpose)
static __device__ __nv_bfloat16 g_woh[DMDM];
static __device__ __nv_bfloat16 g_ewh[3*NE*DMDM];    // [q experts][k][v], [K,N]
static __device__ __nv_bfloat16 g_ewoh[NE*DMDM];
static __device__ float g_bqkv[3*Dm];

static __device__ int   g_i0[NT], g_i1[NT];
static __device__ float g_g0[NT], g_g1[NT];
static __device__ int   g_p0[NT], g_p1[NT];
static __device__ int   g_k0[NT], g_k1[NT];

static __device__ float g_Psum[NE];
static __device__ float g_fcnt[NE];
static __device__ float g_zsum;

// ---------------- PTX helpers ----------------
__device__ __forceinline__ uint32_t smem_u32(const void* p) {
    uint32_t a;
    asm("{ .reg .u64 t; cvta.to.shared.u64 t, %1; cvt.u32.u64 %0, t; }" : "=r"(a) : "l"(p));
    return a;
}
__device__ __forceinline__ void cp16(uint32_t dst, const void* src) {
    asm volatile("cp.async.cg.shared.global [%0], [%1], 16;" :: "r"(dst), "l"(src));
}
__device__ __forceinline__ void ldmA(uint32_t* a, uint32_t addr) {
    asm volatile("ldmatrix.sync.aligned.m8n8.x4.shared.b16 {%0,%1,%2,%3}, [%4];"
        : "=r"(a[0]), "=r"(a[1]), "=r"(a[2]), "=r"(a[3]) : "r"(addr));
}
__device__ __forceinline__ void ldmT(uint32_t* a, uint32_t addr) {
    asm volatile("ldmatrix.sync.aligned.m8n8.x4.trans.shared.b16 {%0,%1,%2,%3}, [%4];"
        : "=r"(a[0]), "=r"(a[1]), "=r"(a[2]), "=r"(a[3]) : "r"(addr));
}
__device__ __forceinline__ void mma_bf16(float* d, const uint32_t* a, const uint32_t* b) {
    asm volatile(
        "mma.sync.aligned.m16n8k16.row.col.f32.bf16.bf16.f32 "
        "{%0,%1,%2,%3}, {%4,%5,%6,%7}, {%8,%9}, {%0,%1,%2,%3};"
        : "+f"(d[0]), "+f"(d[1]), "+f"(d[2]), "+f"(d[3])
        : "r"(a[0]), "r"(a[1]), "r"(a[2]), "r"(a[3]), "r"(b[0]), "r"(b[1]));
}
__device__ __forceinline__ uint32_t packbf(float a, float b) {
    __nv_bfloat162 v = __float22bfloat162_rn(make_float2(a, b));
    return *(uint32_t*)&v;
}

// ---------------- GEMM via mma.sync (bf16, BK=64, B in natural [K,N]) -------
// C[z][M,N] = A[z%zmod][M,K] @ W[z]  with W[K,N] row-major (ldmatrix.trans).
// OUTBF: 0 fp32 out, 1 bf16 out.
#define BK 64
#define ROWA 144               // A row: 64 bf16 = 128B + 16 pad
#define ROWBB 272              // B row: 128 bf16 = 256B + 16 pad
#define ASTG (128*ROWA)        // 18432
#define BSTG (64*ROWBB)        // 17408
#define STG2 (ASTG+BSTG)       // 35840
#define NSTG 3
#define GEMM_SMEM (NSTG*STG2)  // 107520

template <int OUTBF>
__global__ __launch_bounds__(256, 2) void gemm_mma_kernel(
    const __nv_bfloat16* __restrict__ A, const __nv_bfloat16* __restrict__ W,
    const float* __restrict__ bias, void* __restrict__ Cv,
    int M, int N, int K, size_t sA, size_t sB, size_t sC, size_t sbias, int zmod)
{
    extern __shared__ char sm_[];
    uint32_t smb = smem_u32(sm_);

    int t = threadIdx.x, lane = t & 31, wid = t >> 5;
    int n0 = blockIdx.x * 128, m0 = blockIdx.y * 128;
    int z = blockIdx.z;
    A += (size_t)(z % zmod) * sA;
    W += (size_t)z * sB;
    if (bias) bias += (size_t)z * sbias;

    int wm = (wid & 3) * 32;
    int wn = (wid >> 2) * 64;
    const int NC = K / BK;   // 16

    float acc[2][8][4];
#pragma unroll
    for (int i = 0; i < 2; i++)
#pragma unroll
        for (int j = 0; j < 8; j++)
#pragma unroll
            for (int q = 0; q < 4; q++) acc[i][j][q] = 0.f;

    // A cp.async coords: 4 row-groups of 32
    int rb = t >> 3, c8 = t & 7;
    const __nv_bfloat16* Ap = A + (size_t)(m0 + rb) * K + c8 * 8;
    uint32_t waA = (uint32_t)rb * ROWA + c8 * 16;
    const size_t rstepA = (size_t)32 * K;
    // B cp.async coords: 64 k-rows x 16 chunks; idx = t + 256*j
    int rB = t >> 4, cB = t & 15;   // covers idx<1024 via j offsets of +16 rows
    const __nv_bfloat16* Wp = W + (size_t)rB * N + n0 + cB * 8;
    uint32_t waB = (uint32_t)rB * ROWBB + cB * 16;
    const size_t rstepB = (size_t)16 * N;

    // prefetch 2 stages
#pragma unroll
    for (int s = 0; s < 2; s++) {
        uint32_t stg = smb + s * STG2;
        int kc = s * BK;
#pragma unroll
        for (int j = 0; j < 4; j++) {
            cp16(stg + waA + j * (32 * ROWA), Ap + kc + j * rstepA);
            cp16(stg + ASTG + waB + j * (16 * ROWBB), Wp + (size_t)kc * N + j * rstepB);
        }
        asm volatile("cp.async.commit_group;");
    }

    uint32_t a_row = (uint32_t)(wm + (lane & 15)) * ROWA + (lane >> 4) * 16;
    uint32_t b_col = (uint32_t)(lane & 15) * ROWBB + wn * 2 + (lane >> 4) * 16;

    int sidx = 0;
    for (int c = 0; c < NC; c++) {
        asm volatile("cp.async.wait_group 1;");
        __syncthreads();
        if (c + 2 < NC) {
            int sn = sidx + 2; if (sn >= NSTG) sn -= NSTG;
            uint32_t stg = smb + sn * STG2;
            int kc = (c + 2) * BK;
#pragma unroll
            for (int j = 0; j < 4; j++) {
                cp16(stg + waA + j * (32 * ROWA), Ap + kc + j * rstepA);
                cp16(stg + ASTG + waB + j * (16 * ROWBB), Wp + (size_t)kc * N + j * rstepB);
            }
        }
        asm volatile("cp.async.commit_group;");

        uint32_t ab = smb + sidx * STG2;
        uint32_t bb = ab + ASTG;

#pragma unroll
        for (int ks = 0; ks < 4; ks++) {
            uint32_t afr[2][4];
#pragma unroll
            for (int mt = 0; mt < 2; mt++)
                ldmA(afr[mt], ab + a_row + mt * (16 * ROWA) + ks * 32);

            uint32_t bfr[8][2];
#pragma unroll
            for (int nb = 0; nb < 4; nb++) {
                uint32_t q[4];
                ldmT(q, bb + b_col + ks * (16 * ROWBB) + nb * 32);
                bfr[nb * 2][0]     = q[0]; bfr[nb * 2][1]     = q[1];
                bfr[nb * 2 + 1][0] = q[2]; bfr[nb * 2 + 1][1] = q[3];
            }
#pragma unroll
            for (int mt = 0; mt < 2; mt++)
#pragma unroll
                for (int nt = 0; nt < 8; nt++)
                    mma_bf16(acc[mt][nt], afr[mt], bfr[nt]);
        }
        if (++sidx == NSTG) sidx = 0;
    }

    // epilogue
#pragma unroll
    for (int mt = 0; mt < 2; mt++) {
        int m = m0 + wm + mt * 16 + (lane >> 2);
#pragma unroll
        for (int nt = 0; nt < 8; nt++) {
            int n = n0 + wn + nt * 8 + (lane & 3) * 2;
            float bv0 = bias ? bias[n] : 0.f;
            float bv1 = bias ? bias[n + 1] : 0.f;
            float v0 = acc[mt][nt][0] + bv0, v1 = acc[mt][nt][1] + bv1;
            float v2 = acc[mt][nt][2] + bv0, v3 = acc[mt][nt][3] + bv1;
            if (OUTBF == 0) {
                float* C = (float*)Cv + (size_t)z * sC;
                *(float2*)&C[(size_t)m * N + n]       = make_float2(v0, v1);
                *(float2*)&C[(size_t)(m + 8) * N + n] = make_float2(v2, v3);
            } else {
                __nv_bfloat16* C = (__nv_bfloat16*)Cv + (size_t)z * sC;
                *(uint32_t*)&C[(size_t)m * N + n]       = packbf(v0, v1);
                *(uint32_t*)&C[(size_t)(m + 8) * N + n] = packbf(v2, v3);
            }
        }
    }
}

// ---------------- expert flash (bf16 mma, HD=128) ----------------
#define EF_PITCH 272
#define EF_QS 0
#define EF_KS 17408
#define EF_VS 34816
#define EF_OB 52224
#define EF_MS 86016
#define EF_LS 86272
#define EF_AS 86528
#define EF_RM 86784
#define EF_RS 87296
#define EF_SMEM 87808

__global__ __launch_bounds__(256) void eflash_kernel(
    const __nv_bfloat16* __restrict__ Q, const __nv_bfloat16* __restrict__ K,
    const __nv_bfloat16* __restrict__ V, __nv_bfloat16* __restrict__ O,
    float scale)
{
    extern __shared__ char sm_[];
    float* Obuf = (float*)(sm_ + EF_OB);
    float* m_s  = (float*)(sm_ + EF_MS);
    float* l_s  = (float*)(sm_ + EF_LS);
    float* a_s  = (float*)(sm_ + EF_AS);
    float* redm = (float*)(sm_ + EF_RM);
    float* reds = (float*)(sm_ + EF_RS);
    uint32_t smb = smem_u32(sm_);

    int t = threadIdx.x, lane = t & 31, wid = t >> 5;
    int half = wid >> 2, wm = (wid & 3) * 16, wn2 = half * 32;
    int slice = blockIdx.y;
    int sb = slice >> 3, h = slice & 7;
    size_t base = (size_t)sb * CAP * 1024 + (size_t)h * HDM;
    int q0 = blockIdx.x * 64;

#pragma unroll
    for (int j = 0; j < 4; j++) {
        int id = t + 256 * j;
        int r = id >> 4, c = id & 15;
        *(uint4*)(sm_ + EF_QS + r * EF_PITCH + c * 16) =
            *(const uint4*)(Q + base + (size_t)(q0 + r) * 1024 + c * 8);
    }
    if (t < 64) { m_s[t] = -1e30f; l_s[t] = 0.f; }

    float o[16][4];
#pragma unroll
    for (int i = 0; i < 16; i++)
#pragma unroll
        for (int q = 0; q < 4; q++) o[i][q] = 0.f;

    int rl = wm + (lane >> 2), rh = rl + 8;
    int nq = lane >> 2, kr = lane & 3;

    for (int kt = 0; kt < CAP / 64; kt++) {
        __syncthreads();
#pragma unroll
        for (int j = 0; j < 4; j++) {
            int id = t + 256 * j;
            int r = id >> 4, c = id & 15;
            *(uint4*)(sm_ + EF_KS + r * EF_PITCH + c * 16) =
                *(const uint4*)(K + base + (size_t)(kt * 64 + r) * 1024 + c * 8);
            *(uint4*)(sm_ + EF_VS + r * EF_PITCH + c * 16) =
                *(const uint4*)(V + base + (size_t)(kt * 64 + r) * 1024 + c * 8);
        }
        __syncthreads();

        float s[4][4];
#pragma unroll
        for (int nt = 0; nt < 4; nt++)
#pragma unroll
            for (int q = 0; q < 4; q++) s[nt][q] = 0.f;
#pragma unroll
        for (int ks = 0; ks < 8; ks++) {
            uint32_t af[4];
            ldmA(af, smb + EF_QS + (wm + (lane & 15)) * EF_PITCH + ks * 32 + (lane >> 4) * 16);
#pragma unroll
            for (int nt = 0; nt < 4; nt++) {
                const char* p = sm_ + EF_KS + (wn2 + nt * 8 + nq) * EF_PITCH + ks * 32 + kr * 4;
                uint32_t bb[2];
                bb[0] = *(const uint32_t*)p;
                bb[1] = *(const uint32_t*)(p + 16);
                mma_bf16(s[nt], af, bb);
            }
        }

        float mxlo = -1e30f, mxhi = -1e30f;
#pragma unroll
        for (int nt = 0; nt < 4; nt++) {
            s[nt][0] *= scale; s[nt][1] *= scale; s[nt][2] *= scale; s[nt][3] *= scale;
            mxlo = fmaxf(mxlo, fmaxf(s[nt][0], s[nt][1]));
            mxhi = fmaxf(mxhi, fmaxf(s[nt][2], s[nt][3]));
        }
        mxlo = fmaxf(mxlo, __shfl_xor_sync(0xffffffff, mxlo, 1));
        mxlo = fmaxf(mxlo, __shfl_xor_sync(0xffffffff, mxlo, 2));
        mxhi = fmaxf(mxhi, __shfl_xor_sync(0xffffffff, mxhi, 1));
        mxhi = fmaxf(mxhi, __shfl_xor_sync(0xffffffff, mxhi, 2));
        if ((lane & 3) == 0) { redm[half * 64 + rl] = mxlo; redm[half * 64 + rh] = mxhi; }
        __syncthreads();
        if (t < 64) {
            float mo = m_s[t];
            float mn = fmaxf(mo, fmaxf(redm[t], redm[64 + t]));
            float al = __expf(mo - mn);
            a_s[t] = al; m_s[t] = mn; l_s[t] *= al;
        }
        __syncthreads();

        float mlo = m_s[rl], mhi = m_s[rh], alo = a_s[rl], ahi = a_s[rh];
        float slo = 0.f, shi = 0.f;
        uint32_t afr[2][4];
#pragma unroll
        for (int ks = 0; ks < 2; ks++) {
#pragma unroll
            for (int jj = 0; jj < 2; jj++) {
                int nt = ks * 2 + jj;
                float p0 = __expf(s[nt][0] - mlo), p1 = __expf(s[nt][1] - mlo);
                float p2 = __expf(s[nt][2] - mhi), p3 = __expf(s[nt][3] - mhi);
                slo += p0 + p1; shi += p2 + p3;
                afr[ks][jj * 2 + 0] = packbf(p0, p1);
                afr[ks][jj * 2 + 1] = packbf(p2, p3);
            }
        }
        slo += __shfl_xor_sync(0xffffffff, slo, 1);
        slo += __shfl_xor_sync(0xffffffff, slo, 2);
        shi += __shfl_xor_sync(0xffffffff, shi, 1);
        shi += __shfl_xor_sync(0xffffffff, shi, 2);
        if ((lane & 3) == 0) { reds[half * 64 + rl] = slo; reds[half * 64 + rh] = shi; }

#pragma unroll
        for (int nt = 0; nt < 16; nt++) {
            o[nt][0] *= alo; o[nt][1] *= alo; o[nt][2] *= ahi; o[nt][3] *= ahi;
        }

#pragma unroll
        for (int ks = 0; ks < 2; ks++) {
#pragma unroll
            for (int nb = 0; nb < 8; nb++) {
                uint32_t b4[4];
                ldmT(b4, smb + EF_VS + (wn2 + ks * 16 + (lane & 15)) * EF_PITCH
                         + nb * 32 + (lane >> 4) * 16);
                mma_bf16(o[2 * nb],     afr[ks], b4);
                mma_bf16(o[2 * nb + 1], afr[ks], b4 + 2);
            }
        }
        __syncthreads();
        if (t < 64) l_s[t] += reds[t] + reds[64 + t];
    }

    __syncthreads();
    if (half == 0) {
#pragma unroll
        for (int nt = 0; nt < 16; nt++) {
            float* plo = Obuf + rl * 132 + nt * 8 + (lane & 3) * 2;
            float* phi = Obuf + rh * 132 + nt * 8 + (lane & 3) * 2;
            plo[0] = o[nt][0]; plo[1] = o[nt][1];
            phi[0] = o[nt][2]; phi[1] = o[nt][3];
        }
    }
    __syncthreads();
    if (half == 1) {
#pragma unroll
        for (int nt = 0; nt < 16; nt++) {
            float* plo = Obuf + rl * 132 + nt * 8 + (lane & 3) * 2;
            float* phi = Obuf + rh * 132 + nt * 8 + (lane & 3) * 2;
            plo[0] += o[nt][0]; plo[1] += o[nt][1];
            phi[0] += o[nt][2]; phi[1] += o[nt][3];
        }
    }
    __syncthreads();
#pragma unroll
    for (int j = 0; j < 16; j++) {
        int id = t + 256 * j;
        int r = id >> 6, cp = id & 63;
        float inv = 1.f / l_s[r];
        float2 v = *(float2*)(Obuf + r * 132 + cp * 2);
        __nv_bfloat162 ob = __float22bfloat162_rn(make_float2(v.x * inv, v.y * inv));
        *(__nv_bfloat162*)(O + base + (size_t)(q0 + r) * 1024 + cp * 2) = ob;
    }
}

// ---------------- main flash (bf16 mma, HD=64) ----------------
#define MF_PITCH 144
#define MF_QS 0
#define MF_KS 9216
#define MF_VS 18432
#define MF_OB 27648
#define MF_MS 45056
#define MF_LS 45312
#define MF_AS 45568
#define MF_RM 45824
#define MF_RS 46336
#define MF_SMEM 46848

__global__ __launch_bounds__(256) void mflash_kernel(
    const __nv_bfloat16* __restrict__ Q, const __nv_bfloat16* __restrict__ K,
    const __nv_bfloat16* __restrict__ V, __nv_bfloat16* __restrict__ O,
    float scale)
{
    extern __shared__ char sm_[];
    float* Obuf = (float*)(sm_ + MF_OB);
    float* m_s  = (float*)(sm_ + MF_MS);
    float* l_s  = (float*)(sm_ + MF_LS);
    float* a_s  = (float*)(sm_ + MF_AS);
    float* redm = (float*)(sm_ + MF_RM);
    float* reds = (float*)(sm_ + MF_RS);
    uint32_t smb = smem_u32(sm_);

    int t = threadIdx.x, lane = t & 31, wid = t >> 5;
    int half = wid >> 2, wm = (wid & 3) * 16, wn2 = half * 32;
    int slice = blockIdx.y;
    int sb = slice >> 4, h = slice & 15;
    size_t base = (size_t)sb * Sq * 1024 + (size_t)h * HD1;
    int q0 = blockIdx.x * 64;

#pragma unroll
    for (int j = 0; j < 2; j++) {
        int id = t + 256 * j;
        int r = id >> 3, c = id & 7;
        *(uint4*)(sm_ + MF_QS + r * MF_PITCH + c * 16) =
            *(const uint4*)(Q + base + (size_t)(q0 + r) * 1024 + c * 8);
    }
    if (t < 64) { m_s[t] = -1e30f; l_s[t] = 0.f; }

    float o[8][4];
#pragma unroll
    for (int i = 0; i < 8; i++)
#pragma unroll
        for (int q = 0; q < 4; q++) o[i][q] = 0.f;

    int rl = wm + (lane >> 2), rh = rl + 8;
    int nq = lane >> 2, kr = lane & 3;

    for (int kt = 0; kt < Sq / 64; kt++) {
        __syncthreads();
#pragma unroll
        for (int j = 0; j < 2; j++) {
            int id = t + 256 * j;
            int r = id >> 3, c = id & 7;
            size_t g = base + (size_t)(kt * 64 + r) * 1024 + c * 8;
            *(uint4*)(sm_ + MF_KS + r * MF_PITCH + c * 16) = *(const uint4*)(K + g);
            *(uint4*)(sm_ + MF_VS + r * MF_PITCH + c * 16) = *(const uint4*)(V + g);
        }
        __syncthreads();

        float s[4][4];
#pragma unroll
        for (int nt = 0; nt < 4; nt++)
#pragma unroll
            for (int q = 0; q < 4; q++) s[nt][q] = 0.f;
#pragma unroll
        for (int ks = 0; ks < 4; ks++) {
            uint32_t af[4];
            ldmA(af, smb + MF_QS + (wm + (lane & 15)) * MF_PITCH + ks * 32 + (lane >> 4) * 16);
#pragma unroll
            for (int nt = 0; nt < 4; nt++) {
                const char* p = sm_ + MF_KS + (wn2 + nt * 8 + nq) * MF_PITCH + ks * 32 + kr * 4;
                uint32_t bb[2];
                bb[0] = *(const uint32_t*)p;
                bb[1] = *(const uint32_t*)(p + 16);
                mma_bf16(s[nt], af, bb);
            }
        }

        float mxlo = -1e30f, mxhi = -1e30f;
#pragma unroll
        for (int nt = 0; nt < 4; nt++) {
            s[nt][0] *= scale; s[nt][1] *= scale; s[nt][2] *= scale; s[nt][3] *= scale;
            mxlo = fmaxf(mxlo, fmaxf(s[nt][0], s[nt][1]));
            mxhi = fmaxf(mxhi, fmaxf(s[nt][2], s[nt][3]));
        }
        mxlo = fmaxf(mxlo, __shfl_xor_sync(0xffffffff, mxlo, 1));
        mxlo = fmaxf(mxlo, __shfl_xor_sync(0xffffffff, mxlo, 2));
        mxhi = fmaxf(mxhi, __shfl_xor_sync(0xffffffff, mxhi, 1));
        mxhi = fmaxf(mxhi, __shfl_xor_sync(0xffffffff, mxhi, 2));
        if ((lane & 3) == 0) { redm[half * 64 + rl] = mxlo; redm[half * 64 + rh] = mxhi; }
        __syncthreads();
        if (t < 64) {
            float mo = m_s[t];
            float mn = fmaxf(mo, fmaxf(redm[t], redm[64 + t]));
            float al = __expf(mo - mn);
            a_s[t] = al; m_s[t] = mn; l_s[t] *= al;
        }
        __syncthreads();

        float mlo = m_s[rl], mhi = m_s[rh], alo = a_s[rl], ahi = a_s[rh];
        float slo = 0.f, shi = 0.f;
        uint32_t afr[2][4];
#pragma unroll
        for (int ks = 0; ks < 2; ks++) {
#pragma unroll
            for (int jj = 0; jj < 2; jj++) {
                int nt = ks * 2 + jj;
                float p0 = __expf(s[nt][0] - mlo), p1 = __expf(s[nt][1] - mlo);
                float p2 = __expf(s[nt][2] - mhi), p3 = __expf(s[nt][3] - mhi);
                slo += p0 + p1; shi += p2 + p3;
                afr[ks][jj * 2 + 0] = packbf(p0, p1);
                afr[ks][jj * 2 + 1] = packbf(p2, p3);
            }
        }
        slo += __shfl_xor_sync(0xffffffff, slo, 1);
        slo += __shfl_xor_sync(0xffffffff, slo, 2);
        shi += __shfl_xor_sync(0xffffffff, shi, 1);
        shi += __shfl_xor_sync(0xffffffff, shi, 2);
        if ((lane & 3) == 0) { reds[half * 64 + rl] = slo; reds[half * 64 + rh] = shi; }

#pragma unroll
        for (int nt = 0; nt < 8; nt++) {
            o[nt][0] *= alo; o[nt][1] *= alo; o[nt][2] *= ahi; o[nt][3] *= ahi;
        }

#pragma unroll
        for (int ks = 0; ks < 2; ks++) {
#pragma unroll
            for (int nb = 0; nb < 4; nb++) {
                uint32_t b4[4];
                ldmT(b4, smb + MF_VS + (wn2 + ks * 16 + (lane & 15)) * MF_PITCH
                         + nb * 32 + (lane >> 4) * 16);
                mma_bf16(o[2 * nb],     afr[ks], b4);
                mma_bf16(o[2 * nb + 1], afr[ks], b4 + 2);
            }
        }
        __syncthreads();
        if (t < 64) l_s[t] += reds[t] + reds[64 + t];
    }

    __syncthreads();
    if (half == 0) {
#pragma unroll
        for (int nt = 0; nt < 8; nt++) {
            float* plo = Obuf + rl * 68 + nt * 8 + (lane & 3) * 2;
            float* phi = Obuf + rh * 68 + nt * 8 + (lane & 3) * 2;
            plo[0] = o[nt][0]; plo[1] = o[nt][1];
            phi[0] = o[nt][2]; phi[1] = o[nt][3];
        }
    }
    __syncthreads();
    if (half == 1) {
#pragma unroll
        for (int nt = 0; nt < 8; nt++) {
            float* plo = Obuf + rl * 68 + nt * 8 + (lane & 3) * 2;
            float* phi = Obuf + rh * 68 + nt * 8 + (lane & 3) * 2;
            plo[0] += o[nt][0]; plo[1] += o[nt][1];
            phi[0] += o[nt][2]; phi[1] += o[nt][3];
        }
    }
    __syncthreads();
#pragma unroll
    for (int j = 0; j < 8; j++) {
        int id = t + 256 * j;
        int r = id >> 5, cp = id & 31;
        float inv = 1.f / l_s[r];
        float2 v = *(float2*)(Obuf + r * 68 + cp * 2);
        __nv_bfloat162 ob = __float22bfloat162_rn(make_float2(v.x * inv, v.y * inv));
        *(__nv_bfloat162*)(O + base + (size_t)(q0 + r) * 1024 + cp * 2) = ob;
    }
}

// ---------------- fp32 -> bf16 convert (streaming) ----------------
__global__ __launch_bounds__(256) void cvt_kernel(
    const float4* __restrict__ s, uint2* __restrict__ h, int n4)
{
    int i = blockIdx.x * 256 + threadIdx.x;
    if (i >= n4) return;
    float4 v = s[i];
    uint2 hh;
    hh.x = packbf(v.x, v.y);
    hh.y = packbf(v.z, v.w);
    h[i] = hh;
}

// ---------------- zero (ein + stats merged) ----------------
__global__ void zero_ein_kernel() {
    if (blockIdx.x == 0 && threadIdx.x < 32) {
        int t = threadIdx.x;
        if (t < NE) { g_Psum[t] = 0.f; g_fcnt[t] = 0.f; }
        if (t == 0) g_zsum = 0.f;
    }
    size_t n = EINSZ / 8;
    uint4 z = make_uint4(0, 0, 0, 0);
    uint4* ph = (uint4*)g_einh;
    for (size_t i = blockIdx.x * (size_t)blockDim.x + threadIdx.x; i < n;
         i += (size_t)gridDim.x * blockDim.x) ph[i] = z;
}

// ---------------- block reduce ----------------
__device__ __forceinline__ void block_reduce2(float& s, float& s2) {
    __shared__ float rs[8], rs2[8];
#pragma unroll
    for (int o = 16; o > 0; o >>= 1) {
        s  += __shfl_xor_sync(0xffffffff, s, o);
        s2 += __shfl_xor_sync(0xffffffff, s2, o);
    }
    int lane = threadIdx.x & 31, w = threadIdx.x >> 5;
    if (lane == 0) { rs[w] = s; rs2[w] = s2; }
    __syncthreads();
    float ts = 0.f, ts2 = 0.f;
#pragma unroll
    for (int i = 0; i < 8; i++) { ts += rs[i]; ts2 += rs2[i]; }
    s = ts; s2 = ts2;
}

// ---------------- LN1 ----------------
__global__ __launch_bounds__(256) void ln1_kernel(
    const float* __restrict__ x, const float* __restrict__ g,
    const float* __restrict__ b)
{
    size_t tok = blockIdx.x;
    int t = threadIdx.x;
    float v[4], s = 0.f, s2 = 0.f;
#pragma unroll
    for (int u = 0; u < 4; u++) {
        int j = t + u * 256;
        float val = x[tok * Dm + j] + g_attn[tok * Dm + j];
        v[u] = val; s += val; s2 += val * val;
    }
    block_reduce2(s, s2);
    float mean = s * (1.f / Dm);
    float var  = s2 * (1.f / Dm) - mean * mean;
    float inv  = rsqrtf(var + 1e-5f);
#pragma unroll
    for (int u = 0; u < 4; u++) {
        int j = t + u * 256;
        g_x1[tok * Dm + j] = (v[u] - mean) * inv * g[j] + b[j];
    }
}

// ---------------- gate ----------------
__global__ __launch_bounds__(256) void gate_kernel(const float* __restrict__ gateW) {
    int warp = threadIdx.x >> 5, lane = threadIdx.x & 31;
    int tok = blockIdx.x * 8 + warp;
    const float* xr = g_x1 + (size_t)tok * Dm;
    float acc[NE];
#pragma unroll
    for (int e = 0; e < NE; e++) acc[e] = 0.f;
    for (int k = lane; k < Dm; k += 32) {
        float xv = xr[k];
        const float* wr = gateW + (size_t)k * NE;
#pragma unroll
        for (int e = 0; e < NE; e++) acc[e] += xv * wr[e];
    }
#pragma unroll
    for (int e = 0; e < NE; e++)
#pragma unroll
        for (int o = 16; o > 0; o >>= 1)
            acc[e] += __shfl_xor_sync(0xffffffff, acc[e], o);
    if (lane == 0) {
        float mx = acc[0];
#pragma unroll
        for (int e = 1; e < NE; e++) mx = fmaxf(mx, acc[e]);
        float p[NE], se = 0.f;
#pragma unroll
        for (int e = 0; e < NE; e++) { p[e] = __expf(acc[e] - mx); se += p[e]; }
        float invs = 1.f / se;
        float lse = mx + logf(se);
        atomicAdd(&g_zsum, lse * lse);
        int i0 = 0, i1 = -1;
        float b0 = -1.f, b1 = -1.f;
#pragma unroll
        for (int e = 0; e < NE; e++) {
            float pe = p[e] * invs;
            atomicAdd(&g_Psum[e], pe);
            if (pe > b0) { b1 = b0; i1 = i0; b0 = pe; i0 = e; }
            else if (pe > b1) { b1 = pe; i1 = e; }
        }
        atomicAdd(&g_fcnt[i0], 1.f);
        g_i0[tok] = i0; g_i1[tok] = i1;
        g_g0[tok] = b0; g_g1[tok] = b1;
    }
}

// ---------------- routing positions ----------------
__global__ __launch_bounds__(256) void pos_kernel() {
    int warp = threadIdx.x >> 5, lane = threadIdx.x & 31;
    if (warp >= Bt) return;
    int b = warp;
    unsigned lt = (1u << lane) - 1u;
    int cnt[NE];
#pragma unroll
    for (int e = 0; e < NE; e++) cnt[e] = 0;

    for (int ch = 0; ch < Sq / 32; ch++) {
        int tok = b * Sq + ch * 32 + lane;
        int e0 = g_i0[tok];
        int myp = 0;
#pragma unroll
        for (int e = 0; e < NE; e++) {
            unsigned m = __ballot_sync(0xffffffff, e0 == e);
            if (e0 == e) myp = cnt[e] + __popc(m & lt);
            cnt[e] += __popc(m);
        }
        g_k0[tok] = (myp < CAP) ? 1 : 0;
        g_p0[tok] = min(myp, CAP - 1);
    }
    for (int ch = 0; ch < Sq / 32; ch++) {
        int tok = b * Sq + ch * 32 + lane;
        int e1 = g_i1[tok];
        bool valid = g_g1[tok] > 0.2f;
        int myp = 0;
#pragma unroll
        for (int e = 0; e < NE; e++) {
            unsigned m = __ballot_sync(0xffffffff, valid && (e1 == e));
            if (valid && (e1 == e)) myp = cnt[e] + __popc(m & lt);
            cnt[e] += __popc(m);
        }
        bool keep = valid && (myp < CAP);
        g_k1[tok] = keep ? 1 : 0;
        g_p1[tok] = valid ? min(myp, CAP - 1) : 0;
    }
}

// ---------------- scatter (x1 fp32 -> einh bf16) ----------------
__global__ __launch_bounds__(256) void scatter_kernel() {
    int idx = blockIdx.x;
    int tok = idx >> 1, slot = idx & 1;
    int keep = slot ? g_k1[tok] : g_k0[tok];
    if (!keep) return;
    int e = slot ? g_i1[tok] : g_i0[tok];
    int p = slot ? g_p1[tok] : g_p0[tok];
    int b = tok / Sq;
    const float4* src = (const float4*)(g_x1 + (size_t)tok * Dm);
    size_t ro = (((size_t)e * Bt + b) * CAP + p) * Dm;
    uint2* dh = (uint2*)(g_einh + ro);
    float4 v = src[threadIdx.x];
    uint2 hh;
    hh.x = packbf(v.x, v.y);
    hh.y = packbf(v.z, v.w);
    dh[threadIdx.x] = hh;
}

// ---------------- combine + LN2 (expert out in bf16) ----------------
__global__ __launch_bounds__(256) void combine_ln_kernel(
    const float* __restrict__ g2, const float* __restrict__ b2,
    float* __restrict__ out)
{
    size_t tok = blockIdx.x;
    int t = threadIdx.x;
    int b = (int)(tok >> 10);
    float w0 = g_k0[tok] ? g_g0[tok] : 0.f;
    float w1 = g_k1[tok] ? g_g1[tok] : 0.f;
    const __nv_bfloat16* r0 = g_eoutb + (((size_t)g_i0[tok] * Bt + b) * CAP + g_p0[tok]) * Dm;
    const __nv_bfloat16* r1 = g_eoutb + (((size_t)g_i1[tok] * Bt + b) * CAP + g_p1[tok]) * Dm;

    float v[4], s = 0.f, s2 = 0.f;
#pragma unroll
    for (int u = 0; u < 4; u++) {
        int j = t + u * 256;
        float val = g_x1[tok * Dm + j]
                  + w0 * __bfloat162float(r0[j]) + w1 * __bfloat162float(r1[j]);
        v[u] = val; s += val; s2 += val * val;
    }
    block_reduce2(s, s2);
    float mean = s * (1.f / Dm);
    float var  = s2 * (1.f / Dm) - mean * mean;
    float inv  = rsqrtf(var + 1e-5f);
#pragma unroll
    for (int u = 0; u < 4; u++) {
        int j = t + u * 256;
        out[tok * Dm + j] = (v[u] - mean) * inv * g2[j] + b2[j];
    }
}

// ---------------- finalize aux ----------------
__global__ void finalize_kernel(float* __restrict__ out) {
    if (threadIdx.x == 0 && blockIdx.x == 0) {
        float invN = 1.f / (float)NT;
        float sfp = 0.f;
#pragma unroll
        for (int e = 0; e < NE; e++)
            sfp += (g_fcnt[e] * invN) * (g_Psum[e] * invN);
        float bal = 0.01f * (float)NE * sfp;
        float zl  = 0.001f * g_zsum * invN;
        out[NTD + 0] = bal + zl;
        out[NTD + 1] = bal;
        out[NTD + 2] = zl;
    }
}

// ---------------- host launcher ----------------
extern "C" void kernel_launch(void* const* d_in, const int* in_sizes, int n_in,
                              void* d_out, int out_size)
{
    const float* x      = (const float*)d_in[0];
    const float* Wq     = (const float*)d_in[1];
    const float* Wk     = (const float*)d_in[2];
    const float* Wv     = (const float*)d_in[3];
    const float* Wo     = (const float*)d_in[4];
    const float* bq     = (const float*)d_in[5];
    const float* bk     = (const float*)d_in[6];
    const float* bv     = (const float*)d_in[7];
    const float* bo     = (const float*)d_in[8];
    const float* ln1_g  = (const float*)d_in[9];
    const float* ln1_b  = (const float*)d_in[10];
    const float* ln2_g  = (const float*)d_in[11];
    const float* ln2_b  = (const float*)d_in[12];
    const float* gate_W = (const float*)d_in[13];
    const float* eWq    = (const float*)d_in[14];
    const float* eWk    = (const float*)d_in[15];
    const float* eWv    = (const float*)d_in[16];
    const float* eWo    = (const float*)d_in[17];
    float* out = (float*)d_out;

    void *pattn, *px1, *peoutb, *pxh, *pqkvh, *poh;
    void *peinh, *peqkv, *peoh;
    void *pwqkvh, *pwoh, *pewh, *pewoh, *pbqkv;
    cudaGetSymbolAddress(&pattn, g_attn);   cudaGetSymbolAddress(&px1, g_x1);
    cudaGetSymbolAddress(&peoutb, g_eoutb); cudaGetSymbolAddress(&pxh, g_xh);
    cudaGetSymbolAddress(&pqkvh, g_qkvh);   cudaGetSymbolAddress(&poh, g_oh);
    cudaGetSymbolAddress(&peinh, g_einh);   cudaGetSymbolAddress(&peqkv, g_eqkv);
    cudaGetSymbolAddress(&peoh, g_eoh);
    cudaGetSymbolAddress(&pwqkvh, g_wqkvh); cudaGetSymbolAddress(&pwoh, g_woh);
    cudaGetSymbolAddress(&pewh, g_ewh);     cudaGetSymbolAddress(&pewoh, g_ewoh);
    cudaGetSymbolAddress(&pbqkv, g_bqkv);

    cudaFuncSetAttribute(gemm_mma_kernel<0>, cudaFuncAttributeMaxDynamicSharedMemorySize, GEMM_SMEM);
    cudaFuncSetAttribute(gemm_mma_kernel<1>, cudaFuncAttributeMaxDynamicSharedMemorySize, GEMM_SMEM);
    cudaFuncSetAttribute(mflash_kernel, cudaFuncAttributeMaxDynamicSharedMemorySize, MF_SMEM);
    cudaFuncSetAttribute(eflash_kernel, cudaFuncAttributeMaxDynamicSharedMemorySize, EF_SMEM);

    zero_ein_kernel<<<2048, 256>>>();

    cudaMemcpyAsync((float*)pbqkv,          bq, Dm * sizeof(float), cudaMemcpyDeviceToDevice);
    cudaMemcpyAsync((float*)pbqkv + Dm,     bk, Dm * sizeof(float), cudaMemcpyDeviceToDevice);
    cudaMemcpyAsync((float*)pbqkv + 2 * Dm, bv, Dm * sizeof(float), cudaMemcpyDeviceToDevice);

    // weight conversion: straight fp32 -> bf16, natural [K,N] layout
    __nv_bfloat16* wqkv = (__nv_bfloat16*)pwqkvh;
    __nv_bfloat16* ewh  = (__nv_bfloat16*)pewh;
    const int WB1 = (int)(DMDM / 4);          // blocks' elements per single weight
    cvt_kernel<<<WB1 / 256, 256>>>((const float4*)Wq, (uint2*)wqkv, WB1);
    cvt_kernel<<<WB1 / 256, 256>>>((const float4*)Wk, (uint2*)(wqkv + DMDM), WB1);
    cvt_kernel<<<WB1 / 256, 256>>>((const float4*)Wv, (uint2*)(wqkv + 2 * DMDM), WB1);
    cvt_kernel<<<WB1 / 256, 256>>>((const float4*)Wo, (uint2*)pwoh, WB1);
    const int WBE = (int)(NE * DMDM / 4);
    cvt_kernel<<<WBE / 256, 256>>>((const float4*)eWq, (uint2*)ewh, WBE);
    cvt_kernel<<<WBE / 256, 256>>>((const float4*)eWk, (uint2*)(ewh + NE * DMDM), WBE);
    cvt_kernel<<<WBE / 256, 256>>>((const float4*)eWv, (uint2*)(ewh + 2 * NE * DMDM), WBE);
    cvt_kernel<<<WBE / 256, 256>>>((const float4*)eWo, (uint2*)pewoh, WBE);

    cvt_kernel<<<(int)(NTD / 4 / 256), 256>>>((const float4*)x, (uint2*)pxh, (int)(NTD / 4));

    // main QKV: one batched launch, z in [0,3)
    gemm_mma_kernel<1><<<dim3(Dm / 128, NT / 128, 3), 256, GEMM_SMEM>>>(
        (__nv_bfloat16*)pxh, wqkv, (const float*)pbqkv, pqkvh,
        NT, Dm, Dm, 0, DMDM, NTD, Dm, 3);

    __nv_bfloat16* qkv = (__nv_bfloat16*)pqkvh;
    mflash_kernel<<<dim3(Sq / 64, Bt * NH), 256, MF_SMEM>>>(
        qkv, qkv + NTD, qkv + 2 * NTD, (__nv_bfloat16*)poh, 0.125f);

    // Wo
    gemm_mma_kernel<0><<<dim3(Dm / 128, NT / 128, 1), 256, GEMM_SMEM>>>(
        (__nv_bfloat16*)poh, (__nv_bfloat16*)pwoh, bo, pattn,
        NT, Dm, Dm, 0, 0, 0, 0, 1);

    ln1_kernel<<<NT, 256>>>(x, ln1_g, ln1_b);
    gate_kernel<<<NT / 8, 256>>>(gate_W);
    pos_kernel<<<1, 256>>>();
    scatter_kernel<<<NT * 2, 256>>>();

    // expert QKV: one batched launch, z = p*NE + e in [0,24)
    size_t sA = (size_t)EROWS * Dm;
    gemm_mma_kernel<1><<<dim3(Dm / 128, EROWS / 128, 24), 256, GEMM_SMEM>>>(
        (__nv_bfloat16*)peinh, ewh, nullptr, peqkv,
        EROWS, Dm, Dm, sA, DMDM, sA, 0, NE);

    __nv_bfloat16* eqkv = (__nv_bfloat16*)peqkv;
    eflash_kernel<<<dim3(CAP / 64, NE * Bt * NHM), 256, EF_SMEM>>>(
        eqkv, eqkv + EINSZ, eqkv + 2 * EINSZ, (__nv_bfloat16*)peoh, 0.0883883476483184f);

    // expert Wo: bf16 out
    gemm_mma_kernel<1><<<dim3(Dm / 128, EROWS / 128, NE), 256, GEMM_SMEM>>>(
        (__nv_bfloat16*)peoh, (__nv_bfloat16*)pewoh, nullptr, peoutb,
        EROWS, Dm, Dm, sA, DMDM, sA, 0, NE);

    combine_ln_kernel<<<NT, 256>>>(ln2_g, ln2_b, out);
    finalize_kernel<<<1, 32>>>(out);
}

// round 10
// speedup vs baseline: 7.0212x; 1.0109x over previous
#include <cuda_runtime.h>
#include <cuda_bf16.h>
#include <math.h>
#include <stdint.h>

// ---------------- problem dims ----------------
#define Bt   8
#define Sq   1024
#define Dm   1024
#define NH   16
#define HD1  64
#define NE   8
#define NHM  8
#define HDM  128
#define CAP  320
#define NT   (Bt*Sq)
#define NTD  ((size_t)NT*Dm)
#define EROWS (Bt*CAP)
#define EINSZ ((size_t)NE*Bt*CAP*Dm)
#define DMDM ((size_t)Dm*Dm)

// ---------------- scratch ----------------
static __device__ float g_attn[NTD];
static __device__ float g_x1[NTD];

static __device__ __nv_bfloat16 g_xh[NTD];
static __device__ __nv_bfloat16 g_qkvh[3*NTD];       // [q|k|v]
static __device__ __nv_bfloat16 g_oh[NTD];
static __device__ __nv_bfloat16 g_einh[EINSZ];
static __device__ __nv_bfloat16 g_eqkv[3*EINSZ];     // [q|k|v] expert
static __device__ __nv_bfloat16 g_eoh[EINSZ];
static __device__ __nv_bfloat16 g_eoutb[EINSZ];      // expert output (bf16)
static __device__ __nv_bfloat16 g_wqkvh[3*DMDM];     // [K,N] bf16 (no transpose)
static __device__ __nv_bfloat16 g_woh[DMDM];
static __device__ __nv_bfloat16 g_ewh[3*NE*DMDM];    // [q experts][k][v], [K,N]
static __device__ __nv_bfloat16 g_ewoh[NE*DMDM];
static __device__ float g_bqkv[3*Dm];

static __device__ int   g_i0[NT], g_i1[NT];
static __device__ float g_g0[NT], g_g1[NT];
static __device__ int   g_p0[NT], g_p1[NT];
static __device__ int   g_k0[NT], g_k1[NT];

static __device__ float g_Psum[NE];
static __device__ float g_fcnt[NE];
static __device__ float g_zsum;

// ---------------- PTX helpers ----------------
__device__ __forceinline__ uint32_t smem_u32(const void* p) {
    uint32_t a;
    asm("{ .reg .u64 t; cvta.to.shared.u64 t, %1; cvt.u32.u64 %0, t; }" : "=r"(a) : "l"(p));
    return a;
}
__device__ __forceinline__ void cp16(uint32_t dst, const void* src) {
    asm volatile("cp.async.cg.shared.global [%0], [%1], 16;" :: "r"(dst), "l"(src));
}
__device__ __forceinline__ void ldmA(uint32_t* a, uint32_t addr) {
    asm volatile("ldmatrix.sync.aligned.m8n8.x4.shared.b16 {%0,%1,%2,%3}, [%4];"
        : "=r"(a[0]), "=r"(a[1]), "=r"(a[2]), "=r"(a[3]) : "r"(addr));
}
__device__ __forceinline__ void ldmT(uint32_t* a, uint32_t addr) {
    asm volatile("ldmatrix.sync.aligned.m8n8.x4.trans.shared.b16 {%0,%1,%2,%3}, [%4];"
        : "=r"(a[0]), "=r"(a[1]), "=r"(a[2]), "=r"(a[3]) : "r"(addr));
}
__device__ __forceinline__ void mma_bf16(float* d, const uint32_t* a, const uint32_t* b) {
    asm volatile(
        "mma.sync.aligned.m16n8k16.row.col.f32.bf16.bf16.f32 "
        "{%0,%1,%2,%3}, {%4,%5,%6,%7}, {%8,%9}, {%0,%1,%2,%3};"
        : "+f"(d[0]), "+f"(d[1]), "+f"(d[2]), "+f"(d[3])
        : "r"(a[0]), "r"(a[1]), "r"(a[2]), "r"(a[3]), "r"(b[0]), "r"(b[1]));
}
__device__ __forceinline__ uint32_t packbf(float a, float b) {
    __nv_bfloat162 v = __float22bfloat162_rn(make_float2(a, b));
    return *(uint32_t*)&v;
}

// ---------------- GEMM via mma.sync (bf16, BK=64, B in natural [K,N]) -------
#define BK 64
#define ROWA 144
#define ROWBB 272
#define ASTG (128*ROWA)
#define BSTG (64*ROWBB)
#define STG2 (ASTG+BSTG)
#define NSTG 3
#define GEMM_SMEM (NSTG*STG2)  // 107520

template <int OUTBF>
__global__ __launch_bounds__(256, 2) void gemm_mma_kernel(
    const __nv_bfloat16* __restrict__ A, const __nv_bfloat16* __restrict__ W,
    const float* __restrict__ bias, void* __restrict__ Cv,
    int M, int N, int K, size_t sA, size_t sB, size_t sC, size_t sbias, int zmod)
{
    extern __shared__ char sm_[];
    uint32_t smb = smem_u32(sm_);

    int t = threadIdx.x, lane = t & 31, wid = t >> 5;
    int n0 = blockIdx.x * 128, m0 = blockIdx.y * 128;
    int z = blockIdx.z;
    A += (size_t)(z % zmod) * sA;
    W += (size_t)z * sB;
    if (bias) bias += (size_t)z * sbias;

    int wm = (wid & 3) * 32;
    int wn = (wid >> 2) * 64;
    const int NC = K / BK;

    float acc[2][8][4];
#pragma unroll
    for (int i = 0; i < 2; i++)
#pragma unroll
        for (int j = 0; j < 8; j++)
#pragma unroll
            for (int q = 0; q < 4; q++) acc[i][j][q] = 0.f;

    int rb = t >> 3, c8 = t & 7;
    const __nv_bfloat16* Ap = A + (size_t)(m0 + rb) * K + c8 * 8;
    uint32_t waA = (uint32_t)rb * ROWA + c8 * 16;
    const size_t rstepA = (size_t)32 * K;
    int rB = t >> 4, cB = t & 15;
    const __nv_bfloat16* Wp = W + (size_t)rB * N + n0 + cB * 8;
    uint32_t waB = (uint32_t)rB * ROWBB + cB * 16;
    const size_t rstepB = (size_t)16 * N;

#pragma unroll
    for (int s = 0; s < 2; s++) {
        uint32_t stg = smb + s * STG2;
        int kc = s * BK;
#pragma unroll
        for (int j = 0; j < 4; j++) {
            cp16(stg + waA + j * (32 * ROWA), Ap + kc + j * rstepA);
            cp16(stg + ASTG + waB + j * (16 * ROWBB), Wp + (size_t)kc * N + j * rstepB);
        }
        asm volatile("cp.async.commit_group;");
    }

    uint32_t a_row = (uint32_t)(wm + (lane & 15)) * ROWA + (lane >> 4) * 16;
    uint32_t b_col = (uint32_t)(lane & 15) * ROWBB + wn * 2 + (lane >> 4) * 16;

    int sidx = 0;
    for (int c = 0; c < NC; c++) {
        asm volatile("cp.async.wait_group 1;");
        __syncthreads();
        if (c + 2 < NC) {
            int sn = sidx + 2; if (sn >= NSTG) sn -= NSTG;
            uint32_t stg = smb + sn * STG2;
            int kc = (c + 2) * BK;
#pragma unroll
            for (int j = 0; j < 4; j++) {
                cp16(stg + waA + j * (32 * ROWA), Ap + kc + j * rstepA);
                cp16(stg + ASTG + waB + j * (16 * ROWBB), Wp + (size_t)kc * N + j * rstepB);
            }
        }
        asm volatile("cp.async.commit_group;");

        uint32_t ab = smb + sidx * STG2;
        uint32_t bb = ab + ASTG;

#pragma unroll
        for (int ks = 0; ks < 4; ks++) {
            uint32_t afr[2][4];
#pragma unroll
            for (int mt = 0; mt < 2; mt++)
                ldmA(afr[mt], ab + a_row + mt * (16 * ROWA) + ks * 32);

            uint32_t bfr[8][2];
#pragma unroll
            for (int nb = 0; nb < 4; nb++) {
                uint32_t q[4];
                ldmT(q, bb + b_col + ks * (16 * ROWBB) + nb * 32);
                bfr[nb * 2][0]     = q[0]; bfr[nb * 2][1]     = q[1];
                bfr[nb * 2 + 1][0] = q[2]; bfr[nb * 2 + 1][1] = q[3];
            }
#pragma unroll
            for (int mt = 0; mt < 2; mt++)
#pragma unroll
                for (int nt = 0; nt < 8; nt++)
                    mma_bf16(acc[mt][nt], afr[mt], bfr[nt]);
        }
        if (++sidx == NSTG) sidx = 0;
    }

#pragma unroll
    for (int mt = 0; mt < 2; mt++) {
        int m = m0 + wm + mt * 16 + (lane >> 2);
#pragma unroll
        for (int nt = 0; nt < 8; nt++) {
            int n = n0 + wn + nt * 8 + (lane & 3) * 2;
            float bv0 = bias ? bias[n] : 0.f;
            float bv1 = bias ? bias[n + 1] : 0.f;
            float v0 = acc[mt][nt][0] + bv0, v1 = acc[mt][nt][1] + bv1;
            float v2 = acc[mt][nt][2] + bv0, v3 = acc[mt][nt][3] + bv1;
            if (OUTBF == 0) {
                float* C = (float*)Cv + (size_t)z * sC;
                *(float2*)&C[(size_t)m * N + n]       = make_float2(v0, v1);
                *(float2*)&C[(size_t)(m + 8) * N + n] = make_float2(v2, v3);
            } else {
                __nv_bfloat16* C = (__nv_bfloat16*)Cv + (size_t)z * sC;
                *(uint32_t*)&C[(size_t)m * N + n]       = packbf(v0, v1);
                *(uint32_t*)&C[(size_t)(m + 8) * N + n] = packbf(v2, v3);
            }
        }
    }
}

// ---------------- expert flash (bf16 mma, HD=128) ----------------
#define EF_PITCH 272
#define EF_QS 0
#define EF_KS 17408
#define EF_VS 34816
#define EF_OB 52224
#define EF_MS 86016
#define EF_LS 86272
#define EF_AS 86528
#define EF_RM 86784
#define EF_RS 87296
#define EF_SMEM 87808

__global__ __launch_bounds__(256) void eflash_kernel(
    const __nv_bfloat16* __restrict__ Q, const __nv_bfloat16* __restrict__ K,
    const __nv_bfloat16* __restrict__ V, __nv_bfloat16* __restrict__ O,
    float scale)
{
    extern __shared__ char sm_[];
    float* Obuf = (float*)(sm_ + EF_OB);
    float* m_s  = (float*)(sm_ + EF_MS);
    float* l_s  = (float*)(sm_ + EF_LS);
    float* a_s  = (float*)(sm_ + EF_AS);
    float* redm = (float*)(sm_ + EF_RM);
    float* reds = (float*)(sm_ + EF_RS);
    uint32_t smb = smem_u32(sm_);

    int t = threadIdx.x, lane = t & 31, wid = t >> 5;
    int half = wid >> 2, wm = (wid & 3) * 16, wn2 = half * 32;
    int slice = blockIdx.y;
    int sb = slice >> 3, h = slice & 7;
    size_t base = (size_t)sb * CAP * 1024 + (size_t)h * HDM;
    int q0 = blockIdx.x * 64;

#pragma unroll
    for (int j = 0; j < 4; j++) {
        int id = t + 256 * j;
        int r = id >> 4, c = id & 15;
        *(uint4*)(sm_ + EF_QS + r * EF_PITCH + c * 16) =
            *(const uint4*)(Q + base + (size_t)(q0 + r) * 1024 + c * 8);
    }
    if (t < 64) { m_s[t] = -1e30f; l_s[t] = 0.f; }

    float o[16][4];
#pragma unroll
    for (int i = 0; i < 16; i++)
#pragma unroll
        for (int q = 0; q < 4; q++) o[i][q] = 0.f;

    int rl = wm + (lane >> 2), rh = rl + 8;
    int nq = lane >> 2, kr = lane & 3;

    for (int kt = 0; kt < CAP / 64; kt++) {
        __syncthreads();
#pragma unroll
        for (int j = 0; j < 4; j++) {
            int id = t + 256 * j;
            int r = id >> 4, c = id & 15;
            *(uint4*)(sm_ + EF_KS + r * EF_PITCH + c * 16) =
                *(const uint4*)(K + base + (size_t)(kt * 64 + r) * 1024 + c * 8);
            *(uint4*)(sm_ + EF_VS + r * EF_PITCH + c * 16) =
                *(const uint4*)(V + base + (size_t)(kt * 64 + r) * 1024 + c * 8);
        }
        __syncthreads();

        float s[4][4];
#pragma unroll
        for (int nt = 0; nt < 4; nt++)
#pragma unroll
            for (int q = 0; q < 4; q++) s[nt][q] = 0.f;
#pragma unroll
        for (int ks = 0; ks < 8; ks++) {
            uint32_t af[4];
            ldmA(af, smb + EF_QS + (wm + (lane & 15)) * EF_PITCH + ks * 32 + (lane >> 4) * 16);
#pragma unroll
            for (int nt = 0; nt < 4; nt++) {
                const char* p = sm_ + EF_KS + (wn2 + nt * 8 + nq) * EF_PITCH + ks * 32 + kr * 4;
                uint32_t bb[2];
                bb[0] = *(const uint32_t*)p;
                bb[1] = *(const uint32_t*)(p + 16);
                mma_bf16(s[nt], af, bb);
            }
        }

        float mxlo = -1e30f, mxhi = -1e30f;
#pragma unroll
        for (int nt = 0; nt < 4; nt++) {
            s[nt][0] *= scale; s[nt][1] *= scale; s[nt][2] *= scale; s[nt][3] *= scale;
            mxlo = fmaxf(mxlo, fmaxf(s[nt][0], s[nt][1]));
            mxhi = fmaxf(mxhi, fmaxf(s[nt][2], s[nt][3]));
        }
        mxlo = fmaxf(mxlo, __shfl_xor_sync(0xffffffff, mxlo, 1));
        mxlo = fmaxf(mxlo, __shfl_xor_sync(0xffffffff, mxlo, 2));
        mxhi = fmaxf(mxhi, __shfl_xor_sync(0xffffffff, mxhi, 1));
        mxhi = fmaxf(mxhi, __shfl_xor_sync(0xffffffff, mxhi, 2));
        if ((lane & 3) == 0) { redm[half * 64 + rl] = mxlo; redm[half * 64 + rh] = mxhi; }
        __syncthreads();
        if (t < 64) {
            float mo = m_s[t];
            float mn = fmaxf(mo, fmaxf(redm[t], redm[64 + t]));
            float al = __expf(mo - mn);
            a_s[t] = al; m_s[t] = mn; l_s[t] *= al;
        }
        __syncthreads();

        float mlo = m_s[rl], mhi = m_s[rh], alo = a_s[rl], ahi = a_s[rh];
        float slo = 0.f, shi = 0.f;
        uint32_t afr[2][4];
#pragma unroll
        for (int ks = 0; ks < 2; ks++) {
#pragma unroll
            for (int jj = 0; jj < 2; jj++) {
                int nt = ks * 2 + jj;
                float p0 = __expf(s[nt][0] - mlo), p1 = __expf(s[nt][1] - mlo);
                float p2 = __expf(s[nt][2] - mhi), p3 = __expf(s[nt][3] - mhi);
                slo += p0 + p1; shi += p2 + p3;
                afr[ks][jj * 2 + 0] = packbf(p0, p1);
                afr[ks][jj * 2 + 1] = packbf(p2, p3);
            }
        }
        slo += __shfl_xor_sync(0xffffffff, slo, 1);
        slo += __shfl_xor_sync(0xffffffff, slo, 2);
        shi += __shfl_xor_sync(0xffffffff, shi, 1);
        shi += __shfl_xor_sync(0xffffffff, shi, 2);
        if ((lane & 3) == 0) { reds[half * 64 + rl] = slo; reds[half * 64 + rh] = shi; }

#pragma unroll
        for (int nt = 0; nt < 16; nt++) {
            o[nt][0] *= alo; o[nt][1] *= alo; o[nt][2] *= ahi; o[nt][3] *= ahi;
        }

#pragma unroll
        for (int ks = 0; ks < 2; ks++) {
#pragma unroll
            for (int nb = 0; nb < 8; nb++) {
                uint32_t b4[4];
                ldmT(b4, smb + EF_VS + (wn2 + ks * 16 + (lane & 15)) * EF_PITCH
                         + nb * 32 + (lane >> 4) * 16);
                mma_bf16(o[2 * nb],     afr[ks], b4);
                mma_bf16(o[2 * nb + 1], afr[ks], b4 + 2);
            }
        }
        __syncthreads();
        if (t < 64) l_s[t] += reds[t] + reds[64 + t];
    }

    __syncthreads();
    if (half == 0) {
#pragma unroll
        for (int nt = 0; nt < 16; nt++) {
            float* plo = Obuf + rl * 132 + nt * 8 + (lane & 3) * 2;
            float* phi = Obuf + rh * 132 + nt * 8 + (lane & 3) * 2;
            plo[0] = o[nt][0]; plo[1] = o[nt][1];
            phi[0] = o[nt][2]; phi[1] = o[nt][3];
        }
    }
    __syncthreads();
    if (half == 1) {
#pragma unroll
        for (int nt = 0; nt < 16; nt++) {
            float* plo = Obuf + rl * 132 + nt * 8 + (lane & 3) * 2;
            float* phi = Obuf + rh * 132 + nt * 8 + (lane & 3) * 2;
            plo[0] += o[nt][0]; plo[1] += o[nt][1];
            phi[0] += o[nt][2]; phi[1] += o[nt][3];
        }
    }
    __syncthreads();
#pragma unroll
    for (int j = 0; j < 16; j++) {
        int id = t + 256 * j;
        int r = id >> 6, cp = id & 63;
        float inv = 1.f / l_s[r];
        float2 v = *(float2*)(Obuf + r * 132 + cp * 2);
        __nv_bfloat162 ob = __float22bfloat162_rn(make_float2(v.x * inv, v.y * inv));
        *(__nv_bfloat162*)(O + base + (size_t)(q0 + r) * 1024 + cp * 2) = ob;
    }
}

// ---------------- main flash (bf16 mma, HD=64) ----------------
#define MF_PITCH 144
#define MF_QS 0
#define MF_KS 9216
#define MF_VS 18432
#define MF_OB 27648
#define MF_MS 45056
#define MF_LS 45312
#define MF_AS 45568
#define MF_RM 45824
#define MF_RS 46336
#define MF_SMEM 46848

__global__ __launch_bounds__(256) void mflash_kernel(
    const __nv_bfloat16* __restrict__ Q, const __nv_bfloat16* __restrict__ K,
    const __nv_bfloat16* __restrict__ V, __nv_bfloat16* __restrict__ O,
    float scale)
{
    extern __shared__ char sm_[];
    float* Obuf = (float*)(sm_ + MF_OB);
    float* m_s  = (float*)(sm_ + MF_MS);
    float* l_s  = (float*)(sm_ + MF_LS);
    float* a_s  = (float*)(sm_ + MF_AS);
    float* redm = (float*)(sm_ + MF_RM);
    float* reds = (float*)(sm_ + MF_RS);
    uint32_t smb = smem_u32(sm_);

    int t = threadIdx.x, lane = t & 31, wid = t >> 5;
    int half = wid >> 2, wm = (wid & 3) * 16, wn2 = half * 32;
    int slice = blockIdx.y;
    int sb = slice >> 4, h = slice & 15;
    size_t base = (size_t)sb * Sq * 1024 + (size_t)h * HD1;
    int q0 = blockIdx.x * 64;

#pragma unroll
    for (int j = 0; j < 2; j++) {
        int id = t + 256 * j;
        int r = id >> 3, c = id & 7;
        *(uint4*)(sm_ + MF_QS + r * MF_PITCH + c * 16) =
            *(const uint4*)(Q + base + (size_t)(q0 + r) * 1024 + c * 8);
    }
    if (t < 64) { m_s[t] = -1e30f; l_s[t] = 0.f; }

    float o[8][4];
#pragma unroll
    for (int i = 0; i < 8; i++)
#pragma unroll
        for (int q = 0; q < 4; q++) o[i][q] = 0.f;

    int rl = wm + (lane >> 2), rh = rl + 8;
    int nq = lane >> 2, kr = lane & 3;

    for (int kt = 0; kt < Sq / 64; kt++) {
        __syncthreads();
#pragma unroll
        for (int j = 0; j < 2; j++) {
            int id = t + 256 * j;
            int r = id >> 3, c = id & 7;
            size_t g = base + (size_t)(kt * 64 + r) * 1024 + c * 8;
            *(uint4*)(sm_ + MF_KS + r * MF_PITCH + c * 16) = *(const uint4*)(K + g);
            *(uint4*)(sm_ + MF_VS + r * MF_PITCH + c * 16) = *(const uint4*)(V + g);
        }
        __syncthreads();

        float s[4][4];
#pragma unroll
        for (int nt = 0; nt < 4; nt++)
#pragma unroll
            for (int q = 0; q < 4; q++) s[nt][q] = 0.f;
#pragma unroll
        for (int ks = 0; ks < 4; ks++) {
            uint32_t af[4];
            ldmA(af, smb + MF_QS + (wm + (lane & 15)) * MF_PITCH + ks * 32 + (lane >> 4) * 16);
#pragma unroll
            for (int nt = 0; nt < 4; nt++) {
                const char* p = sm_ + MF_KS + (wn2 + nt * 8 + nq) * MF_PITCH + ks * 32 + kr * 4;
                uint32_t bb[2];
                bb[0] = *(const uint32_t*)p;
                bb[1] = *(const uint32_t*)(p + 16);
                mma_bf16(s[nt], af, bb);
            }
        }

        float mxlo = -1e30f, mxhi = -1e30f;
#pragma unroll
        for (int nt = 0; nt < 4; nt++) {
            s[nt][0] *= scale; s[nt][1] *= scale; s[nt][2] *= scale; s[nt][3] *= scale;
            mxlo = fmaxf(mxlo, fmaxf(s[nt][0], s[nt][1]));
            mxhi = fmaxf(mxhi, fmaxf(s[nt][2], s[nt][3]));
        }
        mxlo = fmaxf(mxlo, __shfl_xor_sync(0xffffffff, mxlo, 1));
        mxlo = fmaxf(mxlo, __shfl_xor_sync(0xffffffff, mxlo, 2));
        mxhi = fmaxf(mxhi, __shfl_xor_sync(0xffffffff, mxhi, 1));
        mxhi = fmaxf(mxhi, __shfl_xor_sync(0xffffffff, mxhi, 2));
        if ((lane & 3) == 0) { redm[half * 64 + rl] = mxlo; redm[half * 64 + rh] = mxhi; }
        __syncthreads();
        if (t < 64) {
            float mo = m_s[t];
            float mn = fmaxf(mo, fmaxf(redm[t], redm[64 + t]));
            float al = __expf(mo - mn);
            a_s[t] = al; m_s[t] = mn; l_s[t] *= al;
        }
        __syncthreads();

        float mlo = m_s[rl], mhi = m_s[rh], alo = a_s[rl], ahi = a_s[rh];
        float slo = 0.f, shi = 0.f;
        uint32_t afr[2][4];
#pragma unroll
        for (int ks = 0; ks < 2; ks++) {
#pragma unroll
            for (int jj = 0; jj < 2; jj++) {
                int nt = ks * 2 + jj;
                float p0 = __expf(s[nt][0] - mlo), p1 = __expf(s[nt][1] - mlo);
                float p2 = __expf(s[nt][2] - mhi), p3 = __expf(s[nt][3] - mhi);
                slo += p0 + p1; shi += p2 + p3;
                afr[ks][jj * 2 + 0] = packbf(p0, p1);
                afr[ks][jj * 2 + 1] = packbf(p2, p3);
            }
        }
        slo += __shfl_xor_sync(0xffffffff, slo, 1);
        slo += __shfl_xor_sync(0xffffffff, slo, 2);
        shi += __shfl_xor_sync(0xffffffff, shi, 1);
        shi += __shfl_xor_sync(0xffffffff, shi, 2);
        if ((lane & 3) == 0) { reds[half * 64 + rl] = slo; reds[half * 64 + rh] = shi; }

#pragma unroll
        for (int nt = 0; nt < 8; nt++) {
            o[nt][0] *= alo; o[nt][1] *= alo; o[nt][2] *= ahi; o[nt][3] *= ahi;
        }

#pragma unroll
        for (int ks = 0; ks < 2; ks++) {
#pragma unroll
            for (int nb = 0; nb < 4; nb++) {
                uint32_t b4[4];
                ldmT(b4, smb + MF_VS + (wn2 + ks * 16 + (lane & 15)) * MF_PITCH
                         + nb * 32 + (lane >> 4) * 16);
                mma_bf16(o[2 * nb],     afr[ks], b4);
                mma_bf16(o[2 * nb + 1], afr[ks], b4 + 2);
            }
        }
        __syncthreads();
        if (t < 64) l_s[t] += reds[t] + reds[64 + t];
    }

    __syncthreads();
    if (half == 0) {
#pragma unroll
        for (int nt = 0; nt < 8; nt++) {
            float* plo = Obuf + rl * 68 + nt * 8 + (lane & 3) * 2;
            float* phi = Obuf + rh * 68 + nt * 8 + (lane & 3) * 2;
            plo[0] = o[nt][0]; plo[1] = o[nt][1];
            phi[0] = o[nt][2]; phi[1] = o[nt][3];
        }
    }
    __syncthreads();
    if (half == 1) {
#pragma unroll
        for (int nt = 0; nt < 8; nt++) {
            float* plo = Obuf + rl * 68 + nt * 8 + (lane & 3) * 2;
            float* phi = Obuf + rh * 68 + nt * 8 + (lane & 3) * 2;
            plo[0] += o[nt][0]; plo[1] += o[nt][1];
            phi[0] += o[nt][2]; phi[1] += o[nt][3];
        }
    }
    __syncthreads();
#pragma unroll
    for (int j = 0; j < 8; j++) {
        int id = t + 256 * j;
        int r = id >> 5, cp = id & 31;
        float inv = 1.f / l_s[r];
        float2 v = *(float2*)(Obuf + r * 68 + cp * 2);
        __nv_bfloat162 ob = __float22bfloat162_rn(make_float2(v.x * inv, v.y * inv));
        *(__nv_bfloat162*)(O + base + (size_t)(q0 + r) * 1024 + cp * 2) = ob;
    }
}

// ---------------- fp32 -> bf16 convert (ILP-4 streaming, single tensor) -----
__global__ __launch_bounds__(256) void cvt_kernel(
    const float4* __restrict__ s, uint2* __restrict__ h, int n4)
{
    int i = blockIdx.x * 1024 + threadIdx.x;
#pragma unroll
    for (int j = 0; j < 4; j++, i += 256) {
        if (i < n4) {
            float4 v = s[i];
            uint2 hh;
            hh.x = packbf(v.x, v.y);
            hh.y = packbf(v.z, v.w);
            h[i] = hh;
        }
    }
}

// ---------------- batched fp32 -> bf16 convert (4 tensors, ILP-4) -----------
__global__ __launch_bounds__(256) void cvt4_kernel(
    const float4* __restrict__ s0, const float4* __restrict__ s1,
    const float4* __restrict__ s2, const float4* __restrict__ s3,
    uint2* __restrict__ d0, uint2* __restrict__ d1,
    uint2* __restrict__ d2, uint2* __restrict__ d3, int n4)
{
    const float4* s; uint2* d;
    switch (blockIdx.y) {
        case 0:  s = s0; d = d0; break;
        case 1:  s = s1; d = d1; break;
        case 2:  s = s2; d = d2; break;
        default: s = s3; d = d3; break;
    }
    int i = blockIdx.x * 1024 + threadIdx.x;
#pragma unroll
    for (int j = 0; j < 4; j++, i += 256) {
        if (i < n4) {
            float4 v = s[i];
            uint2 hh;
            hh.x = packbf(v.x, v.y);
            hh.y = packbf(v.z, v.w);
            d[i] = hh;
        }
    }
}

// ---------------- zero (ein + stats merged) ----------------
__global__ void zero_ein_kernel() {
    if (blockIdx.x == 0 && threadIdx.x < 32) {
        int t = threadIdx.x;
        if (t < NE) { g_Psum[t] = 0.f; g_fcnt[t] = 0.f; }
        if (t == 0) g_zsum = 0.f;
    }
    size_t n = EINSZ / 8;
    uint4 z = make_uint4(0, 0, 0, 0);
    uint4* ph = (uint4*)g_einh;
    for (size_t i = blockIdx.x * (size_t)blockDim.x + threadIdx.x; i < n;
         i += (size_t)gridDim.x * blockDim.x) ph[i] = z;
}

// ---------------- block reduce ----------------
__device__ __forceinline__ void block_reduce2(float& s, float& s2) {
    __shared__ float rs[8], rs2[8];
#pragma unroll
    for (int o = 16; o > 0; o >>= 1) {
        s  += __shfl_xor_sync(0xffffffff, s, o);
        s2 += __shfl_xor_sync(0xffffffff, s2, o);
    }
    int lane = threadIdx.x & 31, w = threadIdx.x >> 5;
    if (lane == 0) { rs[w] = s; rs2[w] = s2; }
    __syncthreads();
    float ts = 0.f, ts2 = 0.f;
#pragma unroll
    for (int i = 0; i < 8; i++) { ts += rs[i]; ts2 += rs2[i]; }
    s = ts; s2 = ts2;
}

// ---------------- LN1 ----------------
__global__ __launch_bounds__(256) void ln1_kernel(
    const float* __restrict__ x, const float* __restrict__ g,
    const float* __restrict__ b)
{
    size_t tok = blockIdx.x;
    int t = threadIdx.x;
    float v[4], s = 0.f, s2 = 0.f;
#pragma unroll
    for (int u = 0; u < 4; u++) {
        int j = t + u * 256;
        float val = x[tok * Dm + j] + g_attn[tok * Dm + j];
        v[u] = val; s += val; s2 += val * val;
    }
    block_reduce2(s, s2);
    float mean = s * (1.f / Dm);
    float var  = s2 * (1.f / Dm) - mean * mean;
    float inv  = rsqrtf(var + 1e-5f);
#pragma unroll
    for (int u = 0; u < 4; u++) {
        int j = t + u * 256;
        g_x1[tok * Dm + j] = (v[u] - mean) * inv * g[j] + b[j];
    }
}

// ---------------- gate ----------------
__global__ __launch_bounds__(256) void gate_kernel(const float* __restrict__ gateW) {
    int warp = threadIdx.x >> 5, lane = threadIdx.x & 31;
    int tok = blockIdx.x * 8 + warp;
    const float* xr = g_x1 + (size_t)tok * Dm;
    float acc[NE];
#pragma unroll
    for (int e = 0; e < NE; e++) acc[e] = 0.f;
    for (int k = lane; k < Dm; k += 32) {
        float xv = xr[k];
        const float* wr = gateW + (size_t)k * NE;
#pragma unroll
        for (int e = 0; e < NE; e++) acc[e] += xv * wr[e];
    }
#pragma unroll
    for (int e = 0; e < NE; e++)
#pragma unroll
        for (int o = 16; o > 0; o >>= 1)
            acc[e] += __shfl_xor_sync(0xffffffff, acc[e], o);
    if (lane == 0) {
        float mx = acc[0];
#pragma unroll
        for (int e = 1; e < NE; e++) mx = fmaxf(mx, acc[e]);
        float p[NE], se = 0.f;
#pragma unroll
        for (int e = 0; e < NE; e++) { p[e] = __expf(acc[e] - mx); se += p[e]; }
        float invs = 1.f / se;
        float lse = mx + logf(se);
        atomicAdd(&g_zsum, lse * lse);
        int i0 = 0, i1 = -1;
        float b0 = -1.f, b1 = -1.f;
#pragma unroll
        for (int e = 0; e < NE; e++) {
            float pe = p[e] * invs;
            atomicAdd(&g_Psum[e], pe);
            if (pe > b0) { b1 = b0; i1 = i0; b0 = pe; i0 = e; }
            else if (pe > b1) { b1 = pe; i1 = e; }
        }
        atomicAdd(&g_fcnt[i0], 1.f);
        g_i0[tok] = i0; g_i1[tok] = i1;
        g_g0[tok] = b0; g_g1[tok] = b1;
    }
}

// ---------------- routing positions ----------------
__global__ __launch_bounds__(256) void pos_kernel() {
    int warp = threadIdx.x >> 5, lane = threadIdx.x & 31;
    if (warp >= Bt) return;
    int b = warp;
    unsigned lt = (1u << lane) - 1u;
    int cnt[NE];
#pragma unroll
    for (int e = 0; e < NE; e++) cnt[e] = 0;

    for (int ch = 0; ch < Sq / 32; ch++) {
        int tok = b * Sq + ch * 32 + lane;
        int e0 = g_i0[tok];
        int myp = 0;
#pragma unroll
        for (int e = 0; e < NE; e++) {
            unsigned m = __ballot_sync(0xffffffff, e0 == e);
            if (e0 == e) myp = cnt[e] + __popc(m & lt);
            cnt[e] += __popc(m);
        }
        g_k0[tok] = (myp < CAP) ? 1 : 0;
        g_p0[tok] = min(myp, CAP - 1);
    }
    for (int ch = 0; ch < Sq / 32; ch++) {
        int tok = b * Sq + ch * 32 + lane;
        int e1 = g_i1[tok];
        bool valid = g_g1[tok] > 0.2f;
        int myp = 0;
#pragma unroll
        for (int e = 0; e < NE; e++) {
            unsigned m = __ballot_sync(0xffffffff, valid && (e1 == e));
            if (valid && (e1 == e)) myp = cnt[e] + __popc(m & lt);
            cnt[e] += __popc(m);
        }
        bool keep = valid && (myp < CAP);
        g_k1[tok] = keep ? 1 : 0;
        g_p1[tok] = valid ? min(myp, CAP - 1) : 0;
    }
}

// ---------------- scatter (x1 fp32 -> einh bf16) ----------------
__global__ __launch_bounds__(256) void scatter_kernel() {
    int idx = blockIdx.x;
    int tok = idx >> 1, slot = idx & 1;
    int keep = slot ? g_k1[tok] : g_k0[tok];
    if (!keep) return;
    int e = slot ? g_i1[tok] : g_i0[tok];
    int p = slot ? g_p1[tok] : g_p0[tok];
    int b = tok / Sq;
    const float4* src = (const float4*)(g_x1 + (size_t)tok * Dm);
    size_t ro = (((size_t)e * Bt + b) * CAP + p) * Dm;
    uint2* dh = (uint2*)(g_einh + ro);
    float4 v = src[threadIdx.x];
    uint2 hh;
    hh.x = packbf(v.x, v.y);
    hh.y = packbf(v.z, v.w);
    dh[threadIdx.x] = hh;
}

// ---------------- combine + LN2 (expert out in bf16) ----------------
__global__ __launch_bounds__(256) void combine_ln_kernel(
    const float* __restrict__ g2, const float* __restrict__ b2,
    float* __restrict__ out)
{
    size_t tok = blockIdx.x;
    int t = threadIdx.x;
    int b = (int)(tok >> 10);
    float w0 = g_k0[tok] ? g_g0[tok] : 0.f;
    float w1 = g_k1[tok] ? g_g1[tok] : 0.f;
    const __nv_bfloat16* r0 = g_eoutb + (((size_t)g_i0[tok] * Bt + b) * CAP + g_p0[tok]) * Dm;
    const __nv_bfloat16* r1 = g_eoutb + (((size_t)g_i1[tok] * Bt + b) * CAP + g_p1[tok]) * Dm;

    float v[4], s = 0.f, s2 = 0.f;
#pragma unroll
    for (int u = 0; u < 4; u++) {
        int j = t + u * 256;
        float val = g_x1[tok * Dm + j]
                  + w0 * __bfloat162float(r0[j]) + w1 * __bfloat162float(r1[j]);
        v[u] = val; s += val; s2 += val * val;
    }
    block_reduce2(s, s2);
    float mean = s * (1.f / Dm);
    float var  = s2 * (1.f / Dm) - mean * mean;
    float inv  = rsqrtf(var + 1e-5f);
#pragma unroll
    for (int u = 0; u < 4; u++) {
        int j = t + u * 256;
        out[tok * Dm + j] = (v[u] - mean) * inv * g2[j] + b2[j];
    }
}

// ---------------- finalize aux ----------------
__global__ void finalize_kernel(float* __restrict__ out) {
    if (threadIdx.x == 0 && blockIdx.x == 0) {
        float invN = 1.f / (float)NT;
        float sfp = 0.f;
#pragma unroll
        for (int e = 0; e < NE; e++)
            sfp += (g_fcnt[e] * invN) * (g_Psum[e] * invN);
        float bal = 0.01f * (float)NE * sfp;
        float zl  = 0.001f * g_zsum * invN;
        out[NTD + 0] = bal + zl;
        out[NTD + 1] = bal;
        out[NTD + 2] = zl;
    }
}

// ---------------- host launcher ----------------
extern "C" void kernel_launch(void* const* d_in, const int* in_sizes, int n_in,
                              void* d_out, int out_size)
{
    const float* x      = (const float*)d_in[0];
    const float* Wq     = (const float*)d_in[1];
    const float* Wk     = (const float*)d_in[2];
    const float* Wv     = (const float*)d_in[3];
    const float* Wo     = (const float*)d_in[4];
    const float* bq     = (const float*)d_in[5];
    const float* bk     = (const float*)d_in[6];
    const float* bv     = (const float*)d_in[7];
    const float* bo     = (const float*)d_in[8];
    const float* ln1_g  = (const float*)d_in[9];
    const float* ln1_b  = (const float*)d_in[10];
    const float* ln2_g  = (const float*)d_in[11];
    const float* ln2_b  = (const float*)d_in[12];
    const float* gate_W = (const float*)d_in[13];
    const float* eWq    = (const float*)d_in[14];
    const float* eWk    = (const float*)d_in[15];
    const float* eWv    = (const float*)d_in[16];
    const float* eWo    = (const float*)d_in[17];
    float* out = (float*)d_out;

    void *pattn, *px1, *peoutb, *pxh, *pqkvh, *poh;
    void *peinh, *peqkv, *peoh;
    void *pwqkvh, *pwoh, *pewh, *pewoh, *pbqkv;
    cudaGetSymbolAddress(&pattn, g_attn);   cudaGetSymbolAddress(&px1, g_x1);
    cudaGetSymbolAddress(&peoutb, g_eoutb); cudaGetSymbolAddress(&pxh, g_xh);
    cudaGetSymbolAddress(&pqkvh, g_qkvh);   cudaGetSymbolAddress(&poh, g_oh);
    cudaGetSymbolAddress(&peinh, g_einh);   cudaGetSymbolAddress(&peqkv, g_eqkv);
    cudaGetSymbolAddress(&peoh, g_eoh);
    cudaGetSymbolAddress(&pwqkvh, g_wqkvh); cudaGetSymbolAddress(&pwoh, g_woh);
    cudaGetSymbolAddress(&pewh, g_ewh);     cudaGetSymbolAddress(&pewoh, g_ewoh);
    cudaGetSymbolAddress(&pbqkv, g_bqkv);

    cudaFuncSetAttribute(gemm_mma_kernel<0>, cudaFuncAttributeMaxDynamicSharedMemorySize, GEMM_SMEM);
    cudaFuncSetAttribute(gemm_mma_kernel<1>, cudaFuncAttributeMaxDynamicSharedMemorySize, GEMM_SMEM);
    cudaFuncSetAttribute(mflash_kernel, cudaFuncAttributeMaxDynamicSharedMemorySize, MF_SMEM);
    cudaFuncSetAttribute(eflash_kernel, cudaFuncAttributeMaxDynamicSharedMemorySize, EF_SMEM);

    zero_ein_kernel<<<2048, 256>>>();

    cudaMemcpyAsync((float*)pbqkv,          bq, Dm * sizeof(float), cudaMemcpyDeviceToDevice);
    cudaMemcpyAsync((float*)pbqkv + Dm,     bk, Dm * sizeof(float), cudaMemcpyDeviceToDevice);
    cudaMemcpyAsync((float*)pbqkv + 2 * Dm, bv, Dm * sizeof(float), cudaMemcpyDeviceToDevice);

    // weight conversion (batched, ILP-4): 4 main weights in one launch,
    // 4 expert weight groups in one launch
    __nv_bfloat16* wqkv = (__nv_bfloat16*)pwqkvh;
    __nv_bfloat16* ewh  = (__nv_bfloat16*)pewh;
    const int WB1 = (int)(DMDM / 4);            // 262144 float4 per main weight
    cvt4_kernel<<<dim3((WB1 + 1023) / 1024, 4), 256>>>(
        (const float4*)Wq, (const float4*)Wk, (const float4*)Wv, (const float4*)Wo,
        (uint2*)wqkv, (uint2*)(wqkv + DMDM), (uint2*)(wqkv + 2 * DMDM), (uint2*)pwoh, WB1);
    const int WBE = (int)(NE * DMDM / 4);       // 2097152 float4 per expert group
    cvt4_kernel<<<dim3((WBE + 1023) / 1024, 4), 256>>>(
        (const float4*)eWq, (const float4*)eWk, (const float4*)eWv, (const float4*)eWo,
        (uint2*)ewh, (uint2*)(ewh + NE * DMDM), (uint2*)(ewh + 2 * NE * DMDM), (uint2*)pewoh, WBE);

    cvt_kernel<<<(int)(NTD / 4 / 1024), 256>>>((const float4*)x, (uint2*)pxh, (int)(NTD / 4));

    // main QKV: one batched launch, z in [0,3)
    gemm_mma_kernel<1><<<dim3(Dm / 128, NT / 128, 3), 256, GEMM_SMEM>>>(
        (__nv_bfloat16*)pxh, wqkv, (const float*)pbqkv, pqkvh,
        NT, Dm, Dm, 0, DMDM, NTD, Dm, 3);

    __nv_bfloat16* qkv = (__nv_bfloat16*)pqkvh;
    mflash_kernel<<<dim3(Sq / 64, Bt * NH), 256, MF_SMEM>>>(
        qkv, qkv + NTD, qkv + 2 * NTD, (__nv_bfloat16*)poh, 0.125f);

    // Wo
    gemm_mma_kernel<0><<<dim3(Dm / 128, NT / 128, 1), 256, GEMM_SMEM>>>(
        (__nv_bfloat16*)poh, (__nv_bfloat16*)pwoh, bo, pattn,
        NT, Dm, Dm, 0, 0, 0, 0, 1);

    ln1_kernel<<<NT, 256>>>(x, ln1_g, ln1_b);
    gate_kernel<<<NT / 8, 256>>>(gate_W);
    pos_kernel<<<1, 256>>>();
    scatter_kernel<<<NT * 2, 256>>>();

    // expert QKV: one batched launch, z = p*NE + e in [0,24)
    size_t sA = (size_t)EROWS * Dm;
    gemm_mma_kernel<1><<<dim3(Dm / 128, EROWS / 128, 24), 256, GEMM_SMEM>>>(
        (__nv_bfloat16*)peinh, ewh, nullptr, peqkv,
        EROWS, Dm, Dm, sA, DMDM, sA, 0, NE);

    __nv_bfloat16* eqkv = (__nv_bfloat16*)peqkv;
    eflash_kernel<<<dim3(CAP / 64, NE * Bt * NHM), 256, EF_SMEM>>>(
        eqkv, eqkv + EINSZ, eqkv + 2 * EINSZ, (__nv_bfloat16*)peoh, 0.0883883476483184f);

    // expert Wo: bf16 out
    gemm_mma_kernel<1><<<dim3(Dm / 128, EROWS / 128, NE), 256, GEMM_SMEM>>>(
        (__nv_bfloat16*)peoh, (__nv_bfloat16*)pewoh, nullptr, peoutb,
        EROWS, Dm, Dm, sA, DMDM, sA, 0, NE);

    combine_ln_kernel<<<NT, 256>>>(ln2_g, ln2_b, out);
    finalize_kernel<<<1, 32>>>(out);
}

// round 11
// speedup vs baseline: 7.2358x; 1.0306x over previous
#include <cuda_runtime.h>
#include <cuda_bf16.h>
#include <math.h>
#include <stdint.h>

// ---------------- problem dims ----------------
#define Bt   8
#define Sq   1024
#define Dm   1024
#define NH   16
#define HD1  64
#define NE   8
#define NHM  8
#define HDM  128
#define CAP  320
#define NT   (Bt*Sq)
#define NTD  ((size_t)NT*Dm)
#define EROWS (Bt*CAP)
#define EINSZ ((size_t)NE*Bt*CAP*Dm)
#define DMDM ((size_t)Dm*Dm)

// ---------------- scratch ----------------
static __device__ float g_attn[NTD];
static __device__ float g_x1[NTD];

static __device__ __nv_bfloat16 g_xh[NTD];
static __device__ __nv_bfloat16 g_qkvh[3*NTD];
static __device__ __nv_bfloat16 g_oh[NTD];
static __device__ __nv_bfloat16 g_einh[EINSZ];
static __device__ __nv_bfloat16 g_eqkv[3*EINSZ];
static __device__ __nv_bfloat16 g_eoh[EINSZ];
static __device__ __nv_bfloat16 g_eoutb[EINSZ];
static __device__ __nv_bfloat16 g_wqkvh[3*DMDM];
static __device__ __nv_bfloat16 g_woh[DMDM];
static __device__ __nv_bfloat16 g_ewh[3*NE*DMDM];
static __device__ __nv_bfloat16 g_ewoh[NE*DMDM];
static __device__ float g_bqkv[3*Dm];

static __device__ int   g_i0[NT], g_i1[NT];
static __device__ float g_g0[NT], g_g1[NT];
static __device__ int   g_p0[NT], g_p1[NT];
static __device__ int   g_k0[NT], g_k1[NT];

static __device__ float g_Psum[NE];
static __device__ float g_fcnt[NE];
static __device__ float g_zsum;

// ---------------- PTX helpers ----------------
__device__ __forceinline__ uint32_t smem_u32(const void* p) {
    uint32_t a;
    asm("{ .reg .u64 t; cvta.to.shared.u64 t, %1; cvt.u32.u64 %0, t; }" : "=r"(a) : "l"(p));
    return a;
}
__device__ __forceinline__ void cp16(uint32_t dst, const void* src) {
    asm volatile("cp.async.cg.shared.global [%0], [%1], 16;" :: "r"(dst), "l"(src));
}
__device__ __forceinline__ void ldmA(uint32_t* a, uint32_t addr) {
    asm volatile("ldmatrix.sync.aligned.m8n8.x4.shared.b16 {%0,%1,%2,%3}, [%4];"
        : "=r"(a[0]), "=r"(a[1]), "=r"(a[2]), "=r"(a[3]) : "r"(addr));
}
__device__ __forceinline__ void ldmT(uint32_t* a, uint32_t addr) {
    asm volatile("ldmatrix.sync.aligned.m8n8.x4.trans.shared.b16 {%0,%1,%2,%3}, [%4];"
        : "=r"(a[0]), "=r"(a[1]), "=r"(a[2]), "=r"(a[3]) : "r"(addr));
}
__device__ __forceinline__ void mma_bf16(float* d, const uint32_t* a, const uint32_t* b) {
    asm volatile(
        "mma.sync.aligned.m16n8k16.row.col.f32.bf16.bf16.f32 "
        "{%0,%1,%2,%3}, {%4,%5,%6,%7}, {%8,%9}, {%0,%1,%2,%3};"
        : "+f"(d[0]), "+f"(d[1]), "+f"(d[2]), "+f"(d[3])
        : "r"(a[0]), "r"(a[1]), "r"(a[2]), "r"(a[3]), "r"(b[0]), "r"(b[1]));
}
__device__ __forceinline__ uint32_t packbf(float a, float b) {
    __nv_bfloat162 v = __float22bfloat162_rn(make_float2(a, b));
    return *(uint32_t*)&v;
}

// ---------------- GEMM via mma.sync (bf16, BK=64, B in natural [K,N]) -------
#define BK 64
#define ROWA 144
#define ROWBB 272
#define ASTG (128*ROWA)
#define BSTG (64*ROWBB)
#define STG2 (ASTG+BSTG)
#define NSTG 3
#define GEMM_SMEM (NSTG*STG2)

template <int OUTBF>
__global__ __launch_bounds__(256, 2) void gemm_mma_kernel(
    const __nv_bfloat16* __restrict__ A, const __nv_bfloat16* __restrict__ W,
    const float* __restrict__ bias, void* __restrict__ Cv,
    int M, int N, int K, size_t sA, size_t sB, size_t sC, size_t sbias, int zmod)
{
    extern __shared__ char sm_[];
    uint32_t smb = smem_u32(sm_);

    int t = threadIdx.x, lane = t & 31, wid = t >> 5;
    int n0 = blockIdx.x * 128, m0 = blockIdx.y * 128;
    int z = blockIdx.z;
    A += (size_t)(z % zmod) * sA;
    W += (size_t)z * sB;
    if (bias) bias += (size_t)z * sbias;

    int wm = (wid & 3) * 32;
    int wn = (wid >> 2) * 64;
    const int NC = K / BK;

    float acc[2][8][4];
#pragma unroll
    for (int i = 0; i < 2; i++)
#pragma unroll
        for (int j = 0; j < 8; j++)
#pragma unroll
            for (int q = 0; q < 4; q++) acc[i][j][q] = 0.f;

    int rb = t >> 3, c8 = t & 7;
    const __nv_bfloat16* Ap = A + (size_t)(m0 + rb) * K + c8 * 8;
    uint32_t waA = (uint32_t)rb * ROWA + c8 * 16;
    const size_t rstepA = (size_t)32 * K;
    int rB = t >> 4, cB = t & 15;
    const __nv_bfloat16* Wp = W + (size_t)rB * N + n0 + cB * 8;
    uint32_t waB = (uint32_t)rB * ROWBB + cB * 16;
    const size_t rstepB = (size_t)16 * N;

#pragma unroll
    for (int s = 0; s < 2; s++) {
        uint32_t stg = smb + s * STG2;
        int kc = s * BK;
#pragma unroll
        for (int j = 0; j < 4; j++) {
            cp16(stg + waA + j * (32 * ROWA), Ap + kc + j * rstepA);
            cp16(stg + ASTG + waB + j * (16 * ROWBB), Wp + (size_t)kc * N + j * rstepB);
        }
        asm volatile("cp.async.commit_group;");
    }

    uint32_t a_row = (uint32_t)(wm + (lane & 15)) * ROWA + (lane >> 4) * 16;
    uint32_t b_col = (uint32_t)(lane & 15) * ROWBB + wn * 2 + (lane >> 4) * 16;

    int sidx = 0;
    for (int c = 0; c < NC; c++) {
        asm volatile("cp.async.wait_group 1;");
        __syncthreads();
        if (c + 2 < NC) {
            int sn = sidx + 2; if (sn >= NSTG) sn -= NSTG;
            uint32_t stg = smb + sn * STG2;
            int kc = (c + 2) * BK;
#pragma unroll
            for (int j = 0; j < 4; j++) {
                cp16(stg + waA + j * (32 * ROWA), Ap + kc + j * rstepA);
                cp16(stg + ASTG + waB + j * (16 * ROWBB), Wp + (size_t)kc * N + j * rstepB);
            }
        }
        asm volatile("cp.async.commit_group;");

        uint32_t ab = smb + sidx * STG2;
        uint32_t bb = ab + ASTG;

#pragma unroll
        for (int ks = 0; ks < 4; ks++) {
            uint32_t afr[2][4];
#pragma unroll
            for (int mt = 0; mt < 2; mt++)
                ldmA(afr[mt], ab + a_row + mt * (16 * ROWA) + ks * 32);

            uint32_t bfr[8][2];
#pragma unroll
            for (int nb = 0; nb < 4; nb++) {
                uint32_t q[4];
                ldmT(q, bb + b_col + ks * (16 * ROWBB) + nb * 32);
                bfr[nb * 2][0]     = q[0]; bfr[nb * 2][1]     = q[1];
                bfr[nb * 2 + 1][0] = q[2]; bfr[nb * 2 + 1][1] = q[3];
            }
#pragma unroll
            for (int mt = 0; mt < 2; mt++)
#pragma unroll
                for (int nt = 0; nt < 8; nt++)
                    mma_bf16(acc[mt][nt], afr[mt], bfr[nt]);
        }
        if (++sidx == NSTG) sidx = 0;
    }

#pragma unroll
    for (int mt = 0; mt < 2; mt++) {
        int m = m0 + wm + mt * 16 + (lane >> 2);
#pragma unroll
        for (int nt = 0; nt < 8; nt++) {
            int n = n0 + wn + nt * 8 + (lane & 3) * 2;
            float bv0 = bias ? bias[n] : 0.f;
            float bv1 = bias ? bias[n + 1] : 0.f;
            float v0 = acc[mt][nt][0] + bv0, v1 = acc[mt][nt][1] + bv1;
            float v2 = acc[mt][nt][2] + bv0, v3 = acc[mt][nt][3] + bv1;
            if (OUTBF == 0) {
                float* C = (float*)Cv + (size_t)z * sC;
                *(float2*)&C[(size_t)m * N + n]       = make_float2(v0, v1);
                *(float2*)&C[(size_t)(m + 8) * N + n] = make_float2(v2, v3);
            } else {
                __nv_bfloat16* C = (__nv_bfloat16*)Cv + (size_t)z * sC;
                *(uint32_t*)&C[(size_t)m * N + n]       = packbf(v0, v1);
                *(uint32_t*)&C[(size_t)(m + 8) * N + n] = packbf(v2, v3);
            }
        }
    }
}

// ---------------- expert flash (bf16 mma, HD=128, cp.async KV pipeline) -----
#define EF_PITCH 272
#define EF_QS 0
#define EF_KV0 17408                    // K stage base; V = +17408; stage stride 34816
#define EF_OB  87040                    // 64 x 132 fp32
#define EF_MS  120832
#define EF_LS  121088
#define EF_AS  121344
#define EF_RM  121600
#define EF_RS  122112
#define EF_SMEM 122624

__global__ __launch_bounds__(256) void eflash_kernel(
    const __nv_bfloat16* __restrict__ Q, const __nv_bfloat16* __restrict__ K,
    const __nv_bfloat16* __restrict__ V, __nv_bfloat16* __restrict__ O,
    float scale)
{
    extern __shared__ char sm_[];
    float* Obuf = (float*)(sm_ + EF_OB);
    float* m_s  = (float*)(sm_ + EF_MS);
    float* l_s  = (float*)(sm_ + EF_LS);
    float* a_s  = (float*)(sm_ + EF_AS);
    float* redm = (float*)(sm_ + EF_RM);
    float* reds = (float*)(sm_ + EF_RS);
    uint32_t smb = smem_u32(sm_);

    int t = threadIdx.x, lane = t & 31, wid = t >> 5;
    int half = wid >> 2, wm = (wid & 3) * 16, wn2 = half * 32;
    int slice = blockIdx.y;
    int sb = slice >> 3, h = slice & 7;
    size_t base = (size_t)sb * CAP * 1024 + (size_t)h * HDM;
    int q0 = blockIdx.x * 64;

    // Q load (plain)
#pragma unroll
    for (int j = 0; j < 4; j++) {
        int id = t + 256 * j;
        int r = id >> 4, c = id & 15;
        *(uint4*)(sm_ + EF_QS + r * EF_PITCH + c * 16) =
            *(const uint4*)(Q + base + (size_t)(q0 + r) * 1024 + c * 8);
    }
    if (t < 64) { m_s[t] = -1e30f; l_s[t] = 0.f; }

    // prefetch KV tile 0 into stage 0
    {
        int r = t >> 2, c4 = t & 3;      // 4 chunks per thread per matrix via j
#pragma unroll
        for (int j = 0; j < 4; j++) {
            int id = t + 256 * j;
            int rr = id >> 4, cc = id & 15;
            size_t g = base + (size_t)rr * 1024 + cc * 8;
            cp16(smb + EF_KV0 + rr * EF_PITCH + cc * 16, K + g);
            cp16(smb + EF_KV0 + 17408 + rr * EF_PITCH + cc * 16, V + g);
        }
        asm volatile("cp.async.commit_group;");
        (void)r; (void)c4;
    }

    float o[16][4];
#pragma unroll
    for (int i = 0; i < 16; i++)
#pragma unroll
        for (int q = 0; q < 4; q++) o[i][q] = 0.f;

    int rl = wm + (lane >> 2), rh = rl + 8;
    int nq = lane >> 2, kr = lane & 3;
    const int NTILE = CAP / 64;

    for (int kt = 0; kt < NTILE; kt++) {
        __syncthreads();    // all warps done with the stage about to be overwritten
        if (kt + 1 < NTILE) {
            uint32_t stg = smb + EF_KV0 + ((kt + 1) & 1) * 34816;
#pragma unroll
            for (int j = 0; j < 4; j++) {
                int id = t + 256 * j;
                int rr = id >> 4, cc = id & 15;
                size_t g = base + (size_t)((kt + 1) * 64 + rr) * 1024 + cc * 8;
                cp16(stg + rr * EF_PITCH + cc * 16, K + g);
                cp16(stg + 17408 + rr * EF_PITCH + cc * 16, V + g);
            }
        }
        asm volatile("cp.async.commit_group;");
        asm volatile("cp.async.wait_group 1;");
        __syncthreads();

        uint32_t ksb = smb + EF_KV0 + (kt & 1) * 34816;
        uint32_t vsb = ksb + 17408;
        const char* kcp = sm_ + (ksb - smb);

        float s[4][4];
#pragma unroll
        for (int nt = 0; nt < 4; nt++)
#pragma unroll
            for (int q = 0; q < 4; q++) s[nt][q] = 0.f;
#pragma unroll
        for (int ks = 0; ks < 8; ks++) {
            uint32_t af[4];
            ldmA(af, smb + EF_QS + (wm + (lane & 15)) * EF_PITCH + ks * 32 + (lane >> 4) * 16);
#pragma unroll
            for (int nt = 0; nt < 4; nt++) {
                const char* p = kcp + (wn2 + nt * 8 + nq) * EF_PITCH + ks * 32 + kr * 4;
                uint32_t bb[2];
                bb[0] = *(const uint32_t*)p;
                bb[1] = *(const uint32_t*)(p + 16);
                mma_bf16(s[nt], af, bb);
            }
        }

        float mxlo = -1e30f, mxhi = -1e30f;
#pragma unroll
        for (int nt = 0; nt < 4; nt++) {
            s[nt][0] *= scale; s[nt][1] *= scale; s[nt][2] *= scale; s[nt][3] *= scale;
            mxlo = fmaxf(mxlo, fmaxf(s[nt][0], s[nt][1]));
            mxhi = fmaxf(mxhi, fmaxf(s[nt][2], s[nt][3]));
        }
        mxlo = fmaxf(mxlo, __shfl_xor_sync(0xffffffff, mxlo, 1));
        mxlo = fmaxf(mxlo, __shfl_xor_sync(0xffffffff, mxlo, 2));
        mxhi = fmaxf(mxhi, __shfl_xor_sync(0xffffffff, mxhi, 1));
        mxhi = fmaxf(mxhi, __shfl_xor_sync(0xffffffff, mxhi, 2));
        if ((lane & 3) == 0) { redm[half * 64 + rl] = mxlo; redm[half * 64 + rh] = mxhi; }
        __syncthreads();
        if (t < 64) {
            float mo = m_s[t];
            float mn = fmaxf(mo, fmaxf(redm[t], redm[64 + t]));
            float al = __expf(mo - mn);
            a_s[t] = al; m_s[t] = mn; l_s[t] *= al;
        }
        __syncthreads();

        float mlo = m_s[rl], mhi = m_s[rh], alo = a_s[rl], ahi = a_s[rh];
        float slo = 0.f, shi = 0.f;
        uint32_t afr[2][4];
#pragma unroll
        for (int ks = 0; ks < 2; ks++) {
#pragma unroll
            for (int jj = 0; jj < 2; jj++) {
                int nt = ks * 2 + jj;
                float p0 = __expf(s[nt][0] - mlo), p1 = __expf(s[nt][1] - mlo);
                float p2 = __expf(s[nt][2] - mhi), p3 = __expf(s[nt][3] - mhi);
                slo += p0 + p1; shi += p2 + p3;
                afr[ks][jj * 2 + 0] = packbf(p0, p1);
                afr[ks][jj * 2 + 1] = packbf(p2, p3);
            }
        }
        slo += __shfl_xor_sync(0xffffffff, slo, 1);
        slo += __shfl_xor_sync(0xffffffff, slo, 2);
        shi += __shfl_xor_sync(0xffffffff, shi, 1);
        shi += __shfl_xor_sync(0xffffffff, shi, 2);
        if ((lane & 3) == 0) { reds[half * 64 + rl] = slo; reds[half * 64 + rh] = shi; }

#pragma unroll
        for (int nt = 0; nt < 16; nt++) {
            o[nt][0] *= alo; o[nt][1] *= alo; o[nt][2] *= ahi; o[nt][3] *= ahi;
        }

#pragma unroll
        for (int ks = 0; ks < 2; ks++) {
#pragma unroll
            for (int nb = 0; nb < 8; nb++) {
                uint32_t b4[4];
                ldmT(b4, vsb + (wn2 + ks * 16 + (lane & 15)) * EF_PITCH
                         + nb * 32 + (lane >> 4) * 16);
                mma_bf16(o[2 * nb],     afr[ks], b4);
                mma_bf16(o[2 * nb + 1], afr[ks], b4 + 2);
            }
        }
        __syncthreads();
        if (t < 64) l_s[t] += reds[t] + reds[64 + t];
    }

    __syncthreads();
    if (half == 0) {
#pragma unroll
        for (int nt = 0; nt < 16; nt++) {
            float* plo = Obuf + rl * 132 + nt * 8 + (lane & 3) * 2;
            float* phi = Obuf + rh * 132 + nt * 8 + (lane & 3) * 2;
            plo[0] = o[nt][0]; plo[1] = o[nt][1];
            phi[0] = o[nt][2]; phi[1] = o[nt][3];
        }
    }
    __syncthreads();
    if (half == 1) {
#pragma unroll
        for (int nt = 0; nt < 16; nt++) {
            float* plo = Obuf + rl * 132 + nt * 8 + (lane & 3) * 2;
            float* phi = Obuf + rh * 132 + nt * 8 + (lane & 3) * 2;
            plo[0] += o[nt][0]; plo[1] += o[nt][1];
            phi[0] += o[nt][2]; phi[1] += o[nt][3];
        }
    }
    __syncthreads();
#pragma unroll
    for (int j = 0; j < 16; j++) {
        int id = t + 256 * j;
        int r = id >> 6, cp = id & 63;
        float inv = 1.f / l_s[r];
        float2 v = *(float2*)(Obuf + r * 132 + cp * 2);
        __nv_bfloat162 ob = __float22bfloat162_rn(make_float2(v.x * inv, v.y * inv));
        *(__nv_bfloat162*)(O + base + (size_t)(q0 + r) * 1024 + cp * 2) = ob;
    }
}

// ---------------- main flash (bf16 mma, HD=64, cp.async KV pipeline) --------
#define MF_PITCH 144
#define MF_QS 0
#define MF_KV0 9216                     // K stage base; V = +9216; stage stride 18432
#define MF_OB  46080                    // 64 x 68 fp32
#define MF_MS  63488
#define MF_LS  63744
#define MF_AS  64000
#define MF_RM  64256
#define MF_RS  64768
#define MF_SMEM 65280

__global__ __launch_bounds__(256) void mflash_kernel(
    const __nv_bfloat16* __restrict__ Q, const __nv_bfloat16* __restrict__ K,
    const __nv_bfloat16* __restrict__ V, __nv_bfloat16* __restrict__ O,
    float scale)
{
    extern __shared__ char sm_[];
    float* Obuf = (float*)(sm_ + MF_OB);
    float* m_s  = (float*)(sm_ + MF_MS);
    float* l_s  = (float*)(sm_ + MF_LS);
    float* a_s  = (float*)(sm_ + MF_AS);
    float* redm = (float*)(sm_ + MF_RM);
    float* reds = (float*)(sm_ + MF_RS);
    uint32_t smb = smem_u32(sm_);

    int t = threadIdx.x, lane = t & 31, wid = t >> 5;
    int half = wid >> 2, wm = (wid & 3) * 16, wn2 = half * 32;
    int slice = blockIdx.y;
    int sb = slice >> 4, h = slice & 15;
    size_t base = (size_t)sb * Sq * 1024 + (size_t)h * HD1;
    int q0 = blockIdx.x * 64;

#pragma unroll
    for (int j = 0; j < 2; j++) {
        int id = t + 256 * j;
        int r = id >> 3, c = id & 7;
        *(uint4*)(sm_ + MF_QS + r * MF_PITCH + c * 16) =
            *(const uint4*)(Q + base + (size_t)(q0 + r) * 1024 + c * 8);
    }
    if (t < 64) { m_s[t] = -1e30f; l_s[t] = 0.f; }

    // prefetch KV tile 0
    {
#pragma unroll
        for (int j = 0; j < 2; j++) {
            int id = t + 256 * j;
            int r = id >> 3, c = id & 7;
            size_t g = base + (size_t)r * 1024 + c * 8;
            cp16(smb + MF_KV0 + r * MF_PITCH + c * 16, K + g);
            cp16(smb + MF_KV0 + 9216 + r * MF_PITCH + c * 16, V + g);
        }
        asm volatile("cp.async.commit_group;");
    }

    float o[8][4];
#pragma unroll
    for (int i = 0; i < 8; i++)
#pragma unroll
        for (int q = 0; q < 4; q++) o[i][q] = 0.f;

    int rl = wm + (lane >> 2), rh = rl + 8;
    int nq = lane >> 2, kr = lane & 3;
    const int NTILE = Sq / 64;

    for (int kt = 0; kt < NTILE; kt++) {
        __syncthreads();
        if (kt + 1 < NTILE) {
            uint32_t stg = smb + MF_KV0 + ((kt + 1) & 1) * 18432;
#pragma unroll
            for (int j = 0; j < 2; j++) {
                int id = t + 256 * j;
                int r = id >> 3, c = id & 7;
                size_t g = base + (size_t)((kt + 1) * 64 + r) * 1024 + c * 8;
                cp16(stg + r * MF_PITCH + c * 16, K + g);
                cp16(stg + 9216 + r * MF_PITCH + c * 16, V + g);
            }
        }
        asm volatile("cp.async.commit_group;");
        asm volatile("cp.async.wait_group 1;");
        __syncthreads();

        uint32_t ksb = smb + MF_KV0 + (kt & 1) * 18432;
        uint32_t vsb = ksb + 9216;
        const char* kcp = sm_ + (ksb - smb);

        float s[4][4];
#pragma unroll
        for (int nt = 0; nt < 4; nt++)
#pragma unroll
            for (int q = 0; q < 4; q++) s[nt][q] = 0.f;
#pragma unroll
        for (int ks = 0; ks < 4; ks++) {
            uint32_t af[4];
            ldmA(af, smb + MF_QS + (wm + (lane & 15)) * MF_PITCH + ks * 32 + (lane >> 4) * 16);
#pragma unroll
            for (int nt = 0; nt < 4; nt++) {
                const char* p = kcp + (wn2 + nt * 8 + nq) * MF_PITCH + ks * 32 + kr * 4;
                uint32_t bb[2];
                bb[0] = *(const uint32_t*)p;
                bb[1] = *(const uint32_t*)(p + 16);
                mma_bf16(s[nt], af, bb);
            }
        }

        float mxlo = -1e30f, mxhi = -1e30f;
#pragma unroll
        for (int nt = 0; nt < 4; nt++) {
            s[nt][0] *= scale; s[nt][1] *= scale; s[nt][2] *= scale; s[nt][3] *= scale;
            mxlo = fmaxf(mxlo, fmaxf(s[nt][0], s[nt][1]));
            mxhi = fmaxf(mxhi, fmaxf(s[nt][2], s[nt][3]));
        }
        mxlo = fmaxf(mxlo, __shfl_xor_sync(0xffffffff, mxlo, 1));
        mxlo = fmaxf(mxlo, __shfl_xor_sync(0xffffffff, mxlo, 2));
        mxhi = fmaxf(mxhi, __shfl_xor_sync(0xffffffff, mxhi, 1));
        mxhi = fmaxf(mxhi, __shfl_xor_sync(0xffffffff, mxhi, 2));
        if ((lane & 3) == 0) { redm[half * 64 + rl] = mxlo; redm[half * 64 + rh] = mxhi; }
        __syncthreads();
        if (t < 64) {
            float mo = m_s[t];
            float mn = fmaxf(mo, fmaxf(redm[t], redm[64 + t]));
            float al = __expf(mo - mn);
            a_s[t] = al; m_s[t] = mn; l_s[t] *= al;
        }
        __syncthreads();

        float mlo = m_s[rl], mhi = m_s[rh], alo = a_s[rl], ahi = a_s[rh];
        float slo = 0.f, shi = 0.f;
        uint32_t afr[2][4];
#pragma unroll
        for (int ks = 0; ks < 2; ks++) {
#pragma unroll
            for (int jj = 0; jj < 2; jj++) {
                int nt = ks * 2 + jj;
                float p0 = __expf(s[nt][0] - mlo), p1 = __expf(s[nt][1] - mlo);
                float p2 = __expf(s[nt][2] - mhi), p3 = __expf(s[nt][3] - mhi);
                slo += p0 + p1; shi += p2 + p3;
                afr[ks][jj * 2 + 0] = packbf(p0, p1);
                afr[ks][jj * 2 + 1] = packbf(p2, p3);
            }
        }
        slo += __shfl_xor_sync(0xffffffff, slo, 1);
        slo += __shfl_xor_sync(0xffffffff, slo, 2);
        shi += __shfl_xor_sync(0xffffffff, shi, 1);
        shi += __shfl_xor_sync(0xffffffff, shi, 2);
        if ((lane & 3) == 0) { reds[half * 64 + rl] = slo; reds[half * 64 + rh] = shi; }

#pragma unroll
        for (int nt = 0; nt < 8; nt++) {
            o[nt][0] *= alo; o[nt][1] *= alo; o[nt][2] *= ahi; o[nt][3] *= ahi;
        }

#pragma unroll
        for (int ks = 0; ks < 2; ks++) {
#pragma unroll
            for (int nb = 0; nb < 4; nb++) {
                uint32_t b4[4];
                ldmT(b4, vsb + (wn2 + ks * 16 + (lane & 15)) * MF_PITCH
                         + nb * 32 + (lane >> 4) * 16);
                mma_bf16(o[2 * nb],     afr[ks], b4);
                mma_bf16(o[2 * nb + 1], afr[ks], b4 + 2);
            }
        }
        __syncthreads();
        if (t < 64) l_s[t] += reds[t] + reds[64 + t];
    }

    __syncthreads();
    if (half == 0) {
#pragma unroll
        for (int nt = 0; nt < 8; nt++) {
            float* plo = Obuf + rl * 68 + nt * 8 + (lane & 3) * 2;
            float* phi = Obuf + rh * 68 + nt * 8 + (lane & 3) * 2;
            plo[0] = o[nt][0]; plo[1] = o[nt][1];
            phi[0] = o[nt][2]; phi[1] = o[nt][3];
        }
    }
    __syncthreads();
    if (half == 1) {
#pragma unroll
        for (int nt = 0; nt < 8; nt++) {
            float* plo = Obuf + rl * 68 + nt * 8 + (lane & 3) * 2;
            float* phi = Obuf + rh * 68 + nt * 8 + (lane & 3) * 2;
            plo[0] += o[nt][0]; plo[1] += o[nt][1];
            phi[0] += o[nt][2]; phi[1] += o[nt][3];
        }
    }
    __syncthreads();
#pragma unroll
    for (int j = 0; j < 8; j++) {
        int id = t + 256 * j;
        int r = id >> 5, cp = id & 31;
        float inv = 1.f / l_s[r];
        float2 v = *(float2*)(Obuf + r * 68 + cp * 2);
        __nv_bfloat162 ob = __float22bfloat162_rn(make_float2(v.x * inv, v.y * inv));
        *(__nv_bfloat162*)(O + base + (size_t)(q0 + r) * 1024 + cp * 2) = ob;
    }
}

// ---------------- fp32 -> bf16 convert (ILP-4) ----------------
__global__ __launch_bounds__(256) void cvt_kernel(
    const float4* __restrict__ s, uint2* __restrict__ h, int n4)
{
    int i = blockIdx.x * 1024 + threadIdx.x;
#pragma unroll
    for (int j = 0; j < 4; j++, i += 256) {
        if (i < n4) {
            float4 v = s[i];
            uint2 hh;
            hh.x = packbf(v.x, v.y);
            hh.y = packbf(v.z, v.w);
            h[i] = hh;
        }
    }
}

__global__ __launch_bounds__(256) void cvt4_kernel(
    const float4* __restrict__ s0, const float4* __restrict__ s1,
    const float4* __restrict__ s2, const float4* __restrict__ s3,
    uint2* __restrict__ d0, uint2* __restrict__ d1,
    uint2* __restrict__ d2, uint2* __restrict__ d3, int n4)
{
    const float4* s; uint2* d;
    switch (blockIdx.y) {
        case 0:  s = s0; d = d0; break;
        case 1:  s = s1; d = d1; break;
        case 2:  s = s2; d = d2; break;
        default: s = s3; d = d3; break;
    }
    int i = blockIdx.x * 1024 + threadIdx.x;
#pragma unroll
    for (int j = 0; j < 4; j++, i += 256) {
        if (i < n4) {
            float4 v = s[i];
            uint2 hh;
            hh.x = packbf(v.x, v.y);
            hh.y = packbf(v.z, v.w);
            d[i] = hh;
        }
    }
}

// ---------------- zero (ein + stats merged) ----------------
__global__ void zero_ein_kernel() {
    if (blockIdx.x == 0 && threadIdx.x < 32) {
        int t = threadIdx.x;
        if (t < NE) { g_Psum[t] = 0.f; g_fcnt[t] = 0.f; }
        if (t == 0) g_zsum = 0.f;
    }
    size_t n = EINSZ / 8;
    uint4 z = make_uint4(0, 0, 0, 0);
    uint4* ph = (uint4*)g_einh;
    for (size_t i = blockIdx.x * (size_t)blockDim.x + threadIdx.x; i < n;
         i += (size_t)gridDim.x * blockDim.x) ph[i] = z;
}

// ---------------- block reduce ----------------
__device__ __forceinline__ void block_reduce2(float& s, float& s2) {
    __shared__ float rs[8], rs2[8];
#pragma unroll
    for (int o = 16; o > 0; o >>= 1) {
        s  += __shfl_xor_sync(0xffffffff, s, o);
        s2 += __shfl_xor_sync(0xffffffff, s2, o);
    }
    int lane = threadIdx.x & 31, w = threadIdx.x >> 5;
    if (lane == 0) { rs[w] = s; rs2[w] = s2; }
    __syncthreads();
    float ts = 0.f, ts2 = 0.f;
#pragma unroll
    for (int i = 0; i < 8; i++) { ts += rs[i]; ts2 += rs2[i]; }
    s = ts; s2 = ts2;
}

// ---------------- LN1 + gate (fused) ----------------
__global__ __launch_bounds__(256) void ln1gate_kernel(
    const float* __restrict__ x, const float* __restrict__ g,
    const float* __restrict__ b, const float* __restrict__ gateW)
{
    __shared__ float ga[8][NE];
    size_t tok = blockIdx.x;
    int t = threadIdx.x, lane = t & 31, w = t >> 5;
    float v[4], s = 0.f, s2 = 0.f;
#pragma unroll
    for (int u = 0; u < 4; u++) {
        int j = t + u * 256;
        float val = x[tok * Dm + j] + g_attn[tok * Dm + j];
        v[u] = val; s += val; s2 += val * val;
    }
    block_reduce2(s, s2);
    float mean = s * (1.f / Dm);
    float var  = s2 * (1.f / Dm) - mean * mean;
    float inv  = rsqrtf(var + 1e-5f);

    float acc[NE];
#pragma unroll
    for (int e = 0; e < NE; e++) acc[e] = 0.f;
#pragma unroll
    for (int u = 0; u < 4; u++) {
        int j = t + u * 256;
        float x1v = (v[u] - mean) * inv * g[j] + b[j];
        g_x1[tok * Dm + j] = x1v;
        const float* wr = gateW + (size_t)j * NE;
#pragma unroll
        for (int e = 0; e < NE; e++) acc[e] += x1v * wr[e];
    }
#pragma unroll
    for (int e = 0; e < NE; e++)
#pragma unroll
        for (int o = 16; o > 0; o >>= 1)
            acc[e] += __shfl_xor_sync(0xffffffff, acc[e], o);
    if (lane == 0)
#pragma unroll
        for (int e = 0; e < NE; e++) ga[w][e] = acc[e];
    __syncthreads();

    if (t == 0) {
        float lg[NE];
#pragma unroll
        for (int e = 0; e < NE; e++) {
            float sv = 0.f;
#pragma unroll
            for (int i = 0; i < 8; i++) sv += ga[i][e];
            lg[e] = sv;
        }
        float mx = lg[0];
#pragma unroll
        for (int e = 1; e < NE; e++) mx = fmaxf(mx, lg[e]);
        float p[NE], se = 0.f;
#pragma unroll
        for (int e = 0; e < NE; e++) { p[e] = __expf(lg[e] - mx); se += p[e]; }
        float invs = 1.f / se;
        float lse = mx + logf(se);
        atomicAdd(&g_zsum, lse * lse);
        int i0 = 0, i1 = -1;
        float b0 = -1.f, b1 = -1.f;
#pragma unroll
        for (int e = 0; e < NE; e++) {
            float pe = p[e] * invs;
            atomicAdd(&g_Psum[e], pe);
            if (pe > b0) { b1 = b0; i1 = i0; b0 = pe; i0 = e; }
            else if (pe > b1) { b1 = pe; i1 = e; }
        }
        atomicAdd(&g_fcnt[i0], 1.f);
        g_i0[tok] = i0; g_i1[tok] = i1;
        g_g0[tok] = b0; g_g1[tok] = b1;
    }
}

// ---------------- routing positions ----------------
__global__ __launch_bounds__(256) void pos_kernel() {
    int warp = threadIdx.x >> 5, lane = threadIdx.x & 31;
    if (warp >= Bt) return;
    int b = warp;
    unsigned lt = (1u << lane) - 1u;
    int cnt[NE];
#pragma unroll
    for (int e = 0; e < NE; e++) cnt[e] = 0;

    for (int ch = 0; ch < Sq / 32; ch++) {
        int tok = b * Sq + ch * 32 + lane;
        int e0 = g_i0[tok];
        int myp = 0;
#pragma unroll
        for (int e = 0; e < NE; e++) {
            unsigned m = __ballot_sync(0xffffffff, e0 == e);
            if (e0 == e) myp = cnt[e] + __popc(m & lt);
            cnt[e] += __popc(m);
        }
        g_k0[tok] = (myp < CAP) ? 1 : 0;
        g_p0[tok] = min(myp, CAP - 1);
    }
    for (int ch = 0; ch < Sq / 32; ch++) {
        int tok = b * Sq + ch * 32 + lane;
        int e1 = g_i1[tok];
        bool valid = g_g1[tok] > 0.2f;
        int myp = 0;
#pragma unroll
        for (int e = 0; e < NE; e++) {
            unsigned m = __ballot_sync(0xffffffff, valid && (e1 == e));
            if (valid && (e1 == e)) myp = cnt[e] + __popc(m & lt);
            cnt[e] += __popc(m);
        }
        bool keep = valid && (myp < CAP);
        g_k1[tok] = keep ? 1 : 0;
        g_p1[tok] = valid ? min(myp, CAP - 1) : 0;
    }
}

// ---------------- scatter (x1 fp32 -> einh bf16) ----------------
__global__ __launch_bounds__(256) void scatter_kernel() {
    int idx = blockIdx.x;
    int tok = idx >> 1, slot = idx & 1;
    int keep = slot ? g_k1[tok] : g_k0[tok];
    if (!keep) return;
    int e = slot ? g_i1[tok] : g_i0[tok];
    int p = slot ? g_p1[tok] : g_p0[tok];
    int b = tok / Sq;
    const float4* src = (const float4*)(g_x1 + (size_t)tok * Dm);
    size_t ro = (((size_t)e * Bt + b) * CAP + p) * Dm;
    uint2* dh = (uint2*)(g_einh + ro);
    float4 v = src[threadIdx.x];
    uint2 hh;
    hh.x = packbf(v.x, v.y);
    hh.y = packbf(v.z, v.w);
    dh[threadIdx.x] = hh;
}

// ---------------- combine + LN2 ----------------
__global__ __launch_bounds__(256) void combine_ln_kernel(
    const float* __restrict__ g2, const float* __restrict__ b2,
    float* __restrict__ out)
{
    size_t tok = blockIdx.x;
    int t = threadIdx.x;
    int b = (int)(tok >> 10);
    float w0 = g_k0[tok] ? g_g0[tok] : 0.f;
    float w1 = g_k1[tok] ? g_g1[tok] : 0.f;
    const __nv_bfloat16* r0 = g_eoutb + (((size_t)g_i0[tok] * Bt + b) * CAP + g_p0[tok]) * Dm;
    const __nv_bfloat16* r1 = g_eoutb + (((size_t)g_i1[tok] * Bt + b) * CAP + g_p1[tok]) * Dm;

    float v[4], s = 0.f, s2 = 0.f;
#pragma unroll
    for (int u = 0; u < 4; u++) {
        int j = t + u * 256;
        float val = g_x1[tok * Dm + j]
                  + w0 * __bfloat162float(r0[j]) + w1 * __bfloat162float(r1[j]);
        v[u] = val; s += val; s2 += val * val;
    }
    block_reduce2(s, s2);
    float mean = s * (1.f / Dm);
    float var  = s2 * (1.f / Dm) - mean * mean;
    float inv  = rsqrtf(var + 1e-5f);
#pragma unroll
    for (int u = 0; u < 4; u++) {
        int j = t + u * 256;
        out[tok * Dm + j] = (v[u] - mean) * inv * g2[j] + b2[j];
    }
}

// ---------------- finalize aux ----------------
__global__ void finalize_kernel(float* __restrict__ out) {
    if (threadIdx.x == 0 && blockIdx.x == 0) {
        float invN = 1.f / (float)NT;
        float sfp = 0.f;
#pragma unroll
        for (int e = 0; e < NE; e++)
            sfp += (g_fcnt[e] * invN) * (g_Psum[e] * invN);
        float bal = 0.01f * (float)NE * sfp;
        float zl  = 0.001f * g_zsum * invN;
        out[NTD + 0] = bal + zl;
        out[NTD + 1] = bal;
        out[NTD + 2] = zl;
    }
}

// ---------------- host launcher ----------------
extern "C" void kernel_launch(void* const* d_in, const int* in_sizes, int n_in,
                              void* d_out, int out_size)
{
    const float* x      = (const float*)d_in[0];
    const float* Wq     = (const float*)d_in[1];
    const float* Wk     = (const float*)d_in[2];
    const float* Wv     = (const float*)d_in[3];
    const float* Wo     = (const float*)d_in[4];
    const float* bq     = (const float*)d_in[5];
    const float* bk     = (const float*)d_in[6];
    const float* bv     = (const float*)d_in[7];
    const float* bo     = (const float*)d_in[8];
    const float* ln1_g  = (const float*)d_in[9];
    const float* ln1_b  = (const float*)d_in[10];
    const float* ln2_g  = (const float*)d_in[11];
    const float* ln2_b  = (const float*)d_in[12];
    const float* gate_W = (const float*)d_in[13];
    const float* eWq    = (const float*)d_in[14];
    const float* eWk    = (const float*)d_in[15];
    const float* eWv    = (const float*)d_in[16];
    const float* eWo    = (const float*)d_in[17];
    float* out = (float*)d_out;

    void *pattn, *px1, *peoutb, *pxh, *pqkvh, *poh;
    void *peinh, *peqkv, *peoh;
    void *pwqkvh, *pwoh, *pewh, *pewoh, *pbqkv;
    cudaGetSymbolAddress(&pattn, g_attn);   cudaGetSymbolAddress(&px1, g_x1);
    cudaGetSymbolAddress(&peoutb, g_eoutb); cudaGetSymbolAddress(&pxh, g_xh);
    cudaGetSymbolAddress(&pqkvh, g_qkvh);   cudaGetSymbolAddress(&poh, g_oh);
    cudaGetSymbolAddress(&peinh, g_einh);   cudaGetSymbolAddress(&peqkv, g_eqkv);
    cudaGetSymbolAddress(&peoh, g_eoh);
    cudaGetSymbolAddress(&pwqkvh, g_wqkvh); cudaGetSymbolAddress(&pwoh, g_woh);
    cudaGetSymbolAddress(&pewh, g_ewh);     cudaGetSymbolAddress(&pewoh, g_ewoh);
    cudaGetSymbolAddress(&pbqkv, g_bqkv);

    cudaFuncSetAttribute(gemm_mma_kernel<0>, cudaFuncAttributeMaxDynamicSharedMemorySize, GEMM_SMEM);
    cudaFuncSetAttribute(gemm_mma_kernel<1>, cudaFuncAttributeMaxDynamicSharedMemorySize, GEMM_SMEM);
    cudaFuncSetAttribute(mflash_kernel, cudaFuncAttributeMaxDynamicSharedMemorySize, MF_SMEM);
    cudaFuncSetAttribute(eflash_kernel, cudaFuncAttributeMaxDynamicSharedMemorySize, EF_SMEM);

    zero_ein_kernel<<<2048, 256>>>();

    cudaMemcpyAsync((float*)pbqkv,          bq, Dm * sizeof(float), cudaMemcpyDeviceToDevice);
    cudaMemcpyAsync((float*)pbqkv + Dm,     bk, Dm * sizeof(float), cudaMemcpyDeviceToDevice);
    cudaMemcpyAsync((float*)pbqkv + 2 * Dm, bv, Dm * sizeof(float), cudaMemcpyDeviceToDevice);

    __nv_bfloat16* wqkv = (__nv_bfloat16*)pwqkvh;
    __nv_bfloat16* ewh  = (__nv_bfloat16*)pewh;
    const int WB1 = (int)(DMDM / 4);
    cvt4_kernel<<<dim3((WB1 + 1023) / 1024, 4), 256>>>(
        (const float4*)Wq, (const float4*)Wk, (const float4*)Wv, (const float4*)Wo,
        (uint2*)wqkv, (uint2*)(wqkv + DMDM), (uint2*)(wqkv + 2 * DMDM), (uint2*)pwoh, WB1);
    const int WBE = (int)(NE * DMDM / 4);
    cvt4_kernel<<<dim3((WBE + 1023) / 1024, 4), 256>>>(
        (const float4*)eWq, (const float4*)eWk, (const float4*)eWv, (const float4*)eWo,
        (uint2*)ewh, (uint2*)(ewh + NE * DMDM), (uint2*)(ewh + 2 * NE * DMDM), (uint2*)pewoh, WBE);

    cvt_kernel<<<(int)(NTD / 4 / 1024), 256>>>((const float4*)x, (uint2*)pxh, (int)(NTD / 4));

    gemm_mma_kernel<1><<<dim3(Dm / 128, NT / 128, 3), 256, GEMM_SMEM>>>(
        (__nv_bfloat16*)pxh, wqkv, (const float*)pbqkv, pqkvh,
        NT, Dm, Dm, 0, DMDM, NTD, Dm, 3);

    __nv_bfloat16* qkv = (__nv_bfloat16*)pqkvh;
    mflash_kernel<<<dim3(Sq / 64, Bt * NH), 256, MF_SMEM>>>(
        qkv, qkv + NTD, qkv + 2 * NTD, (__nv_bfloat16*)poh, 0.125f);

    gemm_mma_kernel<0><<<dim3(Dm / 128, NT / 128, 1), 256, GEMM_SMEM>>>(
        (__nv_bfloat16*)poh, (__nv_bfloat16*)pwoh, bo, pattn,
        NT, Dm, Dm, 0, 0, 0, 0, 1);

    ln1gate_kernel<<<NT, 256>>>(x, ln1_g, ln1_b, gate_W);
    pos_kernel<<<1, 256>>>();
    scatter_kernel<<<NT * 2, 256>>>();

    size_t sA = (size_t)EROWS * Dm;
    gemm_mma_kernel<1><<<dim3(Dm / 128, EROWS / 128, 24), 256, GEMM_SMEM>>>(
        (__nv_bfloat16*)peinh, ewh, nullptr, peqkv,
        EROWS, Dm, Dm, sA, DMDM, sA, 0, NE);

    __nv_bfloat16* eqkv = (__nv_bfloat16*)peqkv;
    eflash_kernel<<<dim3(CAP / 64, NE * Bt * NHM), 256, EF_SMEM>>>(
        eqkv, eqkv + EINSZ, eqkv + 2 * EINSZ, (__nv_bfloat16*)peoh, 0.0883883476483184f);

    gemm_mma_kernel<1><<<dim3(Dm / 128, EROWS / 128, NE), 256, GEMM_SMEM>>>(
        (__nv_bfloat16*)peoh, (__nv_bfloat16*)pewoh, nullptr, peoutb,
        EROWS, Dm, Dm, sA, DMDM, sA, 0, NE);

    combine_ln_kernel<<<NT, 256>>>(ln2_g, ln2_b, out);
    finalize_kernel<<<1, 32>>>(out);
}

// round 12
// speedup vs baseline: 7.4009x; 1.0228x over previous
#include <cuda_runtime.h>
#include <cuda_bf16.h>
#include <math.h>
#include <stdint.h>

// ---------------- problem dims ----------------
#define Bt   8
#define Sq   1024
#define Dm   1024
#define NH   16
#define HD1  64
#define NE   8
#define NHM  8
#define HDM  128
#define CAP  320
#define NT   (Bt*Sq)
#define NTD  ((size_t)NT*Dm)
#define EROWS (Bt*CAP)
#define EINSZ ((size_t)NE*Bt*CAP*Dm)
#define DMDM ((size_t)Dm*Dm)

// ---------------- scratch ----------------
static __device__ float g_attn[NTD];
static __device__ float g_x1[NTD];

static __device__ __nv_bfloat16 g_xh[NTD];
static __device__ __nv_bfloat16 g_qkvh[3*NTD];
static __device__ __nv_bfloat16 g_oh[NTD];
static __device__ __nv_bfloat16 g_einh[EINSZ];
static __device__ __nv_bfloat16 g_eqkv[3*EINSZ];
static __device__ __nv_bfloat16 g_eoh[EINSZ];
static __device__ __nv_bfloat16 g_eoutb[EINSZ];
static __device__ __nv_bfloat16 g_wqkvh[3*DMDM];
static __device__ __nv_bfloat16 g_woh[DMDM];
static __device__ __nv_bfloat16 g_ewh[3*NE*DMDM];
static __device__ __nv_bfloat16 g_ewoh[NE*DMDM];
static __device__ float g_bqkv[3*Dm];

static __device__ int   g_i0[NT], g_i1[NT];
static __device__ float g_g0[NT], g_g1[NT];
static __device__ int   g_p0[NT], g_p1[NT];
static __device__ int   g_k0[NT], g_k1[NT];

static __device__ float g_Psum[NE];
static __device__ float g_fcnt[NE];
static __device__ float g_zsum;

// ---------------- PTX helpers ----------------
__device__ __forceinline__ uint32_t smem_u32(const void* p) {
    uint32_t a;
    asm("{ .reg .u64 t; cvta.to.shared.u64 t, %1; cvt.u32.u64 %0, t; }" : "=r"(a) : "l"(p));
    return a;
}
__device__ __forceinline__ void cp16(uint32_t dst, const void* src) {
    asm volatile("cp.async.cg.shared.global [%0], [%1], 16;" :: "r"(dst), "l"(src));
}
__device__ __forceinline__ void ldmA(uint32_t* a, uint32_t addr) {
    asm volatile("ldmatrix.sync.aligned.m8n8.x4.shared.b16 {%0,%1,%2,%3}, [%4];"
        : "=r"(a[0]), "=r"(a[1]), "=r"(a[2]), "=r"(a[3]) : "r"(addr));
}
__device__ __forceinline__ void ldmT(uint32_t* a, uint32_t addr) {
    asm volatile("ldmatrix.sync.aligned.m8n8.x4.trans.shared.b16 {%0,%1,%2,%3}, [%4];"
        : "=r"(a[0]), "=r"(a[1]), "=r"(a[2]), "=r"(a[3]) : "r"(addr));
}
__device__ __forceinline__ void mma_bf16(float* d, const uint32_t* a, const uint32_t* b) {
    asm volatile(
        "mma.sync.aligned.m16n8k16.row.col.f32.bf16.bf16.f32 "
        "{%0,%1,%2,%3}, {%4,%5,%6,%7}, {%8,%9}, {%0,%1,%2,%3};"
        : "+f"(d[0]), "+f"(d[1]), "+f"(d[2]), "+f"(d[3])
        : "r"(a[0]), "r"(a[1]), "r"(a[2]), "r"(a[3]), "r"(b[0]), "r"(b[1]));
}
__device__ __forceinline__ uint32_t packbf(float a, float b) {
    __nv_bfloat162 v = __float22bfloat162_rn(make_float2(a, b));
    return *(uint32_t*)&v;
}

// ---------------- GEMM via mma.sync (bf16, BK=64, B in natural [K,N]) -------
#define BK 64
#define ROWA 144
#define ROWBB 272
#define ASTG (128*ROWA)
#define BSTG (64*ROWBB)
#define STG2 (ASTG+BSTG)
#define NSTG 3
#define GEMM_SMEM (NSTG*STG2)

template <int OUTBF>
__global__ __launch_bounds__(256, 2) void gemm_mma_kernel(
    const __nv_bfloat16* __restrict__ A, const __nv_bfloat16* __restrict__ W,
    const float* __restrict__ bias, void* __restrict__ Cv,
    int M, int N, int K, size_t sA, size_t sB, size_t sC, size_t sbias, int zmod)
{
    extern __shared__ char sm_[];
    uint32_t smb = smem_u32(sm_);

    int t = threadIdx.x, lane = t & 31, wid = t >> 5;
    int n0 = blockIdx.x * 128, m0 = blockIdx.y * 128;
    int z = blockIdx.z;
    A += (size_t)(z % zmod) * sA;
    W += (size_t)z * sB;
    if (bias) bias += (size_t)z * sbias;

    int wm = (wid & 3) * 32;
    int wn = (wid >> 2) * 64;
    const int NC = K / BK;

    float acc[2][8][4];
#pragma unroll
    for (int i = 0; i < 2; i++)
#pragma unroll
        for (int j = 0; j < 8; j++)
#pragma unroll
            for (int q = 0; q < 4; q++) acc[i][j][q] = 0.f;

    int rb = t >> 3, c8 = t & 7;
    const __nv_bfloat16* Ap = A + (size_t)(m0 + rb) * K + c8 * 8;
    uint32_t waA = (uint32_t)rb * ROWA + c8 * 16;
    const size_t rstepA = (size_t)32 * K;
    int rB = t >> 4, cB = t & 15;
    const __nv_bfloat16* Wp = W + (size_t)rB * N + n0 + cB * 8;
    uint32_t waB = (uint32_t)rB * ROWBB + cB * 16;
    const size_t rstepB = (size_t)16 * N;

#pragma unroll
    for (int s = 0; s < 2; s++) {
        uint32_t stg = smb + s * STG2;
        int kc = s * BK;
#pragma unroll
        for (int j = 0; j < 4; j++) {
            cp16(stg + waA + j * (32 * ROWA), Ap + kc + j * rstepA);
            cp16(stg + ASTG + waB + j * (16 * ROWBB), Wp + (size_t)kc * N + j * rstepB);
        }
        asm volatile("cp.async.commit_group;");
    }

    uint32_t a_row = (uint32_t)(wm + (lane & 15)) * ROWA + (lane >> 4) * 16;
    uint32_t b_col = (uint32_t)(lane & 15) * ROWBB + wn * 2 + (lane >> 4) * 16;

    int sidx = 0;
    for (int c = 0; c < NC; c++) {
        asm volatile("cp.async.wait_group 1;");
        __syncthreads();
        if (c + 2 < NC) {
            int sn = sidx + 2; if (sn >= NSTG) sn -= NSTG;
            uint32_t stg = smb + sn * STG2;
            int kc = (c + 2) * BK;
#pragma unroll
            for (int j = 0; j < 4; j++) {
                cp16(stg + waA + j * (32 * ROWA), Ap + kc + j * rstepA);
                cp16(stg + ASTG + waB + j * (16 * ROWBB), Wp + (size_t)kc * N + j * rstepB);
            }
        }
        asm volatile("cp.async.commit_group;");

        uint32_t ab = smb + sidx * STG2;
        uint32_t bb = ab + ASTG;

#pragma unroll
        for (int ks = 0; ks < 4; ks++) {
            uint32_t afr[2][4];
#pragma unroll
            for (int mt = 0; mt < 2; mt++)
                ldmA(afr[mt], ab + a_row + mt * (16 * ROWA) + ks * 32);

            uint32_t bfr[8][2];
#pragma unroll
            for (int nb = 0; nb < 4; nb++) {
                uint32_t q[4];
                ldmT(q, bb + b_col + ks * (16 * ROWBB) + nb * 32);
                bfr[nb * 2][0]     = q[0]; bfr[nb * 2][1]     = q[1];
                bfr[nb * 2 + 1][0] = q[2]; bfr[nb * 2 + 1][1] = q[3];
            }
#pragma unroll
            for (int mt = 0; mt < 2; mt++)
#pragma unroll
                for (int nt = 0; nt < 8; nt++)
                    mma_bf16(acc[mt][nt], afr[mt], bfr[nt]);
        }
        if (++sidx == NSTG) sidx = 0;
    }

#pragma unroll
    for (int mt = 0; mt < 2; mt++) {
        int m = m0 + wm + mt * 16 + (lane >> 2);
#pragma unroll
        for (int nt = 0; nt < 8; nt++) {
            int n = n0 + wn + nt * 8 + (lane & 3) * 2;
            float bv0 = bias ? bias[n] : 0.f;
            float bv1 = bias ? bias[n + 1] : 0.f;
            float v0 = acc[mt][nt][0] + bv0, v1 = acc[mt][nt][1] + bv1;
            float v2 = acc[mt][nt][2] + bv0, v3 = acc[mt][nt][3] + bv1;
            if (OUTBF == 0) {
                float* C = (float*)Cv + (size_t)z * sC;
                *(float2*)&C[(size_t)m * N + n]       = make_float2(v0, v1);
                *(float2*)&C[(size_t)(m + 8) * N + n] = make_float2(v2, v3);
            } else {
                __nv_bfloat16* C = (__nv_bfloat16*)Cv + (size_t)z * sC;
                *(uint32_t*)&C[(size_t)m * N + n]       = packbf(v0, v1);
                *(uint32_t*)&C[(size_t)(m + 8) * N + n] = packbf(v2, v3);
            }
        }
    }
}

// ---------------- expert flash (bf16 mma, HD=128, 2 CTA/SM, Obuf aliased) ---
#define EF_PITCH 272
#define EF_QS 0
#define EF_KV0 17408                 // KV ring: 2 stages x 34816; Obuf aliases here
#define EF_MS  87040
#define EF_LS  87296
#define EF_AS  87552
#define EF_RM  87808
#define EF_RS  88320
#define EF_SMEM 88832

__global__ __launch_bounds__(256, 2) void eflash_kernel(
    const __nv_bfloat16* __restrict__ Q, const __nv_bfloat16* __restrict__ K,
    const __nv_bfloat16* __restrict__ V, __nv_bfloat16* __restrict__ O,
    float scale)
{
    extern __shared__ char sm_[];
    float* Obuf = (float*)(sm_ + EF_KV0);    // aliases KV ring (used post-mainloop)
    float* m_s  = (float*)(sm_ + EF_MS);
    float* l_s  = (float*)(sm_ + EF_LS);
    float* a_s  = (float*)(sm_ + EF_AS);
    float* redm = (float*)(sm_ + EF_RM);
    float* reds = (float*)(sm_ + EF_RS);
    uint32_t smb = smem_u32(sm_);

    int t = threadIdx.x, lane = t & 31, wid = t >> 5;
    int half = wid >> 2, wm = (wid & 3) * 16, wn2 = half * 32;
    int slice = blockIdx.y;
    int sb = slice >> 3, h = slice & 7;
    size_t base = (size_t)sb * CAP * 1024 + (size_t)h * HDM;
    int q0 = blockIdx.x * 64;

#pragma unroll
    for (int j = 0; j < 4; j++) {
        int id = t + 256 * j;
        int r = id >> 4, c = id & 15;
        *(uint4*)(sm_ + EF_QS + r * EF_PITCH + c * 16) =
            *(const uint4*)(Q + base + (size_t)(q0 + r) * 1024 + c * 8);
    }
    if (t < 64) { m_s[t] = -1e30f; l_s[t] = 0.f; }

    {
#pragma unroll
        for (int j = 0; j < 4; j++) {
            int id = t + 256 * j;
            int rr = id >> 4, cc = id & 15;
            size_t g = base + (size_t)rr * 1024 + cc * 8;
            cp16(smb + EF_KV0 + rr * EF_PITCH + cc * 16, K + g);
            cp16(smb + EF_KV0 + 17408 + rr * EF_PITCH + cc * 16, V + g);
        }
        asm volatile("cp.async.commit_group;");
    }

    float o[16][4];
#pragma unroll
    for (int i = 0; i < 16; i++)
#pragma unroll
        for (int q = 0; q < 4; q++) o[i][q] = 0.f;

    int rl = wm + (lane >> 2), rh = rl + 8;
    int nq = lane >> 2, kr = lane & 3;
    const int NTILE = CAP / 64;

    for (int kt = 0; kt < NTILE; kt++) {
        __syncthreads();
        if (kt + 1 < NTILE) {
            uint32_t stg = smb + EF_KV0 + ((kt + 1) & 1) * 34816;
#pragma unroll
            for (int j = 0; j < 4; j++) {
                int id = t + 256 * j;
                int rr = id >> 4, cc = id & 15;
                size_t g = base + (size_t)((kt + 1) * 64 + rr) * 1024 + cc * 8;
                cp16(stg + rr * EF_PITCH + cc * 16, K + g);
                cp16(stg + 17408 + rr * EF_PITCH + cc * 16, V + g);
            }
        }
        asm volatile("cp.async.commit_group;");
        asm volatile("cp.async.wait_group 1;");
        __syncthreads();

        uint32_t ksb = smb + EF_KV0 + (kt & 1) * 34816;
        uint32_t vsb = ksb + 17408;
        const char* kcp = sm_ + (ksb - smb);

        float s[4][4];
#pragma unroll
        for (int nt = 0; nt < 4; nt++)
#pragma unroll
            for (int q = 0; q < 4; q++) s[nt][q] = 0.f;
#pragma unroll
        for (int ks = 0; ks < 8; ks++) {
            uint32_t af[4];
            ldmA(af, smb + EF_QS + (wm + (lane & 15)) * EF_PITCH + ks * 32 + (lane >> 4) * 16);
#pragma unroll
            for (int nt = 0; nt < 4; nt++) {
                const char* p = kcp + (wn2 + nt * 8 + nq) * EF_PITCH + ks * 32 + kr * 4;
                uint32_t bb[2];
                bb[0] = *(const uint32_t*)p;
                bb[1] = *(const uint32_t*)(p + 16);
                mma_bf16(s[nt], af, bb);
            }
        }

        float mxlo = -1e30f, mxhi = -1e30f;
#pragma unroll
        for (int nt = 0; nt < 4; nt++) {
            s[nt][0] *= scale; s[nt][1] *= scale; s[nt][2] *= scale; s[nt][3] *= scale;
            mxlo = fmaxf(mxlo, fmaxf(s[nt][0], s[nt][1]));
            mxhi = fmaxf(mxhi, fmaxf(s[nt][2], s[nt][3]));
        }
        mxlo = fmaxf(mxlo, __shfl_xor_sync(0xffffffff, mxlo, 1));
        mxlo = fmaxf(mxlo, __shfl_xor_sync(0xffffffff, mxlo, 2));
        mxhi = fmaxf(mxhi, __shfl_xor_sync(0xffffffff, mxhi, 1));
        mxhi = fmaxf(mxhi, __shfl_xor_sync(0xffffffff, mxhi, 2));
        if ((lane & 3) == 0) { redm[half * 64 + rl] = mxlo; redm[half * 64 + rh] = mxhi; }
        __syncthreads();
        if (t < 64) {
            float mo = m_s[t];
            float mn = fmaxf(mo, fmaxf(redm[t], redm[64 + t]));
            float al = __expf(mo - mn);
            a_s[t] = al; m_s[t] = mn; l_s[t] *= al;
        }
        __syncthreads();

        float mlo = m_s[rl], mhi = m_s[rh], alo = a_s[rl], ahi = a_s[rh];
        float slo = 0.f, shi = 0.f;
        uint32_t afr[2][4];
#pragma unroll
        for (int ks = 0; ks < 2; ks++) {
#pragma unroll
            for (int jj = 0; jj < 2; jj++) {
                int nt = ks * 2 + jj;
                float p0 = __expf(s[nt][0] - mlo), p1 = __expf(s[nt][1] - mlo);
                float p2 = __expf(s[nt][2] - mhi), p3 = __expf(s[nt][3] - mhi);
                slo += p0 + p1; shi += p2 + p3;
                afr[ks][jj * 2 + 0] = packbf(p0, p1);
                afr[ks][jj * 2 + 1] = packbf(p2, p3);
            }
        }
        slo += __shfl_xor_sync(0xffffffff, slo, 1);
        slo += __shfl_xor_sync(0xffffffff, slo, 2);
        shi += __shfl_xor_sync(0xffffffff, shi, 1);
        shi += __shfl_xor_sync(0xffffffff, shi, 2);
        if ((lane & 3) == 0) { reds[half * 64 + rl] = slo; reds[half * 64 + rh] = shi; }

#pragma unroll
        for (int nt = 0; nt < 16; nt++) {
            o[nt][0] *= alo; o[nt][1] *= alo; o[nt][2] *= ahi; o[nt][3] *= ahi;
        }

#pragma unroll
        for (int ks = 0; ks < 2; ks++) {
#pragma unroll
            for (int nb = 0; nb < 8; nb++) {
                uint32_t b4[4];
                ldmT(b4, vsb + (wn2 + ks * 16 + (lane & 15)) * EF_PITCH
                         + nb * 32 + (lane >> 4) * 16);
                mma_bf16(o[2 * nb],     afr[ks], b4);
                mma_bf16(o[2 * nb + 1], afr[ks], b4 + 2);
            }
        }
        __syncthreads();
        if (t < 64) l_s[t] += reds[t] + reds[64 + t];
    }

    __syncthreads();   // all KV reads done; Obuf (aliasing KV) now safe to write
    if (half == 0) {
#pragma unroll
        for (int nt = 0; nt < 16; nt++) {
            float* plo = Obuf + rl * 132 + nt * 8 + (lane & 3) * 2;
            float* phi = Obuf + rh * 132 + nt * 8 + (lane & 3) * 2;
            plo[0] = o[nt][0]; plo[1] = o[nt][1];
            phi[0] = o[nt][2]; phi[1] = o[nt][3];
        }
    }
    __syncthreads();
    if (half == 1) {
#pragma unroll
        for (int nt = 0; nt < 16; nt++) {
            float* plo = Obuf + rl * 132 + nt * 8 + (lane & 3) * 2;
            float* phi = Obuf + rh * 132 + nt * 8 + (lane & 3) * 2;
            plo[0] += o[nt][0]; plo[1] += o[nt][1];
            phi[0] += o[nt][2]; phi[1] += o[nt][3];
        }
    }
    __syncthreads();
#pragma unroll
    for (int j = 0; j < 16; j++) {
        int id = t + 256 * j;
        int r = id >> 6, cp = id & 63;
        float inv = 1.f / l_s[r];
        float2 v = *(float2*)(Obuf + r * 132 + cp * 2);
        __nv_bfloat162 ob = __float22bfloat162_rn(make_float2(v.x * inv, v.y * inv));
        *(__nv_bfloat162*)(O + base + (size_t)(q0 + r) * 1024 + cp * 2) = ob;
    }
}

// ---------------- main flash (bf16 mma, HD=64, 2 CTA/SM, Obuf aliased) ------
#define MF_PITCH 144
#define MF_QS 0
#define MF_KV0 9216                  // KV ring: 2 stages x 18432; Obuf aliases here
#define MF_MS  46080
#define MF_LS  46336
#define MF_AS  46592
#define MF_RM  46848
#define MF_RS  47360
#define MF_SMEM 47872

__global__ __launch_bounds__(256, 2) void mflash_kernel(
    const __nv_bfloat16* __restrict__ Q, const __nv_bfloat16* __restrict__ K,
    const __nv_bfloat16* __restrict__ V, __nv_bfloat16* __restrict__ O,
    float scale)
{
    extern __shared__ char sm_[];
    float* Obuf = (float*)(sm_ + MF_KV0);    // aliases KV ring
    float* m_s  = (float*)(sm_ + MF_MS);
    float* l_s  = (float*)(sm_ + MF_LS);
    float* a_s  = (float*)(sm_ + MF_AS);
    float* redm = (float*)(sm_ + MF_RM);
    float* reds = (float*)(sm_ + MF_RS);
    uint32_t smb = smem_u32(sm_);

    int t = threadIdx.x, lane = t & 31, wid = t >> 5;
    int half = wid >> 2, wm = (wid & 3) * 16, wn2 = half * 32;
    int slice = blockIdx.y;
    int sb = slice >> 4, h = slice & 15;
    size_t base = (size_t)sb * Sq * 1024 + (size_t)h * HD1;
    int q0 = blockIdx.x * 64;

#pragma unroll
    for (int j = 0; j < 2; j++) {
        int id = t + 256 * j;
        int r = id >> 3, c = id & 7;
        *(uint4*)(sm_ + MF_QS + r * MF_PITCH + c * 16) =
            *(const uint4*)(Q + base + (size_t)(q0 + r) * 1024 + c * 8);
    }
    if (t < 64) { m_s[t] = -1e30f; l_s[t] = 0.f; }

    {
#pragma unroll
        for (int j = 0; j < 2; j++) {
            int id = t + 256 * j;
            int r = id >> 3, c = id & 7;
            size_t g = base + (size_t)r * 1024 + c * 8;
            cp16(smb + MF_KV0 + r * MF_PITCH + c * 16, K + g);
            cp16(smb + MF_KV0 + 9216 + r * MF_PITCH + c * 16, V + g);
        }
        asm volatile("cp.async.commit_group;");
    }

    float o[8][4];
#pragma unroll
    for (int i = 0; i < 8; i++)
#pragma unroll
        for (int q = 0; q < 4; q++) o[i][q] = 0.f;

    int rl = wm + (lane >> 2), rh = rl + 8;
    int nq = lane >> 2, kr = lane & 3;
    const int NTILE = Sq / 64;

    for (int kt = 0; kt < NTILE; kt++) {
        __syncthreads();
        if (kt + 1 < NTILE) {
            uint32_t stg = smb + MF_KV0 + ((kt + 1) & 1) * 18432;
#pragma unroll
            for (int j = 0; j < 2; j++) {
                int id = t + 256 * j;
                int r = id >> 3, c = id & 7;
                size_t g = base + (size_t)((kt + 1) * 64 + r) * 1024 + c * 8;
                cp16(stg + r * MF_PITCH + c * 16, K + g);
                cp16(stg + 9216 + r * MF_PITCH + c * 16, V + g);
            }
        }
        asm volatile("cp.async.commit_group;");
        asm volatile("cp.async.wait_group 1;");
        __syncthreads();

        uint32_t ksb = smb + MF_KV0 + (kt & 1) * 18432;
        uint32_t vsb = ksb + 9216;
        const char* kcp = sm_ + (ksb - smb);

        float s[4][4];
#pragma unroll
        for (int nt = 0; nt < 4; nt++)
#pragma unroll
            for (int q = 0; q < 4; q++) s[nt][q] = 0.f;
#pragma unroll
        for (int ks = 0; ks < 4; ks++) {
            uint32_t af[4];
            ldmA(af, smb + MF_QS + (wm + (lane & 15)) * MF_PITCH + ks * 32 + (lane >> 4) * 16);
#pragma unroll
            for (int nt = 0; nt < 4; nt++) {
                const char* p = kcp + (wn2 + nt * 8 + nq) * MF_PITCH + ks * 32 + kr * 4;
                uint32_t bb[2];
                bb[0] = *(const uint32_t*)p;
                bb[1] = *(const uint32_t*)(p + 16);
                mma_bf16(s[nt], af, bb);
            }
        }

        float mxlo = -1e30f, mxhi = -1e30f;
#pragma unroll
        for (int nt = 0; nt < 4; nt++) {
            s[nt][0] *= scale; s[nt][1] *= scale; s[nt][2] *= scale; s[nt][3] *= scale;
            mxlo = fmaxf(mxlo, fmaxf(s[nt][0], s[nt][1]));
            mxhi = fmaxf(mxhi, fmaxf(s[nt][2], s[nt][3]));
        }
        mxlo = fmaxf(mxlo, __shfl_xor_sync(0xffffffff, mxlo, 1));
        mxlo = fmaxf(mxlo, __shfl_xor_sync(0xffffffff, mxlo, 2));
        mxhi = fmaxf(mxhi, __shfl_xor_sync(0xffffffff, mxhi, 1));
        mxhi = fmaxf(mxhi, __shfl_xor_sync(0xffffffff, mxhi, 2));
        if ((lane & 3) == 0) { redm[half * 64 + rl] = mxlo; redm[half * 64 + rh] = mxhi; }
        __syncthreads();
        if (t < 64) {
            float mo = m_s[t];
            float mn = fmaxf(mo, fmaxf(redm[t], redm[64 + t]));
            float al = __expf(mo - mn);
            a_s[t] = al; m_s[t] = mn; l_s[t] *= al;
        }
        __syncthreads();

        float mlo = m_s[rl], mhi = m_s[rh], alo = a_s[rl], ahi = a_s[rh];
        float slo = 0.f, shi = 0.f;
        uint32_t afr[2][4];
#pragma unroll
        for (int ks = 0; ks < 2; ks++) {
#pragma unroll
            for (int jj = 0; jj < 2; jj++) {
                int nt = ks * 2 + jj;
                float p0 = __expf(s[nt][0] - mlo), p1 = __expf(s[nt][1] - mlo);
                float p2 = __expf(s[nt][2] - mhi), p3 = __expf(s[nt][3] - mhi);
                slo += p0 + p1; shi += p2 + p3;
                afr[ks][jj * 2 + 0] = packbf(p0, p1);
                afr[ks][jj * 2 + 1] = packbf(p2, p3);
            }
        }
        slo += __shfl_xor_sync(0xffffffff, slo, 1);
        slo += __shfl_xor_sync(0xffffffff, slo, 2);
        shi += __shfl_xor_sync(0xffffffff, shi, 1);
        shi += __shfl_xor_sync(0xffffffff, shi, 2);
        if ((lane & 3) == 0) { reds[half * 64 + rl] = slo; reds[half * 64 + rh] = shi; }

#pragma unroll
        for (int nt = 0; nt < 8; nt++) {
            o[nt][0] *= alo; o[nt][1] *= alo; o[nt][2] *= ahi; o[nt][3] *= ahi;
        }

#pragma unroll
        for (int ks = 0; ks < 2; ks++) {
#pragma unroll
            for (int nb = 0; nb < 4; nb++) {
                uint32_t b4[4];
                ldmT(b4, vsb + (wn2 + ks * 16 + (lane & 15)) * MF_PITCH
                         + nb * 32 + (lane >> 4) * 16);
                mma_bf16(o[2 * nb],     afr[ks], b4);
                mma_bf16(o[2 * nb + 1], afr[ks], b4 + 2);
            }
        }
        __syncthreads();
        if (t < 64) l_s[t] += reds[t] + reds[64 + t];
    }

    __syncthreads();   // KV reads done; Obuf alias safe
    if (half == 0) {
#pragma unroll
        for (int nt = 0; nt < 8; nt++) {
            float* plo = Obuf + rl * 68 + nt * 8 + (lane & 3) * 2;
            float* phi = Obuf + rh * 68 + nt * 8 + (lane & 3) * 2;
            plo[0] = o[nt][0]; plo[1] = o[nt][1];
            phi[0] = o[nt][2]; phi[1] = o[nt][3];
        }
    }
    __syncthreads();
    if (half == 1) {
#pragma unroll
        for (int nt = 0; nt < 8; nt++) {
            float* plo = Obuf + rl * 68 + nt * 8 + (lane & 3) * 2;
            float* phi = Obuf + rh * 68 + nt * 8 + (lane & 3) * 2;
            plo[0] += o[nt][0]; plo[1] += o[nt][1];
            phi[0] += o[nt][2]; phi[1] += o[nt][3];
        }
    }
    __syncthreads();
#pragma unroll
    for (int j = 0; j < 8; j++) {
        int id = t + 256 * j;
        int r = id >> 5, cp = id & 31;
        float inv = 1.f / l_s[r];
        float2 v = *(float2*)(Obuf + r * 68 + cp * 2);
        __nv_bfloat162 ob = __float22bfloat162_rn(make_float2(v.x * inv, v.y * inv));
        *(__nv_bfloat162*)(O + base + (size_t)(q0 + r) * 1024 + cp * 2) = ob;
    }
}

// ---------------- fp32 -> bf16 convert (ILP-4) ----------------
__global__ __launch_bounds__(256) void cvt_kernel(
    const float4* __restrict__ s, uint2* __restrict__ h, int n4)
{
    int i = blockIdx.x * 1024 + threadIdx.x;
#pragma unroll
    for (int j = 0; j < 4; j++, i += 256) {
        if (i < n4) {
            float4 v = s[i];
            uint2 hh;
            hh.x = packbf(v.x, v.y);
            hh.y = packbf(v.z, v.w);
            h[i] = hh;
        }
    }
}

__global__ __launch_bounds__(256) void cvt4_kernel(
    const float4* __restrict__ s0, const float4* __restrict__ s1,
    const float4* __restrict__ s2, const float4* __restrict__ s3,
    uint2* __restrict__ d0, uint2* __restrict__ d1,
    uint2* __restrict__ d2, uint2* __restrict__ d3, int n4)
{
    const float4* s; uint2* d;
    switch (blockIdx.y) {
        case 0:  s = s0; d = d0; break;
        case 1:  s = s1; d = d1; break;
        case 2:  s = s2; d = d2; break;
        default: s = s3; d = d3; break;
    }
    int i = blockIdx.x * 1024 + threadIdx.x;
#pragma unroll
    for (int j = 0; j < 4; j++, i += 256) {
        if (i < n4) {
            float4 v = s[i];
            uint2 hh;
            hh.x = packbf(v.x, v.y);
            hh.y = packbf(v.z, v.w);
            d[i] = hh;
        }
    }
}

// ---------------- zero (ein + stats merged) ----------------
__global__ void zero_ein_kernel() {
    if (blockIdx.x == 0 && threadIdx.x < 32) {
        int t = threadIdx.x;
        if (t < NE) { g_Psum[t] = 0.f; g_fcnt[t] = 0.f; }
        if (t == 0) g_zsum = 0.f;
    }
    size_t n = EINSZ / 8;
    uint4 z = make_uint4(0, 0, 0, 0);
    uint4* ph = (uint4*)g_einh;
    for (size_t i = blockIdx.x * (size_t)blockDim.x + threadIdx.x; i < n;
         i += (size_t)gridDim.x * blockDim.x) ph[i] = z;
}

// ---------------- block reduce ----------------
__device__ __forceinline__ void block_reduce2(float& s, float& s2) {
    __shared__ float rs[8], rs2[8];
#pragma unroll
    for (int o = 16; o > 0; o >>= 1) {
        s  += __shfl_xor_sync(0xffffffff, s, o);
        s2 += __shfl_xor_sync(0xffffffff, s2, o);
    }
    int lane = threadIdx.x & 31, w = threadIdx.x >> 5;
    if (lane == 0) { rs[w] = s; rs2[w] = s2; }
    __syncthreads();
    float ts = 0.f, ts2 = 0.f;
#pragma unroll
    for (int i = 0; i < 8; i++) { ts += rs[i]; ts2 += rs2[i]; }
    s = ts; s2 = ts2;
}

// ---------------- LN1 + gate (fused) ----------------
__global__ __launch_bounds__(256) void ln1gate_kernel(
    const float* __restrict__ x, const float* __restrict__ g,
    const float* __restrict__ b, const float* __restrict__ gateW)
{
    __shared__ float ga[8][NE];
    size_t tok = blockIdx.x;
    int t = threadIdx.x, lane = t & 31, w = t >> 5;
    float v[4], s = 0.f, s2 = 0.f;
#pragma unroll
    for (int u = 0; u < 4; u++) {
        int j = t + u * 256;
        float val = x[tok * Dm + j] + g_attn[tok * Dm + j];
        v[u] = val; s += val; s2 += val * val;
    }
    block_reduce2(s, s2);
    float mean = s * (1.f / Dm);
    float var  = s2 * (1.f / Dm) - mean * mean;
    float inv  = rsqrtf(var + 1e-5f);

    float acc[NE];
#pragma unroll
    for (int e = 0; e < NE; e++) acc[e] = 0.f;
#pragma unroll
    for (int u = 0; u < 4; u++) {
        int j = t + u * 256;
        float x1v = (v[u] - mean) * inv * g[j] + b[j];
        g_x1[tok * Dm + j] = x1v;
        const float* wr = gateW + (size_t)j * NE;
#pragma unroll
        for (int e = 0; e < NE; e++) acc[e] += x1v * wr[e];
    }
#pragma unroll
    for (int e = 0; e < NE; e++)
#pragma unroll
        for (int o = 16; o > 0; o >>= 1)
            acc[e] += __shfl_xor_sync(0xffffffff, acc[e], o);
    if (lane == 0)
#pragma unroll
        for (int e = 0; e < NE; e++) ga[w][e] = acc[e];
    __syncthreads();

    if (t == 0) {
        float lg[NE];
#pragma unroll
        for (int e = 0; e < NE; e++) {
            float sv = 0.f;
#pragma unroll
            for (int i = 0; i < 8; i++) sv += ga[i][e];
            lg[e] = sv;
        }
        float mx = lg[0];
#pragma unroll
        for (int e = 1; e < NE; e++) mx = fmaxf(mx, lg[e]);
        float p[NE], se = 0.f;
#pragma unroll
        for (int e = 0; e < NE; e++) { p[e] = __expf(lg[e] - mx); se += p[e]; }
        float invs = 1.f / se;
        float lse = mx + logf(se);
        atomicAdd(&g_zsum, lse * lse);
        int i0 = 0, i1 = -1;
        float b0 = -1.f, b1 = -1.f;
#pragma unroll
        for (int e = 0; e < NE; e++) {
            float pe = p[e] * invs;
            atomicAdd(&g_Psum[e], pe);
            if (pe > b0) { b1 = b0; i1 = i0; b0 = pe; i0 = e; }
            else if (pe > b1) { b1 = pe; i1 = e; }
        }
        atomicAdd(&g_fcnt[i0], 1.f);
        g_i0[tok] = i0; g_i1[tok] = i1;
        g_g0[tok] = b0; g_g1[tok] = b1;
    }
}

// ---------------- routing positions ----------------
__global__ __launch_bounds__(256) void pos_kernel() {
    int warp = threadIdx.x >> 5, lane = threadIdx.x & 31;
    if (warp >= Bt) return;
    int b = warp;
    unsigned lt = (1u << lane) - 1u;
    int cnt[NE];
#pragma unroll
    for (int e = 0; e < NE; e++) cnt[e] = 0;

    for (int ch = 0; ch < Sq / 32; ch++) {
        int tok = b * Sq + ch * 32 + lane;
        int e0 = g_i0[tok];
        int myp = 0;
#pragma unroll
        for (int e = 0; e < NE; e++) {
            unsigned m = __ballot_sync(0xffffffff, e0 == e);
            if (e0 == e) myp = cnt[e] + __popc(m & lt);
            cnt[e] += __popc(m);
        }
        g_k0[tok] = (myp < CAP) ? 1 : 0;
        g_p0[tok] = min(myp, CAP - 1);
    }
    for (int ch = 0; ch < Sq / 32; ch++) {
        int tok = b * Sq + ch * 32 + lane;
        int e1 = g_i1[tok];
        bool valid = g_g1[tok] > 0.2f;
        int myp = 0;
#pragma unroll
        for (int e = 0; e < NE; e++) {
            unsigned m = __ballot_sync(0xffffffff, valid && (e1 == e));
            if (valid && (e1 == e)) myp = cnt[e] + __popc(m & lt);
            cnt[e] += __popc(m);
        }
        bool keep = valid && (myp < CAP);
        g_k1[tok] = keep ? 1 : 0;
        g_p1[tok] = valid ? min(myp, CAP - 1) : 0;
    }
}

// ---------------- scatter (x1 fp32 -> einh bf16) ----------------
__global__ __launch_bounds__(256) void scatter_kernel() {
    int idx = blockIdx.x;
    int tok = idx >> 1, slot = idx & 1;
    int keep = slot ? g_k1[tok] : g_k0[tok];
    if (!keep) return;
    int e = slot ? g_i1[tok] : g_i0[tok];
    int p = slot ? g_p1[tok] : g_p0[tok];
    int b = tok / Sq;
    const float4* src = (const float4*)(g_x1 + (size_t)tok * Dm);
    size_t ro = (((size_t)e * Bt + b) * CAP + p) * Dm;
    uint2* dh = (uint2*)(g_einh + ro);
    float4 v = src[threadIdx.x];
    uint2 hh;
    hh.x = packbf(v.x, v.y);
    hh.y = packbf(v.z, v.w);
    dh[threadIdx.x] = hh;
}

// ---------------- combine + LN2 ----------------
__global__ __launch_bounds__(256) void combine_ln_kernel(
    const float* __restrict__ g2, const float* __restrict__ b2,
    float* __restrict__ out)
{
    size_t tok = blockIdx.x;
    int t = threadIdx.x;
    int b = (int)(tok >> 10);
    float w0 = g_k0[tok] ? g_g0[tok] : 0.f;
    float w1 = g_k1[tok] ? g_g1[tok] : 0.f;
    const __nv_bfloat16* r0 = g_eoutb + (((size_t)g_i0[tok] * Bt + b) * CAP + g_p0[tok]) * Dm;
    const __nv_bfloat16* r1 = g_eoutb + (((size_t)g_i1[tok] * Bt + b) * CAP + g_p1[tok]) * Dm;

    float v[4], s = 0.f, s2 = 0.f;
#pragma unroll
    for (int u = 0; u < 4; u++) {
        int j = t + u * 256;
        float val = g_x1[tok * Dm + j]
                  + w0 * __bfloat162float(r0[j]) + w1 * __bfloat162float(r1[j]);
        v[u] = val; s += val; s2 += val * val;
    }
    block_reduce2(s, s2);
    float mean = s * (1.f / Dm);
    float var  = s2 * (1.f / Dm) - mean * mean;
    float inv  = rsqrtf(var + 1e-5f);
#pragma unroll
    for (int u = 0; u < 4; u++) {
        int j = t + u * 256;
        out[tok * Dm + j] = (v[u] - mean) * inv * g2[j] + b2[j];
    }
}

// ---------------- finalize aux ----------------
__global__ void finalize_kernel(float* __restrict__ out) {
    if (threadIdx.x == 0 && blockIdx.x == 0) {
        float invN = 1.f / (float)NT;
        float sfp = 0.f;
#pragma unroll
        for (int e = 0; e < NE; e++)
            sfp += (g_fcnt[e] * invN) * (g_Psum[e] * invN);
        float bal = 0.01f * (float)NE * sfp;
        float zl  = 0.001f * g_zsum * invN;
        out[NTD + 0] = bal + zl;
        out[NTD + 1] = bal;
        out[NTD + 2] = zl;
    }
}

// ---------------- host launcher ----------------
extern "C" void kernel_launch(void* const* d_in, const int* in_sizes, int n_in,
                              void* d_out, int out_size)
{
    const float* x      = (const float*)d_in[0];
    const float* Wq     = (const float*)d_in[1];
    const float* Wk     = (const float*)d_in[2];
    const float* Wv     = (const float*)d_in[3];
    const float* Wo     = (const float*)d_in[4];
    const float* bq     = (const float*)d_in[5];
    const float* bk     = (const float*)d_in[6];
    const float* bv     = (const float*)d_in[7];
    const float* bo     = (const float*)d_in[8];
    const float* ln1_g  = (const float*)d_in[9];
    const float* ln1_b  = (const float*)d_in[10];
    const float* ln2_g  = (const float*)d_in[11];
    const float* ln2_b  = (const float*)d_in[12];
    const float* gate_W = (const float*)d_in[13];
    const float* eWq    = (const float*)d_in[14];
    const float* eWk    = (const float*)d_in[15];
    const float* eWv    = (const float*)d_in[16];
    const float* eWo    = (const float*)d_in[17];
    float* out = (float*)d_out;

    void *pattn, *px1, *peoutb, *pxh, *pqkvh, *poh;
    void *peinh, *peqkv, *peoh;
    void *pwqkvh, *pwoh, *pewh, *pewoh, *pbqkv;
    cudaGetSymbolAddress(&pattn, g_attn);   cudaGetSymbolAddress(&px1, g_x1);
    cudaGetSymbolAddress(&peoutb, g_eoutb); cudaGetSymbolAddress(&pxh, g_xh);
    cudaGetSymbolAddress(&pqkvh, g_qkvh);   cudaGetSymbolAddress(&poh, g_oh);
    cudaGetSymbolAddress(&peinh, g_einh);   cudaGetSymbolAddress(&peqkv, g_eqkv);
    cudaGetSymbolAddress(&peoh, g_eoh);
    cudaGetSymbolAddress(&pwqkvh, g_wqkvh); cudaGetSymbolAddress(&pwoh, g_woh);
    cudaGetSymbolAddress(&pewh, g_ewh);     cudaGetSymbolAddress(&pewoh, g_ewoh);
    cudaGetSymbolAddress(&pbqkv, g_bqkv);

    cudaFuncSetAttribute(gemm_mma_kernel<0>, cudaFuncAttributeMaxDynamicSharedMemorySize, GEMM_SMEM);
    cudaFuncSetAttribute(gemm_mma_kernel<1>, cudaFuncAttributeMaxDynamicSharedMemorySize, GEMM_SMEM);
    cudaFuncSetAttribute(mflash_kernel, cudaFuncAttributeMaxDynamicSharedMemorySize, MF_SMEM);
    cudaFuncSetAttribute(eflash_kernel, cudaFuncAttributeMaxDynamicSharedMemorySize, EF_SMEM);

    zero_ein_kernel<<<2048, 256>>>();

    cudaMemcpyAsync((float*)pbqkv,          bq, Dm * sizeof(float), cudaMemcpyDeviceToDevice);
    cudaMemcpyAsync((float*)pbqkv + Dm,     bk, Dm * sizeof(float), cudaMemcpyDeviceToDevice);
    cudaMemcpyAsync((float*)pbqkv + 2 * Dm, bv, Dm * sizeof(float), cudaMemcpyDeviceToDevice);

    __nv_bfloat16* wqkv = (__nv_bfloat16*)pwqkvh;
    __nv_bfloat16* ewh  = (__nv_bfloat16*)pewh;
    const int WB1 = (int)(DMDM / 4);
    cvt4_kernel<<<dim3((WB1 + 1023) / 1024, 4), 256>>>(
        (const float4*)Wq, (const float4*)Wk, (const float4*)Wv, (const float4*)Wo,
        (uint2*)wqkv, (uint2*)(wqkv + DMDM), (uint2*)(wqkv + 2 * DMDM), (uint2*)pwoh, WB1);
    const int WBE = (int)(NE * DMDM / 4);
    cvt4_kernel<<<dim3((WBE + 1023) / 1024, 4), 256>>>(
        (const float4*)eWq, (const float4*)eWk, (const float4*)eWv, (const float4*)eWo,
        (uint2*)ewh, (uint2*)(ewh + NE * DMDM), (uint2*)(ewh + 2 * NE * DMDM), (uint2*)pewoh, WBE);

    cvt_kernel<<<(int)(NTD / 4 / 1024), 256>>>((const float4*)x, (uint2*)pxh, (int)(NTD / 4));

    gemm_mma_kernel<1><<<dim3(Dm / 128, NT / 128, 3), 256, GEMM_SMEM>>>(
        (__nv_bfloat16*)pxh, wqkv, (const float*)pbqkv, pqkvh,
        NT, Dm, Dm, 0, DMDM, NTD, Dm, 3);

    __nv_bfloat16* qkv = (__nv_bfloat16*)pqkvh;
    mflash_kernel<<<dim3(Sq / 64, Bt * NH), 256, MF_SMEM>>>(
        qkv, qkv + NTD, qkv + 2 * NTD, (__nv_bfloat16*)poh, 0.125f);

    gemm_mma_kernel<0><<<dim3(Dm / 128, NT / 128, 1), 256, GEMM_SMEM>>>(
        (__nv_bfloat16*)poh, (__nv_bfloat16*)pwoh, bo, pattn,
        NT, Dm, Dm, 0, 0, 0, 0, 1);

    ln1gate_kernel<<<NT, 256>>>(x, ln1_g, ln1_b, gate_W);
    pos_kernel<<<1, 256>>>();
    scatter_kernel<<<NT * 2, 256>>>();

    size_t sA = (size_t)EROWS * Dm;
    gemm_mma_kernel<1><<<dim3(Dm / 128, EROWS / 128, 24), 256, GEMM_SMEM>>>(
        (__nv_bfloat16*)peinh, ewh, nullptr, peqkv,
        EROWS, Dm, Dm, sA, DMDM, sA, 0, NE);

    __nv_bfloat16* eqkv = (__nv_bfloat16*)peqkv;
    eflash_kernel<<<dim3(CAP / 64, NE * Bt * NHM), 256, EF_SMEM>>>(
        eqkv, eqkv + EINSZ, eqkv + 2 * EINSZ, (__nv_bfloat16*)peoh, 0.0883883476483184f);

    gemm_mma_kernel<1><<<dim3(Dm / 128, EROWS / 128, NE), 256, GEMM_SMEM>>>(
        (__nv_bfloat16*)peoh, (__nv_bfloat16*)pewoh, nullptr, peoutb,
        EROWS, Dm, Dm, sA, DMDM, sA, 0, NE);

    combine_ln_kernel<<<NT, 256>>>(ln2_g, ln2_b, out);
    finalize_kernel<<<1, 32>>>(out);
}